// round 1
// baseline (speedup 1.0000x reference)
#include <cuda_runtime.h>
#include <cuda_bf16.h>
#include <cstdint>

// Problem constants
#define BATCH 4
#define SEQ   2048
#define DIM   1024
#define NHEAD 16
#define HDIM  64
#define FFDIM 4096
#define ROWS  (BATCH * SEQ)            // 8192
#define LN_EPS 1e-6f

// ---------------- scratch (device globals; no allocation) ----------------
__device__ float g_x  [(size_t)ROWS * DIM];
__device__ float g_h  [(size_t)ROWS * DIM];
__device__ float g_q  [(size_t)ROWS * DIM];
__device__ float g_k  [(size_t)ROWS * DIM];
__device__ float g_v  [(size_t)ROWS * DIM];
__device__ float g_ctx[(size_t)ROWS * DIM];
__device__ float g_f1 [(size_t)ROWS * FFDIM];
__device__ float g_f2 [(size_t)ROWS * FFDIM];

// ---------------- RMSNorm: one block per row of 1024 ----------------
__global__ void rmsnorm_kernel(const float* __restrict__ x,
                               const float* __restrict__ w,
                               float* __restrict__ out) {
    int row = blockIdx.x;
    const float* xr = x + (size_t)row * DIM;
    float s = 0.f;
    #pragma unroll
    for (int i = threadIdx.x; i < DIM; i += 256) {
        float v = xr[i];
        s += v * v;
    }
    __shared__ float red[8];
    #pragma unroll
    for (int o = 16; o; o >>= 1) s += __shfl_down_sync(0xffffffffu, s, o);
    if ((threadIdx.x & 31) == 0) red[threadIdx.x >> 5] = s;
    __syncthreads();
    if (threadIdx.x < 8) {
        float t = red[threadIdx.x];
        #pragma unroll
        for (int o = 4; o; o >>= 1) t += __shfl_down_sync(0xffu, t, o);
        if (threadIdx.x == 0) red[0] = t;
    }
    __syncthreads();
    float inv = rsqrtf(red[0] * (1.0f / DIM) + LN_EPS);
    float* orow = out + (size_t)row * DIM;
    #pragma unroll
    for (int i = threadIdx.x; i < DIM; i += 256)
        orow[i] = xr[i] * inv * w[i];
}

// ---------------- GEMM: C[M,N] = A[M,K] @ W[N,K]^T (+res)(+bias) --------
// BM=128, BN=64, BK=16, 256 threads, per-thread 8x4.
#define GBM 128
#define GBN 64
#define GBK 16
__global__ __launch_bounds__(256)
void gemm_kernel(const float* __restrict__ A, const float* __restrict__ W,
                 const float* __restrict__ res, const float* __restrict__ bias,
                 float* __restrict__ C, int M, int N, int K) {
    __shared__ float As[GBK][GBM];
    __shared__ float Ws[GBK][GBN];
    int tid = threadIdx.x;
    int tx = tid & 15, ty = tid >> 4;
    int bm = blockIdx.y * GBM, bn = blockIdx.x * GBN;

    const float* Ap = A + (size_t)bm * K;
    const float* Wp = W + (size_t)bn * K;

    int arow = tid >> 1, ak = (tid & 1) * 8;   // 128 rows x 16 k, 8 per thread
    int wrow = tid >> 2, wk = (tid & 3) * 4;   // 64 rows  x 16 k, 4 per thread

    float acc[8][4];
    #pragma unroll
    for (int i = 0; i < 8; i++)
        #pragma unroll
        for (int j = 0; j < 4; j++) acc[i][j] = 0.f;

    for (int k0 = 0; k0 < K; k0 += GBK) {
        float4 a0 = *(const float4*)(Ap + (size_t)arow * K + k0 + ak);
        float4 a1 = *(const float4*)(Ap + (size_t)arow * K + k0 + ak + 4);
        As[ak + 0][arow] = a0.x; As[ak + 1][arow] = a0.y;
        As[ak + 2][arow] = a0.z; As[ak + 3][arow] = a0.w;
        As[ak + 4][arow] = a1.x; As[ak + 5][arow] = a1.y;
        As[ak + 6][arow] = a1.z; As[ak + 7][arow] = a1.w;
        float4 w0 = *(const float4*)(Wp + (size_t)wrow * K + k0 + wk);
        Ws[wk + 0][wrow] = w0.x; Ws[wk + 1][wrow] = w0.y;
        Ws[wk + 2][wrow] = w0.z; Ws[wk + 3][wrow] = w0.w;
        __syncthreads();

        #pragma unroll
        for (int kk = 0; kk < GBK; kk++) {
            float4 a04 = *(const float4*)(&As[kk][ty * 8]);
            float4 a14 = *(const float4*)(&As[kk][ty * 8 + 4]);
            float4 b4  = *(const float4*)(&Ws[kk][tx * 4]);
            float a[8] = {a04.x, a04.y, a04.z, a04.w, a14.x, a14.y, a14.z, a14.w};
            float b[4] = {b4.x, b4.y, b4.z, b4.w};
            #pragma unroll
            for (int i = 0; i < 8; i++)
                #pragma unroll
                for (int j = 0; j < 4; j++)
                    acc[i][j] = fmaf(a[i], b[j], acc[i][j]);
        }
        __syncthreads();
    }

    #pragma unroll
    for (int i = 0; i < 8; i++) {
        int m = bm + ty * 8 + i;
        #pragma unroll
        for (int j = 0; j < 4; j++) {
            int n = bn + tx * 4 + j;
            float v = acc[i][j];
            if (res)  v += res[(size_t)m * N + n];
            if (bias) v += bias[n];
            C[(size_t)m * N + n] = v;
        }
    }
}

// ---------------- RoPE (in-place on [B,S,H,HD]) ----------------
__global__ void rope_kernel(float* __restrict__ X) {
    int idx = blockIdx.x * 256 + threadIdx.x;          // B*S*H*32 total
    if (idx >= BATCH * SEQ * NHEAD * (HDIM / 2)) return;
    int d = idx & 31;
    int h = (idx >> 5) & (NHEAD - 1);
    int s = (idx >> 9) & (SEQ - 1);
    int b = idx >> 20;
    size_t base = (((size_t)b * SEQ + s) * NHEAD + h) * HDIM;
    // inv = 10000^(-d/32)
    float inv = expf(-(float)d * (9.210340371976184f / 32.f));
    float ang = (float)s * inv;
    float sn, cs;
    sincosf(ang, &sn, &cs);
    float x1 = X[base + d];
    float x2 = X[base + d + 32];
    X[base + d]      = x1 * cs - x2 * sn;
    X[base + d + 32] = x2 * cs + x1 * sn;
}

// ---------------- Flash attention (full/non-causal), HD=64 ----------------
// One block = (b, h, 64 queries); one thread = one query (q, acc in regs).
__global__ __launch_bounds__(64)
void attn_kernel(const float* __restrict__ Q, const float* __restrict__ Kg,
                 const float* __restrict__ Vg, float* __restrict__ O) {
    __shared__ float Ks[64][64];
    __shared__ float Vs[64][64];
    int tid = threadIdx.x;
    int b = blockIdx.z, h = blockIdx.y;
    int qs = blockIdx.x * 64 + tid;
    size_t qoff = (((size_t)b * SEQ + qs) * NHEAD + h) * HDIM;

    float q[64], acc[64];
    #pragma unroll
    for (int d = 0; d < 64; d++) { q[d] = Q[qoff + d]; acc[d] = 0.f; }
    float m = -1e30f, l = 0.f;
    const float scale = 0.125f;  // 1/sqrt(64)

    for (int kt = 0; kt < SEQ; kt += 64) {
        for (int idx = tid; idx < 64 * 64; idx += 64) {
            int r = idx >> 6, c = idx & 63;
            size_t off = (((size_t)b * SEQ + kt + r) * NHEAD + h) * HDIM + c;
            Ks[r][c] = Kg[off];
            Vs[r][c] = Vg[off];
        }
        __syncthreads();

        for (int j0 = 0; j0 < 64; j0 += 8) {
            float sc[8];
            float mt = m;
            #pragma unroll
            for (int jj = 0; jj < 8; jj++) {
                const float4* kr = (const float4*)(&Ks[j0 + jj][0]);
                float s = 0.f;
                #pragma unroll
                for (int d4 = 0; d4 < 16; d4++) {
                    float4 kv = kr[d4];
                    s = fmaf(q[d4 * 4 + 0], kv.x, s);
                    s = fmaf(q[d4 * 4 + 1], kv.y, s);
                    s = fmaf(q[d4 * 4 + 2], kv.z, s);
                    s = fmaf(q[d4 * 4 + 3], kv.w, s);
                }
                s *= scale;
                sc[jj] = s;
                mt = fmaxf(mt, s);
            }
            float corr = __expf(m - mt);
            l *= corr;
            #pragma unroll
            for (int d = 0; d < 64; d++) acc[d] *= corr;
            #pragma unroll
            for (int jj = 0; jj < 8; jj++) {
                float p = __expf(sc[jj] - mt);
                l += p;
                const float4* vr = (const float4*)(&Vs[j0 + jj][0]);
                #pragma unroll
                for (int d4 = 0; d4 < 16; d4++) {
                    float4 vv = vr[d4];
                    acc[d4 * 4 + 0] = fmaf(p, vv.x, acc[d4 * 4 + 0]);
                    acc[d4 * 4 + 1] = fmaf(p, vv.y, acc[d4 * 4 + 1]);
                    acc[d4 * 4 + 2] = fmaf(p, vv.z, acc[d4 * 4 + 2]);
                    acc[d4 * 4 + 3] = fmaf(p, vv.w, acc[d4 * 4 + 3]);
                }
            }
            m = mt;
        }
        __syncthreads();
    }
    float invl = 1.f / l;
    #pragma unroll
    for (int d = 0; d < 64; d++) O[qoff + d] = acc[d] * invl;
}

// ---------------- SwiGLU combine: g = silu(g) * u ----------------
__global__ void silu_mul_kernel(float* __restrict__ g, const float* __restrict__ u,
                                size_t n) {
    size_t i = (size_t)blockIdx.x * 256 + threadIdx.x;
    if (i < n) {
        float x = g[i];
        g[i] = (x / (1.f + expf(-x))) * u[i];
    }
}

// ---------------- launch ----------------
extern "C" void kernel_launch(void* const* d_in, const int* in_sizes, int n_in,
                              void* d_out, int out_size) {
    const float* x_in   = (const float*)d_in[0];
    const float* Wq     = (const float*)d_in[1];
    const float* Wk     = (const float*)d_in[2];
    const float* Wv     = (const float*)d_in[3];
    const float* Wo     = (const float*)d_in[4];
    const float* ln1_w  = (const float*)d_in[5];
    const float* ln2_w  = (const float*)d_in[6];
    const float* Wgate  = (const float*)d_in[7];
    const float* Wup    = (const float*)d_in[8];
    const float* Wdown  = (const float*)d_in[9];
    const float* W_out  = (const float*)d_in[10];
    const float* b_out  = (const float*)d_in[11];
    float* out = (float*)d_out;

    float *x, *h, *q, *k, *v, *ctx, *f1, *f2;
    cudaGetSymbolAddress((void**)&x,   g_x);
    cudaGetSymbolAddress((void**)&h,   g_h);
    cudaGetSymbolAddress((void**)&q,   g_q);
    cudaGetSymbolAddress((void**)&k,   g_k);
    cudaGetSymbolAddress((void**)&v,   g_v);
    cudaGetSymbolAddress((void**)&ctx, g_ctx);
    cudaGetSymbolAddress((void**)&f1,  g_f1);
    cudaGetSymbolAddress((void**)&f2,  g_f2);

    const size_t xbytes = (size_t)ROWS * DIM * sizeof(float);
    cudaMemcpyAsync(x, x_in, xbytes, cudaMemcpyDeviceToDevice);

    // --- attention block ---
    rmsnorm_kernel<<<ROWS, 256>>>(x, ln1_w, h);

    dim3 gq(DIM / GBN, ROWS / GBM);   // (16, 64)
    gemm_kernel<<<gq, 256>>>(h, Wq, nullptr, nullptr, q, ROWS, DIM, DIM);
    gemm_kernel<<<gq, 256>>>(h, Wk, nullptr, nullptr, k, ROWS, DIM, DIM);
    gemm_kernel<<<gq, 256>>>(h, Wv, nullptr, nullptr, v, ROWS, DIM, DIM);

    int rope_total = BATCH * SEQ * NHEAD * (HDIM / 2);
    rope_kernel<<<(rope_total + 255) / 256, 256>>>(q);
    rope_kernel<<<(rope_total + 255) / 256, 256>>>(k);

    dim3 ga(SEQ / 64, NHEAD, BATCH);  // (32, 16, 4)
    attn_kernel<<<ga, 64>>>(q, k, v, ctx);

    // x = x + ctx @ Wo^T (residual in-place: each element read-then-written by same thread)
    gemm_kernel<<<gq, 256>>>(ctx, Wo, x, nullptr, x, ROWS, DIM, DIM);

    // --- MLP block ---
    rmsnorm_kernel<<<ROWS, 256>>>(x, ln2_w, h);
    dim3 gf(FFDIM / GBN, ROWS / GBM); // (64, 64)
    gemm_kernel<<<gf, 256>>>(h, Wgate, nullptr, nullptr, f1, ROWS, FFDIM, DIM);
    gemm_kernel<<<gf, 256>>>(h, Wup,   nullptr, nullptr, f2, ROWS, FFDIM, DIM);

    size_t ffn = (size_t)ROWS * FFDIM;
    silu_mul_kernel<<<(unsigned)((ffn + 255) / 256), 256>>>(f1, f2, ffn);

    gemm_kernel<<<gq, 256>>>(f1, Wdown, x, nullptr, x, ROWS, DIM, FFDIM);

    // --- output head ---
    gemm_kernel<<<gq, 256>>>(x, W_out, nullptr, b_out, out, ROWS, DIM, DIM);
}

// round 3
// speedup vs baseline: 1.7063x; 1.7063x over previous
#include <cuda_runtime.h>
#include <cuda_bf16.h>
#include <cstdint>

// Problem constants
#define BATCH 4
#define SEQ   2048
#define DIM   1024
#define NHEAD 16
#define HDIM  64
#define FFDIM 4096
#define ROWS  (BATCH * SEQ)            // 8192
#define LN_EPS 1e-6f

// ---------------- scratch (device globals; no allocation) ----------------
__device__ float g_x  [(size_t)ROWS * DIM];
__device__ float g_h  [(size_t)ROWS * DIM];
__device__ float g_q  [(size_t)ROWS * DIM];
__device__ float g_k  [(size_t)ROWS * DIM];
__device__ float g_v  [(size_t)ROWS * DIM];
__device__ float g_ctx[(size_t)ROWS * DIM];
__device__ float g_f1 [(size_t)ROWS * FFDIM];
__device__ float g_f2 [(size_t)ROWS * FFDIM];

__device__ __forceinline__ uint32_t smem_u32(const void* p) {
    uint32_t a;
    asm("{ .reg .u64 t; cvta.to.shared.u64 t, %1; cvt.u32.u64 %0, t; }"
        : "=r"(a) : "l"(p));
    return a;
}

// fp32x4 -> bf16 hi/lo x4
__device__ __forceinline__ void cvt_hilo4(float4 v, uint2& hi, uint2& lo) {
    __nv_bfloat162 h01, h23, l01, l23;
    h01.x = __float2bfloat16_rn(v.x);
    h01.y = __float2bfloat16_rn(v.y);
    h23.x = __float2bfloat16_rn(v.z);
    h23.y = __float2bfloat16_rn(v.w);
    l01.x = __float2bfloat16_rn(v.x - __bfloat162float(h01.x));
    l01.y = __float2bfloat16_rn(v.y - __bfloat162float(h01.y));
    l23.x = __float2bfloat16_rn(v.z - __bfloat162float(h23.x));
    l23.y = __float2bfloat16_rn(v.w - __bfloat162float(h23.y));
    hi.x = *(uint32_t*)&h01; hi.y = *(uint32_t*)&h23;
    lo.x = *(uint32_t*)&l01; lo.y = *(uint32_t*)&l23;
}

__device__ __forceinline__ void ldmx4(uint32_t addr, uint32_t& r0, uint32_t& r1,
                                      uint32_t& r2, uint32_t& r3) {
    asm volatile("ldmatrix.sync.aligned.m8n8.x4.shared.b16 {%0,%1,%2,%3}, [%4];"
                 : "=r"(r0), "=r"(r1), "=r"(r2), "=r"(r3) : "r"(addr));
}
__device__ __forceinline__ void mma16816(float* c, uint32_t a0, uint32_t a1,
                                         uint32_t a2, uint32_t a3,
                                         uint32_t b0, uint32_t b1) {
    asm volatile(
        "mma.sync.aligned.m16n8k16.row.col.f32.bf16.bf16.f32 "
        "{%0,%1,%2,%3}, {%4,%5,%6,%7}, {%8,%9}, {%0,%1,%2,%3};"
        : "+f"(c[0]), "+f"(c[1]), "+f"(c[2]), "+f"(c[3])
        : "r"(a0), "r"(a1), "r"(a2), "r"(a3), "r"(b0), "r"(b1));
}

// ================= warp-MMA GEMM: C[M,N] = A[M,K] @ W[N,K]^T (+res)(+bias)
// CTA 128x128, BK=32 bf16, hi/lo 3-term split, double-buffered smem.
#define TBM 128
#define TBN 128
#define TBK 32
#define ROWB 80                       // smem row stride in bytes (40 bf16)
#define OFF_ALO  10240                // 128*80
#define OFF_WHI  20480
#define OFF_WLO  30720
#define STAGE    40960
#define GSMEM    (2 * STAGE)

__global__ __launch_bounds__(256)
void gemm_mma(const float* __restrict__ A, const float* __restrict__ W,
              const float* __restrict__ res, const float* __restrict__ bias,
              float* __restrict__ C, int M, int N, int K) {
    extern __shared__ char smem[];
    uint32_t sb = smem_u32(smem);
    int tid = threadIdx.x, wid = tid >> 5, lane = tid & 31;
    int bm = blockIdx.y * TBM;
    int bn = blockIdx.x * TBN;

    int warp_m = (wid >> 2) * 64;     // 0 or 64
    int warp_n = (wid & 3) * 32;      // 0,32,64,96

    // per-thread ldmatrix base offsets (within a stage)
    uint32_t a_base = (uint32_t)(warp_m + (lane & 15)) * ROWB + ((lane >> 4) & 1) * 16;
    uint32_t b_row  = (uint32_t)(warp_n + (lane & 7) + ((lane >> 4) & 1) * 8);
    uint32_t b_base = b_row * ROWB + ((lane >> 3) & 1) * 16;

    // load mapping: item f -> row=f>>3, c4=f&7 (8 float4 per 32-elem row)
    int lrow = tid >> 1;                 // unused helper removed below
    (void)lrow;

    float acc[4][4][4];
    #pragma unroll
    for (int i = 0; i < 4; i++)
        #pragma unroll
        for (int j = 0; j < 4; j++)
            #pragma unroll
            for (int r = 0; r < 4; r++) acc[i][j][r] = 0.f;

    const int nk = K / TBK;

    // ---- load chunk 0 into stage 0 ----
    {
        char* stg = smem;
        #pragma unroll
        for (int j = 0; j < 4; j++) {
            int f = tid + j * 256;
            int r = f >> 3, c4 = f & 7;
            float4 v = *(const float4*)(A + (size_t)(bm + r) * K + c4 * 4);
            uint2 hi, lo; cvt_hilo4(v, hi, lo);
            uint32_t so = (uint32_t)(r * ROWB + c4 * 8);
            *(uint2*)(stg + so)           = hi;
            *(uint2*)(stg + OFF_ALO + so) = lo;
        }
        #pragma unroll
        for (int j = 0; j < 4; j++) {
            int f = tid + j * 256;
            int r = f >> 3, c4 = f & 7;
            float4 v = *(const float4*)(W + (size_t)(bn + r) * K + c4 * 4);
            uint2 hi, lo; cvt_hilo4(v, hi, lo);
            uint32_t so = (uint32_t)(r * ROWB + c4 * 8);
            *(uint2*)(stg + OFF_WHI + so) = hi;
            *(uint2*)(stg + OFF_WLO + so) = lo;
        }
    }
    __syncthreads();

    for (int i = 0; i < nk; i++) {
        int cur = i & 1;
        uint32_t stg = sb + cur * STAGE;

        // ---- prefetch next chunk into registers ----
        float4 va[4], vw[4];
        if (i + 1 < nk) {
            int k0 = (i + 1) * TBK;
            #pragma unroll
            for (int j = 0; j < 4; j++) {
                int f = tid + j * 256;
                int r = f >> 3, c4 = f & 7;
                va[j] = *(const float4*)(A + (size_t)(bm + r) * K + k0 + c4 * 4);
                vw[j] = *(const float4*)(W + (size_t)(bn + r) * K + k0 + c4 * 4);
            }
        }

        // ---- MMA on current stage ----
        #pragma unroll
        for (int ks = 0; ks < 2; ks++) {
            uint32_t ahr[4][4], alr[4][4];
            #pragma unroll
            for (int mf = 0; mf < 4; mf++) {
                uint32_t ad = stg + a_base + (uint32_t)mf * (16 * ROWB) + ks * 32;
                ldmx4(ad, ahr[mf][0], ahr[mf][1], ahr[mf][2], ahr[mf][3]);
                ldmx4(ad + OFF_ALO, alr[mf][0], alr[mf][1], alr[mf][2], alr[mf][3]);
            }
            uint32_t bhr[2][4], blr[2][4];
            #pragma unroll
            for (int np = 0; np < 2; np++) {
                uint32_t bd = stg + OFF_WHI + b_base + (uint32_t)np * (16 * ROWB) + ks * 32;
                ldmx4(bd, bhr[np][0], bhr[np][1], bhr[np][2], bhr[np][3]);
                ldmx4(bd + OFF_ALO, blr[np][0], blr[np][1], blr[np][2], blr[np][3]);
            }
            #pragma unroll
            for (int mf = 0; mf < 4; mf++) {
                #pragma unroll
                for (int nf = 0; nf < 4; nf++) {
                    uint32_t bh0 = bhr[nf >> 1][(nf & 1) * 2];
                    uint32_t bh1 = bhr[nf >> 1][(nf & 1) * 2 + 1];
                    uint32_t bl0 = blr[nf >> 1][(nf & 1) * 2];
                    uint32_t bl1 = blr[nf >> 1][(nf & 1) * 2 + 1];
                    mma16816(acc[mf][nf], ahr[mf][0], ahr[mf][1], ahr[mf][2], ahr[mf][3], bh0, bh1);
                    mma16816(acc[mf][nf], ahr[mf][0], ahr[mf][1], ahr[mf][2], ahr[mf][3], bl0, bl1);
                    mma16816(acc[mf][nf], alr[mf][0], alr[mf][1], alr[mf][2], alr[mf][3], bh0, bh1);
                }
            }
        }

        // ---- convert + store next chunk ----
        if (i + 1 < nk) {
            char* stn = smem + (cur ^ 1) * STAGE;
            #pragma unroll
            for (int j = 0; j < 4; j++) {
                int f = tid + j * 256;
                int r = f >> 3, c4 = f & 7;
                uint32_t so = (uint32_t)(r * ROWB + c4 * 8);
                uint2 hi, lo;
                cvt_hilo4(va[j], hi, lo);
                *(uint2*)(stn + so)           = hi;
                *(uint2*)(stn + OFF_ALO + so) = lo;
                cvt_hilo4(vw[j], hi, lo);
                *(uint2*)(stn + OFF_WHI + so) = hi;
                *(uint2*)(stn + OFF_WLO + so) = lo;
            }
        }
        __syncthreads();
    }

    // ---- epilogue ----
    int tr = lane >> 2, tc = (lane & 3) * 2;
    #pragma unroll
    for (int mf = 0; mf < 4; mf++) {
        #pragma unroll
        for (int nf = 0; nf < 4; nf++) {
            int row0 = bm + warp_m + mf * 16 + tr;
            int col  = bn + warp_n + nf * 8 + tc;
            float* c = acc[mf][nf];
            float2 v0 = {c[0], c[1]};
            float2 v1 = {c[2], c[3]};
            size_t o0 = (size_t)row0 * N + col;
            size_t o1 = (size_t)(row0 + 8) * N + col;
            if (res) {
                float2 r0 = *(const float2*)(res + o0);
                float2 r1 = *(const float2*)(res + o1);
                v0.x += r0.x; v0.y += r0.y; v1.x += r1.x; v1.y += r1.y;
            }
            if (bias) {
                float2 bb = *(const float2*)(bias + col);
                v0.x += bb.x; v0.y += bb.y; v1.x += bb.x; v1.y += bb.y;
            }
            *(float2*)(C + o0) = v0;
            *(float2*)(C + o1) = v1;
        }
    }
}

// ---------------- RMSNorm: one block per row of 1024 ----------------
__global__ void rmsnorm_kernel(const float* __restrict__ x,
                               const float* __restrict__ w,
                               float* __restrict__ out) {
    int row = blockIdx.x;
    const float* xr = x + (size_t)row * DIM;
    float s = 0.f;
    #pragma unroll
    for (int i = threadIdx.x; i < DIM; i += 256) {
        float v = xr[i];
        s += v * v;
    }
    __shared__ float red[8];
    #pragma unroll
    for (int o = 16; o; o >>= 1) s += __shfl_down_sync(0xffffffffu, s, o);
    if ((threadIdx.x & 31) == 0) red[threadIdx.x >> 5] = s;
    __syncthreads();
    if (threadIdx.x < 8) {
        float t = red[threadIdx.x];
        #pragma unroll
        for (int o = 4; o; o >>= 1) t += __shfl_down_sync(0xffu, t, o);
        if (threadIdx.x == 0) red[0] = t;
    }
    __syncthreads();
    float inv = rsqrtf(red[0] * (1.0f / DIM) + LN_EPS);
    float* orow = out + (size_t)row * DIM;
    #pragma unroll
    for (int i = threadIdx.x; i < DIM; i += 256)
        orow[i] = xr[i] * inv * w[i];
}

// ---------------- RoPE (in-place on [B,S,H,HD]) ----------------
__global__ void rope_kernel(float* __restrict__ X) {
    int idx = blockIdx.x * 256 + threadIdx.x;
    if (idx >= BATCH * SEQ * NHEAD * (HDIM / 2)) return;
    int d = idx & 31;
    int h = (idx >> 5) & (NHEAD - 1);
    int s = (idx >> 9) & (SEQ - 1);
    int b = idx >> 20;
    size_t base = (((size_t)b * SEQ + s) * NHEAD + h) * HDIM;
    float inv = expf(-(float)d * (9.210340371976184f / 32.f));
    float ang = (float)s * inv;
    float sn, cs;
    sincosf(ang, &sn, &cs);
    float x1 = X[base + d];
    float x2 = X[base + d + 32];
    X[base + d]      = x1 * cs - x2 * sn;
    X[base + d + 32] = x2 * cs + x1 * sn;
}

// ---------------- Flash attention (full/non-causal), HD=64 ----------------
__global__ __launch_bounds__(64)
void attn_kernel(const float* __restrict__ Q, const float* __restrict__ Kg,
                 const float* __restrict__ Vg, float* __restrict__ O) {
    __shared__ float Ks[64][64];
    __shared__ float Vs[64][64];
    int tid = threadIdx.x;
    int b = blockIdx.z, h = blockIdx.y;
    int qs = blockIdx.x * 64 + tid;
    size_t qoff = (((size_t)b * SEQ + qs) * NHEAD + h) * HDIM;

    float q[64], acc[64];
    #pragma unroll
    for (int d = 0; d < 64; d++) { q[d] = Q[qoff + d]; acc[d] = 0.f; }
    float m = -1e30f, l = 0.f;
    const float scale = 0.125f;

    for (int kt = 0; kt < SEQ; kt += 64) {
        for (int idx = tid; idx < 64 * 64; idx += 64) {
            int r = idx >> 6, c = idx & 63;
            size_t off = (((size_t)b * SEQ + kt + r) * NHEAD + h) * HDIM + c;
            Ks[r][c] = Kg[off];
            Vs[r][c] = Vg[off];
        }
        __syncthreads();

        for (int j0 = 0; j0 < 64; j0 += 8) {
            float sc[8];
            float mt = m;
            #pragma unroll
            for (int jj = 0; jj < 8; jj++) {
                const float4* kr = (const float4*)(&Ks[j0 + jj][0]);
                float s = 0.f;
                #pragma unroll
                for (int d4 = 0; d4 < 16; d4++) {
                    float4 kv = kr[d4];
                    s = fmaf(q[d4 * 4 + 0], kv.x, s);
                    s = fmaf(q[d4 * 4 + 1], kv.y, s);
                    s = fmaf(q[d4 * 4 + 2], kv.z, s);
                    s = fmaf(q[d4 * 4 + 3], kv.w, s);
                }
                s *= scale;
                sc[jj] = s;
                mt = fmaxf(mt, s);
            }
            float corr = __expf(m - mt);
            l *= corr;
            #pragma unroll
            for (int d = 0; d < 64; d++) acc[d] *= corr;
            #pragma unroll
            for (int jj = 0; jj < 8; jj++) {
                float p = __expf(sc[jj] - mt);
                l += p;
                const float4* vr = (const float4*)(&Vs[j0 + jj][0]);
                #pragma unroll
                for (int d4 = 0; d4 < 16; d4++) {
                    float4 vv = vr[d4];
                    acc[d4 * 4 + 0] = fmaf(p, vv.x, acc[d4 * 4 + 0]);
                    acc[d4 * 4 + 1] = fmaf(p, vv.y, acc[d4 * 4 + 1]);
                    acc[d4 * 4 + 2] = fmaf(p, vv.z, acc[d4 * 4 + 2]);
                    acc[d4 * 4 + 3] = fmaf(p, vv.w, acc[d4 * 4 + 3]);
                }
            }
            m = mt;
        }
        __syncthreads();
    }
    float invl = 1.f / l;
    #pragma unroll
    for (int d = 0; d < 64; d++) O[qoff + d] = acc[d] * invl;
}

// ---------------- SwiGLU combine ----------------
__global__ void silu_mul_kernel(float* __restrict__ g, const float* __restrict__ u,
                                size_t n) {
    size_t i = (size_t)blockIdx.x * 256 + threadIdx.x;
    if (i < n) {
        float x = g[i];
        g[i] = (x / (1.f + expf(-x))) * u[i];
    }
}

// ---------------- launch ----------------
extern "C" void kernel_launch(void* const* d_in, const int* in_sizes, int n_in,
                              void* d_out, int out_size) {
    const float* x_in   = (const float*)d_in[0];
    const float* Wq     = (const float*)d_in[1];
    const float* Wk     = (const float*)d_in[2];
    const float* Wv     = (const float*)d_in[3];
    const float* Wo     = (const float*)d_in[4];
    const float* ln1_w  = (const float*)d_in[5];
    const float* ln2_w  = (const float*)d_in[6];
    const float* Wgate  = (const float*)d_in[7];
    const float* Wup    = (const float*)d_in[8];
    const float* Wdown  = (const float*)d_in[9];
    const float* W_out  = (const float*)d_in[10];
    const float* b_out  = (const float*)d_in[11];
    float* out = (float*)d_out;

    float *x, *h, *q, *k, *v, *ctx, *f1, *f2;
    cudaGetSymbolAddress((void**)&x,   g_x);
    cudaGetSymbolAddress((void**)&h,   g_h);
    cudaGetSymbolAddress((void**)&q,   g_q);
    cudaGetSymbolAddress((void**)&k,   g_k);
    cudaGetSymbolAddress((void**)&v,   g_v);
    cudaGetSymbolAddress((void**)&ctx, g_ctx);
    cudaGetSymbolAddress((void**)&f1,  g_f1);
    cudaGetSymbolAddress((void**)&f2,  g_f2);

    cudaFuncSetAttribute(gemm_mma, cudaFuncAttributeMaxDynamicSharedMemorySize, GSMEM);

    const size_t xbytes = (size_t)ROWS * DIM * sizeof(float);
    cudaMemcpyAsync(x, x_in, xbytes, cudaMemcpyDeviceToDevice);

    // --- attention block ---
    rmsnorm_kernel<<<ROWS, 256>>>(x, ln1_w, h);

    dim3 g1(DIM / TBN, ROWS / TBM);    // (8, 64)
    dim3 g2(FFDIM / TBN, ROWS / TBM);  // (32, 64)

    gemm_mma<<<g1, 256, GSMEM>>>(h, Wq, nullptr, nullptr, q, ROWS, DIM, DIM);
    gemm_mma<<<g1, 256, GSMEM>>>(h, Wk, nullptr, nullptr, k, ROWS, DIM, DIM);
    gemm_mma<<<g1, 256, GSMEM>>>(h, Wv, nullptr, nullptr, v, ROWS, DIM, DIM);

    int rope_total = BATCH * SEQ * NHEAD * (HDIM / 2);
    rope_kernel<<<(rope_total + 255) / 256, 256>>>(q);
    rope_kernel<<<(rope_total + 255) / 256, 256>>>(k);

    dim3 ga(SEQ / 64, NHEAD, BATCH);
    attn_kernel<<<ga, 64>>>(q, k, v, ctx);

    gemm_mma<<<g1, 256, GSMEM>>>(ctx, Wo, x, nullptr, x, ROWS, DIM, DIM);

    // --- MLP block ---
    rmsnorm_kernel<<<ROWS, 256>>>(x, ln2_w, h);
    gemm_mma<<<g2, 256, GSMEM>>>(h, Wgate, nullptr, nullptr, f1, ROWS, FFDIM, DIM);
    gemm_mma<<<g2, 256, GSMEM>>>(h, Wup,   nullptr, nullptr, f2, ROWS, FFDIM, DIM);

    size_t ffn = (size_t)ROWS * FFDIM;
    silu_mul_kernel<<<(unsigned)((ffn + 255) / 256), 256>>>(f1, f2, ffn);

    gemm_mma<<<g1, 256, GSMEM>>>(f1, Wdown, x, nullptr, x, ROWS, DIM, FFDIM);

    // --- output head ---
    gemm_mma<<<g1, 256, GSMEM>>>(x, W_out, nullptr, b_out, out, ROWS, DIM, DIM);
}

// round 5
// speedup vs baseline: 2.9274x; 1.7157x over previous
#include <cuda_runtime.h>
#include <cuda_bf16.h>
#include <cstdint>

// Problem constants
#define BATCH 4
#define SEQ   2048
#define DIM   1024
#define NHEAD 16
#define HDIM  64
#define FFDIM 4096
#define ROWS  (BATCH * SEQ)            // 8192
#define LN_EPS 1e-6f

// ---------------- scratch (device globals; no allocation) ----------------
__device__ float g_x  [(size_t)ROWS * DIM];
__device__ float g_h  [(size_t)ROWS * DIM];
__device__ float g_q  [(size_t)ROWS * DIM];
__device__ float g_k  [(size_t)ROWS * DIM];
__device__ float g_v  [(size_t)ROWS * DIM];
__device__ float g_ctx[(size_t)ROWS * DIM];
__device__ float g_f1 [(size_t)ROWS * FFDIM];
__device__ float g_f2 [(size_t)ROWS * FFDIM];
// bf16 attention operands, [B,H,S,HD] layout
__device__ __nv_bfloat16 g_qhi[(size_t)ROWS * DIM];
__device__ __nv_bfloat16 g_qlo[(size_t)ROWS * DIM];
__device__ __nv_bfloat16 g_khi[(size_t)ROWS * DIM];
__device__ __nv_bfloat16 g_klo[(size_t)ROWS * DIM];
__device__ __nv_bfloat16 g_vb [(size_t)ROWS * DIM];

__device__ __forceinline__ uint32_t smem_u32(const void* p) {
    uint32_t a;
    asm("{ .reg .u64 t; cvta.to.shared.u64 t, %1; cvt.u32.u64 %0, t; }"
        : "=r"(a) : "l"(p));
    return a;
}

// fp32x4 -> bf16 hi/lo x4
__device__ __forceinline__ void cvt_hilo4(float4 v, uint2& hi, uint2& lo) {
    __nv_bfloat162 h01, h23, l01, l23;
    h01.x = __float2bfloat16_rn(v.x);
    h01.y = __float2bfloat16_rn(v.y);
    h23.x = __float2bfloat16_rn(v.z);
    h23.y = __float2bfloat16_rn(v.w);
    l01.x = __float2bfloat16_rn(v.x - __bfloat162float(h01.x));
    l01.y = __float2bfloat16_rn(v.y - __bfloat162float(h01.y));
    l23.x = __float2bfloat16_rn(v.z - __bfloat162float(h23.x));
    l23.y = __float2bfloat16_rn(v.w - __bfloat162float(h23.y));
    hi.x = *(uint32_t*)&h01; hi.y = *(uint32_t*)&h23;
    lo.x = *(uint32_t*)&l01; lo.y = *(uint32_t*)&l23;
}

__device__ __forceinline__ void ldmx4(uint32_t addr, uint32_t& r0, uint32_t& r1,
                                      uint32_t& r2, uint32_t& r3) {
    asm volatile("ldmatrix.sync.aligned.m8n8.x4.shared.b16 {%0,%1,%2,%3}, [%4];"
                 : "=r"(r0), "=r"(r1), "=r"(r2), "=r"(r3) : "r"(addr));
}
__device__ __forceinline__ void ldmx4t(uint32_t addr, uint32_t& r0, uint32_t& r1,
                                       uint32_t& r2, uint32_t& r3) {
    asm volatile("ldmatrix.sync.aligned.m8n8.x4.trans.shared.b16 {%0,%1,%2,%3}, [%4];"
                 : "=r"(r0), "=r"(r1), "=r"(r2), "=r"(r3) : "r"(addr));
}
__device__ __forceinline__ void mma16816(float* c, uint32_t a0, uint32_t a1,
                                         uint32_t a2, uint32_t a3,
                                         uint32_t b0, uint32_t b1) {
    asm volatile(
        "mma.sync.aligned.m16n8k16.row.col.f32.bf16.bf16.f32 "
        "{%0,%1,%2,%3}, {%4,%5,%6,%7}, {%8,%9}, {%0,%1,%2,%3};"
        : "+f"(c[0]), "+f"(c[1]), "+f"(c[2]), "+f"(c[3])
        : "r"(a0), "r"(a1), "r"(a2), "r"(a3), "r"(b0), "r"(b1));
}
__device__ __forceinline__ float ex2f(float x) {
    float r;
    asm("ex2.approx.f32 %0, %1;" : "=f"(r) : "f"(x));
    return r;
}

#define CPA16(dst, src) \
    asm volatile("cp.async.cg.shared.global [%0], [%1], 16;" :: "r"(dst), "l"(src))
#define CPA_COMMIT() asm volatile("cp.async.commit_group;" ::: "memory")
#define CPA_WAIT(n)  asm volatile("cp.async.wait_group %0;" :: "n"(n) : "memory")

// ================= warp-MMA GEMM: C[M,N] = A[M,K] @ W[N,K]^T (+res)(+bias)
#define TBM 128
#define TBN 128
#define TBK 32
#define ROWB 80
#define OFF_ALO  10240
#define OFF_WHI  20480
#define OFF_WLO  30720
#define STAGE    40960
#define GSMEM    (2 * STAGE)

__global__ __launch_bounds__(256)
void gemm_mma(const float* __restrict__ A, const float* __restrict__ W,
              const float* __restrict__ res, const float* __restrict__ bias,
              float* __restrict__ C, int M, int N, int K) {
    extern __shared__ char smem[];
    uint32_t sb = smem_u32(smem);
    int tid = threadIdx.x, wid = tid >> 5, lane = tid & 31;
    int bm = blockIdx.y * TBM;
    int bn = blockIdx.x * TBN;

    int warp_m = (wid >> 2) * 64;
    int warp_n = (wid & 3) * 32;

    uint32_t a_base = (uint32_t)(warp_m + (lane & 15)) * ROWB + ((lane >> 4) & 1) * 16;
    uint32_t b_row  = (uint32_t)(warp_n + (lane & 7) + ((lane >> 4) & 1) * 8);
    uint32_t b_base = b_row * ROWB + ((lane >> 3) & 1) * 16;

    float acc[4][4][4];
    #pragma unroll
    for (int i = 0; i < 4; i++)
        #pragma unroll
        for (int j = 0; j < 4; j++)
            #pragma unroll
            for (int r = 0; r < 4; r++) acc[i][j][r] = 0.f;

    const int nk = K / TBK;

    {
        char* stg = smem;
        #pragma unroll
        for (int j = 0; j < 4; j++) {
            int f = tid + j * 256;
            int r = f >> 3, c4 = f & 7;
            float4 v = *(const float4*)(A + (size_t)(bm + r) * K + c4 * 4);
            uint2 hi, lo; cvt_hilo4(v, hi, lo);
            uint32_t so = (uint32_t)(r * ROWB + c4 * 8);
            *(uint2*)(stg + so)           = hi;
            *(uint2*)(stg + OFF_ALO + so) = lo;
        }
        #pragma unroll
        for (int j = 0; j < 4; j++) {
            int f = tid + j * 256;
            int r = f >> 3, c4 = f & 7;
            float4 v = *(const float4*)(W + (size_t)(bn + r) * K + c4 * 4);
            uint2 hi, lo; cvt_hilo4(v, hi, lo);
            uint32_t so = (uint32_t)(r * ROWB + c4 * 8);
            *(uint2*)(stg + OFF_WHI + so) = hi;
            *(uint2*)(stg + OFF_WLO + so) = lo;
        }
    }
    __syncthreads();

    for (int i = 0; i < nk; i++) {
        int cur = i & 1;
        uint32_t stg = sb + cur * STAGE;

        float4 va[4], vw[4];
        if (i + 1 < nk) {
            int k0 = (i + 1) * TBK;
            #pragma unroll
            for (int j = 0; j < 4; j++) {
                int f = tid + j * 256;
                int r = f >> 3, c4 = f & 7;
                va[j] = *(const float4*)(A + (size_t)(bm + r) * K + k0 + c4 * 4);
                vw[j] = *(const float4*)(W + (size_t)(bn + r) * K + k0 + c4 * 4);
            }
        }

        #pragma unroll
        for (int ks = 0; ks < 2; ks++) {
            uint32_t ahr[4][4], alr[4][4];
            #pragma unroll
            for (int mf = 0; mf < 4; mf++) {
                uint32_t ad = stg + a_base + (uint32_t)mf * (16 * ROWB) + ks * 32;
                ldmx4(ad, ahr[mf][0], ahr[mf][1], ahr[mf][2], ahr[mf][3]);
                ldmx4(ad + OFF_ALO, alr[mf][0], alr[mf][1], alr[mf][2], alr[mf][3]);
            }
            uint32_t bhr[2][4], blr[2][4];
            #pragma unroll
            for (int np = 0; np < 2; np++) {
                uint32_t bd = stg + OFF_WHI + b_base + (uint32_t)np * (16 * ROWB) + ks * 32;
                ldmx4(bd, bhr[np][0], bhr[np][1], bhr[np][2], bhr[np][3]);
                ldmx4(bd + OFF_ALO, blr[np][0], blr[np][1], blr[np][2], blr[np][3]);
            }
            #pragma unroll
            for (int mf = 0; mf < 4; mf++) {
                #pragma unroll
                for (int nf = 0; nf < 4; nf++) {
                    uint32_t bh0 = bhr[nf >> 1][(nf & 1) * 2];
                    uint32_t bh1 = bhr[nf >> 1][(nf & 1) * 2 + 1];
                    uint32_t bl0 = blr[nf >> 1][(nf & 1) * 2];
                    uint32_t bl1 = blr[nf >> 1][(nf & 1) * 2 + 1];
                    mma16816(acc[mf][nf], ahr[mf][0], ahr[mf][1], ahr[mf][2], ahr[mf][3], bh0, bh1);
                    mma16816(acc[mf][nf], ahr[mf][0], ahr[mf][1], ahr[mf][2], ahr[mf][3], bl0, bl1);
                    mma16816(acc[mf][nf], alr[mf][0], alr[mf][1], alr[mf][2], alr[mf][3], bh0, bh1);
                }
            }
        }

        if (i + 1 < nk) {
            char* stn = smem + (cur ^ 1) * STAGE;
            #pragma unroll
            for (int j = 0; j < 4; j++) {
                int f = tid + j * 256;
                int r = f >> 3, c4 = f & 7;
                uint32_t so = (uint32_t)(r * ROWB + c4 * 8);
                uint2 hi, lo;
                cvt_hilo4(va[j], hi, lo);
                *(uint2*)(stn + so)           = hi;
                *(uint2*)(stn + OFF_ALO + so) = lo;
                cvt_hilo4(vw[j], hi, lo);
                *(uint2*)(stn + OFF_WHI + so) = hi;
                *(uint2*)(stn + OFF_WLO + so) = lo;
            }
        }
        __syncthreads();
    }

    int tr = lane >> 2, tc = (lane & 3) * 2;
    #pragma unroll
    for (int mf = 0; mf < 4; mf++) {
        #pragma unroll
        for (int nf = 0; nf < 4; nf++) {
            int row0 = bm + warp_m + mf * 16 + tr;
            int col  = bn + warp_n + nf * 8 + tc;
            float* c = acc[mf][nf];
            float2 v0 = {c[0], c[1]};
            float2 v1 = {c[2], c[3]};
            size_t o0 = (size_t)row0 * N + col;
            size_t o1 = (size_t)(row0 + 8) * N + col;
            if (res) {
                float2 r0 = *(const float2*)(res + o0);
                float2 r1 = *(const float2*)(res + o1);
                v0.x += r0.x; v0.y += r0.y; v1.x += r1.x; v1.y += r1.y;
            }
            if (bias) {
                float2 bb = *(const float2*)(bias + col);
                v0.x += bb.x; v0.y += bb.y; v1.x += bb.x; v1.y += bb.y;
            }
            *(float2*)(C + o0) = v0;
            *(float2*)(C + o1) = v1;
        }
    }
}

// ---------------- RMSNorm ----------------
__global__ void rmsnorm_kernel(const float* __restrict__ x,
                               const float* __restrict__ w,
                               float* __restrict__ out) {
    int row = blockIdx.x;
    const float* xr = x + (size_t)row * DIM;
    float s = 0.f;
    #pragma unroll
    for (int i = threadIdx.x; i < DIM; i += 256) {
        float v = xr[i];
        s += v * v;
    }
    __shared__ float red[8];
    #pragma unroll
    for (int o = 16; o; o >>= 1) s += __shfl_down_sync(0xffffffffu, s, o);
    if ((threadIdx.x & 31) == 0) red[threadIdx.x >> 5] = s;
    __syncthreads();
    if (threadIdx.x < 8) {
        float t = red[threadIdx.x];
        #pragma unroll
        for (int o = 4; o; o >>= 1) t += __shfl_down_sync(0xffu, t, o);
        if (threadIdx.x == 0) red[0] = t;
    }
    __syncthreads();
    float inv = rsqrtf(red[0] * (1.0f / DIM) + LN_EPS);
    float* orow = out + (size_t)row * DIM;
    #pragma unroll
    for (int i = threadIdx.x; i < DIM; i += 256)
        orow[i] = xr[i] * inv * w[i];
}

// ------------- RoPE + bf16 hi/lo convert + [B,S,H,HD]->[B,H,S,HD] ----------
#define QSCALE 0.18033688011111793f   // 0.125 * log2(e)
__global__ void rope_cvt_kernel(const float* __restrict__ Q, const float* __restrict__ K,
                                __nv_bfloat16* __restrict__ qhi, __nv_bfloat16* __restrict__ qlo,
                                __nv_bfloat16* __restrict__ khi, __nv_bfloat16* __restrict__ klo) {
    int idx = blockIdx.x * 256 + threadIdx.x;
    if (idx >= BATCH * SEQ * NHEAD * (HDIM / 2)) return;
    int d = idx & 31;
    int h = (idx >> 5) & (NHEAD - 1);
    int s = (idx >> 9) & (SEQ - 1);
    int b = idx >> 20;
    size_t ibase = (((size_t)b * SEQ + s) * NHEAD + h) * HDIM;
    size_t obase = (((size_t)b * NHEAD + h) * SEQ + s) * HDIM;
    float inv = expf(-(float)d * (9.210340371976184f / 32.f));
    float ang = (float)s * inv;
    float sn, cs;
    sincosf(ang, &sn, &cs);

    {
        float x1 = Q[ibase + d], x2 = Q[ibase + d + 32];
        float r1 = (x1 * cs - x2 * sn) * QSCALE;
        float r2 = (x2 * cs + x1 * sn) * QSCALE;
        __nv_bfloat16 h1 = __float2bfloat16_rn(r1);
        __nv_bfloat16 h2 = __float2bfloat16_rn(r2);
        qhi[obase + d]      = h1;
        qhi[obase + d + 32] = h2;
        qlo[obase + d]      = __float2bfloat16_rn(r1 - __bfloat162float(h1));
        qlo[obase + d + 32] = __float2bfloat16_rn(r2 - __bfloat162float(h2));
    }
    {
        float x1 = K[ibase + d], x2 = K[ibase + d + 32];
        float r1 = x1 * cs - x2 * sn;
        float r2 = x2 * cs + x1 * sn;
        __nv_bfloat16 h1 = __float2bfloat16_rn(r1);
        __nv_bfloat16 h2 = __float2bfloat16_rn(r2);
        khi[obase + d]      = h1;
        khi[obase + d + 32] = h2;
        klo[obase + d]      = __float2bfloat16_rn(r1 - __bfloat162float(h1));
        klo[obase + d + 32] = __float2bfloat16_rn(r2 - __bfloat162float(h2));
    }
}

// ------------- V convert: fp32 [B,S,H,HD] -> bf16 [B,H,S,HD] -------------
__global__ void v_cvt_kernel(const float* __restrict__ V, __nv_bfloat16* __restrict__ vb) {
    int t = blockIdx.x * 256 + threadIdx.x;
    if (t >= ROWS * DIM / 4) return;
    int e = t * 4;
    int c = e & 63;
    int h = (e >> 6) & (NHEAD - 1);
    int s = (e >> 10) & (SEQ - 1);
    int b = e >> 21;
    size_t ioff = (((size_t)b * SEQ + s) * NHEAD + h) * HDIM + c;
    size_t ooff = (((size_t)b * NHEAD + h) * SEQ + s) * HDIM + c;
    float4 v = *(const float4*)(V + ioff);
    __nv_bfloat162 p0, p1;
    p0.x = __float2bfloat16_rn(v.x); p0.y = __float2bfloat16_rn(v.y);
    p1.x = __float2bfloat16_rn(v.z); p1.y = __float2bfloat16_rn(v.w);
    uint2 o = { *(uint32_t*)&p0, *(uint32_t*)&p1 };
    *(uint2*)(vb + ooff) = o;
}

// ================= MMA flash attention =================
// CTA: 64 queries of one (b,h); 4 warps x 16 q rows. K/V tiles of 64 keys,
// double-buffered via cp.async. QK^T hi/lo 3-term; PV plain bf16.
#define AROWB 144
#define A_QHI 0
#define A_QLO 9216
#define A_K0  18432            // + s*18432 : hi, +9216 : lo
#define A_V0  55296            // + s*9216
#define ASMEM 73728

__global__ __launch_bounds__(128)
void attn_mma(const __nv_bfloat16* __restrict__ qhi, const __nv_bfloat16* __restrict__ qlo,
              const __nv_bfloat16* __restrict__ khi, const __nv_bfloat16* __restrict__ klo,
              const __nv_bfloat16* __restrict__ vb,  float* __restrict__ O) {
    extern __shared__ char smem[];
    uint32_t sb = smem_u32(smem);
    int tid = threadIdx.x, wid = tid >> 5, lane = tid & 31;
    int b = blockIdx.z, h = blockIdx.y;
    int q0 = blockIdx.x * 64;
    size_t hoff = ((size_t)b * NHEAD + h) * SEQ * HDIM;

    // ---- load Q tile (hi/lo) to smem ----
    {
        const uint4* qh4 = (const uint4*)(qhi + hoff + (size_t)q0 * HDIM);
        const uint4* ql4 = (const uint4*)(qlo + hoff + (size_t)q0 * HDIM);
        #pragma unroll
        for (int j = 0; j < 4; j++) {
            int f = tid + j * 128;
            int r = f >> 3, c = f & 7;
            *(uint4*)(smem + A_QHI + r * AROWB + c * 16) = qh4[r * 8 + c];
            *(uint4*)(smem + A_QLO + r * AROWB + c * 16) = ql4[r * 8 + c];
        }
    }
    __syncthreads();

    // ---- Q fragments (register resident) ----
    uint32_t qh[4][4], ql[4][4];
    {
        uint32_t a_base = sb + (uint32_t)(wid * 16 + (lane & 15)) * AROWB + ((lane >> 4) & 1) * 16;
        #pragma unroll
        for (int ks = 0; ks < 4; ks++) {
            ldmx4(a_base + ks * 32,         qh[ks][0], qh[ks][1], qh[ks][2], qh[ks][3]);
            ldmx4(a_base + A_QLO + ks * 32, ql[ks][0], ql[ks][1], ql[ks][2], ql[ks][3]);
        }
    }

    float ctx[8][4];
    #pragma unroll
    for (int j = 0; j < 8; j++)
        #pragma unroll
        for (int r = 0; r < 4; r++) ctx[j][r] = 0.f;
    float m0 = -1e30f, m1 = -1e30f, l0 = 0.f, l1 = 0.f;

    const __nv_bfloat16* kh_g = khi + hoff;
    const __nv_bfloat16* kl_g = klo + hoff;
    const __nv_bfloat16* v_g  = vb + hoff;

    // issue tile 0
    {
        #pragma unroll
        for (int j = 0; j < 4; j++) {
            int f = tid + j * 128;
            int r = f >> 3, c = f & 7;
            uint32_t so = (uint32_t)(r * AROWB + c * 16);
            CPA16(sb + A_K0 + so,        (const char*)(kh_g + r * 64 + c * 8));
            CPA16(sb + A_K0 + 9216 + so, (const char*)(kl_g + r * 64 + c * 8));
            CPA16(sb + A_V0 + so,        (const char*)(v_g  + r * 64 + c * 8));
        }
        CPA_COMMIT();
    }

    const int NT = SEQ / 64;
    for (int t = 0; t < NT; t++) {
        int s = t & 1;
        if (t + 1 < NT) {
            int nxt = s ^ 1;
            size_t goff = (size_t)(t + 1) * 64 * 64;
            #pragma unroll
            for (int j = 0; j < 4; j++) {
                int f = tid + j * 128;
                int r = f >> 3, c = f & 7;
                uint32_t so = (uint32_t)(r * AROWB + c * 16);
                CPA16(sb + A_K0 + nxt * 18432 + so,        (const char*)(kh_g + goff + r * 64 + c * 8));
                CPA16(sb + A_K0 + nxt * 18432 + 9216 + so, (const char*)(kl_g + goff + r * 64 + c * 8));
                CPA16(sb + A_V0 + nxt * 9216 + so,         (const char*)(v_g  + goff + r * 64 + c * 8));
            }
            CPA_COMMIT();
            CPA_WAIT(1);
        } else {
            CPA_WAIT(0);
        }
        __syncthreads();

        uint32_t kb_hi = sb + A_K0 + s * 18432;
        uint32_t kb_lo = kb_hi + 9216;
        uint32_t vbse  = sb + A_V0 + s * 9216;

        // ---- scores = Qhi*Khi + Qhi*Klo + Qlo*Khi ----
        float sc[8][4];
        #pragma unroll
        for (int j = 0; j < 8; j++)
            #pragma unroll
            for (int r = 0; r < 4; r++) sc[j][r] = 0.f;

        uint32_t b_off = (uint32_t)((lane & 7) + ((lane >> 4) & 1) * 8) * AROWB +
                         ((lane >> 3) & 1) * 16;
        #pragma unroll
        for (int ks = 0; ks < 4; ks++) {
            #pragma unroll
            for (int ng = 0; ng < 4; ng++) {
                uint32_t bh0, bh1, bh2, bh3, bl0, bl1, bl2, bl3;
                uint32_t ad = b_off + (uint32_t)ng * (16 * AROWB) + ks * 32;
                ldmx4(kb_hi + ad, bh0, bh1, bh2, bh3);
                ldmx4(kb_lo + ad, bl0, bl1, bl2, bl3);
                mma16816(sc[2 * ng],     qh[ks][0], qh[ks][1], qh[ks][2], qh[ks][3], bh0, bh1);
                mma16816(sc[2 * ng],     qh[ks][0], qh[ks][1], qh[ks][2], qh[ks][3], bl0, bl1);
                mma16816(sc[2 * ng],     ql[ks][0], ql[ks][1], ql[ks][2], ql[ks][3], bh0, bh1);
                mma16816(sc[2 * ng + 1], qh[ks][0], qh[ks][1], qh[ks][2], qh[ks][3], bh2, bh3);
                mma16816(sc[2 * ng + 1], qh[ks][0], qh[ks][1], qh[ks][2], qh[ks][3], bl2, bl3);
                mma16816(sc[2 * ng + 1], ql[ks][0], ql[ks][1], ql[ks][2], ql[ks][3], bh2, bh3);
            }
        }

        // ---- online softmax (exp2 domain) ----
        float mn0 = m0, mn1 = m1;
        #pragma unroll
        for (int j = 0; j < 8; j++) {
            mn0 = fmaxf(mn0, fmaxf(sc[j][0], sc[j][1]));
            mn1 = fmaxf(mn1, fmaxf(sc[j][2], sc[j][3]));
        }
        mn0 = fmaxf(mn0, __shfl_xor_sync(0xffffffffu, mn0, 1));
        mn0 = fmaxf(mn0, __shfl_xor_sync(0xffffffffu, mn0, 2));
        mn1 = fmaxf(mn1, __shfl_xor_sync(0xffffffffu, mn1, 1));
        mn1 = fmaxf(mn1, __shfl_xor_sync(0xffffffffu, mn1, 2));
        float corr0 = ex2f(m0 - mn0);
        float corr1 = ex2f(m1 - mn1);
        m0 = mn0; m1 = mn1;
        l0 *= corr0; l1 *= corr1;
        #pragma unroll
        for (int j = 0; j < 8; j++) {
            ctx[j][0] *= corr0; ctx[j][1] *= corr0;
            ctx[j][2] *= corr1; ctx[j][3] *= corr1;
        }
        uint32_t pa[8], pb[8];
        #pragma unroll
        for (int j = 0; j < 8; j++) {
            float p0 = ex2f(sc[j][0] - mn0);
            float p1 = ex2f(sc[j][1] - mn0);
            float p2 = ex2f(sc[j][2] - mn1);
            float p3 = ex2f(sc[j][3] - mn1);
            l0 += p0 + p1; l1 += p2 + p3;
            __nv_bfloat162 t0 = __floats2bfloat162_rn(p0, p1);
            __nv_bfloat162 t1 = __floats2bfloat162_rn(p2, p3);
            pa[j] = *(uint32_t*)&t0;
            pb[j] = *(uint32_t*)&t1;
        }

        // ---- ctx += P @ V ----
        // x4t at byte col nd*32 (+16 for lanes>=16) covers d = nd*16 + 0..15:
        //   (r0,r1) -> d nd*16+0..7 (keys 0-7 / 8-15), (r2,r3) -> d nd*16+8..15
        uint32_t v_off = (uint32_t)(lane & 15) * AROWB + ((lane >> 4) & 1) * 16;
        #pragma unroll
        for (int ks = 0; ks < 4; ks++) {
            #pragma unroll
            for (int nd = 0; nd < 4; nd++) {
                uint32_t r0, r1, r2, r3;
                ldmx4t(vbse + v_off + (uint32_t)ks * (16 * AROWB) + nd * 32, r0, r1, r2, r3);
                mma16816(ctx[nd * 2],     pa[2 * ks], pb[2 * ks], pa[2 * ks + 1], pb[2 * ks + 1], r0, r1);
                mma16816(ctx[nd * 2 + 1], pa[2 * ks], pb[2 * ks], pa[2 * ks + 1], pb[2 * ks + 1], r2, r3);
            }
        }
        __syncthreads();
    }

    // ---- finalize ----
    l0 += __shfl_xor_sync(0xffffffffu, l0, 1);
    l0 += __shfl_xor_sync(0xffffffffu, l0, 2);
    l1 += __shfl_xor_sync(0xffffffffu, l1, 1);
    l1 += __shfl_xor_sync(0xffffffffu, l1, 2);
    float i0 = 1.f / l0, i1 = 1.f / l1;

    int tr = lane >> 2, tc = (lane & 3) * 2;
    int row0 = q0 + wid * 16 + tr;
    // ctx frag f covers d = f*8 + tc; rows row0 (c0,c1) and row0+8 (c2,c3)
    #pragma unroll
    for (int f = 0; f < 8; f++) {
        int d = f * 8 + tc;
        float* c = ctx[f];
        size_t o0 = ((size_t)b * SEQ + row0) * DIM + (size_t)h * HDIM + d;
        size_t o1 = ((size_t)b * SEQ + row0 + 8) * DIM + (size_t)h * HDIM + d;
        float2 w0 = {c[0] * i0, c[1] * i0};
        float2 w1 = {c[2] * i1, c[3] * i1};
        *(float2*)(O + o0) = w0;
        *(float2*)(O + o1) = w1;
    }
}

// ---------------- SwiGLU combine ----------------
__global__ void silu_mul_kernel(float* __restrict__ g, const float* __restrict__ u,
                                size_t n) {
    size_t i = (size_t)blockIdx.x * 256 + threadIdx.x;
    if (i < n) {
        float x = g[i];
        g[i] = (x / (1.f + expf(-x))) * u[i];
    }
}

// ---------------- launch ----------------
extern "C" void kernel_launch(void* const* d_in, const int* in_sizes, int n_in,
                              void* d_out, int out_size) {
    const float* x_in   = (const float*)d_in[0];
    const float* Wq     = (const float*)d_in[1];
    const float* Wk     = (const float*)d_in[2];
    const float* Wv     = (const float*)d_in[3];
    const float* Wo     = (const float*)d_in[4];
    const float* ln1_w  = (const float*)d_in[5];
    const float* ln2_w  = (const float*)d_in[6];
    const float* Wgate  = (const float*)d_in[7];
    const float* Wup    = (const float*)d_in[8];
    const float* Wdown  = (const float*)d_in[9];
    const float* W_out  = (const float*)d_in[10];
    const float* b_out  = (const float*)d_in[11];
    float* out = (float*)d_out;

    float *x, *h, *q, *k, *v, *ctx, *f1, *f2;
    __nv_bfloat16 *qhi, *qlo, *khi, *klo, *vbp;
    cudaGetSymbolAddress((void**)&x,   g_x);
    cudaGetSymbolAddress((void**)&h,   g_h);
    cudaGetSymbolAddress((void**)&q,   g_q);
    cudaGetSymbolAddress((void**)&k,   g_k);
    cudaGetSymbolAddress((void**)&v,   g_v);
    cudaGetSymbolAddress((void**)&ctx, g_ctx);
    cudaGetSymbolAddress((void**)&f1,  g_f1);
    cudaGetSymbolAddress((void**)&f2,  g_f2);
    cudaGetSymbolAddress((void**)&qhi, g_qhi);
    cudaGetSymbolAddress((void**)&qlo, g_qlo);
    cudaGetSymbolAddress((void**)&khi, g_khi);
    cudaGetSymbolAddress((void**)&klo, g_klo);
    cudaGetSymbolAddress((void**)&vbp, g_vb);

    cudaFuncSetAttribute(gemm_mma, cudaFuncAttributeMaxDynamicSharedMemorySize, GSMEM);
    cudaFuncSetAttribute(attn_mma, cudaFuncAttributeMaxDynamicSharedMemorySize, ASMEM);

    const size_t xbytes = (size_t)ROWS * DIM * sizeof(float);
    cudaMemcpyAsync(x, x_in, xbytes, cudaMemcpyDeviceToDevice);

    // --- attention block ---
    rmsnorm_kernel<<<ROWS, 256>>>(x, ln1_w, h);

    dim3 g1(DIM / TBN, ROWS / TBM);
    dim3 g2(FFDIM / TBN, ROWS / TBM);

    gemm_mma<<<g1, 256, GSMEM>>>(h, Wq, nullptr, nullptr, q, ROWS, DIM, DIM);
    gemm_mma<<<g1, 256, GSMEM>>>(h, Wk, nullptr, nullptr, k, ROWS, DIM, DIM);
    gemm_mma<<<g1, 256, GSMEM>>>(h, Wv, nullptr, nullptr, v, ROWS, DIM, DIM);

    int rope_total = BATCH * SEQ * NHEAD * (HDIM / 2);
    rope_cvt_kernel<<<(rope_total + 255) / 256, 256>>>(q, k, qhi, qlo, khi, klo);
    v_cvt_kernel<<<(ROWS * DIM / 4 + 255) / 256, 256>>>(v, vbp);

    dim3 ga(SEQ / 64, NHEAD, BATCH);
    attn_mma<<<ga, 128, ASMEM>>>(qhi, qlo, khi, klo, vbp, ctx);

    gemm_mma<<<g1, 256, GSMEM>>>(ctx, Wo, x, nullptr, x, ROWS, DIM, DIM);

    // --- MLP block ---
    rmsnorm_kernel<<<ROWS, 256>>>(x, ln2_w, h);
    gemm_mma<<<g2, 256, GSMEM>>>(h, Wgate, nullptr, nullptr, f1, ROWS, FFDIM, DIM);
    gemm_mma<<<g2, 256, GSMEM>>>(h, Wup,   nullptr, nullptr, f2, ROWS, FFDIM, DIM);

    size_t ffn = (size_t)ROWS * FFDIM;
    silu_mul_kernel<<<(unsigned)((ffn + 255) / 256), 256>>>(f1, f2, ffn);

    gemm_mma<<<g1, 256, GSMEM>>>(f1, Wdown, x, nullptr, x, ROWS, DIM, FFDIM);

    // --- output head ---
    gemm_mma<<<g1, 256, GSMEM>>>(x, W_out, nullptr, b_out, out, ROWS, DIM, DIM);
}

// round 6
// speedup vs baseline: 3.5971x; 1.2288x over previous
#include <cuda_runtime.h>
#include <cuda_bf16.h>
#include <cstdint>

// Problem constants
#define BATCH 4
#define SEQ   2048
#define DIM   1024
#define NHEAD 16
#define HDIM  64
#define FFDIM 4096
#define ROWS  (BATCH * SEQ)            // 8192
#define LN_EPS 1e-6f

// ---------------- scratch (device globals; no allocation) ----------------
__device__ float g_x  [(size_t)ROWS * DIM];
__device__ float g_q  [(size_t)ROWS * DIM];
__device__ float g_k  [(size_t)ROWS * DIM];
__device__ float g_v  [(size_t)ROWS * DIM];
__device__ float g_f1 [(size_t)ROWS * FFDIM];
__device__ float g_f2 [(size_t)ROWS * FFDIM];
// bf16 hi/lo activation operands
__device__ __nv_bfloat16 g_hhi [(size_t)ROWS * DIM];
__device__ __nv_bfloat16 g_hlo [(size_t)ROWS * DIM];
__device__ __nv_bfloat16 g_chi [(size_t)ROWS * DIM];     // ctx hi
__device__ __nv_bfloat16 g_clo [(size_t)ROWS * DIM];     // ctx lo
__device__ __nv_bfloat16 g_f1hi[(size_t)ROWS * FFDIM];
__device__ __nv_bfloat16 g_f1lo[(size_t)ROWS * FFDIM];
__device__ __nv_bfloat16 g_xhi [(size_t)ROWS * DIM];
__device__ __nv_bfloat16 g_xlo [(size_t)ROWS * DIM];
// bf16 hi/lo weights (Wq|Wk|Wv|Wo|Wgate|Wup|Wdown|W_out)
#define WOFF_Q  0
#define WOFF_K  1048576
#define WOFF_V  2097152
#define WOFF_O  3145728
#define WOFF_G  4194304
#define WOFF_U  8388608
#define WOFF_D  12582912
#define WOFF_H  16777216
#define WTOT    17825792
__device__ __nv_bfloat16 g_whi[(size_t)WTOT];
__device__ __nv_bfloat16 g_wlo[(size_t)WTOT];
// bf16 attention operands, [B,H,S,HD] layout
__device__ __nv_bfloat16 g_qhi[(size_t)ROWS * DIM];
__device__ __nv_bfloat16 g_qlo[(size_t)ROWS * DIM];
__device__ __nv_bfloat16 g_khi[(size_t)ROWS * DIM];
__device__ __nv_bfloat16 g_klo[(size_t)ROWS * DIM];
__device__ __nv_bfloat16 g_vb [(size_t)ROWS * DIM];

__device__ __forceinline__ uint32_t smem_u32(const void* p) {
    uint32_t a;
    asm("{ .reg .u64 t; cvta.to.shared.u64 t, %1; cvt.u32.u64 %0, t; }"
        : "=r"(a) : "l"(p));
    return a;
}
__device__ __forceinline__ void cvt_hilo4(float4 v, uint2& hi, uint2& lo) {
    __nv_bfloat162 h01, h23, l01, l23;
    h01.x = __float2bfloat16_rn(v.x);
    h01.y = __float2bfloat16_rn(v.y);
    h23.x = __float2bfloat16_rn(v.z);
    h23.y = __float2bfloat16_rn(v.w);
    l01.x = __float2bfloat16_rn(v.x - __bfloat162float(h01.x));
    l01.y = __float2bfloat16_rn(v.y - __bfloat162float(h01.y));
    l23.x = __float2bfloat16_rn(v.z - __bfloat162float(h23.x));
    l23.y = __float2bfloat16_rn(v.w - __bfloat162float(h23.y));
    hi.x = *(uint32_t*)&h01; hi.y = *(uint32_t*)&h23;
    lo.x = *(uint32_t*)&l01; lo.y = *(uint32_t*)&l23;
}
__device__ __forceinline__ void ldmx4(uint32_t addr, uint32_t& r0, uint32_t& r1,
                                      uint32_t& r2, uint32_t& r3) {
    asm volatile("ldmatrix.sync.aligned.m8n8.x4.shared.b16 {%0,%1,%2,%3}, [%4];"
                 : "=r"(r0), "=r"(r1), "=r"(r2), "=r"(r3) : "r"(addr));
}
__device__ __forceinline__ void ldmx4t(uint32_t addr, uint32_t& r0, uint32_t& r1,
                                       uint32_t& r2, uint32_t& r3) {
    asm volatile("ldmatrix.sync.aligned.m8n8.x4.trans.shared.b16 {%0,%1,%2,%3}, [%4];"
                 : "=r"(r0), "=r"(r1), "=r"(r2), "=r"(r3) : "r"(addr));
}
__device__ __forceinline__ void mma16816(float* c, uint32_t a0, uint32_t a1,
                                         uint32_t a2, uint32_t a3,
                                         uint32_t b0, uint32_t b1) {
    asm volatile(
        "mma.sync.aligned.m16n8k16.row.col.f32.bf16.bf16.f32 "
        "{%0,%1,%2,%3}, {%4,%5,%6,%7}, {%8,%9}, {%0,%1,%2,%3};"
        : "+f"(c[0]), "+f"(c[1]), "+f"(c[2]), "+f"(c[3])
        : "r"(a0), "r"(a1), "r"(a2), "r"(a3), "r"(b0), "r"(b1));
}
__device__ __forceinline__ float ex2f(float x) {
    float r;
    asm("ex2.approx.f32 %0, %1;" : "=f"(r) : "f"(x));
    return r;
}
#define CPA16(dst, src) \
    asm volatile("cp.async.cg.shared.global [%0], [%1], 16;" :: "r"(dst), "l"(src))
#define CPA_COMMIT() asm volatile("cp.async.commit_group;" ::: "memory")
#define CPA_WAIT(n)  asm volatile("cp.async.wait_group %0;" :: "n"(n) : "memory")

// ---------------- weight convert: fp32 -> bf16 hi/lo ----------------
__global__ void wcvt_kernel(const float* __restrict__ src,
                            __nv_bfloat16* __restrict__ hi,
                            __nv_bfloat16* __restrict__ lo, int n4) {
    int t = blockIdx.x * 256 + threadIdx.x;
    if (t >= n4) return;
    float4 v = *(const float4*)(src + (size_t)t * 4);
    uint2 h, l;
    cvt_hilo4(v, h, l);
    *(uint2*)(hi + (size_t)t * 4) = h;
    *(uint2*)(lo + (size_t)t * 4) = l;
}

// ================= bf16 pipelined GEMM ===============================
// C[M,N] = A[M,K] @ W[N,K]^T  (A,W given as bf16 hi/lo; 3-term split)
// Tile 128x128, BK=64, 3-stage cp.async, SW128 swizzle (128B rows).
#define GBM 128
#define GBN 128
#define GBK 64
#define GA_LO 16384
#define GW_HI 32768
#define GW_LO 49152
#define GSTG  65536
#define GSMEM2 (3 * GSTG)      // 196608

__global__ __launch_bounds__(256)
void gemm_bf(const __nv_bfloat16* __restrict__ Ahi, const __nv_bfloat16* __restrict__ Alo,
             const __nv_bfloat16* __restrict__ Whi, const __nv_bfloat16* __restrict__ Wlo,
             const float* __restrict__ res, const float* __restrict__ bias,
             float* __restrict__ C,
             __nv_bfloat16* __restrict__ Chi, __nv_bfloat16* __restrict__ Clo,
             int M, int N, int K) {
    extern __shared__ char smem[];
    uint32_t sb = smem_u32(smem);
    int tid = threadIdx.x, wid = tid >> 5, lane = tid & 31;
    int bm = blockIdx.y * GBM, bn = blockIdx.x * GBN;
    int warp_m = (wid >> 2) * 64, warp_n = (wid & 3) * 32;

    // --- cp.async mapping: r = tid>>3 (+j*32), 16B chunk col = (tid&7)*16 ---
    uint32_t xw = (((uint32_t)(tid >> 3) & 7u) << 4);
    uint32_t st_off = (uint32_t)(tid >> 3) * 128 + (((uint32_t)(tid & 7) * 16) ^ xw);
    const __nv_bfloat16* Ah = Ahi + (size_t)(bm + (tid >> 3)) * K + (tid & 7) * 8;
    const __nv_bfloat16* Al = Alo + (size_t)(bm + (tid >> 3)) * K + (tid & 7) * 8;
    const __nv_bfloat16* Wh = Whi + (size_t)(bn + (tid >> 3)) * K + (tid & 7) * 8;
    const __nv_bfloat16* Wl = Wlo + (size_t)(bn + (tid >> 3)) * K + (tid & 7) * 8;

    auto load_stage = [&](int s, int chunk) {
        uint32_t base = sb + (uint32_t)s * GSTG;
        size_t ko = (size_t)chunk * GBK;
        #pragma unroll
        for (int j = 0; j < 4; j++) {
            uint32_t d = base + st_off + j * 4096;
            size_t ro = (size_t)j * 32 * K + ko;
            CPA16(d,         (const char*)(Ah + ro));
            CPA16(d + GA_LO, (const char*)(Al + ro));
            CPA16(d + GW_HI, (const char*)(Wh + ro));
            CPA16(d + GW_LO, (const char*)(Wl + ro));
        }
    };

    // --- ldmatrix addressing (swizzle folded into per-thread constants) ---
    int r_a = warp_m + (lane & 15);
    uint32_t xa = ((uint32_t)(r_a & 7) << 4);
    uint32_t a_row = (uint32_t)r_a * 128;
    int r_b = warp_n + (lane & 7) + ((lane >> 4) & 1) * 8;
    uint32_t xb = ((uint32_t)(r_b & 7) << 4);
    uint32_t b_row = (uint32_t)r_b * 128;
    uint32_t col_a[4], col_b[4];
    int ha = ((lane >> 4) & 1) * 16;
    int hb = ((lane >> 3) & 1) * 16;
    #pragma unroll
    for (int ks = 0; ks < 4; ks++) {
        col_a[ks] = ((uint32_t)(ha + ks * 32)) ^ xa;
        col_b[ks] = ((uint32_t)(hb + ks * 32)) ^ xb;
    }

    float acc[4][4][4];
    #pragma unroll
    for (int i = 0; i < 4; i++)
        #pragma unroll
        for (int j = 0; j < 4; j++)
            #pragma unroll
            for (int r = 0; r < 4; r++) acc[i][j][r] = 0.f;

    const int nk = K / GBK;

    load_stage(0, 0);
    CPA_COMMIT();
    if (nk > 1) load_stage(1, 1);
    CPA_COMMIT();

    int sc = 0;              // stage of chunk i
    for (int i = 0; i < nk; i++) {
        int snx = sc + 2; if (snx >= 3) snx -= 3;
        if (i + 2 < nk) load_stage(snx, i + 2);
        CPA_COMMIT();
        CPA_WAIT(2);
        __syncthreads();

        uint32_t base = sb + (uint32_t)sc * GSTG;
        #pragma unroll
        for (int ks = 0; ks < 4; ks++) {
            uint32_t ahr[4][4], alr[4][4];
            #pragma unroll
            for (int mf = 0; mf < 4; mf++) {
                uint32_t ad = base + a_row + (uint32_t)mf * 2048 + col_a[ks];
                ldmx4(ad,         ahr[mf][0], ahr[mf][1], ahr[mf][2], ahr[mf][3]);
                ldmx4(ad + GA_LO, alr[mf][0], alr[mf][1], alr[mf][2], alr[mf][3]);
            }
            uint32_t bhr[2][4], blr[2][4];
            #pragma unroll
            for (int np = 0; np < 2; np++) {
                uint32_t bd = base + GW_HI + b_row + (uint32_t)np * 2048 + col_b[ks];
                ldmx4(bd,         bhr[np][0], bhr[np][1], bhr[np][2], bhr[np][3]);
                ldmx4(bd + 16384, blr[np][0], blr[np][1], blr[np][2], blr[np][3]);
            }
            #pragma unroll
            for (int mf = 0; mf < 4; mf++) {
                #pragma unroll
                for (int nf = 0; nf < 4; nf++) {
                    uint32_t bh0 = bhr[nf >> 1][(nf & 1) * 2];
                    uint32_t bh1 = bhr[nf >> 1][(nf & 1) * 2 + 1];
                    uint32_t bl0 = blr[nf >> 1][(nf & 1) * 2];
                    uint32_t bl1 = blr[nf >> 1][(nf & 1) * 2 + 1];
                    mma16816(acc[mf][nf], ahr[mf][0], ahr[mf][1], ahr[mf][2], ahr[mf][3], bh0, bh1);
                    mma16816(acc[mf][nf], ahr[mf][0], ahr[mf][1], ahr[mf][2], ahr[mf][3], bl0, bl1);
                    mma16816(acc[mf][nf], alr[mf][0], alr[mf][1], alr[mf][2], alr[mf][3], bh0, bh1);
                }
            }
        }
        __syncthreads();
        sc = (sc == 2) ? 0 : sc + 1;
    }

    // ---- epilogue ----
    int tr = lane >> 2, tc = (lane & 3) * 2;
    #pragma unroll
    for (int mf = 0; mf < 4; mf++) {
        #pragma unroll
        for (int nf = 0; nf < 4; nf++) {
            int row0 = bm + warp_m + mf * 16 + tr;
            int col  = bn + warp_n + nf * 8 + tc;
            float* c = acc[mf][nf];
            float2 v0 = {c[0], c[1]};
            float2 v1 = {c[2], c[3]};
            size_t o0 = (size_t)row0 * N + col;
            size_t o1 = (size_t)(row0 + 8) * N + col;
            if (res) {
                float2 r0 = *(const float2*)(res + o0);
                float2 r1 = *(const float2*)(res + o1);
                v0.x += r0.x; v0.y += r0.y; v1.x += r1.x; v1.y += r1.y;
            }
            if (bias) {
                float2 bb = *(const float2*)(bias + col);
                v0.x += bb.x; v0.y += bb.y; v1.x += bb.x; v1.y += bb.y;
            }
            if (C) {
                *(float2*)(C + o0) = v0;
                *(float2*)(C + o1) = v1;
            }
            if (Chi) {
                __nv_bfloat162 h0, h1, l0, l1;
                h0.x = __float2bfloat16_rn(v0.x); h0.y = __float2bfloat16_rn(v0.y);
                h1.x = __float2bfloat16_rn(v1.x); h1.y = __float2bfloat16_rn(v1.y);
                l0.x = __float2bfloat16_rn(v0.x - __bfloat162float(h0.x));
                l0.y = __float2bfloat16_rn(v0.y - __bfloat162float(h0.y));
                l1.x = __float2bfloat16_rn(v1.x - __bfloat162float(h1.x));
                l1.y = __float2bfloat16_rn(v1.y - __bfloat162float(h1.y));
                *(__nv_bfloat162*)(Chi + o0) = h0;
                *(__nv_bfloat162*)(Chi + o1) = h1;
                *(__nv_bfloat162*)(Clo + o0) = l0;
                *(__nv_bfloat162*)(Clo + o1) = l1;
            }
        }
    }
}

// ---------------- RMSNorm -> bf16 hi/lo ----------------
__global__ void rmsnorm_kernel(const float* __restrict__ x,
                               const float* __restrict__ w,
                               __nv_bfloat16* __restrict__ ohi,
                               __nv_bfloat16* __restrict__ olo) {
    int row = blockIdx.x;
    const float* xr = x + (size_t)row * DIM;
    float s = 0.f;
    #pragma unroll
    for (int i = threadIdx.x; i < DIM; i += 256) {
        float v = xr[i];
        s += v * v;
    }
    __shared__ float red[8];
    #pragma unroll
    for (int o = 16; o; o >>= 1) s += __shfl_down_sync(0xffffffffu, s, o);
    if ((threadIdx.x & 31) == 0) red[threadIdx.x >> 5] = s;
    __syncthreads();
    if (threadIdx.x < 8) {
        float t = red[threadIdx.x];
        #pragma unroll
        for (int o = 4; o; o >>= 1) t += __shfl_down_sync(0xffu, t, o);
        if (threadIdx.x == 0) red[0] = t;
    }
    __syncthreads();
    float inv = rsqrtf(red[0] * (1.0f / DIM) + LN_EPS);
    #pragma unroll
    for (int i = threadIdx.x; i < DIM; i += 256) {
        float v = xr[i] * inv * w[i];
        __nv_bfloat16 hi = __float2bfloat16_rn(v);
        ohi[(size_t)row * DIM + i] = hi;
        olo[(size_t)row * DIM + i] = __float2bfloat16_rn(v - __bfloat162float(hi));
    }
}

// ------------- RoPE + bf16 hi/lo convert + [B,S,H,HD]->[B,H,S,HD] ----------
#define QSCALE 0.18033688011111793f   // 0.125 * log2(e)
__global__ void rope_cvt_kernel(const float* __restrict__ Q, const float* __restrict__ K,
                                __nv_bfloat16* __restrict__ qhi, __nv_bfloat16* __restrict__ qlo,
                                __nv_bfloat16* __restrict__ khi, __nv_bfloat16* __restrict__ klo) {
    int idx = blockIdx.x * 256 + threadIdx.x;
    if (idx >= BATCH * SEQ * NHEAD * (HDIM / 2)) return;
    int d = idx & 31;
    int h = (idx >> 5) & (NHEAD - 1);
    int s = (idx >> 9) & (SEQ - 1);
    int b = idx >> 20;
    size_t ibase = (((size_t)b * SEQ + s) * NHEAD + h) * HDIM;
    size_t obase = (((size_t)b * NHEAD + h) * SEQ + s) * HDIM;
    float inv = expf(-(float)d * (9.210340371976184f / 32.f));
    float ang = (float)s * inv;
    float sn, cs;
    sincosf(ang, &sn, &cs);
    {
        float x1 = Q[ibase + d], x2 = Q[ibase + d + 32];
        float r1 = (x1 * cs - x2 * sn) * QSCALE;
        float r2 = (x2 * cs + x1 * sn) * QSCALE;
        __nv_bfloat16 h1 = __float2bfloat16_rn(r1);
        __nv_bfloat16 h2 = __float2bfloat16_rn(r2);
        qhi[obase + d]      = h1;
        qhi[obase + d + 32] = h2;
        qlo[obase + d]      = __float2bfloat16_rn(r1 - __bfloat162float(h1));
        qlo[obase + d + 32] = __float2bfloat16_rn(r2 - __bfloat162float(h2));
    }
    {
        float x1 = K[ibase + d], x2 = K[ibase + d + 32];
        float r1 = x1 * cs - x2 * sn;
        float r2 = x2 * cs + x1 * sn;
        __nv_bfloat16 h1 = __float2bfloat16_rn(r1);
        __nv_bfloat16 h2 = __float2bfloat16_rn(r2);
        khi[obase + d]      = h1;
        khi[obase + d + 32] = h2;
        klo[obase + d]      = __float2bfloat16_rn(r1 - __bfloat162float(h1));
        klo[obase + d + 32] = __float2bfloat16_rn(r2 - __bfloat162float(h2));
    }
}

// ------------- V convert: fp32 [B,S,H,HD] -> bf16 [B,H,S,HD] -------------
__global__ void v_cvt_kernel(const float* __restrict__ V, __nv_bfloat16* __restrict__ vb) {
    int t = blockIdx.x * 256 + threadIdx.x;
    if (t >= ROWS * DIM / 4) return;
    int e = t * 4;
    int c = e & 63;
    int h = (e >> 6) & (NHEAD - 1);
    int s = (e >> 10) & (SEQ - 1);
    int b = e >> 21;
    size_t ioff = (((size_t)b * SEQ + s) * NHEAD + h) * HDIM + c;
    size_t ooff = (((size_t)b * NHEAD + h) * SEQ + s) * HDIM + c;
    float4 v = *(const float4*)(V + ioff);
    __nv_bfloat162 p0, p1;
    p0.x = __float2bfloat16_rn(v.x); p0.y = __float2bfloat16_rn(v.y);
    p1.x = __float2bfloat16_rn(v.z); p1.y = __float2bfloat16_rn(v.w);
    uint2 o = { *(uint32_t*)&p0, *(uint32_t*)&p1 };
    *(uint2*)(vb + ooff) = o;
}

// ================= MMA flash attention =================
#define AROWB 144
#define A_QHI 0
#define A_QLO 9216
#define A_K0  18432
#define A_V0  55296
#define ASMEM 73728

__global__ __launch_bounds__(128)
void attn_mma(const __nv_bfloat16* __restrict__ qhi, const __nv_bfloat16* __restrict__ qlo,
              const __nv_bfloat16* __restrict__ khi, const __nv_bfloat16* __restrict__ klo,
              const __nv_bfloat16* __restrict__ vb,
              __nv_bfloat16* __restrict__ Ohi, __nv_bfloat16* __restrict__ Olo) {
    extern __shared__ char smem[];
    uint32_t sb = smem_u32(smem);
    int tid = threadIdx.x, wid = tid >> 5, lane = tid & 31;
    int b = blockIdx.z, h = blockIdx.y;
    int q0 = blockIdx.x * 64;
    size_t hoff = ((size_t)b * NHEAD + h) * SEQ * HDIM;

    {
        const uint4* qh4 = (const uint4*)(qhi + hoff + (size_t)q0 * HDIM);
        const uint4* ql4 = (const uint4*)(qlo + hoff + (size_t)q0 * HDIM);
        #pragma unroll
        for (int j = 0; j < 4; j++) {
            int f = tid + j * 128;
            int r = f >> 3, c = f & 7;
            *(uint4*)(smem + A_QHI + r * AROWB + c * 16) = qh4[r * 8 + c];
            *(uint4*)(smem + A_QLO + r * AROWB + c * 16) = ql4[r * 8 + c];
        }
    }
    __syncthreads();

    uint32_t qh[4][4], ql[4][4];
    {
        uint32_t a_base = sb + (uint32_t)(wid * 16 + (lane & 15)) * AROWB + ((lane >> 4) & 1) * 16;
        #pragma unroll
        for (int ks = 0; ks < 4; ks++) {
            ldmx4(a_base + ks * 32,         qh[ks][0], qh[ks][1], qh[ks][2], qh[ks][3]);
            ldmx4(a_base + A_QLO + ks * 32, ql[ks][0], ql[ks][1], ql[ks][2], ql[ks][3]);
        }
    }

    float ctx[8][4];
    #pragma unroll
    for (int j = 0; j < 8; j++)
        #pragma unroll
        for (int r = 0; r < 4; r++) ctx[j][r] = 0.f;
    float m0 = -1e30f, m1 = -1e30f, l0 = 0.f, l1 = 0.f;

    const __nv_bfloat16* kh_g = khi + hoff;
    const __nv_bfloat16* kl_g = klo + hoff;
    const __nv_bfloat16* v_g  = vb + hoff;

    {
        #pragma unroll
        for (int j = 0; j < 4; j++) {
            int f = tid + j * 128;
            int r = f >> 3, c = f & 7;
            uint32_t so = (uint32_t)(r * AROWB + c * 16);
            CPA16(sb + A_K0 + so,        (const char*)(kh_g + r * 64 + c * 8));
            CPA16(sb + A_K0 + 9216 + so, (const char*)(kl_g + r * 64 + c * 8));
            CPA16(sb + A_V0 + so,        (const char*)(v_g  + r * 64 + c * 8));
        }
        CPA_COMMIT();
    }

    const int NT = SEQ / 64;
    for (int t = 0; t < NT; t++) {
        int s = t & 1;
        if (t + 1 < NT) {
            int nxt = s ^ 1;
            size_t goff = (size_t)(t + 1) * 64 * 64;
            #pragma unroll
            for (int j = 0; j < 4; j++) {
                int f = tid + j * 128;
                int r = f >> 3, c = f & 7;
                uint32_t so = (uint32_t)(r * AROWB + c * 16);
                CPA16(sb + A_K0 + nxt * 18432 + so,        (const char*)(kh_g + goff + r * 64 + c * 8));
                CPA16(sb + A_K0 + nxt * 18432 + 9216 + so, (const char*)(kl_g + goff + r * 64 + c * 8));
                CPA16(sb + A_V0 + nxt * 9216 + so,         (const char*)(v_g  + goff + r * 64 + c * 8));
            }
            CPA_COMMIT();
            CPA_WAIT(1);
        } else {
            CPA_WAIT(0);
        }
        __syncthreads();

        uint32_t kb_hi = sb + A_K0 + s * 18432;
        uint32_t kb_lo = kb_hi + 9216;
        uint32_t vbse  = sb + A_V0 + s * 9216;

        float sc[8][4];
        #pragma unroll
        for (int j = 0; j < 8; j++)
            #pragma unroll
            for (int r = 0; r < 4; r++) sc[j][r] = 0.f;

        uint32_t b_off = (uint32_t)((lane & 7) + ((lane >> 4) & 1) * 8) * AROWB +
                         ((lane >> 3) & 1) * 16;
        #pragma unroll
        for (int ks = 0; ks < 4; ks++) {
            #pragma unroll
            for (int ng = 0; ng < 4; ng++) {
                uint32_t bh0, bh1, bh2, bh3, bl0, bl1, bl2, bl3;
                uint32_t ad = b_off + (uint32_t)ng * (16 * AROWB) + ks * 32;
                ldmx4(kb_hi + ad, bh0, bh1, bh2, bh3);
                ldmx4(kb_lo + ad, bl0, bl1, bl2, bl3);
                mma16816(sc[2 * ng],     qh[ks][0], qh[ks][1], qh[ks][2], qh[ks][3], bh0, bh1);
                mma16816(sc[2 * ng],     qh[ks][0], qh[ks][1], qh[ks][2], qh[ks][3], bl0, bl1);
                mma16816(sc[2 * ng],     ql[ks][0], ql[ks][1], ql[ks][2], ql[ks][3], bh0, bh1);
                mma16816(sc[2 * ng + 1], qh[ks][0], qh[ks][1], qh[ks][2], qh[ks][3], bh2, bh3);
                mma16816(sc[2 * ng + 1], qh[ks][0], qh[ks][1], qh[ks][2], qh[ks][3], bl2, bl3);
                mma16816(sc[2 * ng + 1], ql[ks][0], ql[ks][1], ql[ks][2], ql[ks][3], bh2, bh3);
            }
        }

        float mn0 = m0, mn1 = m1;
        #pragma unroll
        for (int j = 0; j < 8; j++) {
            mn0 = fmaxf(mn0, fmaxf(sc[j][0], sc[j][1]));
            mn1 = fmaxf(mn1, fmaxf(sc[j][2], sc[j][3]));
        }
        mn0 = fmaxf(mn0, __shfl_xor_sync(0xffffffffu, mn0, 1));
        mn0 = fmaxf(mn0, __shfl_xor_sync(0xffffffffu, mn0, 2));
        mn1 = fmaxf(mn1, __shfl_xor_sync(0xffffffffu, mn1, 1));
        mn1 = fmaxf(mn1, __shfl_xor_sync(0xffffffffu, mn1, 2));
        float corr0 = ex2f(m0 - mn0);
        float corr1 = ex2f(m1 - mn1);
        m0 = mn0; m1 = mn1;
        l0 *= corr0; l1 *= corr1;
        #pragma unroll
        for (int j = 0; j < 8; j++) {
            ctx[j][0] *= corr0; ctx[j][1] *= corr0;
            ctx[j][2] *= corr1; ctx[j][3] *= corr1;
        }
        uint32_t pa[8], pb[8];
        #pragma unroll
        for (int j = 0; j < 8; j++) {
            float p0 = ex2f(sc[j][0] - mn0);
            float p1 = ex2f(sc[j][1] - mn0);
            float p2 = ex2f(sc[j][2] - mn1);
            float p3 = ex2f(sc[j][3] - mn1);
            l0 += p0 + p1; l1 += p2 + p3;
            __nv_bfloat162 t0 = __floats2bfloat162_rn(p0, p1);
            __nv_bfloat162 t1 = __floats2bfloat162_rn(p2, p3);
            pa[j] = *(uint32_t*)&t0;
            pb[j] = *(uint32_t*)&t1;
        }

        uint32_t v_off = (uint32_t)(lane & 15) * AROWB + ((lane >> 4) & 1) * 16;
        #pragma unroll
        for (int ks = 0; ks < 4; ks++) {
            #pragma unroll
            for (int nd = 0; nd < 4; nd++) {
                uint32_t r0, r1, r2, r3;
                ldmx4t(vbse + v_off + (uint32_t)ks * (16 * AROWB) + nd * 32, r0, r1, r2, r3);
                mma16816(ctx[nd * 2],     pa[2 * ks], pb[2 * ks], pa[2 * ks + 1], pb[2 * ks + 1], r0, r1);
                mma16816(ctx[nd * 2 + 1], pa[2 * ks], pb[2 * ks], pa[2 * ks + 1], pb[2 * ks + 1], r2, r3);
            }
        }
        __syncthreads();
    }

    l0 += __shfl_xor_sync(0xffffffffu, l0, 1);
    l0 += __shfl_xor_sync(0xffffffffu, l0, 2);
    l1 += __shfl_xor_sync(0xffffffffu, l1, 1);
    l1 += __shfl_xor_sync(0xffffffffu, l1, 2);
    float i0 = 1.f / l0, i1 = 1.f / l1;

    int tr = lane >> 2, tc = (lane & 3) * 2;
    int row0 = q0 + wid * 16 + tr;
    #pragma unroll
    for (int f = 0; f < 8; f++) {
        int d = f * 8 + tc;
        float* c = ctx[f];
        size_t o0 = ((size_t)b * SEQ + row0) * DIM + (size_t)h * HDIM + d;
        size_t o1 = ((size_t)b * SEQ + row0 + 8) * DIM + (size_t)h * HDIM + d;
        float w0 = c[0] * i0, w1 = c[1] * i0;
        float w2 = c[2] * i1, w3 = c[3] * i1;
        __nv_bfloat162 h0, h1, l0v, l1v;
        h0.x = __float2bfloat16_rn(w0); h0.y = __float2bfloat16_rn(w1);
        h1.x = __float2bfloat16_rn(w2); h1.y = __float2bfloat16_rn(w3);
        l0v.x = __float2bfloat16_rn(w0 - __bfloat162float(h0.x));
        l0v.y = __float2bfloat16_rn(w1 - __bfloat162float(h0.y));
        l1v.x = __float2bfloat16_rn(w2 - __bfloat162float(h1.x));
        l1v.y = __float2bfloat16_rn(w3 - __bfloat162float(h1.y));
        *(__nv_bfloat162*)(Ohi + o0) = h0;
        *(__nv_bfloat162*)(Ohi + o1) = h1;
        *(__nv_bfloat162*)(Olo + o0) = l0v;
        *(__nv_bfloat162*)(Olo + o1) = l1v;
    }
}

// ---------------- SwiGLU combine -> bf16 hi/lo ----------------
__global__ void silu_mul_kernel(const float* __restrict__ g, const float* __restrict__ u,
                                __nv_bfloat16* __restrict__ ohi,
                                __nv_bfloat16* __restrict__ olo, size_t n) {
    size_t i = (size_t)blockIdx.x * 256 + threadIdx.x;
    if (i < n) {
        float x = g[i];
        float v = (x / (1.f + expf(-x))) * u[i];
        __nv_bfloat16 hi = __float2bfloat16_rn(v);
        ohi[i] = hi;
        olo[i] = __float2bfloat16_rn(v - __bfloat162float(hi));
    }
}

// ---------------- launch ----------------
extern "C" void kernel_launch(void* const* d_in, const int* in_sizes, int n_in,
                              void* d_out, int out_size) {
    const float* x_in   = (const float*)d_in[0];
    const float* Wq     = (const float*)d_in[1];
    const float* Wk     = (const float*)d_in[2];
    const float* Wv     = (const float*)d_in[3];
    const float* Wo     = (const float*)d_in[4];
    const float* ln1_w  = (const float*)d_in[5];
    const float* ln2_w  = (const float*)d_in[6];
    const float* Wgate  = (const float*)d_in[7];
    const float* Wup    = (const float*)d_in[8];
    const float* Wdown  = (const float*)d_in[9];
    const float* W_out  = (const float*)d_in[10];
    const float* b_out  = (const float*)d_in[11];
    float* out = (float*)d_out;

    float *x, *q, *k, *v, *f1, *f2;
    __nv_bfloat16 *hhi, *hlo, *chi, *clo, *f1hi, *f1lo, *xhi, *xlo, *whi, *wlo;
    __nv_bfloat16 *qhi, *qlo, *khi, *klo, *vbp;
    cudaGetSymbolAddress((void**)&x,    g_x);
    cudaGetSymbolAddress((void**)&q,    g_q);
    cudaGetSymbolAddress((void**)&k,    g_k);
    cudaGetSymbolAddress((void**)&v,    g_v);
    cudaGetSymbolAddress((void**)&f1,   g_f1);
    cudaGetSymbolAddress((void**)&f2,   g_f2);
    cudaGetSymbolAddress((void**)&hhi,  g_hhi);
    cudaGetSymbolAddress((void**)&hlo,  g_hlo);
    cudaGetSymbolAddress((void**)&chi,  g_chi);
    cudaGetSymbolAddress((void**)&clo,  g_clo);
    cudaGetSymbolAddress((void**)&f1hi, g_f1hi);
    cudaGetSymbolAddress((void**)&f1lo, g_f1lo);
    cudaGetSymbolAddress((void**)&xhi,  g_xhi);
    cudaGetSymbolAddress((void**)&xlo,  g_xlo);
    cudaGetSymbolAddress((void**)&whi,  g_whi);
    cudaGetSymbolAddress((void**)&wlo,  g_wlo);
    cudaGetSymbolAddress((void**)&qhi,  g_qhi);
    cudaGetSymbolAddress((void**)&qlo,  g_qlo);
    cudaGetSymbolAddress((void**)&khi,  g_khi);
    cudaGetSymbolAddress((void**)&klo,  g_klo);
    cudaGetSymbolAddress((void**)&vbp,  g_vb);

    cudaFuncSetAttribute(gemm_bf, cudaFuncAttributeMaxDynamicSharedMemorySize, GSMEM2);
    cudaFuncSetAttribute(attn_mma, cudaFuncAttributeMaxDynamicSharedMemorySize, ASMEM);

    const size_t xbytes = (size_t)ROWS * DIM * sizeof(float);
    cudaMemcpyAsync(x, x_in, xbytes, cudaMemcpyDeviceToDevice);

    // --- weight converts (fp32 -> bf16 hi/lo) ---
    const int DD4 = DIM * DIM / 4, FD4 = FFDIM * DIM / 4;
    wcvt_kernel<<<DD4 / 256, 256>>>(Wq,    whi + WOFF_Q, wlo + WOFF_Q, DD4);
    wcvt_kernel<<<DD4 / 256, 256>>>(Wk,    whi + WOFF_K, wlo + WOFF_K, DD4);
    wcvt_kernel<<<DD4 / 256, 256>>>(Wv,    whi + WOFF_V, wlo + WOFF_V, DD4);
    wcvt_kernel<<<DD4 / 256, 256>>>(Wo,    whi + WOFF_O, wlo + WOFF_O, DD4);
    wcvt_kernel<<<FD4 / 256, 256>>>(Wgate, whi + WOFF_G, wlo + WOFF_G, FD4);
    wcvt_kernel<<<FD4 / 256, 256>>>(Wup,   whi + WOFF_U, wlo + WOFF_U, FD4);
    wcvt_kernel<<<FD4 / 256, 256>>>(Wdown, whi + WOFF_D, wlo + WOFF_D, FD4);
    wcvt_kernel<<<DD4 / 256, 256>>>(W_out, whi + WOFF_H, wlo + WOFF_H, DD4);

    // --- attention block ---
    rmsnorm_kernel<<<ROWS, 256>>>(x, ln1_w, hhi, hlo);

    dim3 g1(DIM / GBN, ROWS / GBM);    // (8, 64)
    dim3 g2(FFDIM / GBN, ROWS / GBM);  // (32, 64)

    gemm_bf<<<g1, 256, GSMEM2>>>(hhi, hlo, whi + WOFF_Q, wlo + WOFF_Q,
                                 nullptr, nullptr, q, nullptr, nullptr, ROWS, DIM, DIM);
    gemm_bf<<<g1, 256, GSMEM2>>>(hhi, hlo, whi + WOFF_K, wlo + WOFF_K,
                                 nullptr, nullptr, k, nullptr, nullptr, ROWS, DIM, DIM);
    gemm_bf<<<g1, 256, GSMEM2>>>(hhi, hlo, whi + WOFF_V, wlo + WOFF_V,
                                 nullptr, nullptr, v, nullptr, nullptr, ROWS, DIM, DIM);

    int rope_total = BATCH * SEQ * NHEAD * (HDIM / 2);
    rope_cvt_kernel<<<(rope_total + 255) / 256, 256>>>(q, k, qhi, qlo, khi, klo);
    v_cvt_kernel<<<(ROWS * DIM / 4 + 255) / 256, 256>>>(v, vbp);

    dim3 ga(SEQ / 64, NHEAD, BATCH);
    attn_mma<<<ga, 128, ASMEM>>>(qhi, qlo, khi, klo, vbp, chi, clo);

    // x = x + ctx @ Wo^T
    gemm_bf<<<g1, 256, GSMEM2>>>(chi, clo, whi + WOFF_O, wlo + WOFF_O,
                                 x, nullptr, x, nullptr, nullptr, ROWS, DIM, DIM);

    // --- MLP block ---
    rmsnorm_kernel<<<ROWS, 256>>>(x, ln2_w, hhi, hlo);
    gemm_bf<<<g2, 256, GSMEM2>>>(hhi, hlo, whi + WOFF_G, wlo + WOFF_G,
                                 nullptr, nullptr, f1, nullptr, nullptr, ROWS, FFDIM, DIM);
    gemm_bf<<<g2, 256, GSMEM2>>>(hhi, hlo, whi + WOFF_U, wlo + WOFF_U,
                                 nullptr, nullptr, f2, nullptr, nullptr, ROWS, FFDIM, DIM);

    size_t ffn = (size_t)ROWS * FFDIM;
    silu_mul_kernel<<<(unsigned)((ffn + 255) / 256), 256>>>(f1, f2, f1hi, f1lo, ffn);

    // x_new = x + f1b @ Wdown^T  -> emit bf16 hi/lo only (feeds head GEMM)
    gemm_bf<<<g1, 256, GSMEM2>>>(f1hi, f1lo, whi + WOFF_D, wlo + WOFF_D,
                                 x, nullptr, nullptr, xhi, xlo, ROWS, DIM, FFDIM);

    // --- output head ---
    gemm_bf<<<g1, 256, GSMEM2>>>(xhi, xlo, whi + WOFF_H, wlo + WOFF_H,
                                 nullptr, b_out, out, nullptr, nullptr, ROWS, DIM, DIM);
}

// round 7
// speedup vs baseline: 3.7135x; 1.0323x over previous
#include <cuda_runtime.h>
#include <cuda_bf16.h>
#include <cstdint>

// Problem constants
#define BATCH 4
#define SEQ   2048
#define DIM   1024
#define NHEAD 16
#define HDIM  64
#define FFDIM 4096
#define ROWS  (BATCH * SEQ)            // 8192
#define LN_EPS 1e-6f

// ---------------- scratch (device globals; no allocation) ----------------
__device__ float g_x  [(size_t)ROWS * DIM];
__device__ float g_qkv[(size_t)ROWS * 3 * DIM];
__device__ float g_f1 [(size_t)ROWS * FFDIM];
// bf16 hi/lo activation operands
__device__ __nv_bfloat16 g_hhi [(size_t)ROWS * DIM];
__device__ __nv_bfloat16 g_hlo [(size_t)ROWS * DIM];
__device__ __nv_bfloat16 g_chi [(size_t)ROWS * DIM];
__device__ __nv_bfloat16 g_clo [(size_t)ROWS * DIM];
__device__ __nv_bfloat16 g_f1hi[(size_t)ROWS * FFDIM];
__device__ __nv_bfloat16 g_f1lo[(size_t)ROWS * FFDIM];
__device__ __nv_bfloat16 g_xhi [(size_t)ROWS * DIM];
__device__ __nv_bfloat16 g_xlo [(size_t)ROWS * DIM];
// bf16 hi/lo weights (Wq|Wk|Wv|Wo|Wgate|Wup|Wdown|W_out)
#define WOFF_Q  0
#define WOFF_K  1048576
#define WOFF_V  2097152
#define WOFF_O  3145728
#define WOFF_G  4194304
#define WOFF_U  8388608
#define WOFF_D  12582912
#define WOFF_H  16777216
#define WTOT    17825792
__device__ __nv_bfloat16 g_whi[(size_t)WTOT];
__device__ __nv_bfloat16 g_wlo[(size_t)WTOT];
// bf16 attention operands, [B,H,S,HD] layout
__device__ __nv_bfloat16 g_qhi[(size_t)ROWS * DIM];
__device__ __nv_bfloat16 g_qlo[(size_t)ROWS * DIM];
__device__ __nv_bfloat16 g_khi[(size_t)ROWS * DIM];
__device__ __nv_bfloat16 g_klo[(size_t)ROWS * DIM];
__device__ __nv_bfloat16 g_vb [(size_t)ROWS * DIM];

__device__ __forceinline__ uint32_t smem_u32(const void* p) {
    uint32_t a;
    asm("{ .reg .u64 t; cvta.to.shared.u64 t, %1; cvt.u32.u64 %0, t; }"
        : "=r"(a) : "l"(p));
    return a;
}
__device__ __forceinline__ void cvt_hilo4(float4 v, uint2& hi, uint2& lo) {
    __nv_bfloat162 h01, h23, l01, l23;
    h01.x = __float2bfloat16_rn(v.x);
    h01.y = __float2bfloat16_rn(v.y);
    h23.x = __float2bfloat16_rn(v.z);
    h23.y = __float2bfloat16_rn(v.w);
    l01.x = __float2bfloat16_rn(v.x - __bfloat162float(h01.x));
    l01.y = __float2bfloat16_rn(v.y - __bfloat162float(h01.y));
    l23.x = __float2bfloat16_rn(v.z - __bfloat162float(h23.x));
    l23.y = __float2bfloat16_rn(v.w - __bfloat162float(h23.y));
    hi.x = *(uint32_t*)&h01; hi.y = *(uint32_t*)&h23;
    lo.x = *(uint32_t*)&l01; lo.y = *(uint32_t*)&l23;
}
__device__ __forceinline__ void ldmx4(uint32_t addr, uint32_t& r0, uint32_t& r1,
                                      uint32_t& r2, uint32_t& r3) {
    asm volatile("ldmatrix.sync.aligned.m8n8.x4.shared.b16 {%0,%1,%2,%3}, [%4];"
                 : "=r"(r0), "=r"(r1), "=r"(r2), "=r"(r3) : "r"(addr));
}
__device__ __forceinline__ void ldmx4t(uint32_t addr, uint32_t& r0, uint32_t& r1,
                                       uint32_t& r2, uint32_t& r3) {
    asm volatile("ldmatrix.sync.aligned.m8n8.x4.trans.shared.b16 {%0,%1,%2,%3}, [%4];"
                 : "=r"(r0), "=r"(r1), "=r"(r2), "=r"(r3) : "r"(addr));
}
__device__ __forceinline__ void mma16816(float* c, uint32_t a0, uint32_t a1,
                                         uint32_t a2, uint32_t a3,
                                         uint32_t b0, uint32_t b1) {
    asm volatile(
        "mma.sync.aligned.m16n8k16.row.col.f32.bf16.bf16.f32 "
        "{%0,%1,%2,%3}, {%4,%5,%6,%7}, {%8,%9}, {%0,%1,%2,%3};"
        : "+f"(c[0]), "+f"(c[1]), "+f"(c[2]), "+f"(c[3])
        : "r"(a0), "r"(a1), "r"(a2), "r"(a3), "r"(b0), "r"(b1));
}
__device__ __forceinline__ float ex2f(float x) {
    float r;
    asm("ex2.approx.f32 %0, %1;" : "=f"(r) : "f"(x));
    return r;
}
#define CPA16(dst, src) \
    asm volatile("cp.async.cg.shared.global [%0], [%1], 16;" :: "r"(dst), "l"(src))
#define CPA_COMMIT() asm volatile("cp.async.commit_group;" ::: "memory")
#define CPA_WAIT(n)  asm volatile("cp.async.wait_group %0;" :: "n"(n) : "memory")

// ---------------- weight convert: fp32 -> bf16 hi/lo ----------------
__global__ void wcvt_kernel(const float* __restrict__ src,
                            __nv_bfloat16* __restrict__ hi,
                            __nv_bfloat16* __restrict__ lo, int n4) {
    int t = blockIdx.x * 256 + threadIdx.x;
    if (t >= n4) return;
    float4 v = *(const float4*)(src + (size_t)t * 4);
    uint2 h, l;
    cvt_hilo4(v, h, l);
    *(uint2*)(hi + (size_t)t * 4) = h;
    *(uint2*)(lo + (size_t)t * 4) = l;
}

// ================= gemm256: tile 128x256, BK=64, 2-stage, warp 64x64 ======
// C[M,N] = A @ W^T ; optional gate (silu fusion), fp32 out, hi/lo out.
#define QBM 128
#define QBN 256
#define QBK 64
#define Q_ALO 16384
#define Q_WHI 32768
#define Q_WLO 65536
#define QSTG  98304
#define QSMEM (2 * QSTG)       // 196608

__global__ __launch_bounds__(256)
void gemm256(const __nv_bfloat16* __restrict__ Ahi, const __nv_bfloat16* __restrict__ Alo,
             const __nv_bfloat16* __restrict__ Whi, const __nv_bfloat16* __restrict__ Wlo,
             const float* __restrict__ gate,
             float* __restrict__ C,
             __nv_bfloat16* __restrict__ Chi, __nv_bfloat16* __restrict__ Clo,
             int M, int N, int K) {
    extern __shared__ char smem[];
    uint32_t sb = smem_u32(smem);
    int tid = threadIdx.x, wid = tid >> 5, lane = tid & 31;
    int bm = blockIdx.y * QBM, bn = blockIdx.x * QBN;
    int warp_m = (wid >> 2) * 64, warp_n = (wid & 3) * 64;

    uint32_t xw = (((uint32_t)(tid >> 3) & 7u) << 4);
    uint32_t st_off = (uint32_t)(tid >> 3) * 128 + (((uint32_t)(tid & 7) * 16) ^ xw);
    const __nv_bfloat16* Ah = Ahi + (size_t)(bm + (tid >> 3)) * K + (tid & 7) * 8;
    const __nv_bfloat16* Al = Alo + (size_t)(bm + (tid >> 3)) * K + (tid & 7) * 8;
    const __nv_bfloat16* Wh = Whi + (size_t)(bn + (tid >> 3)) * K + (tid & 7) * 8;
    const __nv_bfloat16* Wl = Wlo + (size_t)(bn + (tid >> 3)) * K + (tid & 7) * 8;

    auto load_stage = [&](int s, int chunk) {
        uint32_t base = sb + (uint32_t)s * QSTG;
        size_t ko = (size_t)chunk * QBK;
        #pragma unroll
        for (int j = 0; j < 4; j++) {
            uint32_t d = base + st_off + j * 4096;
            size_t ro = (size_t)j * 32 * K + ko;
            CPA16(d,         (const char*)(Ah + ro));
            CPA16(d + Q_ALO, (const char*)(Al + ro));
        }
        #pragma unroll
        for (int j = 0; j < 8; j++) {
            uint32_t d = base + Q_WHI + st_off + j * 4096;
            size_t ro = (size_t)j * 32 * K + ko;
            CPA16(d,                     (const char*)(Wh + ro));
            CPA16(d + (Q_WLO - Q_WHI),   (const char*)(Wl + ro));
        }
    };

    int r_a = warp_m + (lane & 15);
    uint32_t xa = ((uint32_t)(r_a & 7) << 4);
    uint32_t a_row = (uint32_t)r_a * 128;
    int r_b = warp_n + (lane & 7) + ((lane >> 4) & 1) * 8;
    uint32_t xb = ((uint32_t)(r_b & 7) << 4);
    uint32_t b_row = (uint32_t)r_b * 128;
    uint32_t col_a[4], col_b[4];
    int ha = ((lane >> 4) & 1) * 16;
    int hb = ((lane >> 3) & 1) * 16;
    #pragma unroll
    for (int ks = 0; ks < 4; ks++) {
        col_a[ks] = ((uint32_t)(ha + ks * 32)) ^ xa;
        col_b[ks] = ((uint32_t)(hb + ks * 32)) ^ xb;
    }

    float acc[4][8][4];
    #pragma unroll
    for (int i = 0; i < 4; i++)
        #pragma unroll
        for (int j = 0; j < 8; j++)
            #pragma unroll
            for (int r = 0; r < 4; r++) acc[i][j][r] = 0.f;

    const int nk = K / QBK;
    load_stage(0, 0);
    CPA_COMMIT();

    for (int i = 0; i < nk; i++) {
        if (i + 1 < nk) {
            load_stage((i + 1) & 1, i + 1);
            CPA_COMMIT();
            CPA_WAIT(1);
        } else {
            CPA_WAIT(0);
        }
        __syncthreads();

        uint32_t base = sb + (uint32_t)(i & 1) * QSTG;
        #pragma unroll
        for (int ks = 0; ks < 4; ks++) {
            uint32_t ahr[4][4], alr[4][4];
            #pragma unroll
            for (int mf = 0; mf < 4; mf++) {
                uint32_t ad = base + a_row + (uint32_t)mf * 2048 + col_a[ks];
                ldmx4(ad,         ahr[mf][0], ahr[mf][1], ahr[mf][2], ahr[mf][3]);
                ldmx4(ad + Q_ALO, alr[mf][0], alr[mf][1], alr[mf][2], alr[mf][3]);
            }
            uint32_t bhr[4][4], blr[4][4];
            #pragma unroll
            for (int np = 0; np < 4; np++) {
                uint32_t bd = base + Q_WHI + b_row + (uint32_t)np * 2048 + col_b[ks];
                ldmx4(bd,                   bhr[np][0], bhr[np][1], bhr[np][2], bhr[np][3]);
                ldmx4(bd + (Q_WLO - Q_WHI), blr[np][0], blr[np][1], blr[np][2], blr[np][3]);
            }
            #pragma unroll
            for (int mf = 0; mf < 4; mf++) {
                #pragma unroll
                for (int nf = 0; nf < 8; nf++) {
                    uint32_t bh0 = bhr[nf >> 1][(nf & 1) * 2];
                    uint32_t bh1 = bhr[nf >> 1][(nf & 1) * 2 + 1];
                    uint32_t bl0 = blr[nf >> 1][(nf & 1) * 2];
                    uint32_t bl1 = blr[nf >> 1][(nf & 1) * 2 + 1];
                    mma16816(acc[mf][nf], ahr[mf][0], ahr[mf][1], ahr[mf][2], ahr[mf][3], bh0, bh1);
                    mma16816(acc[mf][nf], ahr[mf][0], ahr[mf][1], ahr[mf][2], ahr[mf][3], bl0, bl1);
                    mma16816(acc[mf][nf], alr[mf][0], alr[mf][1], alr[mf][2], alr[mf][3], bh0, bh1);
                }
            }
        }
        __syncthreads();
    }

    // ---- epilogue ----
    int tr = lane >> 2, tc = (lane & 3) * 2;
    #pragma unroll
    for (int mf = 0; mf < 4; mf++) {
        #pragma unroll
        for (int nf = 0; nf < 8; nf++) {
            int row0 = bm + warp_m + mf * 16 + tr;
            int col  = bn + warp_n + nf * 8 + tc;
            float* c = acc[mf][nf];
            float v[4] = {c[0], c[1], c[2], c[3]};
            size_t o0 = (size_t)row0 * N + col;
            size_t o1 = (size_t)(row0 + 8) * N + col;
            if (gate) {
                float2 g0 = *(const float2*)(gate + o0);
                float2 g1 = *(const float2*)(gate + o1);
                v[0] *= g0.x / (1.f + expf(-g0.x));
                v[1] *= g0.y / (1.f + expf(-g0.y));
                v[2] *= g1.x / (1.f + expf(-g1.x));
                v[3] *= g1.y / (1.f + expf(-g1.y));
            }
            if (C) {
                *(float2*)(C + o0) = {v[0], v[1]};
                *(float2*)(C + o1) = {v[2], v[3]};
            }
            if (Chi) {
                __nv_bfloat162 h0, h1, l0, l1;
                h0.x = __float2bfloat16_rn(v[0]); h0.y = __float2bfloat16_rn(v[1]);
                h1.x = __float2bfloat16_rn(v[2]); h1.y = __float2bfloat16_rn(v[3]);
                l0.x = __float2bfloat16_rn(v[0] - __bfloat162float(h0.x));
                l0.y = __float2bfloat16_rn(v[1] - __bfloat162float(h0.y));
                l1.x = __float2bfloat16_rn(v[2] - __bfloat162float(h1.x));
                l1.y = __float2bfloat16_rn(v[3] - __bfloat162float(h1.y));
                *(__nv_bfloat162*)(Chi + o0) = h0;
                *(__nv_bfloat162*)(Chi + o1) = h1;
                *(__nv_bfloat162*)(Clo + o0) = l0;
                *(__nv_bfloat162*)(Clo + o1) = l1;
            }
        }
    }
}

// ================= gemm_bf: tile 128x128, BK=64, 3-stage ==================
#define GBM 128
#define GBN 128
#define GBK 64
#define GA_LO 16384
#define GW_HI 32768
#define GW_LO 49152
#define GSTG  65536
#define GSMEM2 (3 * GSTG)      // 196608

__global__ __launch_bounds__(256)
void gemm_bf(const __nv_bfloat16* __restrict__ Ahi, const __nv_bfloat16* __restrict__ Alo,
             const __nv_bfloat16* __restrict__ Whi, const __nv_bfloat16* __restrict__ Wlo,
             const float* __restrict__ res, const float* __restrict__ bias,
             float* __restrict__ C,
             __nv_bfloat16* __restrict__ Chi, __nv_bfloat16* __restrict__ Clo,
             int M, int N, int K) {
    extern __shared__ char smem[];
    uint32_t sb = smem_u32(smem);
    int tid = threadIdx.x, wid = tid >> 5, lane = tid & 31;
    int bm = blockIdx.y * GBM, bn = blockIdx.x * GBN;
    int warp_m = (wid >> 2) * 64, warp_n = (wid & 3) * 32;

    uint32_t xw = (((uint32_t)(tid >> 3) & 7u) << 4);
    uint32_t st_off = (uint32_t)(tid >> 3) * 128 + (((uint32_t)(tid & 7) * 16) ^ xw);
    const __nv_bfloat16* Ah = Ahi + (size_t)(bm + (tid >> 3)) * K + (tid & 7) * 8;
    const __nv_bfloat16* Al = Alo + (size_t)(bm + (tid >> 3)) * K + (tid & 7) * 8;
    const __nv_bfloat16* Wh = Whi + (size_t)(bn + (tid >> 3)) * K + (tid & 7) * 8;
    const __nv_bfloat16* Wl = Wlo + (size_t)(bn + (tid >> 3)) * K + (tid & 7) * 8;

    auto load_stage = [&](int s, int chunk) {
        uint32_t base = sb + (uint32_t)s * GSTG;
        size_t ko = (size_t)chunk * GBK;
        #pragma unroll
        for (int j = 0; j < 4; j++) {
            uint32_t d = base + st_off + j * 4096;
            size_t ro = (size_t)j * 32 * K + ko;
            CPA16(d,         (const char*)(Ah + ro));
            CPA16(d + GA_LO, (const char*)(Al + ro));
            CPA16(d + GW_HI, (const char*)(Wh + ro));
            CPA16(d + GW_LO, (const char*)(Wl + ro));
        }
    };

    int r_a = warp_m + (lane & 15);
    uint32_t xa = ((uint32_t)(r_a & 7) << 4);
    uint32_t a_row = (uint32_t)r_a * 128;
    int r_b = warp_n + (lane & 7) + ((lane >> 4) & 1) * 8;
    uint32_t xb = ((uint32_t)(r_b & 7) << 4);
    uint32_t b_row = (uint32_t)r_b * 128;
    uint32_t col_a[4], col_b[4];
    int ha = ((lane >> 4) & 1) * 16;
    int hb = ((lane >> 3) & 1) * 16;
    #pragma unroll
    for (int ks = 0; ks < 4; ks++) {
        col_a[ks] = ((uint32_t)(ha + ks * 32)) ^ xa;
        col_b[ks] = ((uint32_t)(hb + ks * 32)) ^ xb;
    }

    float acc[4][4][4];
    #pragma unroll
    for (int i = 0; i < 4; i++)
        #pragma unroll
        for (int j = 0; j < 4; j++)
            #pragma unroll
            for (int r = 0; r < 4; r++) acc[i][j][r] = 0.f;

    const int nk = K / GBK;
    load_stage(0, 0);
    CPA_COMMIT();
    if (nk > 1) load_stage(1, 1);
    CPA_COMMIT();

    int sc = 0;
    for (int i = 0; i < nk; i++) {
        int snx = sc + 2; if (snx >= 3) snx -= 3;
        if (i + 2 < nk) load_stage(snx, i + 2);
        CPA_COMMIT();
        CPA_WAIT(2);
        __syncthreads();

        uint32_t base = sb + (uint32_t)sc * GSTG;
        #pragma unroll
        for (int ks = 0; ks < 4; ks++) {
            uint32_t ahr[4][4], alr[4][4];
            #pragma unroll
            for (int mf = 0; mf < 4; mf++) {
                uint32_t ad = base + a_row + (uint32_t)mf * 2048 + col_a[ks];
                ldmx4(ad,         ahr[mf][0], ahr[mf][1], ahr[mf][2], ahr[mf][3]);
                ldmx4(ad + GA_LO, alr[mf][0], alr[mf][1], alr[mf][2], alr[mf][3]);
            }
            uint32_t bhr[2][4], blr[2][4];
            #pragma unroll
            for (int np = 0; np < 2; np++) {
                uint32_t bd = base + GW_HI + b_row + (uint32_t)np * 2048 + col_b[ks];
                ldmx4(bd,         bhr[np][0], bhr[np][1], bhr[np][2], bhr[np][3]);
                ldmx4(bd + 16384, blr[np][0], blr[np][1], blr[np][2], blr[np][3]);
            }
            #pragma unroll
            for (int mf = 0; mf < 4; mf++) {
                #pragma unroll
                for (int nf = 0; nf < 4; nf++) {
                    uint32_t bh0 = bhr[nf >> 1][(nf & 1) * 2];
                    uint32_t bh1 = bhr[nf >> 1][(nf & 1) * 2 + 1];
                    uint32_t bl0 = blr[nf >> 1][(nf & 1) * 2];
                    uint32_t bl1 = blr[nf >> 1][(nf & 1) * 2 + 1];
                    mma16816(acc[mf][nf], ahr[mf][0], ahr[mf][1], ahr[mf][2], ahr[mf][3], bh0, bh1);
                    mma16816(acc[mf][nf], ahr[mf][0], ahr[mf][1], ahr[mf][2], ahr[mf][3], bl0, bl1);
                    mma16816(acc[mf][nf], alr[mf][0], alr[mf][1], alr[mf][2], alr[mf][3], bh0, bh1);
                }
            }
        }
        __syncthreads();
        sc = (sc == 2) ? 0 : sc + 1;
    }

    int tr = lane >> 2, tc = (lane & 3) * 2;
    #pragma unroll
    for (int mf = 0; mf < 4; mf++) {
        #pragma unroll
        for (int nf = 0; nf < 4; nf++) {
            int row0 = bm + warp_m + mf * 16 + tr;
            int col  = bn + warp_n + nf * 8 + tc;
            float* c = acc[mf][nf];
            float2 v0 = {c[0], c[1]};
            float2 v1 = {c[2], c[3]};
            size_t o0 = (size_t)row0 * N + col;
            size_t o1 = (size_t)(row0 + 8) * N + col;
            if (res) {
                float2 r0 = *(const float2*)(res + o0);
                float2 r1 = *(const float2*)(res + o1);
                v0.x += r0.x; v0.y += r0.y; v1.x += r1.x; v1.y += r1.y;
            }
            if (bias) {
                float2 bb = *(const float2*)(bias + col);
                v0.x += bb.x; v0.y += bb.y; v1.x += bb.x; v1.y += bb.y;
            }
            if (C) {
                *(float2*)(C + o0) = v0;
                *(float2*)(C + o1) = v1;
            }
            if (Chi) {
                __nv_bfloat162 h0, h1, l0, l1;
                h0.x = __float2bfloat16_rn(v0.x); h0.y = __float2bfloat16_rn(v0.y);
                h1.x = __float2bfloat16_rn(v1.x); h1.y = __float2bfloat16_rn(v1.y);
                l0.x = __float2bfloat16_rn(v0.x - __bfloat162float(h0.x));
                l0.y = __float2bfloat16_rn(v0.y - __bfloat162float(h0.y));
                l1.x = __float2bfloat16_rn(v1.x - __bfloat162float(h1.x));
                l1.y = __float2bfloat16_rn(v1.y - __bfloat162float(h1.y));
                *(__nv_bfloat162*)(Chi + o0) = h0;
                *(__nv_bfloat162*)(Chi + o1) = h1;
                *(__nv_bfloat162*)(Clo + o0) = l0;
                *(__nv_bfloat162*)(Clo + o1) = l1;
            }
        }
    }
}

// ---------------- RMSNorm -> bf16 hi/lo ----------------
__global__ void rmsnorm_kernel(const float* __restrict__ x,
                               const float* __restrict__ w,
                               __nv_bfloat16* __restrict__ ohi,
                               __nv_bfloat16* __restrict__ olo) {
    int row = blockIdx.x;
    const float* xr = x + (size_t)row * DIM;
    float s = 0.f;
    #pragma unroll
    for (int i = threadIdx.x; i < DIM; i += 256) {
        float v = xr[i];
        s += v * v;
    }
    __shared__ float red[8];
    #pragma unroll
    for (int o = 16; o; o >>= 1) s += __shfl_down_sync(0xffffffffu, s, o);
    if ((threadIdx.x & 31) == 0) red[threadIdx.x >> 5] = s;
    __syncthreads();
    if (threadIdx.x < 8) {
        float t = red[threadIdx.x];
        #pragma unroll
        for (int o = 4; o; o >>= 1) t += __shfl_down_sync(0xffu, t, o);
        if (threadIdx.x == 0) red[0] = t;
    }
    __syncthreads();
    float inv = rsqrtf(red[0] * (1.0f / DIM) + LN_EPS);
    #pragma unroll
    for (int i = threadIdx.x; i < DIM; i += 256) {
        float v = xr[i] * inv * w[i];
        __nv_bfloat16 hi = __float2bfloat16_rn(v);
        ohi[(size_t)row * DIM + i] = hi;
        olo[(size_t)row * DIM + i] = __float2bfloat16_rn(v - __bfloat162float(hi));
    }
}

// ------------- RoPE on qkv buffer [rows,3072] -> hi/lo [B,H,S,HD] ----------
#define QSCALE 0.18033688011111793f   // 0.125 * log2(e)
__global__ void rope_cvt_kernel(const float* __restrict__ QKV,
                                __nv_bfloat16* __restrict__ qhi, __nv_bfloat16* __restrict__ qlo,
                                __nv_bfloat16* __restrict__ khi, __nv_bfloat16* __restrict__ klo) {
    int idx = blockIdx.x * 256 + threadIdx.x;
    if (idx >= BATCH * SEQ * NHEAD * (HDIM / 2)) return;
    int d = idx & 31;
    int h = (idx >> 5) & (NHEAD - 1);
    int s = (idx >> 9) & (SEQ - 1);
    int b = idx >> 20;
    size_t ibase = ((size_t)b * SEQ + s) * (3 * DIM) + (size_t)h * HDIM;
    size_t obase = (((size_t)b * NHEAD + h) * SEQ + s) * HDIM;
    float inv = expf(-(float)d * (9.210340371976184f / 32.f));
    float ang = (float)s * inv;
    float sn, cs;
    sincosf(ang, &sn, &cs);
    {
        float x1 = QKV[ibase + d], x2 = QKV[ibase + d + 32];
        float r1 = (x1 * cs - x2 * sn) * QSCALE;
        float r2 = (x2 * cs + x1 * sn) * QSCALE;
        __nv_bfloat16 h1 = __float2bfloat16_rn(r1);
        __nv_bfloat16 h2 = __float2bfloat16_rn(r2);
        qhi[obase + d]      = h1;
        qhi[obase + d + 32] = h2;
        qlo[obase + d]      = __float2bfloat16_rn(r1 - __bfloat162float(h1));
        qlo[obase + d + 32] = __float2bfloat16_rn(r2 - __bfloat162float(h2));
    }
    {
        float x1 = QKV[ibase + DIM + d], x2 = QKV[ibase + DIM + d + 32];
        float r1 = x1 * cs - x2 * sn;
        float r2 = x2 * cs + x1 * sn;
        __nv_bfloat16 h1 = __float2bfloat16_rn(r1);
        __nv_bfloat16 h2 = __float2bfloat16_rn(r2);
        khi[obase + d]      = h1;
        khi[obase + d + 32] = h2;
        klo[obase + d]      = __float2bfloat16_rn(r1 - __bfloat162float(h1));
        klo[obase + d + 32] = __float2bfloat16_rn(r2 - __bfloat162float(h2));
    }
}

// ------------- V convert: qkv fp32 -> bf16 [B,H,S,HD] -------------
__global__ void v_cvt_kernel(const float* __restrict__ QKV, __nv_bfloat16* __restrict__ vb) {
    int t = blockIdx.x * 256 + threadIdx.x;
    if (t >= ROWS * DIM / 4) return;
    int e = t * 4;
    int c = e & 63;
    int h = (e >> 6) & (NHEAD - 1);
    int s = (e >> 10) & (SEQ - 1);
    int b = e >> 21;
    size_t ioff = ((size_t)b * SEQ + s) * (3 * DIM) + 2 * DIM + (size_t)h * HDIM + c;
    size_t ooff = (((size_t)b * NHEAD + h) * SEQ + s) * HDIM + c;
    float4 v = *(const float4*)(QKV + ioff);
    __nv_bfloat162 p0, p1;
    p0.x = __float2bfloat16_rn(v.x); p0.y = __float2bfloat16_rn(v.y);
    p1.x = __float2bfloat16_rn(v.z); p1.y = __float2bfloat16_rn(v.w);
    uint2 o = { *(uint32_t*)&p0, *(uint32_t*)&p1 };
    *(uint2*)(vb + ooff) = o;
}

// ================= MMA flash attention =================
#define AROWB 144
#define A_QHI 0
#define A_QLO 9216
#define A_K0  18432
#define A_V0  55296
#define ASMEM 73728

__global__ __launch_bounds__(128)
void attn_mma(const __nv_bfloat16* __restrict__ qhi, const __nv_bfloat16* __restrict__ qlo,
              const __nv_bfloat16* __restrict__ khi, const __nv_bfloat16* __restrict__ klo,
              const __nv_bfloat16* __restrict__ vb,
              __nv_bfloat16* __restrict__ Ohi, __nv_bfloat16* __restrict__ Olo) {
    extern __shared__ char smem[];
    uint32_t sb = smem_u32(smem);
    int tid = threadIdx.x, wid = tid >> 5, lane = tid & 31;
    int b = blockIdx.z, h = blockIdx.y;
    int q0 = blockIdx.x * 64;
    size_t hoff = ((size_t)b * NHEAD + h) * SEQ * HDIM;

    {
        const uint4* qh4 = (const uint4*)(qhi + hoff + (size_t)q0 * HDIM);
        const uint4* ql4 = (const uint4*)(qlo + hoff + (size_t)q0 * HDIM);
        #pragma unroll
        for (int j = 0; j < 4; j++) {
            int f = tid + j * 128;
            int r = f >> 3, c = f & 7;
            *(uint4*)(smem + A_QHI + r * AROWB + c * 16) = qh4[r * 8 + c];
            *(uint4*)(smem + A_QLO + r * AROWB + c * 16) = ql4[r * 8 + c];
        }
    }
    __syncthreads();

    uint32_t qh[4][4], ql[4][4];
    {
        uint32_t a_base = sb + (uint32_t)(wid * 16 + (lane & 15)) * AROWB + ((lane >> 4) & 1) * 16;
        #pragma unroll
        for (int ks = 0; ks < 4; ks++) {
            ldmx4(a_base + ks * 32,         qh[ks][0], qh[ks][1], qh[ks][2], qh[ks][3]);
            ldmx4(a_base + A_QLO + ks * 32, ql[ks][0], ql[ks][1], ql[ks][2], ql[ks][3]);
        }
    }

    float ctx[8][4];
    #pragma unroll
    for (int j = 0; j < 8; j++)
        #pragma unroll
        for (int r = 0; r < 4; r++) ctx[j][r] = 0.f;
    float m0 = -1e30f, m1 = -1e30f, l0 = 0.f, l1 = 0.f;

    const __nv_bfloat16* kh_g = khi + hoff;
    const __nv_bfloat16* kl_g = klo + hoff;
    const __nv_bfloat16* v_g  = vb + hoff;

    {
        #pragma unroll
        for (int j = 0; j < 4; j++) {
            int f = tid + j * 128;
            int r = f >> 3, c = f & 7;
            uint32_t so = (uint32_t)(r * AROWB + c * 16);
            CPA16(sb + A_K0 + so,        (const char*)(kh_g + r * 64 + c * 8));
            CPA16(sb + A_K0 + 9216 + so, (const char*)(kl_g + r * 64 + c * 8));
            CPA16(sb + A_V0 + so,        (const char*)(v_g  + r * 64 + c * 8));
        }
        CPA_COMMIT();
    }

    const int NT = SEQ / 64;
    for (int t = 0; t < NT; t++) {
        int s = t & 1;
        if (t + 1 < NT) {
            int nxt = s ^ 1;
            size_t goff = (size_t)(t + 1) * 64 * 64;
            #pragma unroll
            for (int j = 0; j < 4; j++) {
                int f = tid + j * 128;
                int r = f >> 3, c = f & 7;
                uint32_t so = (uint32_t)(r * AROWB + c * 16);
                CPA16(sb + A_K0 + nxt * 18432 + so,        (const char*)(kh_g + goff + r * 64 + c * 8));
                CPA16(sb + A_K0 + nxt * 18432 + 9216 + so, (const char*)(kl_g + goff + r * 64 + c * 8));
                CPA16(sb + A_V0 + nxt * 9216 + so,         (const char*)(v_g  + goff + r * 64 + c * 8));
            }
            CPA_COMMIT();
            CPA_WAIT(1);
        } else {
            CPA_WAIT(0);
        }
        __syncthreads();

        uint32_t kb_hi = sb + A_K0 + s * 18432;
        uint32_t kb_lo = kb_hi + 9216;
        uint32_t vbse  = sb + A_V0 + s * 9216;

        float sc[8][4];
        #pragma unroll
        for (int j = 0; j < 8; j++)
            #pragma unroll
            for (int r = 0; r < 4; r++) sc[j][r] = 0.f;

        uint32_t b_off = (uint32_t)((lane & 7) + ((lane >> 4) & 1) * 8) * AROWB +
                         ((lane >> 3) & 1) * 16;
        #pragma unroll
        for (int ks = 0; ks < 4; ks++) {
            #pragma unroll
            for (int ng = 0; ng < 4; ng++) {
                uint32_t bh0, bh1, bh2, bh3, bl0, bl1, bl2, bl3;
                uint32_t ad = b_off + (uint32_t)ng * (16 * AROWB) + ks * 32;
                ldmx4(kb_hi + ad, bh0, bh1, bh2, bh3);
                ldmx4(kb_lo + ad, bl0, bl1, bl2, bl3);
                mma16816(sc[2 * ng],     qh[ks][0], qh[ks][1], qh[ks][2], qh[ks][3], bh0, bh1);
                mma16816(sc[2 * ng],     qh[ks][0], qh[ks][1], qh[ks][2], qh[ks][3], bl0, bl1);
                mma16816(sc[2 * ng],     ql[ks][0], ql[ks][1], ql[ks][2], ql[ks][3], bh0, bh1);
                mma16816(sc[2 * ng + 1], qh[ks][0], qh[ks][1], qh[ks][2], qh[ks][3], bh2, bh3);
                mma16816(sc[2 * ng + 1], qh[ks][0], qh[ks][1], qh[ks][2], qh[ks][3], bl2, bl3);
                mma16816(sc[2 * ng + 1], ql[ks][0], ql[ks][1], ql[ks][2], ql[ks][3], bh2, bh3);
            }
        }

        float mn0 = m0, mn1 = m1;
        #pragma unroll
        for (int j = 0; j < 8; j++) {
            mn0 = fmaxf(mn0, fmaxf(sc[j][0], sc[j][1]));
            mn1 = fmaxf(mn1, fmaxf(sc[j][2], sc[j][3]));
        }
        mn0 = fmaxf(mn0, __shfl_xor_sync(0xffffffffu, mn0, 1));
        mn0 = fmaxf(mn0, __shfl_xor_sync(0xffffffffu, mn0, 2));
        mn1 = fmaxf(mn1, __shfl_xor_sync(0xffffffffu, mn1, 1));
        mn1 = fmaxf(mn1, __shfl_xor_sync(0xffffffffu, mn1, 2));
        float corr0 = ex2f(m0 - mn0);
        float corr1 = ex2f(m1 - mn1);
        m0 = mn0; m1 = mn1;
        l0 *= corr0; l1 *= corr1;
        #pragma unroll
        for (int j = 0; j < 8; j++) {
            ctx[j][0] *= corr0; ctx[j][1] *= corr0;
            ctx[j][2] *= corr1; ctx[j][3] *= corr1;
        }
        uint32_t pa[8], pb[8];
        #pragma unroll
        for (int j = 0; j < 8; j++) {
            float p0 = ex2f(sc[j][0] - mn0);
            float p1 = ex2f(sc[j][1] - mn0);
            float p2 = ex2f(sc[j][2] - mn1);
            float p3 = ex2f(sc[j][3] - mn1);
            l0 += p0 + p1; l1 += p2 + p3;
            __nv_bfloat162 t0 = __floats2bfloat162_rn(p0, p1);
            __nv_bfloat162 t1 = __floats2bfloat162_rn(p2, p3);
            pa[j] = *(uint32_t*)&t0;
            pb[j] = *(uint32_t*)&t1;
        }

        uint32_t v_off = (uint32_t)(lane & 15) * AROWB + ((lane >> 4) & 1) * 16;
        #pragma unroll
        for (int ks = 0; ks < 4; ks++) {
            #pragma unroll
            for (int nd = 0; nd < 4; nd++) {
                uint32_t r0, r1, r2, r3;
                ldmx4t(vbse + v_off + (uint32_t)ks * (16 * AROWB) + nd * 32, r0, r1, r2, r3);
                mma16816(ctx[nd * 2],     pa[2 * ks], pb[2 * ks], pa[2 * ks + 1], pb[2 * ks + 1], r0, r1);
                mma16816(ctx[nd * 2 + 1], pa[2 * ks], pb[2 * ks], pa[2 * ks + 1], pb[2 * ks + 1], r2, r3);
            }
        }
        __syncthreads();
    }

    l0 += __shfl_xor_sync(0xffffffffu, l0, 1);
    l0 += __shfl_xor_sync(0xffffffffu, l0, 2);
    l1 += __shfl_xor_sync(0xffffffffu, l1, 1);
    l1 += __shfl_xor_sync(0xffffffffu, l1, 2);
    float i0 = 1.f / l0, i1 = 1.f / l1;

    int tr = lane >> 2, tc = (lane & 3) * 2;
    int row0 = q0 + wid * 16 + tr;
    #pragma unroll
    for (int f = 0; f < 8; f++) {
        int d = f * 8 + tc;
        float* c = ctx[f];
        size_t o0 = ((size_t)b * SEQ + row0) * DIM + (size_t)h * HDIM + d;
        size_t o1 = ((size_t)b * SEQ + row0 + 8) * DIM + (size_t)h * HDIM + d;
        float w0 = c[0] * i0, w1 = c[1] * i0;
        float w2 = c[2] * i1, w3 = c[3] * i1;
        __nv_bfloat162 h0, h1, l0v, l1v;
        h0.x = __float2bfloat16_rn(w0); h0.y = __float2bfloat16_rn(w1);
        h1.x = __float2bfloat16_rn(w2); h1.y = __float2bfloat16_rn(w3);
        l0v.x = __float2bfloat16_rn(w0 - __bfloat162float(h0.x));
        l0v.y = __float2bfloat16_rn(w1 - __bfloat162float(h0.y));
        l1v.x = __float2bfloat16_rn(w2 - __bfloat162float(h1.x));
        l1v.y = __float2bfloat16_rn(w3 - __bfloat162float(h1.y));
        *(__nv_bfloat162*)(Ohi + o0) = h0;
        *(__nv_bfloat162*)(Ohi + o1) = h1;
        *(__nv_bfloat162*)(Olo + o0) = l0v;
        *(__nv_bfloat162*)(Olo + o1) = l1v;
    }
}

// ---------------- launch ----------------
extern "C" void kernel_launch(void* const* d_in, const int* in_sizes, int n_in,
                              void* d_out, int out_size) {
    const float* x_in   = (const float*)d_in[0];
    const float* Wq     = (const float*)d_in[1];
    const float* Wk     = (const float*)d_in[2];
    const float* Wv     = (const float*)d_in[3];
    const float* Wo     = (const float*)d_in[4];
    const float* ln1_w  = (const float*)d_in[5];
    const float* ln2_w  = (const float*)d_in[6];
    const float* Wgate  = (const float*)d_in[7];
    const float* Wup    = (const float*)d_in[8];
    const float* Wdown  = (const float*)d_in[9];
    const float* W_out  = (const float*)d_in[10];
    const float* b_out  = (const float*)d_in[11];
    float* out = (float*)d_out;

    float *x, *qkv, *f1;
    __nv_bfloat16 *hhi, *hlo, *chi, *clo, *f1hi, *f1lo, *xhi, *xlo, *whi, *wlo;
    __nv_bfloat16 *qhi, *qlo, *khi, *klo, *vbp;
    cudaGetSymbolAddress((void**)&x,    g_x);
    cudaGetSymbolAddress((void**)&qkv,  g_qkv);
    cudaGetSymbolAddress((void**)&f1,   g_f1);
    cudaGetSymbolAddress((void**)&hhi,  g_hhi);
    cudaGetSymbolAddress((void**)&hlo,  g_hlo);
    cudaGetSymbolAddress((void**)&chi,  g_chi);
    cudaGetSymbolAddress((void**)&clo,  g_clo);
    cudaGetSymbolAddress((void**)&f1hi, g_f1hi);
    cudaGetSymbolAddress((void**)&f1lo, g_f1lo);
    cudaGetSymbolAddress((void**)&xhi,  g_xhi);
    cudaGetSymbolAddress((void**)&xlo,  g_xlo);
    cudaGetSymbolAddress((void**)&whi,  g_whi);
    cudaGetSymbolAddress((void**)&wlo,  g_wlo);
    cudaGetSymbolAddress((void**)&qhi,  g_qhi);
    cudaGetSymbolAddress((void**)&qlo,  g_qlo);
    cudaGetSymbolAddress((void**)&khi,  g_khi);
    cudaGetSymbolAddress((void**)&klo,  g_klo);
    cudaGetSymbolAddress((void**)&vbp,  g_vb);

    cudaFuncSetAttribute(gemm_bf,  cudaFuncAttributeMaxDynamicSharedMemorySize, GSMEM2);
    cudaFuncSetAttribute(gemm256,  cudaFuncAttributeMaxDynamicSharedMemorySize, QSMEM);
    cudaFuncSetAttribute(attn_mma, cudaFuncAttributeMaxDynamicSharedMemorySize, ASMEM);

    const size_t xbytes = (size_t)ROWS * DIM * sizeof(float);
    cudaMemcpyAsync(x, x_in, xbytes, cudaMemcpyDeviceToDevice);

    // --- weight converts (fp32 -> bf16 hi/lo) ---
    const int DD4 = DIM * DIM / 4, FD4 = FFDIM * DIM / 4;
    wcvt_kernel<<<DD4 / 256, 256>>>(Wq,    whi + WOFF_Q, wlo + WOFF_Q, DD4);
    wcvt_kernel<<<DD4 / 256, 256>>>(Wk,    whi + WOFF_K, wlo + WOFF_K, DD4);
    wcvt_kernel<<<DD4 / 256, 256>>>(Wv,    whi + WOFF_V, wlo + WOFF_V, DD4);
    wcvt_kernel<<<DD4 / 256, 256>>>(Wo,    whi + WOFF_O, wlo + WOFF_O, DD4);
    wcvt_kernel<<<FD4 / 256, 256>>>(Wgate, whi + WOFF_G, wlo + WOFF_G, FD4);
    wcvt_kernel<<<FD4 / 256, 256>>>(Wup,   whi + WOFF_U, wlo + WOFF_U, FD4);
    wcvt_kernel<<<FD4 / 256, 256>>>(Wdown, whi + WOFF_D, wlo + WOFF_D, FD4);
    wcvt_kernel<<<DD4 / 256, 256>>>(W_out, whi + WOFF_H, wlo + WOFF_H, DD4);

    // --- attention block ---
    rmsnorm_kernel<<<ROWS, 256>>>(x, ln1_w, hhi, hlo);

    // fused QKV GEMM: [8192,1024] @ [3072,1024]^T -> [8192,3072]
    dim3 gqkv(3 * DIM / QBN, ROWS / QBM);   // (12, 64)
    gemm256<<<gqkv, 256, QSMEM>>>(hhi, hlo, whi + WOFF_Q, wlo + WOFF_Q,
                                  nullptr, qkv, nullptr, nullptr, ROWS, 3 * DIM, DIM);

    int rope_total = BATCH * SEQ * NHEAD * (HDIM / 2);
    rope_cvt_kernel<<<(rope_total + 255) / 256, 256>>>(qkv, qhi, qlo, khi, klo);
    v_cvt_kernel<<<(ROWS * DIM / 4 + 255) / 256, 256>>>(qkv, vbp);

    dim3 ga(SEQ / 64, NHEAD, BATCH);
    attn_mma<<<ga, 128, ASMEM>>>(qhi, qlo, khi, klo, vbp, chi, clo);

    dim3 g1(DIM / GBN, ROWS / GBM);    // (8, 64)
    // x = x + ctx @ Wo^T
    gemm_bf<<<g1, 256, GSMEM2>>>(chi, clo, whi + WOFF_O, wlo + WOFF_O,
                                 x, nullptr, x, nullptr, nullptr, ROWS, DIM, DIM);

    // --- MLP block ---
    rmsnorm_kernel<<<ROWS, 256>>>(x, ln2_w, hhi, hlo);
    dim3 gff(FFDIM / QBN, ROWS / QBM); // (16, 64)
    // gate -> f1 (fp32)
    gemm256<<<gff, 256, QSMEM>>>(hhi, hlo, whi + WOFF_G, wlo + WOFF_G,
                                 nullptr, f1, nullptr, nullptr, ROWS, FFDIM, DIM);
    // up with fused silu(gate)*up -> f1 hi/lo
    gemm256<<<gff, 256, QSMEM>>>(hhi, hlo, whi + WOFF_U, wlo + WOFF_U,
                                 f1, nullptr, f1hi, f1lo, ROWS, FFDIM, DIM);

    // x_new = x + f1b @ Wdown^T -> bf16 hi/lo (feeds head GEMM)
    gemm_bf<<<g1, 256, GSMEM2>>>(f1hi, f1lo, whi + WOFF_D, wlo + WOFF_D,
                                 x, nullptr, nullptr, xhi, xlo, ROWS, DIM, FFDIM);

    // --- output head ---
    gemm_bf<<<g1, 256, GSMEM2>>>(xhi, xlo, whi + WOFF_H, wlo + WOFF_H,
                                 nullptr, b_out, out, nullptr, nullptr, ROWS, DIM, DIM);
}

// round 8
// speedup vs baseline: 3.7196x; 1.0016x over previous
#include <cuda_runtime.h>
#include <cuda_bf16.h>
#include <cstdint>

// Problem constants
#define BATCH 4
#define SEQ   2048
#define DIM   1024
#define NHEAD 16
#define HDIM  64
#define FFDIM 4096
#define ROWS  (BATCH * SEQ)            // 8192
#define LN_EPS 1e-6f

// ---------------- scratch (device globals; no allocation) ----------------
__device__ float g_x  [(size_t)ROWS * DIM];
__device__ float g_qkv[(size_t)ROWS * 3 * DIM];
__device__ float g_f1 [(size_t)ROWS * FFDIM];
// bf16 hi/lo activation operands
__device__ __nv_bfloat16 g_hhi [(size_t)ROWS * DIM];
__device__ __nv_bfloat16 g_hlo [(size_t)ROWS * DIM];
__device__ __nv_bfloat16 g_chi [(size_t)ROWS * DIM];
__device__ __nv_bfloat16 g_clo [(size_t)ROWS * DIM];
__device__ __nv_bfloat16 g_f1hi[(size_t)ROWS * FFDIM];
__device__ __nv_bfloat16 g_f1lo[(size_t)ROWS * FFDIM];
__device__ __nv_bfloat16 g_xhi [(size_t)ROWS * DIM];
__device__ __nv_bfloat16 g_xlo [(size_t)ROWS * DIM];
// bf16 hi/lo weights (Wq|Wk|Wv|Wo|Wgate|Wup|Wdown|W_out)
#define WOFF_Q  0
#define WOFF_K  1048576
#define WOFF_V  2097152
#define WOFF_O  3145728
#define WOFF_G  4194304
#define WOFF_U  8388608
#define WOFF_D  12582912
#define WOFF_H  16777216
#define WTOT    17825792
__device__ __nv_bfloat16 g_whi[(size_t)WTOT];
__device__ __nv_bfloat16 g_wlo[(size_t)WTOT];
// bf16 attention operands, [B,H,S,HD] layout
__device__ __nv_bfloat16 g_qhi[(size_t)ROWS * DIM];
__device__ __nv_bfloat16 g_qlo[(size_t)ROWS * DIM];
__device__ __nv_bfloat16 g_khi[(size_t)ROWS * DIM];
__device__ __nv_bfloat16 g_klo[(size_t)ROWS * DIM];
__device__ __nv_bfloat16 g_vb [(size_t)ROWS * DIM];

__device__ __forceinline__ uint32_t smem_u32(const void* p) {
    uint32_t a;
    asm("{ .reg .u64 t; cvta.to.shared.u64 t, %1; cvt.u32.u64 %0, t; }"
        : "=r"(a) : "l"(p));
    return a;
}
__device__ __forceinline__ void cvt_hilo4(float4 v, uint2& hi, uint2& lo) {
    __nv_bfloat162 h01, h23, l01, l23;
    h01.x = __float2bfloat16_rn(v.x);
    h01.y = __float2bfloat16_rn(v.y);
    h23.x = __float2bfloat16_rn(v.z);
    h23.y = __float2bfloat16_rn(v.w);
    l01.x = __float2bfloat16_rn(v.x - __bfloat162float(h01.x));
    l01.y = __float2bfloat16_rn(v.y - __bfloat162float(h01.y));
    l23.x = __float2bfloat16_rn(v.z - __bfloat162float(h23.x));
    l23.y = __float2bfloat16_rn(v.w - __bfloat162float(h23.y));
    hi.x = *(uint32_t*)&h01; hi.y = *(uint32_t*)&h23;
    lo.x = *(uint32_t*)&l01; lo.y = *(uint32_t*)&l23;
}
__device__ __forceinline__ void ldmx4(uint32_t addr, uint32_t& r0, uint32_t& r1,
                                      uint32_t& r2, uint32_t& r3) {
    asm volatile("ldmatrix.sync.aligned.m8n8.x4.shared.b16 {%0,%1,%2,%3}, [%4];"
                 : "=r"(r0), "=r"(r1), "=r"(r2), "=r"(r3) : "r"(addr));
}
__device__ __forceinline__ void ldmx4t(uint32_t addr, uint32_t& r0, uint32_t& r1,
                                       uint32_t& r2, uint32_t& r3) {
    asm volatile("ldmatrix.sync.aligned.m8n8.x4.trans.shared.b16 {%0,%1,%2,%3}, [%4];"
                 : "=r"(r0), "=r"(r1), "=r"(r2), "=r"(r3) : "r"(addr));
}
__device__ __forceinline__ void mma16816(float* c, uint32_t a0, uint32_t a1,
                                         uint32_t a2, uint32_t a3,
                                         uint32_t b0, uint32_t b1) {
    asm volatile(
        "mma.sync.aligned.m16n8k16.row.col.f32.bf16.bf16.f32 "
        "{%0,%1,%2,%3}, {%4,%5,%6,%7}, {%8,%9}, {%0,%1,%2,%3};"
        : "+f"(c[0]), "+f"(c[1]), "+f"(c[2]), "+f"(c[3])
        : "r"(a0), "r"(a1), "r"(a2), "r"(a3), "r"(b0), "r"(b1));
}
__device__ __forceinline__ float ex2f(float x) {
    float r;
    asm("ex2.approx.f32 %0, %1;" : "=f"(r) : "f"(x));
    return r;
}
#define CPA16(dst, src) \
    asm volatile("cp.async.cg.shared.global [%0], [%1], 16;" :: "r"(dst), "l"(src))
#define CPA_COMMIT() asm volatile("cp.async.commit_group;" ::: "memory")
#define CPA_WAIT(n)  asm volatile("cp.async.wait_group %0;" :: "n"(n) : "memory")

// ---------------- weight convert: fp32 -> bf16 hi/lo ----------------
__global__ void wcvt_kernel(const float* __restrict__ src,
                            __nv_bfloat16* __restrict__ hi,
                            __nv_bfloat16* __restrict__ lo, int n4) {
    int t = blockIdx.x * 256 + threadIdx.x;
    if (t >= n4) return;
    float4 v = *(const float4*)(src + (size_t)t * 4);
    uint2 h, l;
    cvt_hilo4(v, h, l);
    *(uint2*)(hi + (size_t)t * 4) = h;
    *(uint2*)(lo + (size_t)t * 4) = l;
}

// ================= gemm_s: unified GEMM ====================================
// Tile 128x128, BK=32, 3-stage cp.async, SW64 swizzle (64B rows), 2 CTAs/SM.
// C[M,N] = A @ W^T with optional: gate (silu fusion), res, bias; outputs
// fp32 C and/or bf16 hi/lo (Chi/Clo).
#define SBM 128
#define SBN 128
#define SBK 32
#define S_ALO 8192
#define S_WHI 16384
#define S_WLO 24576
#define SSTG  32768
#define SMEM3 (3 * SSTG)       // 98304 -> 2 CTAs/SM

__global__ __launch_bounds__(256, 2)
void gemm_s(const __nv_bfloat16* __restrict__ Ahi, const __nv_bfloat16* __restrict__ Alo,
            const __nv_bfloat16* __restrict__ Whi, const __nv_bfloat16* __restrict__ Wlo,
            const float* __restrict__ gate, const float* __restrict__ res,
            const float* __restrict__ bias,
            float* __restrict__ C,
            __nv_bfloat16* __restrict__ Chi, __nv_bfloat16* __restrict__ Clo,
            int M, int N, int K) {
    extern __shared__ char smem[];
    uint32_t sb = smem_u32(smem);
    int tid = threadIdx.x, wid = tid >> 5, lane = tid & 31;
    int bm = blockIdx.y * SBM, bn = blockIdx.x * SBN;
    int warp_m = (wid >> 2) * 64, warp_n = (wid & 3) * 32;

    // --- cp.async mapping: 64 rows per pass, 4 x 16B chunks per 64B row ---
    uint32_t strow = (uint32_t)(tid >> 2);
    uint32_t stc   = (uint32_t)(tid & 3) * 16;
    uint32_t st_off = strow * 64 + (stc ^ (((strow >> 1) & 3u) << 4));
    const __nv_bfloat16* Ah = Ahi + (size_t)(bm + strow) * K + (tid & 3) * 8;
    const __nv_bfloat16* Al = Alo + (size_t)(bm + strow) * K + (tid & 3) * 8;
    const __nv_bfloat16* Wh = Whi + (size_t)(bn + strow) * K + (tid & 3) * 8;
    const __nv_bfloat16* Wl = Wlo + (size_t)(bn + strow) * K + (tid & 3) * 8;

    auto load_stage = [&](int s, int chunk) {
        uint32_t base = sb + (uint32_t)s * SSTG;
        size_t ko = (size_t)chunk * SBK;
        #pragma unroll
        for (int j = 0; j < 2; j++) {
            uint32_t d = base + st_off + j * 4096;     // 64 rows * 64B
            size_t ro = (size_t)j * 64 * K + ko;
            CPA16(d,         (const char*)(Ah + ro));
            CPA16(d + S_ALO, (const char*)(Al + ro));
            CPA16(d + S_WHI, (const char*)(Wh + ro));
            CPA16(d + S_WLO, (const char*)(Wl + ro));
        }
    };

    // --- ldmatrix addressing (SW64: col ^= ((row>>1)&3)<<4) ---
    int ra = warp_m + (lane & 15);
    uint32_t a_row = (uint32_t)ra * 64;
    uint32_t swa = (((uint32_t)ra >> 1) & 3u) << 4;
    int rb = warp_n + (lane & 7) + ((lane >> 4) & 1) * 8;
    uint32_t b_row = (uint32_t)rb * 64;
    uint32_t swb = (((uint32_t)rb >> 1) & 3u) << 4;
    uint32_t col_a[2], col_b[2];
    int ha = ((lane >> 4) & 1) * 16;
    int hb = ((lane >> 3) & 1) * 16;
    #pragma unroll
    for (int ks = 0; ks < 2; ks++) {
        col_a[ks] = ((uint32_t)(ks * 32 + ha)) ^ swa;
        col_b[ks] = ((uint32_t)(ks * 32 + hb)) ^ swb;
    }

    float acc[4][4][4];
    #pragma unroll
    for (int i = 0; i < 4; i++)
        #pragma unroll
        for (int j = 0; j < 4; j++)
            #pragma unroll
            for (int r = 0; r < 4; r++) acc[i][j][r] = 0.f;

    const int nk = K / SBK;
    load_stage(0, 0);
    CPA_COMMIT();
    if (nk > 1) load_stage(1, 1);
    CPA_COMMIT();

    int sc = 0;
    for (int i = 0; i < nk; i++) {
        int snx = sc + 2; if (snx >= 3) snx -= 3;
        if (i + 2 < nk) load_stage(snx, i + 2);
        CPA_COMMIT();
        CPA_WAIT(2);
        __syncthreads();

        uint32_t base = sb + (uint32_t)sc * SSTG;
        #pragma unroll
        for (int ks = 0; ks < 2; ks++) {
            // B fragments (held across mf loop)
            uint32_t bhr[2][4], blr[2][4];
            #pragma unroll
            for (int np = 0; np < 2; np++) {
                uint32_t bd = base + S_WHI + b_row + (uint32_t)np * 1024 + col_b[ks];
                ldmx4(bd,        bhr[np][0], bhr[np][1], bhr[np][2], bhr[np][3]);
                ldmx4(bd + 8192, blr[np][0], blr[np][1], blr[np][2], blr[np][3]);
            }
            #pragma unroll
            for (int mf = 0; mf < 4; mf++) {
                uint32_t ah0, ah1, ah2, ah3, al0, al1, al2, al3;
                uint32_t ad = base + a_row + (uint32_t)mf * 1024 + col_a[ks];
                ldmx4(ad,         ah0, ah1, ah2, ah3);
                ldmx4(ad + S_ALO, al0, al1, al2, al3);
                #pragma unroll
                for (int nf = 0; nf < 4; nf++) {
                    uint32_t bh0 = bhr[nf >> 1][(nf & 1) * 2];
                    uint32_t bh1 = bhr[nf >> 1][(nf & 1) * 2 + 1];
                    uint32_t bl0 = blr[nf >> 1][(nf & 1) * 2];
                    uint32_t bl1 = blr[nf >> 1][(nf & 1) * 2 + 1];
                    mma16816(acc[mf][nf], ah0, ah1, ah2, ah3, bh0, bh1);
                    mma16816(acc[mf][nf], ah0, ah1, ah2, ah3, bl0, bl1);
                    mma16816(acc[mf][nf], al0, al1, al2, al3, bh0, bh1);
                }
            }
        }
        __syncthreads();
        sc = (sc == 2) ? 0 : sc + 1;
    }

    // ---- epilogue ----
    int tr = lane >> 2, tc = (lane & 3) * 2;
    #pragma unroll
    for (int mf = 0; mf < 4; mf++) {
        #pragma unroll
        for (int nf = 0; nf < 4; nf++) {
            int row0 = bm + warp_m + mf * 16 + tr;
            int col  = bn + warp_n + nf * 8 + tc;
            float* c = acc[mf][nf];
            float v[4] = {c[0], c[1], c[2], c[3]};
            size_t o0 = (size_t)row0 * N + col;
            size_t o1 = (size_t)(row0 + 8) * N + col;
            if (gate) {
                float2 g0 = *(const float2*)(gate + o0);
                float2 g1 = *(const float2*)(gate + o1);
                v[0] *= g0.x / (1.f + expf(-g0.x));
                v[1] *= g0.y / (1.f + expf(-g0.y));
                v[2] *= g1.x / (1.f + expf(-g1.x));
                v[3] *= g1.y / (1.f + expf(-g1.y));
            }
            if (res) {
                float2 r0 = *(const float2*)(res + o0);
                float2 r1 = *(const float2*)(res + o1);
                v[0] += r0.x; v[1] += r0.y; v[2] += r1.x; v[3] += r1.y;
            }
            if (bias) {
                float2 bb = *(const float2*)(bias + col);
                v[0] += bb.x; v[1] += bb.y; v[2] += bb.x; v[3] += bb.y;
            }
            if (C) {
                *(float2*)(C + o0) = {v[0], v[1]};
                *(float2*)(C + o1) = {v[2], v[3]};
            }
            if (Chi) {
                __nv_bfloat162 h0, h1, l0, l1;
                h0.x = __float2bfloat16_rn(v[0]); h0.y = __float2bfloat16_rn(v[1]);
                h1.x = __float2bfloat16_rn(v[2]); h1.y = __float2bfloat16_rn(v[3]);
                l0.x = __float2bfloat16_rn(v[0] - __bfloat162float(h0.x));
                l0.y = __float2bfloat16_rn(v[1] - __bfloat162float(h0.y));
                l1.x = __float2bfloat16_rn(v[2] - __bfloat162float(h1.x));
                l1.y = __float2bfloat16_rn(v[3] - __bfloat162float(h1.y));
                *(__nv_bfloat162*)(Chi + o0) = h0;
                *(__nv_bfloat162*)(Chi + o1) = h1;
                *(__nv_bfloat162*)(Clo + o0) = l0;
                *(__nv_bfloat162*)(Clo + o1) = l1;
            }
        }
    }
}

// ---------------- RMSNorm -> bf16 hi/lo ----------------
__global__ void rmsnorm_kernel(const float* __restrict__ x,
                               const float* __restrict__ w,
                               __nv_bfloat16* __restrict__ ohi,
                               __nv_bfloat16* __restrict__ olo) {
    int row = blockIdx.x;
    const float* xr = x + (size_t)row * DIM;
    float s = 0.f;
    #pragma unroll
    for (int i = threadIdx.x; i < DIM; i += 256) {
        float v = xr[i];
        s += v * v;
    }
    __shared__ float red[8];
    #pragma unroll
    for (int o = 16; o; o >>= 1) s += __shfl_down_sync(0xffffffffu, s, o);
    if ((threadIdx.x & 31) == 0) red[threadIdx.x >> 5] = s;
    __syncthreads();
    if (threadIdx.x < 8) {
        float t = red[threadIdx.x];
        #pragma unroll
        for (int o = 4; o; o >>= 1) t += __shfl_down_sync(0xffu, t, o);
        if (threadIdx.x == 0) red[0] = t;
    }
    __syncthreads();
    float inv = rsqrtf(red[0] * (1.0f / DIM) + LN_EPS);
    #pragma unroll
    for (int i = threadIdx.x; i < DIM; i += 256) {
        float v = xr[i] * inv * w[i];
        __nv_bfloat16 hi = __float2bfloat16_rn(v);
        ohi[(size_t)row * DIM + i] = hi;
        olo[(size_t)row * DIM + i] = __float2bfloat16_rn(v - __bfloat162float(hi));
    }
}

// ------------- RoPE on qkv buffer [rows,3072] -> hi/lo [B,H,S,HD] ----------
#define QSCALE 0.18033688011111793f   // 0.125 * log2(e)
__global__ void rope_cvt_kernel(const float* __restrict__ QKV,
                                __nv_bfloat16* __restrict__ qhi, __nv_bfloat16* __restrict__ qlo,
                                __nv_bfloat16* __restrict__ khi, __nv_bfloat16* __restrict__ klo) {
    int idx = blockIdx.x * 256 + threadIdx.x;
    if (idx >= BATCH * SEQ * NHEAD * (HDIM / 2)) return;
    int d = idx & 31;
    int h = (idx >> 5) & (NHEAD - 1);
    int s = (idx >> 9) & (SEQ - 1);
    int b = idx >> 20;
    size_t ibase = ((size_t)b * SEQ + s) * (3 * DIM) + (size_t)h * HDIM;
    size_t obase = (((size_t)b * NHEAD + h) * SEQ + s) * HDIM;
    float inv = expf(-(float)d * (9.210340371976184f / 32.f));
    float ang = (float)s * inv;
    float sn, cs;
    sincosf(ang, &sn, &cs);
    {
        float x1 = QKV[ibase + d], x2 = QKV[ibase + d + 32];
        float r1 = (x1 * cs - x2 * sn) * QSCALE;
        float r2 = (x2 * cs + x1 * sn) * QSCALE;
        __nv_bfloat16 h1 = __float2bfloat16_rn(r1);
        __nv_bfloat16 h2 = __float2bfloat16_rn(r2);
        qhi[obase + d]      = h1;
        qhi[obase + d + 32] = h2;
        qlo[obase + d]      = __float2bfloat16_rn(r1 - __bfloat162float(h1));
        qlo[obase + d + 32] = __float2bfloat16_rn(r2 - __bfloat162float(h2));
    }
    {
        float x1 = QKV[ibase + DIM + d], x2 = QKV[ibase + DIM + d + 32];
        float r1 = x1 * cs - x2 * sn;
        float r2 = x2 * cs + x1 * sn;
        __nv_bfloat16 h1 = __float2bfloat16_rn(r1);
        __nv_bfloat16 h2 = __float2bfloat16_rn(r2);
        khi[obase + d]      = h1;
        khi[obase + d + 32] = h2;
        klo[obase + d]      = __float2bfloat16_rn(r1 - __bfloat162float(h1));
        klo[obase + d + 32] = __float2bfloat16_rn(r2 - __bfloat162float(h2));
    }
}

// ------------- V convert: qkv fp32 -> bf16 [B,H,S,HD] -------------
__global__ void v_cvt_kernel(const float* __restrict__ QKV, __nv_bfloat16* __restrict__ vb) {
    int t = blockIdx.x * 256 + threadIdx.x;
    if (t >= ROWS * DIM / 4) return;
    int e = t * 4;
    int c = e & 63;
    int h = (e >> 6) & (NHEAD - 1);
    int s = (e >> 10) & (SEQ - 1);
    int b = e >> 21;
    size_t ioff = ((size_t)b * SEQ + s) * (3 * DIM) + 2 * DIM + (size_t)h * HDIM + c;
    size_t ooff = (((size_t)b * NHEAD + h) * SEQ + s) * HDIM + c;
    float4 v = *(const float4*)(QKV + ioff);
    __nv_bfloat162 p0, p1;
    p0.x = __float2bfloat16_rn(v.x); p0.y = __float2bfloat16_rn(v.y);
    p1.x = __float2bfloat16_rn(v.z); p1.y = __float2bfloat16_rn(v.w);
    uint2 o = { *(uint32_t*)&p0, *(uint32_t*)&p1 };
    *(uint2*)(vb + ooff) = o;
}

// ================= MMA flash attention =================
#define AROWB 144
#define A_QHI 0
#define A_QLO 9216
#define A_K0  18432
#define A_V0  55296
#define ASMEM 73728

__global__ __launch_bounds__(128)
void attn_mma(const __nv_bfloat16* __restrict__ qhi, const __nv_bfloat16* __restrict__ qlo,
              const __nv_bfloat16* __restrict__ khi, const __nv_bfloat16* __restrict__ klo,
              const __nv_bfloat16* __restrict__ vb,
              __nv_bfloat16* __restrict__ Ohi, __nv_bfloat16* __restrict__ Olo) {
    extern __shared__ char smem[];
    uint32_t sb = smem_u32(smem);
    int tid = threadIdx.x, wid = tid >> 5, lane = tid & 31;
    int b = blockIdx.z, h = blockIdx.y;
    int q0 = blockIdx.x * 64;
    size_t hoff = ((size_t)b * NHEAD + h) * SEQ * HDIM;

    {
        const uint4* qh4 = (const uint4*)(qhi + hoff + (size_t)q0 * HDIM);
        const uint4* ql4 = (const uint4*)(qlo + hoff + (size_t)q0 * HDIM);
        #pragma unroll
        for (int j = 0; j < 4; j++) {
            int f = tid + j * 128;
            int r = f >> 3, c = f & 7;
            *(uint4*)(smem + A_QHI + r * AROWB + c * 16) = qh4[r * 8 + c];
            *(uint4*)(smem + A_QLO + r * AROWB + c * 16) = ql4[r * 8 + c];
        }
    }
    __syncthreads();

    uint32_t qh[4][4], ql[4][4];
    {
        uint32_t a_base = sb + (uint32_t)(wid * 16 + (lane & 15)) * AROWB + ((lane >> 4) & 1) * 16;
        #pragma unroll
        for (int ks = 0; ks < 4; ks++) {
            ldmx4(a_base + ks * 32,         qh[ks][0], qh[ks][1], qh[ks][2], qh[ks][3]);
            ldmx4(a_base + A_QLO + ks * 32, ql[ks][0], ql[ks][1], ql[ks][2], ql[ks][3]);
        }
    }

    float ctx[8][4];
    #pragma unroll
    for (int j = 0; j < 8; j++)
        #pragma unroll
        for (int r = 0; r < 4; r++) ctx[j][r] = 0.f;
    float m0 = -1e30f, m1 = -1e30f, l0 = 0.f, l1 = 0.f;

    const __nv_bfloat16* kh_g = khi + hoff;
    const __nv_bfloat16* kl_g = klo + hoff;
    const __nv_bfloat16* v_g  = vb + hoff;

    {
        #pragma unroll
        for (int j = 0; j < 4; j++) {
            int f = tid + j * 128;
            int r = f >> 3, c = f & 7;
            uint32_t so = (uint32_t)(r * AROWB + c * 16);
            CPA16(sb + A_K0 + so,        (const char*)(kh_g + r * 64 + c * 8));
            CPA16(sb + A_K0 + 9216 + so, (const char*)(kl_g + r * 64 + c * 8));
            CPA16(sb + A_V0 + so,        (const char*)(v_g  + r * 64 + c * 8));
        }
        CPA_COMMIT();
    }

    const int NT = SEQ / 64;
    for (int t = 0; t < NT; t++) {
        int s = t & 1;
        if (t + 1 < NT) {
            int nxt = s ^ 1;
            size_t goff = (size_t)(t + 1) * 64 * 64;
            #pragma unroll
            for (int j = 0; j < 4; j++) {
                int f = tid + j * 128;
                int r = f >> 3, c = f & 7;
                uint32_t so = (uint32_t)(r * AROWB + c * 16);
                CPA16(sb + A_K0 + nxt * 18432 + so,        (const char*)(kh_g + goff + r * 64 + c * 8));
                CPA16(sb + A_K0 + nxt * 18432 + 9216 + so, (const char*)(kl_g + goff + r * 64 + c * 8));
                CPA16(sb + A_V0 + nxt * 9216 + so,         (const char*)(v_g  + goff + r * 64 + c * 8));
            }
            CPA_COMMIT();
            CPA_WAIT(1);
        } else {
            CPA_WAIT(0);
        }
        __syncthreads();

        uint32_t kb_hi = sb + A_K0 + s * 18432;
        uint32_t kb_lo = kb_hi + 9216;
        uint32_t vbse  = sb + A_V0 + s * 9216;

        float sc[8][4];
        #pragma unroll
        for (int j = 0; j < 8; j++)
            #pragma unroll
            for (int r = 0; r < 4; r++) sc[j][r] = 0.f;

        uint32_t b_off = (uint32_t)((lane & 7) + ((lane >> 4) & 1) * 8) * AROWB +
                         ((lane >> 3) & 1) * 16;
        #pragma unroll
        for (int ks = 0; ks < 4; ks++) {
            #pragma unroll
            for (int ng = 0; ng < 4; ng++) {
                uint32_t bh0, bh1, bh2, bh3, bl0, bl1, bl2, bl3;
                uint32_t ad = b_off + (uint32_t)ng * (16 * AROWB) + ks * 32;
                ldmx4(kb_hi + ad, bh0, bh1, bh2, bh3);
                ldmx4(kb_lo + ad, bl0, bl1, bl2, bl3);
                mma16816(sc[2 * ng],     qh[ks][0], qh[ks][1], qh[ks][2], qh[ks][3], bh0, bh1);
                mma16816(sc[2 * ng],     qh[ks][0], qh[ks][1], qh[ks][2], qh[ks][3], bl0, bl1);
                mma16816(sc[2 * ng],     ql[ks][0], ql[ks][1], ql[ks][2], ql[ks][3], bh0, bh1);
                mma16816(sc[2 * ng + 1], qh[ks][0], qh[ks][1], qh[ks][2], qh[ks][3], bh2, bh3);
                mma16816(sc[2 * ng + 1], qh[ks][0], qh[ks][1], qh[ks][2], qh[ks][3], bl2, bl3);
                mma16816(sc[2 * ng + 1], ql[ks][0], ql[ks][1], ql[ks][2], ql[ks][3], bh2, bh3);
            }
        }

        float mn0 = m0, mn1 = m1;
        #pragma unroll
        for (int j = 0; j < 8; j++) {
            mn0 = fmaxf(mn0, fmaxf(sc[j][0], sc[j][1]));
            mn1 = fmaxf(mn1, fmaxf(sc[j][2], sc[j][3]));
        }
        mn0 = fmaxf(mn0, __shfl_xor_sync(0xffffffffu, mn0, 1));
        mn0 = fmaxf(mn0, __shfl_xor_sync(0xffffffffu, mn0, 2));
        mn1 = fmaxf(mn1, __shfl_xor_sync(0xffffffffu, mn1, 1));
        mn1 = fmaxf(mn1, __shfl_xor_sync(0xffffffffu, mn1, 2));
        float corr0 = ex2f(m0 - mn0);
        float corr1 = ex2f(m1 - mn1);
        m0 = mn0; m1 = mn1;
        l0 *= corr0; l1 *= corr1;
        #pragma unroll
        for (int j = 0; j < 8; j++) {
            ctx[j][0] *= corr0; ctx[j][1] *= corr0;
            ctx[j][2] *= corr1; ctx[j][3] *= corr1;
        }
        uint32_t pa[8], pb[8];
        #pragma unroll
        for (int j = 0; j < 8; j++) {
            float p0 = ex2f(sc[j][0] - mn0);
            float p1 = ex2f(sc[j][1] - mn0);
            float p2 = ex2f(sc[j][2] - mn1);
            float p3 = ex2f(sc[j][3] - mn1);
            l0 += p0 + p1; l1 += p2 + p3;
            __nv_bfloat162 t0 = __floats2bfloat162_rn(p0, p1);
            __nv_bfloat162 t1 = __floats2bfloat162_rn(p2, p3);
            pa[j] = *(uint32_t*)&t0;
            pb[j] = *(uint32_t*)&t1;
        }

        uint32_t v_off = (uint32_t)(lane & 15) * AROWB + ((lane >> 4) & 1) * 16;
        #pragma unroll
        for (int ks = 0; ks < 4; ks++) {
            #pragma unroll
            for (int nd = 0; nd < 4; nd++) {
                uint32_t r0, r1, r2, r3;
                ldmx4t(vbse + v_off + (uint32_t)ks * (16 * AROWB) + nd * 32, r0, r1, r2, r3);
                mma16816(ctx[nd * 2],     pa[2 * ks], pb[2 * ks], pa[2 * ks + 1], pb[2 * ks + 1], r0, r1);
                mma16816(ctx[nd * 2 + 1], pa[2 * ks], pb[2 * ks], pa[2 * ks + 1], pb[2 * ks + 1], r2, r3);
            }
        }
        __syncthreads();
    }

    l0 += __shfl_xor_sync(0xffffffffu, l0, 1);
    l0 += __shfl_xor_sync(0xffffffffu, l0, 2);
    l1 += __shfl_xor_sync(0xffffffffu, l1, 1);
    l1 += __shfl_xor_sync(0xffffffffu, l1, 2);
    float i0 = 1.f / l0, i1 = 1.f / l1;

    int tr = lane >> 2, tc = (lane & 3) * 2;
    int row0 = q0 + wid * 16 + tr;
    #pragma unroll
    for (int f = 0; f < 8; f++) {
        int d = f * 8 + tc;
        float* c = ctx[f];
        size_t o0 = ((size_t)b * SEQ + row0) * DIM + (size_t)h * HDIM + d;
        size_t o1 = ((size_t)b * SEQ + row0 + 8) * DIM + (size_t)h * HDIM + d;
        float w0 = c[0] * i0, w1 = c[1] * i0;
        float w2 = c[2] * i1, w3 = c[3] * i1;
        __nv_bfloat162 h0, h1, l0v, l1v;
        h0.x = __float2bfloat16_rn(w0); h0.y = __float2bfloat16_rn(w1);
        h1.x = __float2bfloat16_rn(w2); h1.y = __float2bfloat16_rn(w3);
        l0v.x = __float2bfloat16_rn(w0 - __bfloat162float(h0.x));
        l0v.y = __float2bfloat16_rn(w1 - __bfloat162float(h0.y));
        l1v.x = __float2bfloat16_rn(w2 - __bfloat162float(h1.x));
        l1v.y = __float2bfloat16_rn(w3 - __bfloat162float(h1.y));
        *(__nv_bfloat162*)(Ohi + o0) = h0;
        *(__nv_bfloat162*)(Ohi + o1) = h1;
        *(__nv_bfloat162*)(Olo + o0) = l0v;
        *(__nv_bfloat162*)(Olo + o1) = l1v;
    }
}

// ---------------- launch ----------------
extern "C" void kernel_launch(void* const* d_in, const int* in_sizes, int n_in,
                              void* d_out, int out_size) {
    const float* x_in   = (const float*)d_in[0];
    const float* Wq     = (const float*)d_in[1];
    const float* Wk     = (const float*)d_in[2];
    const float* Wv     = (const float*)d_in[3];
    const float* Wo     = (const float*)d_in[4];
    const float* ln1_w  = (const float*)d_in[5];
    const float* ln2_w  = (const float*)d_in[6];
    const float* Wgate  = (const float*)d_in[7];
    const float* Wup    = (const float*)d_in[8];
    const float* Wdown  = (const float*)d_in[9];
    const float* W_out  = (const float*)d_in[10];
    const float* b_out  = (const float*)d_in[11];
    float* out = (float*)d_out;

    float *x, *qkv, *f1;
    __nv_bfloat16 *hhi, *hlo, *chi, *clo, *f1hi, *f1lo, *xhi, *xlo, *whi, *wlo;
    __nv_bfloat16 *qhi, *qlo, *khi, *klo, *vbp;
    cudaGetSymbolAddress((void**)&x,    g_x);
    cudaGetSymbolAddress((void**)&qkv,  g_qkv);
    cudaGetSymbolAddress((void**)&f1,   g_f1);
    cudaGetSymbolAddress((void**)&hhi,  g_hhi);
    cudaGetSymbolAddress((void**)&hlo,  g_hlo);
    cudaGetSymbolAddress((void**)&chi,  g_chi);
    cudaGetSymbolAddress((void**)&clo,  g_clo);
    cudaGetSymbolAddress((void**)&f1hi, g_f1hi);
    cudaGetSymbolAddress((void**)&f1lo, g_f1lo);
    cudaGetSymbolAddress((void**)&xhi,  g_xhi);
    cudaGetSymbolAddress((void**)&xlo,  g_xlo);
    cudaGetSymbolAddress((void**)&whi,  g_whi);
    cudaGetSymbolAddress((void**)&wlo,  g_wlo);
    cudaGetSymbolAddress((void**)&qhi,  g_qhi);
    cudaGetSymbolAddress((void**)&qlo,  g_qlo);
    cudaGetSymbolAddress((void**)&khi,  g_khi);
    cudaGetSymbolAddress((void**)&klo,  g_klo);
    cudaGetSymbolAddress((void**)&vbp,  g_vb);

    cudaFuncSetAttribute(gemm_s,   cudaFuncAttributeMaxDynamicSharedMemorySize, SMEM3);
    cudaFuncSetAttribute(attn_mma, cudaFuncAttributeMaxDynamicSharedMemorySize, ASMEM);

    const size_t xbytes = (size_t)ROWS * DIM * sizeof(float);
    cudaMemcpyAsync(x, x_in, xbytes, cudaMemcpyDeviceToDevice);

    // --- weight converts (fp32 -> bf16 hi/lo) ---
    const int DD4 = DIM * DIM / 4, FD4 = FFDIM * DIM / 4;
    wcvt_kernel<<<DD4 / 256, 256>>>(Wq,    whi + WOFF_Q, wlo + WOFF_Q, DD4);
    wcvt_kernel<<<DD4 / 256, 256>>>(Wk,    whi + WOFF_K, wlo + WOFF_K, DD4);
    wcvt_kernel<<<DD4 / 256, 256>>>(Wv,    whi + WOFF_V, wlo + WOFF_V, DD4);
    wcvt_kernel<<<DD4 / 256, 256>>>(Wo,    whi + WOFF_O, wlo + WOFF_O, DD4);
    wcvt_kernel<<<FD4 / 256, 256>>>(Wgate, whi + WOFF_G, wlo + WOFF_G, FD4);
    wcvt_kernel<<<FD4 / 256, 256>>>(Wup,   whi + WOFF_U, wlo + WOFF_U, FD4);
    wcvt_kernel<<<FD4 / 256, 256>>>(Wdown, whi + WOFF_D, wlo + WOFF_D, FD4);
    wcvt_kernel<<<DD4 / 256, 256>>>(W_out, whi + WOFF_H, wlo + WOFF_H, DD4);

    // --- attention block ---
    rmsnorm_kernel<<<ROWS, 256>>>(x, ln1_w, hhi, hlo);

    // fused QKV GEMM: [8192,1024] @ [3072,1024]^T -> [8192,3072]
    dim3 gqkv(3 * DIM / SBN, ROWS / SBM);   // (24, 64)
    gemm_s<<<gqkv, 256, SMEM3>>>(hhi, hlo, whi + WOFF_Q, wlo + WOFF_Q,
                                 nullptr, nullptr, nullptr,
                                 qkv, nullptr, nullptr, ROWS, 3 * DIM, DIM);

    int rope_total = BATCH * SEQ * NHEAD * (HDIM / 2);
    rope_cvt_kernel<<<(rope_total + 255) / 256, 256>>>(qkv, qhi, qlo, khi, klo);
    v_cvt_kernel<<<(ROWS * DIM / 4 + 255) / 256, 256>>>(qkv, vbp);

    dim3 ga(SEQ / 64, NHEAD, BATCH);
    attn_mma<<<ga, 128, ASMEM>>>(qhi, qlo, khi, klo, vbp, chi, clo);

    dim3 g1(DIM / SBN, ROWS / SBM);    // (8, 64)
    // x = x + ctx @ Wo^T
    gemm_s<<<g1, 256, SMEM3>>>(chi, clo, whi + WOFF_O, wlo + WOFF_O,
                               nullptr, x, nullptr,
                               x, nullptr, nullptr, ROWS, DIM, DIM);

    // --- MLP block ---
    rmsnorm_kernel<<<ROWS, 256>>>(x, ln2_w, hhi, hlo);
    dim3 gff(FFDIM / SBN, ROWS / SBM); // (32, 64)
    // gate -> f1 (fp32)
    gemm_s<<<gff, 256, SMEM3>>>(hhi, hlo, whi + WOFF_G, wlo + WOFF_G,
                                nullptr, nullptr, nullptr,
                                f1, nullptr, nullptr, ROWS, FFDIM, DIM);
    // up with fused silu(gate)*up -> f1 hi/lo
    gemm_s<<<gff, 256, SMEM3>>>(hhi, hlo, whi + WOFF_U, wlo + WOFF_U,
                                f1, nullptr, nullptr,
                                nullptr, f1hi, f1lo, ROWS, FFDIM, DIM);

    // x_new = x + f1b @ Wdown^T -> bf16 hi/lo (feeds head GEMM)
    gemm_s<<<g1, 256, SMEM3>>>(f1hi, f1lo, whi + WOFF_D, wlo + WOFF_D,
                               nullptr, x, nullptr,
                               nullptr, xhi, xlo, ROWS, DIM, FFDIM);

    // --- output head ---
    gemm_s<<<g1, 256, SMEM3>>>(xhi, xlo, whi + WOFF_H, wlo + WOFF_H,
                               nullptr, nullptr, b_out,
                               out, nullptr, nullptr, ROWS, DIM, DIM);
}

// round 9
// speedup vs baseline: 3.8546x; 1.0363x over previous
#include <cuda_runtime.h>
#include <cuda_bf16.h>
#include <cstdint>

// Problem constants
#define BATCH 4
#define SEQ   2048
#define DIM   1024
#define NHEAD 16
#define HDIM  64
#define FFDIM 4096
#define ROWS  (BATCH * SEQ)            // 8192
#define LN_EPS 1e-6f

// ---------------- scratch (device globals; no allocation) ----------------
__device__ float g_x  [(size_t)ROWS * DIM];
__device__ float g_qkv[(size_t)ROWS * 3 * DIM];
__device__ float g_f1 [(size_t)ROWS * FFDIM];
// bf16 hi/lo activation operands
__device__ __nv_bfloat16 g_hhi [(size_t)ROWS * DIM];
__device__ __nv_bfloat16 g_hlo [(size_t)ROWS * DIM];
__device__ __nv_bfloat16 g_chi [(size_t)ROWS * DIM];
__device__ __nv_bfloat16 g_clo [(size_t)ROWS * DIM];
__device__ __nv_bfloat16 g_f1hi[(size_t)ROWS * FFDIM];
__device__ __nv_bfloat16 g_f1lo[(size_t)ROWS * FFDIM];
__device__ __nv_bfloat16 g_xhi [(size_t)ROWS * DIM];
__device__ __nv_bfloat16 g_xlo [(size_t)ROWS * DIM];
// bf16 hi/lo weights (Wq|Wk|Wv|Wo|Wgate|Wup|Wdown|W_out)
#define WOFF_Q  0
#define WOFF_K  1048576
#define WOFF_V  2097152
#define WOFF_O  3145728
#define WOFF_G  4194304
#define WOFF_U  8388608
#define WOFF_D  12582912
#define WOFF_H  16777216
#define WTOT    17825792
__device__ __nv_bfloat16 g_whi[(size_t)WTOT];
__device__ __nv_bfloat16 g_wlo[(size_t)WTOT];
// bf16 attention operands, [B,H,S,HD] layout
__device__ __nv_bfloat16 g_qhi[(size_t)ROWS * DIM];
__device__ __nv_bfloat16 g_qlo[(size_t)ROWS * DIM];
__device__ __nv_bfloat16 g_khi[(size_t)ROWS * DIM];
__device__ __nv_bfloat16 g_klo[(size_t)ROWS * DIM];
__device__ __nv_bfloat16 g_vb [(size_t)ROWS * DIM];

__device__ __forceinline__ uint32_t smem_u32(const void* p) {
    uint32_t a;
    asm("{ .reg .u64 t; cvta.to.shared.u64 t, %1; cvt.u32.u64 %0, t; }"
        : "=r"(a) : "l"(p));
    return a;
}
__device__ __forceinline__ void cvt_hilo4(float4 v, uint2& hi, uint2& lo) {
    __nv_bfloat162 h01, h23, l01, l23;
    h01.x = __float2bfloat16_rn(v.x);
    h01.y = __float2bfloat16_rn(v.y);
    h23.x = __float2bfloat16_rn(v.z);
    h23.y = __float2bfloat16_rn(v.w);
    l01.x = __float2bfloat16_rn(v.x - __bfloat162float(h01.x));
    l01.y = __float2bfloat16_rn(v.y - __bfloat162float(h01.y));
    l23.x = __float2bfloat16_rn(v.z - __bfloat162float(h23.x));
    l23.y = __float2bfloat16_rn(v.w - __bfloat162float(h23.y));
    hi.x = *(uint32_t*)&h01; hi.y = *(uint32_t*)&h23;
    lo.x = *(uint32_t*)&l01; lo.y = *(uint32_t*)&l23;
}
__device__ __forceinline__ void ldmx4(uint32_t addr, uint32_t& r0, uint32_t& r1,
                                      uint32_t& r2, uint32_t& r3) {
    asm volatile("ldmatrix.sync.aligned.m8n8.x4.shared.b16 {%0,%1,%2,%3}, [%4];"
                 : "=r"(r0), "=r"(r1), "=r"(r2), "=r"(r3) : "r"(addr));
}
__device__ __forceinline__ void ldmx4t(uint32_t addr, uint32_t& r0, uint32_t& r1,
                                       uint32_t& r2, uint32_t& r3) {
    asm volatile("ldmatrix.sync.aligned.m8n8.x4.trans.shared.b16 {%0,%1,%2,%3}, [%4];"
                 : "=r"(r0), "=r"(r1), "=r"(r2), "=r"(r3) : "r"(addr));
}
__device__ __forceinline__ void mma16816(float* c, uint32_t a0, uint32_t a1,
                                         uint32_t a2, uint32_t a3,
                                         uint32_t b0, uint32_t b1) {
    asm volatile(
        "mma.sync.aligned.m16n8k16.row.col.f32.bf16.bf16.f32 "
        "{%0,%1,%2,%3}, {%4,%5,%6,%7}, {%8,%9}, {%0,%1,%2,%3};"
        : "+f"(c[0]), "+f"(c[1]), "+f"(c[2]), "+f"(c[3])
        : "r"(a0), "r"(a1), "r"(a2), "r"(a3), "r"(b0), "r"(b1));
}
__device__ __forceinline__ float ex2f(float x) {
    float r;
    asm("ex2.approx.f32 %0, %1;" : "=f"(r) : "f"(x));
    return r;
}
#define CPA16(dst, src) \
    asm volatile("cp.async.cg.shared.global [%0], [%1], 16;" :: "r"(dst), "l"(src))
#define CPA_COMMIT() asm volatile("cp.async.commit_group;" ::: "memory")
#define CPA_WAIT(n)  asm volatile("cp.async.wait_group %0;" :: "n"(n) : "memory")

// ---------------- weight convert: fp32 -> bf16 hi/lo ----------------
__global__ void wcvt_kernel(const float* __restrict__ src,
                            __nv_bfloat16* __restrict__ hi,
                            __nv_bfloat16* __restrict__ lo, int n4) {
    int t = blockIdx.x * 256 + threadIdx.x;
    if (t >= n4) return;
    float4 v = *(const float4*)(src + (size_t)t * 4);
    uint2 h, l;
    cvt_hilo4(v, h, l);
    *(uint2*)(hi + (size_t)t * 4) = h;
    *(uint2*)(lo + (size_t)t * 4) = l;
}

// ================= gemm_s: unified GEMM ====================================
// Tile 128x128, BK=32, 3-stage cp.async, SW64 swizzle, 2 CTAs/SM.
// Term-major MMA scheduling (acc reuse distance 8) to hide HMMA latency.
#define SBM 128
#define SBN 128
#define SBK 32
#define S_ALO 8192
#define S_WHI 16384
#define S_WLO 24576
#define SSTG  32768
#define SMEM3 (3 * SSTG)       // 98304 -> 2 CTAs/SM

__global__ __launch_bounds__(256, 2)
void gemm_s(const __nv_bfloat16* __restrict__ Ahi, const __nv_bfloat16* __restrict__ Alo,
            const __nv_bfloat16* __restrict__ Whi, const __nv_bfloat16* __restrict__ Wlo,
            const float* __restrict__ gate, const float* __restrict__ res,
            const float* __restrict__ bias,
            float* __restrict__ C,
            __nv_bfloat16* __restrict__ Chi, __nv_bfloat16* __restrict__ Clo,
            int M, int N, int K) {
    extern __shared__ char smem[];
    uint32_t sb = smem_u32(smem);
    int tid = threadIdx.x, wid = tid >> 5, lane = tid & 31;
    int bm = blockIdx.y * SBM, bn = blockIdx.x * SBN;
    int warp_m = (wid >> 2) * 64, warp_n = (wid & 3) * 32;

    // --- cp.async mapping: 64 rows per pass, 4 x 16B chunks per 64B row ---
    uint32_t strow = (uint32_t)(tid >> 2);
    uint32_t stc   = (uint32_t)(tid & 3) * 16;
    uint32_t st_off = strow * 64 + (stc ^ (((strow >> 1) & 3u) << 4));
    const __nv_bfloat16* Ah = Ahi + (size_t)(bm + strow) * K + (tid & 3) * 8;
    const __nv_bfloat16* Al = Alo + (size_t)(bm + strow) * K + (tid & 3) * 8;
    const __nv_bfloat16* Wh = Whi + (size_t)(bn + strow) * K + (tid & 3) * 8;
    const __nv_bfloat16* Wl = Wlo + (size_t)(bn + strow) * K + (tid & 3) * 8;

    auto load_stage = [&](int s, int chunk) {
        uint32_t base = sb + (uint32_t)s * SSTG;
        size_t ko = (size_t)chunk * SBK;
        #pragma unroll
        for (int j = 0; j < 2; j++) {
            uint32_t d = base + st_off + j * 4096;     // 64 rows * 64B
            size_t ro = (size_t)j * 64 * K + ko;
            CPA16(d,         (const char*)(Ah + ro));
            CPA16(d + S_ALO, (const char*)(Al + ro));
            CPA16(d + S_WHI, (const char*)(Wh + ro));
            CPA16(d + S_WLO, (const char*)(Wl + ro));
        }
    };

    // --- ldmatrix addressing (SW64: col ^= ((row>>1)&3)<<4) ---
    int ra = warp_m + (lane & 15);
    uint32_t a_row = (uint32_t)ra * 64;
    uint32_t swa = (((uint32_t)ra >> 1) & 3u) << 4;
    int rb = warp_n + (lane & 7) + ((lane >> 4) & 1) * 8;
    uint32_t b_row = (uint32_t)rb * 64;
    uint32_t swb = (((uint32_t)rb >> 1) & 3u) << 4;
    uint32_t col_a[2], col_b[2];
    int ha = ((lane >> 4) & 1) * 16;
    int hb = ((lane >> 3) & 1) * 16;
    #pragma unroll
    for (int ks = 0; ks < 2; ks++) {
        col_a[ks] = ((uint32_t)(ks * 32 + ha)) ^ swa;
        col_b[ks] = ((uint32_t)(ks * 32 + hb)) ^ swb;
    }

    float acc[4][4][4];
    #pragma unroll
    for (int i = 0; i < 4; i++)
        #pragma unroll
        for (int j = 0; j < 4; j++)
            #pragma unroll
            for (int r = 0; r < 4; r++) acc[i][j][r] = 0.f;

    const int nk = K / SBK;
    load_stage(0, 0);
    CPA_COMMIT();
    if (nk > 1) load_stage(1, 1);
    CPA_COMMIT();

    int sc = 0;
    for (int i = 0; i < nk; i++) {
        int snx = sc + 2; if (snx >= 3) snx -= 3;
        if (i + 2 < nk) load_stage(snx, i + 2);
        CPA_COMMIT();
        CPA_WAIT(2);
        __syncthreads();

        uint32_t base = sb + (uint32_t)sc * SSTG;
        #pragma unroll
        for (int ks = 0; ks < 2; ks++) {
            // B fragments (held across the whole ks step)
            uint32_t bhr[2][4], blr[2][4];
            #pragma unroll
            for (int np = 0; np < 2; np++) {
                uint32_t bd = base + S_WHI + b_row + (uint32_t)np * 1024 + col_b[ks];
                ldmx4(bd,        bhr[np][0], bhr[np][1], bhr[np][2], bhr[np][3]);
                ldmx4(bd + 8192, blr[np][0], blr[np][1], blr[np][2], blr[np][3]);
            }
            // Process mf in pairs; within a pair, term-major ordering gives
            // same-accumulator reuse distance of 8 independent MMAs.
            #pragma unroll
            for (int mfp = 0; mfp < 4; mfp += 2) {
                uint32_t ah[2][4], al[2][4];
                #pragma unroll
                for (int m2 = 0; m2 < 2; m2++) {
                    uint32_t ad = base + a_row + (uint32_t)(mfp + m2) * 1024 + col_a[ks];
                    ldmx4(ad,         ah[m2][0], ah[m2][1], ah[m2][2], ah[m2][3]);
                    ldmx4(ad + S_ALO, al[m2][0], al[m2][1], al[m2][2], al[m2][3]);
                }
                // term 1: hi * hi
                #pragma unroll
                for (int m2 = 0; m2 < 2; m2++)
                    #pragma unroll
                    for (int nf = 0; nf < 4; nf++)
                        mma16816(acc[mfp + m2][nf],
                                 ah[m2][0], ah[m2][1], ah[m2][2], ah[m2][3],
                                 bhr[nf >> 1][(nf & 1) * 2], bhr[nf >> 1][(nf & 1) * 2 + 1]);
                // term 2: hi * lo
                #pragma unroll
                for (int m2 = 0; m2 < 2; m2++)
                    #pragma unroll
                    for (int nf = 0; nf < 4; nf++)
                        mma16816(acc[mfp + m2][nf],
                                 ah[m2][0], ah[m2][1], ah[m2][2], ah[m2][3],
                                 blr[nf >> 1][(nf & 1) * 2], blr[nf >> 1][(nf & 1) * 2 + 1]);
                // term 3: lo * hi
                #pragma unroll
                for (int m2 = 0; m2 < 2; m2++)
                    #pragma unroll
                    for (int nf = 0; nf < 4; nf++)
                        mma16816(acc[mfp + m2][nf],
                                 al[m2][0], al[m2][1], al[m2][2], al[m2][3],
                                 bhr[nf >> 1][(nf & 1) * 2], bhr[nf >> 1][(nf & 1) * 2 + 1]);
            }
        }
        __syncthreads();
        sc = (sc == 2) ? 0 : sc + 1;
    }

    // ---- epilogue ----
    int tr = lane >> 2, tc = (lane & 3) * 2;
    #pragma unroll
    for (int mf = 0; mf < 4; mf++) {
        #pragma unroll
        for (int nf = 0; nf < 4; nf++) {
            int row0 = bm + warp_m + mf * 16 + tr;
            int col  = bn + warp_n + nf * 8 + tc;
            float* c = acc[mf][nf];
            float v[4] = {c[0], c[1], c[2], c[3]};
            size_t o0 = (size_t)row0 * N + col;
            size_t o1 = (size_t)(row0 + 8) * N + col;
            if (gate) {
                float2 g0 = *(const float2*)(gate + o0);
                float2 g1 = *(const float2*)(gate + o1);
                v[0] *= g0.x / (1.f + expf(-g0.x));
                v[1] *= g0.y / (1.f + expf(-g0.y));
                v[2] *= g1.x / (1.f + expf(-g1.x));
                v[3] *= g1.y / (1.f + expf(-g1.y));
            }
            if (res) {
                float2 r0 = *(const float2*)(res + o0);
                float2 r1 = *(const float2*)(res + o1);
                v[0] += r0.x; v[1] += r0.y; v[2] += r1.x; v[3] += r1.y;
            }
            if (bias) {
                float2 bb = *(const float2*)(bias + col);
                v[0] += bb.x; v[1] += bb.y; v[2] += bb.x; v[3] += bb.y;
            }
            if (C) {
                *(float2*)(C + o0) = {v[0], v[1]};
                *(float2*)(C + o1) = {v[2], v[3]};
            }
            if (Chi) {
                __nv_bfloat162 h0, h1, l0, l1;
                h0.x = __float2bfloat16_rn(v[0]); h0.y = __float2bfloat16_rn(v[1]);
                h1.x = __float2bfloat16_rn(v[2]); h1.y = __float2bfloat16_rn(v[3]);
                l0.x = __float2bfloat16_rn(v[0] - __bfloat162float(h0.x));
                l0.y = __float2bfloat16_rn(v[1] - __bfloat162float(h0.y));
                l1.x = __float2bfloat16_rn(v[2] - __bfloat162float(h1.x));
                l1.y = __float2bfloat16_rn(v[3] - __bfloat162float(h1.y));
                *(__nv_bfloat162*)(Chi + o0) = h0;
                *(__nv_bfloat162*)(Chi + o1) = h1;
                *(__nv_bfloat162*)(Clo + o0) = l0;
                *(__nv_bfloat162*)(Clo + o1) = l1;
            }
        }
    }
}

// ---------------- RMSNorm -> bf16 hi/lo ----------------
__global__ void rmsnorm_kernel(const float* __restrict__ x,
                               const float* __restrict__ w,
                               __nv_bfloat16* __restrict__ ohi,
                               __nv_bfloat16* __restrict__ olo) {
    int row = blockIdx.x;
    const float* xr = x + (size_t)row * DIM;
    float s = 0.f;
    #pragma unroll
    for (int i = threadIdx.x; i < DIM; i += 256) {
        float v = xr[i];
        s += v * v;
    }
    __shared__ float red[8];
    #pragma unroll
    for (int o = 16; o; o >>= 1) s += __shfl_down_sync(0xffffffffu, s, o);
    if ((threadIdx.x & 31) == 0) red[threadIdx.x >> 5] = s;
    __syncthreads();
    if (threadIdx.x < 8) {
        float t = red[threadIdx.x];
        #pragma unroll
        for (int o = 4; o; o >>= 1) t += __shfl_down_sync(0xffu, t, o);
        if (threadIdx.x == 0) red[0] = t;
    }
    __syncthreads();
    float inv = rsqrtf(red[0] * (1.0f / DIM) + LN_EPS);
    #pragma unroll
    for (int i = threadIdx.x; i < DIM; i += 256) {
        float v = xr[i] * inv * w[i];
        __nv_bfloat16 hi = __float2bfloat16_rn(v);
        ohi[(size_t)row * DIM + i] = hi;
        olo[(size_t)row * DIM + i] = __float2bfloat16_rn(v - __bfloat162float(hi));
    }
}

// ------------- RoPE on qkv buffer [rows,3072] -> hi/lo [B,H,S,HD] ----------
#define QSCALE 0.18033688011111793f   // 0.125 * log2(e)
__global__ void rope_cvt_kernel(const float* __restrict__ QKV,
                                __nv_bfloat16* __restrict__ qhi, __nv_bfloat16* __restrict__ qlo,
                                __nv_bfloat16* __restrict__ khi, __nv_bfloat16* __restrict__ klo) {
    int idx = blockIdx.x * 256 + threadIdx.x;
    if (idx >= BATCH * SEQ * NHEAD * (HDIM / 2)) return;
    int d = idx & 31;
    int h = (idx >> 5) & (NHEAD - 1);
    int s = (idx >> 9) & (SEQ - 1);
    int b = idx >> 20;
    size_t ibase = ((size_t)b * SEQ + s) * (3 * DIM) + (size_t)h * HDIM;
    size_t obase = (((size_t)b * NHEAD + h) * SEQ + s) * HDIM;
    float inv = expf(-(float)d * (9.210340371976184f / 32.f));
    float ang = (float)s * inv;
    float sn, cs;
    sincosf(ang, &sn, &cs);
    {
        float x1 = QKV[ibase + d], x2 = QKV[ibase + d + 32];
        float r1 = (x1 * cs - x2 * sn) * QSCALE;
        float r2 = (x2 * cs + x1 * sn) * QSCALE;
        __nv_bfloat16 h1 = __float2bfloat16_rn(r1);
        __nv_bfloat16 h2 = __float2bfloat16_rn(r2);
        qhi[obase + d]      = h1;
        qhi[obase + d + 32] = h2;
        qlo[obase + d]      = __float2bfloat16_rn(r1 - __bfloat162float(h1));
        qlo[obase + d + 32] = __float2bfloat16_rn(r2 - __bfloat162float(h2));
    }
    {
        float x1 = QKV[ibase + DIM + d], x2 = QKV[ibase + DIM + d + 32];
        float r1 = x1 * cs - x2 * sn;
        float r2 = x2 * cs + x1 * sn;
        __nv_bfloat16 h1 = __float2bfloat16_rn(r1);
        __nv_bfloat16 h2 = __float2bfloat16_rn(r2);
        khi[obase + d]      = h1;
        khi[obase + d + 32] = h2;
        klo[obase + d]      = __float2bfloat16_rn(r1 - __bfloat162float(h1));
        klo[obase + d + 32] = __float2bfloat16_rn(r2 - __bfloat162float(h2));
    }
}

// ------------- V convert: qkv fp32 -> bf16 [B,H,S,HD] -------------
__global__ void v_cvt_kernel(const float* __restrict__ QKV, __nv_bfloat16* __restrict__ vb) {
    int t = blockIdx.x * 256 + threadIdx.x;
    if (t >= ROWS * DIM / 4) return;
    int e = t * 4;
    int c = e & 63;
    int h = (e >> 6) & (NHEAD - 1);
    int s = (e >> 10) & (SEQ - 1);
    int b = e >> 21;
    size_t ioff = ((size_t)b * SEQ + s) * (3 * DIM) + 2 * DIM + (size_t)h * HDIM + c;
    size_t ooff = (((size_t)b * NHEAD + h) * SEQ + s) * HDIM + c;
    float4 v = *(const float4*)(QKV + ioff);
    __nv_bfloat162 p0, p1;
    p0.x = __float2bfloat16_rn(v.x); p0.y = __float2bfloat16_rn(v.y);
    p1.x = __float2bfloat16_rn(v.z); p1.y = __float2bfloat16_rn(v.w);
    uint2 o = { *(uint32_t*)&p0, *(uint32_t*)&p1 };
    *(uint2*)(vb + ooff) = o;
}

// ================= MMA flash attention =================
#define AROWB 144
#define A_QHI 0
#define A_QLO 9216
#define A_K0  18432
#define A_V0  55296
#define ASMEM 73728

__global__ __launch_bounds__(128)
void attn_mma(const __nv_bfloat16* __restrict__ qhi, const __nv_bfloat16* __restrict__ qlo,
              const __nv_bfloat16* __restrict__ khi, const __nv_bfloat16* __restrict__ klo,
              const __nv_bfloat16* __restrict__ vb,
              __nv_bfloat16* __restrict__ Ohi, __nv_bfloat16* __restrict__ Olo) {
    extern __shared__ char smem[];
    uint32_t sb = smem_u32(smem);
    int tid = threadIdx.x, wid = tid >> 5, lane = tid & 31;
    int b = blockIdx.z, h = blockIdx.y;
    int q0 = blockIdx.x * 64;
    size_t hoff = ((size_t)b * NHEAD + h) * SEQ * HDIM;

    {
        const uint4* qh4 = (const uint4*)(qhi + hoff + (size_t)q0 * HDIM);
        const uint4* ql4 = (const uint4*)(qlo + hoff + (size_t)q0 * HDIM);
        #pragma unroll
        for (int j = 0; j < 4; j++) {
            int f = tid + j * 128;
            int r = f >> 3, c = f & 7;
            *(uint4*)(smem + A_QHI + r * AROWB + c * 16) = qh4[r * 8 + c];
            *(uint4*)(smem + A_QLO + r * AROWB + c * 16) = ql4[r * 8 + c];
        }
    }
    __syncthreads();

    uint32_t qh[4][4], ql[4][4];
    {
        uint32_t a_base = sb + (uint32_t)(wid * 16 + (lane & 15)) * AROWB + ((lane >> 4) & 1) * 16;
        #pragma unroll
        for (int ks = 0; ks < 4; ks++) {
            ldmx4(a_base + ks * 32,         qh[ks][0], qh[ks][1], qh[ks][2], qh[ks][3]);
            ldmx4(a_base + A_QLO + ks * 32, ql[ks][0], ql[ks][1], ql[ks][2], ql[ks][3]);
        }
    }

    float ctx[8][4];
    #pragma unroll
    for (int j = 0; j < 8; j++)
        #pragma unroll
        for (int r = 0; r < 4; r++) ctx[j][r] = 0.f;
    float m0 = -1e30f, m1 = -1e30f, l0 = 0.f, l1 = 0.f;

    const __nv_bfloat16* kh_g = khi + hoff;
    const __nv_bfloat16* kl_g = klo + hoff;
    const __nv_bfloat16* v_g  = vb + hoff;

    {
        #pragma unroll
        for (int j = 0; j < 4; j++) {
            int f = tid + j * 128;
            int r = f >> 3, c = f & 7;
            uint32_t so = (uint32_t)(r * AROWB + c * 16);
            CPA16(sb + A_K0 + so,        (const char*)(kh_g + r * 64 + c * 8));
            CPA16(sb + A_K0 + 9216 + so, (const char*)(kl_g + r * 64 + c * 8));
            CPA16(sb + A_V0 + so,        (const char*)(v_g  + r * 64 + c * 8));
        }
        CPA_COMMIT();
    }

    const int NT = SEQ / 64;
    for (int t = 0; t < NT; t++) {
        int s = t & 1;
        if (t + 1 < NT) {
            int nxt = s ^ 1;
            size_t goff = (size_t)(t + 1) * 64 * 64;
            #pragma unroll
            for (int j = 0; j < 4; j++) {
                int f = tid + j * 128;
                int r = f >> 3, c = f & 7;
                uint32_t so = (uint32_t)(r * AROWB + c * 16);
                CPA16(sb + A_K0 + nxt * 18432 + so,        (const char*)(kh_g + goff + r * 64 + c * 8));
                CPA16(sb + A_K0 + nxt * 18432 + 9216 + so, (const char*)(kl_g + goff + r * 64 + c * 8));
                CPA16(sb + A_V0 + nxt * 9216 + so,         (const char*)(v_g  + goff + r * 64 + c * 8));
            }
            CPA_COMMIT();
            CPA_WAIT(1);
        } else {
            CPA_WAIT(0);
        }
        __syncthreads();

        uint32_t kb_hi = sb + A_K0 + s * 18432;
        uint32_t kb_lo = kb_hi + 9216;
        uint32_t vbse  = sb + A_V0 + s * 9216;

        float sc[8][4];
        #pragma unroll
        for (int j = 0; j < 8; j++)
            #pragma unroll
            for (int r = 0; r < 4; r++) sc[j][r] = 0.f;

        uint32_t b_off = (uint32_t)((lane & 7) + ((lane >> 4) & 1) * 8) * AROWB +
                         ((lane >> 3) & 1) * 16;
        #pragma unroll
        for (int ks = 0; ks < 4; ks++) {
            #pragma unroll
            for (int ng = 0; ng < 4; ng++) {
                uint32_t bh0, bh1, bh2, bh3, bl0, bl1, bl2, bl3;
                uint32_t ad = b_off + (uint32_t)ng * (16 * AROWB) + ks * 32;
                ldmx4(kb_hi + ad, bh0, bh1, bh2, bh3);
                ldmx4(kb_lo + ad, bl0, bl1, bl2, bl3);
                // term-major interleave across the two accumulators
                mma16816(sc[2 * ng],     qh[ks][0], qh[ks][1], qh[ks][2], qh[ks][3], bh0, bh1);
                mma16816(sc[2 * ng + 1], qh[ks][0], qh[ks][1], qh[ks][2], qh[ks][3], bh2, bh3);
                mma16816(sc[2 * ng],     qh[ks][0], qh[ks][1], qh[ks][2], qh[ks][3], bl0, bl1);
                mma16816(sc[2 * ng + 1], qh[ks][0], qh[ks][1], qh[ks][2], qh[ks][3], bl2, bl3);
                mma16816(sc[2 * ng],     ql[ks][0], ql[ks][1], ql[ks][2], ql[ks][3], bh0, bh1);
                mma16816(sc[2 * ng + 1], ql[ks][0], ql[ks][1], ql[ks][2], ql[ks][3], bh2, bh3);
            }
        }

        float mn0 = m0, mn1 = m1;
        #pragma unroll
        for (int j = 0; j < 8; j++) {
            mn0 = fmaxf(mn0, fmaxf(sc[j][0], sc[j][1]));
            mn1 = fmaxf(mn1, fmaxf(sc[j][2], sc[j][3]));
        }
        mn0 = fmaxf(mn0, __shfl_xor_sync(0xffffffffu, mn0, 1));
        mn0 = fmaxf(mn0, __shfl_xor_sync(0xffffffffu, mn0, 2));
        mn1 = fmaxf(mn1, __shfl_xor_sync(0xffffffffu, mn1, 1));
        mn1 = fmaxf(mn1, __shfl_xor_sync(0xffffffffu, mn1, 2));
        float corr0 = ex2f(m0 - mn0);
        float corr1 = ex2f(m1 - mn1);
        m0 = mn0; m1 = mn1;
        l0 *= corr0; l1 *= corr1;
        #pragma unroll
        for (int j = 0; j < 8; j++) {
            ctx[j][0] *= corr0; ctx[j][1] *= corr0;
            ctx[j][2] *= corr1; ctx[j][3] *= corr1;
        }
        uint32_t pa[8], pb[8];
        #pragma unroll
        for (int j = 0; j < 8; j++) {
            float p0 = ex2f(sc[j][0] - mn0);
            float p1 = ex2f(sc[j][1] - mn0);
            float p2 = ex2f(sc[j][2] - mn1);
            float p3 = ex2f(sc[j][3] - mn1);
            l0 += p0 + p1; l1 += p2 + p3;
            __nv_bfloat162 t0 = __floats2bfloat162_rn(p0, p1);
            __nv_bfloat162 t1 = __floats2bfloat162_rn(p2, p3);
            pa[j] = *(uint32_t*)&t0;
            pb[j] = *(uint32_t*)&t1;
        }

        uint32_t v_off = (uint32_t)(lane & 15) * AROWB + ((lane >> 4) & 1) * 16;
        #pragma unroll
        for (int ks = 0; ks < 4; ks++) {
            #pragma unroll
            for (int nd = 0; nd < 4; nd++) {
                uint32_t r0, r1, r2, r3;
                ldmx4t(vbse + v_off + (uint32_t)ks * (16 * AROWB) + nd * 32, r0, r1, r2, r3);
                mma16816(ctx[nd * 2],     pa[2 * ks], pb[2 * ks], pa[2 * ks + 1], pb[2 * ks + 1], r0, r1);
                mma16816(ctx[nd * 2 + 1], pa[2 * ks], pb[2 * ks], pa[2 * ks + 1], pb[2 * ks + 1], r2, r3);
            }
        }
        __syncthreads();
    }

    l0 += __shfl_xor_sync(0xffffffffu, l0, 1);
    l0 += __shfl_xor_sync(0xffffffffu, l0, 2);
    l1 += __shfl_xor_sync(0xffffffffu, l1, 1);
    l1 += __shfl_xor_sync(0xffffffffu, l1, 2);
    float i0 = 1.f / l0, i1 = 1.f / l1;

    int tr = lane >> 2, tc = (lane & 3) * 2;
    int row0 = q0 + wid * 16 + tr;
    #pragma unroll
    for (int f = 0; f < 8; f++) {
        int d = f * 8 + tc;
        float* c = ctx[f];
        size_t o0 = ((size_t)b * SEQ + row0) * DIM + (size_t)h * HDIM + d;
        size_t o1 = ((size_t)b * SEQ + row0 + 8) * DIM + (size_t)h * HDIM + d;
        float w0 = c[0] * i0, w1 = c[1] * i0;
        float w2 = c[2] * i1, w3 = c[3] * i1;
        __nv_bfloat162 h0, h1, l0v, l1v;
        h0.x = __float2bfloat16_rn(w0); h0.y = __float2bfloat16_rn(w1);
        h1.x = __float2bfloat16_rn(w2); h1.y = __float2bfloat16_rn(w3);
        l0v.x = __float2bfloat16_rn(w0 - __bfloat162float(h0.x));
        l0v.y = __float2bfloat16_rn(w1 - __bfloat162float(h0.y));
        l1v.x = __float2bfloat16_rn(w2 - __bfloat162float(h1.x));
        l1v.y = __float2bfloat16_rn(w3 - __bfloat162float(h1.y));
        *(__nv_bfloat162*)(Ohi + o0) = h0;
        *(__nv_bfloat162*)(Ohi + o1) = h1;
        *(__nv_bfloat162*)(Olo + o0) = l0v;
        *(__nv_bfloat162*)(Olo + o1) = l1v;
    }
}

// ---------------- launch ----------------
extern "C" void kernel_launch(void* const* d_in, const int* in_sizes, int n_in,
                              void* d_out, int out_size) {
    const float* x_in   = (const float*)d_in[0];
    const float* Wq     = (const float*)d_in[1];
    const float* Wk     = (const float*)d_in[2];
    const float* Wv     = (const float*)d_in[3];
    const float* Wo     = (const float*)d_in[4];
    const float* ln1_w  = (const float*)d_in[5];
    const float* ln2_w  = (const float*)d_in[6];
    const float* Wgate  = (const float*)d_in[7];
    const float* Wup    = (const float*)d_in[8];
    const float* Wdown  = (const float*)d_in[9];
    const float* W_out  = (const float*)d_in[10];
    const float* b_out  = (const float*)d_in[11];
    float* out = (float*)d_out;

    float *x, *qkv, *f1;
    __nv_bfloat16 *hhi, *hlo, *chi, *clo, *f1hi, *f1lo, *xhi, *xlo, *whi, *wlo;
    __nv_bfloat16 *qhi, *qlo, *khi, *klo, *vbp;
    cudaGetSymbolAddress((void**)&x,    g_x);
    cudaGetSymbolAddress((void**)&qkv,  g_qkv);
    cudaGetSymbolAddress((void**)&f1,   g_f1);
    cudaGetSymbolAddress((void**)&hhi,  g_hhi);
    cudaGetSymbolAddress((void**)&hlo,  g_hlo);
    cudaGetSymbolAddress((void**)&chi,  g_chi);
    cudaGetSymbolAddress((void**)&clo,  g_clo);
    cudaGetSymbolAddress((void**)&f1hi, g_f1hi);
    cudaGetSymbolAddress((void**)&f1lo, g_f1lo);
    cudaGetSymbolAddress((void**)&xhi,  g_xhi);
    cudaGetSymbolAddress((void**)&xlo,  g_xlo);
    cudaGetSymbolAddress((void**)&whi,  g_whi);
    cudaGetSymbolAddress((void**)&wlo,  g_wlo);
    cudaGetSymbolAddress((void**)&qhi,  g_qhi);
    cudaGetSymbolAddress((void**)&qlo,  g_qlo);
    cudaGetSymbolAddress((void**)&khi,  g_khi);
    cudaGetSymbolAddress((void**)&klo,  g_klo);
    cudaGetSymbolAddress((void**)&vbp,  g_vb);

    cudaFuncSetAttribute(gemm_s,   cudaFuncAttributeMaxDynamicSharedMemorySize, SMEM3);
    cudaFuncSetAttribute(attn_mma, cudaFuncAttributeMaxDynamicSharedMemorySize, ASMEM);

    const size_t xbytes = (size_t)ROWS * DIM * sizeof(float);
    cudaMemcpyAsync(x, x_in, xbytes, cudaMemcpyDeviceToDevice);

    // --- weight converts (fp32 -> bf16 hi/lo) ---
    const int DD4 = DIM * DIM / 4, FD4 = FFDIM * DIM / 4;
    wcvt_kernel<<<DD4 / 256, 256>>>(Wq,    whi + WOFF_Q, wlo + WOFF_Q, DD4);
    wcvt_kernel<<<DD4 / 256, 256>>>(Wk,    whi + WOFF_K, wlo + WOFF_K, DD4);
    wcvt_kernel<<<DD4 / 256, 256>>>(Wv,    whi + WOFF_V, wlo + WOFF_V, DD4);
    wcvt_kernel<<<DD4 / 256, 256>>>(Wo,    whi + WOFF_O, wlo + WOFF_O, DD4);
    wcvt_kernel<<<FD4 / 256, 256>>>(Wgate, whi + WOFF_G, wlo + WOFF_G, FD4);
    wcvt_kernel<<<FD4 / 256, 256>>>(Wup,   whi + WOFF_U, wlo + WOFF_U, FD4);
    wcvt_kernel<<<FD4 / 256, 256>>>(Wdown, whi + WOFF_D, wlo + WOFF_D, FD4);
    wcvt_kernel<<<DD4 / 256, 256>>>(W_out, whi + WOFF_H, wlo + WOFF_H, DD4);

    // --- attention block ---
    rmsnorm_kernel<<<ROWS, 256>>>(x, ln1_w, hhi, hlo);

    // fused QKV GEMM: [8192,1024] @ [3072,1024]^T -> [8192,3072]
    dim3 gqkv(3 * DIM / SBN, ROWS / SBM);   // (24, 64)
    gemm_s<<<gqkv, 256, SMEM3>>>(hhi, hlo, whi + WOFF_Q, wlo + WOFF_Q,
                                 nullptr, nullptr, nullptr,
                                 qkv, nullptr, nullptr, ROWS, 3 * DIM, DIM);

    int rope_total = BATCH * SEQ * NHEAD * (HDIM / 2);
    rope_cvt_kernel<<<(rope_total + 255) / 256, 256>>>(qkv, qhi, qlo, khi, klo);
    v_cvt_kernel<<<(ROWS * DIM / 4 + 255) / 256, 256>>>(qkv, vbp);

    dim3 ga(SEQ / 64, NHEAD, BATCH);
    attn_mma<<<ga, 128, ASMEM>>>(qhi, qlo, khi, klo, vbp, chi, clo);

    dim3 g1(DIM / SBN, ROWS / SBM);    // (8, 64)
    // x = x + ctx @ Wo^T
    gemm_s<<<g1, 256, SMEM3>>>(chi, clo, whi + WOFF_O, wlo + WOFF_O,
                               nullptr, x, nullptr,
                               x, nullptr, nullptr, ROWS, DIM, DIM);

    // --- MLP block ---
    rmsnorm_kernel<<<ROWS, 256>>>(x, ln2_w, hhi, hlo);
    dim3 gff(FFDIM / SBN, ROWS / SBM); // (32, 64)
    // gate -> f1 (fp32)
    gemm_s<<<gff, 256, SMEM3>>>(hhi, hlo, whi + WOFF_G, wlo + WOFF_G,
                                nullptr, nullptr, nullptr,
                                f1, nullptr, nullptr, ROWS, FFDIM, DIM);
    // up with fused silu(gate)*up -> f1 hi/lo
    gemm_s<<<gff, 256, SMEM3>>>(hhi, hlo, whi + WOFF_U, wlo + WOFF_U,
                                f1, nullptr, nullptr,
                                nullptr, f1hi, f1lo, ROWS, FFDIM, DIM);

    // x_new = x + f1b @ Wdown^T -> bf16 hi/lo (feeds head GEMM)
    gemm_s<<<g1, 256, SMEM3>>>(f1hi, f1lo, whi + WOFF_D, wlo + WOFF_D,
                               nullptr, x, nullptr,
                               nullptr, xhi, xlo, ROWS, DIM, FFDIM);

    // --- output head ---
    gemm_s<<<g1, 256, SMEM3>>>(xhi, xlo, whi + WOFF_H, wlo + WOFF_H,
                               nullptr, nullptr, b_out,
                               out, nullptr, nullptr, ROWS, DIM, DIM);
}

// round 10
// speedup vs baseline: 5.0940x; 1.3216x over previous
#include <cuda_runtime.h>
#include <cuda_bf16.h>
#include <cuda_fp16.h>
#include <cstdint>

// Problem constants
#define BATCH 4
#define SEQ   2048
#define DIM   1024
#define NHEAD 16
#define HDIM  64
#define FFDIM 4096
#define ROWS  (BATCH * SEQ)            // 8192
#define LN_EPS 1e-6f

// ---------------- scratch (device globals; no allocation) ----------------
__device__ float g_x  [(size_t)ROWS * DIM];
__device__ float g_qkv[(size_t)ROWS * 3 * DIM];
__device__ float g_f1 [(size_t)ROWS * FFDIM];
// fp16 single activation operands (GEMM A inputs)
__device__ __half g_h16 [(size_t)ROWS * DIM];
__device__ __half g_c16 [(size_t)ROWS * DIM];
__device__ __half g_f116[(size_t)ROWS * FFDIM];
__device__ __half g_x16 [(size_t)ROWS * DIM];
// fp16 hi/lo weights (Wq|Wk|Wv|Wo|Wgate|Wup|Wdown|W_out)
#define WOFF_Q  0
#define WOFF_K  1048576
#define WOFF_V  2097152
#define WOFF_O  3145728
#define WOFF_G  4194304
#define WOFF_U  8388608
#define WOFF_D  12582912
#define WOFF_H  16777216
#define WTOT    17825792
__device__ __half g_whi[(size_t)WTOT];
__device__ __half g_wlo[(size_t)WTOT];
// bf16 attention operands, [B,H,S,HD] layout
__device__ __nv_bfloat16 g_qhi[(size_t)ROWS * DIM];
__device__ __nv_bfloat16 g_qlo[(size_t)ROWS * DIM];
__device__ __nv_bfloat16 g_khi[(size_t)ROWS * DIM];
__device__ __nv_bfloat16 g_klo[(size_t)ROWS * DIM];
__device__ __nv_bfloat16 g_vb [(size_t)ROWS * DIM];

__device__ __forceinline__ uint32_t smem_u32(const void* p) {
    uint32_t a;
    asm("{ .reg .u64 t; cvta.to.shared.u64 t, %1; cvt.u32.u64 %0, t; }"
        : "=r"(a) : "l"(p));
    return a;
}
__device__ __forceinline__ void ldmx4(uint32_t addr, uint32_t& r0, uint32_t& r1,
                                      uint32_t& r2, uint32_t& r3) {
    asm volatile("ldmatrix.sync.aligned.m8n8.x4.shared.b16 {%0,%1,%2,%3}, [%4];"
                 : "=r"(r0), "=r"(r1), "=r"(r2), "=r"(r3) : "r"(addr));
}
__device__ __forceinline__ void ldmx4t(uint32_t addr, uint32_t& r0, uint32_t& r1,
                                       uint32_t& r2, uint32_t& r3) {
    asm volatile("ldmatrix.sync.aligned.m8n8.x4.trans.shared.b16 {%0,%1,%2,%3}, [%4];"
                 : "=r"(r0), "=r"(r1), "=r"(r2), "=r"(r3) : "r"(addr));
}
// bf16 MMA (attention)
__device__ __forceinline__ void mma16816(float* c, uint32_t a0, uint32_t a1,
                                         uint32_t a2, uint32_t a3,
                                         uint32_t b0, uint32_t b1) {
    asm volatile(
        "mma.sync.aligned.m16n8k16.row.col.f32.bf16.bf16.f32 "
        "{%0,%1,%2,%3}, {%4,%5,%6,%7}, {%8,%9}, {%0,%1,%2,%3};"
        : "+f"(c[0]), "+f"(c[1]), "+f"(c[2]), "+f"(c[3])
        : "r"(a0), "r"(a1), "r"(a2), "r"(a3), "r"(b0), "r"(b1));
}
// fp16 MMA (GEMMs)
__device__ __forceinline__ void mma16816h(float* c, uint32_t a0, uint32_t a1,
                                          uint32_t a2, uint32_t a3,
                                          uint32_t b0, uint32_t b1) {
    asm volatile(
        "mma.sync.aligned.m16n8k16.row.col.f32.f16.f16.f32 "
        "{%0,%1,%2,%3}, {%4,%5,%6,%7}, {%8,%9}, {%0,%1,%2,%3};"
        : "+f"(c[0]), "+f"(c[1]), "+f"(c[2]), "+f"(c[3])
        : "r"(a0), "r"(a1), "r"(a2), "r"(a3), "r"(b0), "r"(b1));
}
__device__ __forceinline__ float ex2f(float x) {
    float r;
    asm("ex2.approx.f32 %0, %1;" : "=f"(r) : "f"(x));
    return r;
}
#define CPA16(dst, src) \
    asm volatile("cp.async.cg.shared.global [%0], [%1], 16;" :: "r"(dst), "l"(src))
#define CPA_COMMIT() asm volatile("cp.async.commit_group;" ::: "memory")
#define CPA_WAIT(n)  asm volatile("cp.async.wait_group %0;" :: "n"(n) : "memory")

// ---------------- weight convert: fp32 -> fp16 hi/lo ----------------
__global__ void wcvt_kernel(const float* __restrict__ src,
                            __half* __restrict__ hi,
                            __half* __restrict__ lo, int n4) {
    int t = blockIdx.x * 256 + threadIdx.x;
    if (t >= n4) return;
    float4 v = *(const float4*)(src + (size_t)t * 4);
    __half h0 = __float2half_rn(v.x), h1 = __float2half_rn(v.y);
    __half h2 = __float2half_rn(v.z), h3 = __float2half_rn(v.w);
    __half l0 = __float2half_rn(v.x - __half2float(h0));
    __half l1 = __float2half_rn(v.y - __half2float(h1));
    __half l2 = __float2half_rn(v.z - __half2float(h2));
    __half l3 = __float2half_rn(v.w - __half2float(h3));
    __half2 hp0 = __halves2half2(h0, h1), hp1 = __halves2half2(h2, h3);
    __half2 lp0 = __halves2half2(l0, l1), lp1 = __halves2half2(l2, l3);
    uint2 ho = { *(uint32_t*)&hp0, *(uint32_t*)&hp1 };
    uint2 lw = { *(uint32_t*)&lp0, *(uint32_t*)&lp1 };
    *(uint2*)(hi + (size_t)t * 4) = ho;
    *(uint2*)(lo + (size_t)t * 4) = lw;
}

// ================= gemm_s: fp16 2-term GEMM ================================
// C[M,N] = A[M,K] @ (Whi+Wlo)[N,K]^T ; A single fp16, W fp16 hi/lo.
// Tile 128x128, BK=32, 3-stage cp.async, SW64 swizzle, 2 CTAs/SM.
#define SBM 128
#define SBN 128
#define SBK 32
#define S_WHI 8192
#define S_WLO 16384
#define SSTG  24576
#define SMEM3 (3 * SSTG)       // 73728 -> 2 CTAs/SM

__global__ __launch_bounds__(256, 2)
void gemm_s(const __half* __restrict__ A,
            const __half* __restrict__ Whi, const __half* __restrict__ Wlo,
            const float* __restrict__ gate, const float* __restrict__ res,
            const float* __restrict__ bias,
            float* __restrict__ C, __half* __restrict__ C16,
            int M, int N, int K) {
    extern __shared__ char smem[];
    uint32_t sb = smem_u32(smem);
    int tid = threadIdx.x, wid = tid >> 5, lane = tid & 31;
    int bm = blockIdx.y * SBM, bn = blockIdx.x * SBN;
    int warp_m = (wid >> 2) * 64, warp_n = (wid & 3) * 32;

    // --- cp.async mapping: 64 rows per pass, 4 x 16B chunks per 64B row ---
    uint32_t strow = (uint32_t)(tid >> 2);
    uint32_t stc   = (uint32_t)(tid & 3) * 16;
    uint32_t st_off = strow * 64 + (stc ^ (((strow >> 1) & 3u) << 4));
    const __half* Ap = A   + (size_t)(bm + strow) * K + (tid & 3) * 8;
    const __half* Wh = Whi + (size_t)(bn + strow) * K + (tid & 3) * 8;
    const __half* Wl = Wlo + (size_t)(bn + strow) * K + (tid & 3) * 8;

    auto load_stage = [&](int s, int chunk) {
        uint32_t base = sb + (uint32_t)s * SSTG;
        size_t ko = (size_t)chunk * SBK;
        #pragma unroll
        for (int j = 0; j < 2; j++) {
            uint32_t d = base + st_off + j * 4096;     // 64 rows * 64B
            size_t ro = (size_t)j * 64 * K + ko;
            CPA16(d,         (const char*)(Ap + ro));
            CPA16(d + S_WHI, (const char*)(Wh + ro));
            CPA16(d + S_WLO, (const char*)(Wl + ro));
        }
    };

    // --- ldmatrix addressing (SW64: col ^= ((row>>1)&3)<<4) ---
    int ra = warp_m + (lane & 15);
    uint32_t a_row = (uint32_t)ra * 64;
    uint32_t swa = (((uint32_t)ra >> 1) & 3u) << 4;
    int rb = warp_n + (lane & 7) + ((lane >> 4) & 1) * 8;
    uint32_t b_row = (uint32_t)rb * 64;
    uint32_t swb = (((uint32_t)rb >> 1) & 3u) << 4;
    uint32_t col_a[2], col_b[2];
    int ha = ((lane >> 4) & 1) * 16;
    int hb = ((lane >> 3) & 1) * 16;
    #pragma unroll
    for (int ks = 0; ks < 2; ks++) {
        col_a[ks] = ((uint32_t)(ks * 32 + ha)) ^ swa;
        col_b[ks] = ((uint32_t)(ks * 32 + hb)) ^ swb;
    }

    float acc[4][4][4];
    #pragma unroll
    for (int i = 0; i < 4; i++)
        #pragma unroll
        for (int j = 0; j < 4; j++)
            #pragma unroll
            for (int r = 0; r < 4; r++) acc[i][j][r] = 0.f;

    const int nk = K / SBK;
    load_stage(0, 0);
    CPA_COMMIT();
    if (nk > 1) load_stage(1, 1);
    CPA_COMMIT();

    int sc = 0;
    for (int i = 0; i < nk; i++) {
        int snx = sc + 2; if (snx >= 3) snx -= 3;
        if (i + 2 < nk) load_stage(snx, i + 2);
        CPA_COMMIT();
        CPA_WAIT(2);
        __syncthreads();

        uint32_t base = sb + (uint32_t)sc * SSTG;
        #pragma unroll
        for (int ks = 0; ks < 2; ks++) {
            uint32_t bhr[2][4], blr[2][4];
            #pragma unroll
            for (int np = 0; np < 2; np++) {
                uint32_t bd = base + S_WHI + b_row + (uint32_t)np * 1024 + col_b[ks];
                ldmx4(bd,        bhr[np][0], bhr[np][1], bhr[np][2], bhr[np][3]);
                ldmx4(bd + 8192, blr[np][0], blr[np][1], blr[np][2], blr[np][3]);
            }
            uint32_t ar[4][4];
            #pragma unroll
            for (int mf = 0; mf < 4; mf++) {
                uint32_t ad = base + a_row + (uint32_t)mf * 1024 + col_a[ks];
                ldmx4(ad, ar[mf][0], ar[mf][1], ar[mf][2], ar[mf][3]);
            }
            // term 1: A * Whi  (16 independent MMAs)
            #pragma unroll
            for (int mf = 0; mf < 4; mf++)
                #pragma unroll
                for (int nf = 0; nf < 4; nf++)
                    mma16816h(acc[mf][nf],
                              ar[mf][0], ar[mf][1], ar[mf][2], ar[mf][3],
                              bhr[nf >> 1][(nf & 1) * 2], bhr[nf >> 1][(nf & 1) * 2 + 1]);
            // term 2: A * Wlo
            #pragma unroll
            for (int mf = 0; mf < 4; mf++)
                #pragma unroll
                for (int nf = 0; nf < 4; nf++)
                    mma16816h(acc[mf][nf],
                              ar[mf][0], ar[mf][1], ar[mf][2], ar[mf][3],
                              blr[nf >> 1][(nf & 1) * 2], blr[nf >> 1][(nf & 1) * 2 + 1]);
        }
        __syncthreads();
        sc = (sc == 2) ? 0 : sc + 1;
    }

    // ---- epilogue ----
    int tr = lane >> 2, tc = (lane & 3) * 2;
    #pragma unroll
    for (int mf = 0; mf < 4; mf++) {
        #pragma unroll
        for (int nf = 0; nf < 4; nf++) {
            int row0 = bm + warp_m + mf * 16 + tr;
            int col  = bn + warp_n + nf * 8 + tc;
            float* c = acc[mf][nf];
            float v[4] = {c[0], c[1], c[2], c[3]};
            size_t o0 = (size_t)row0 * N + col;
            size_t o1 = (size_t)(row0 + 8) * N + col;
            if (gate) {
                float2 g0 = *(const float2*)(gate + o0);
                float2 g1 = *(const float2*)(gate + o1);
                v[0] *= g0.x / (1.f + expf(-g0.x));
                v[1] *= g0.y / (1.f + expf(-g0.y));
                v[2] *= g1.x / (1.f + expf(-g1.x));
                v[3] *= g1.y / (1.f + expf(-g1.y));
            }
            if (res) {
                float2 r0 = *(const float2*)(res + o0);
                float2 r1 = *(const float2*)(res + o1);
                v[0] += r0.x; v[1] += r0.y; v[2] += r1.x; v[3] += r1.y;
            }
            if (bias) {
                float2 bb = *(const float2*)(bias + col);
                v[0] += bb.x; v[1] += bb.y; v[2] += bb.x; v[3] += bb.y;
            }
            if (C) {
                *(float2*)(C + o0) = {v[0], v[1]};
                *(float2*)(C + o1) = {v[2], v[3]};
            }
            if (C16) {
                __half2 h0 = __floats2half2_rn(v[0], v[1]);
                __half2 h1 = __floats2half2_rn(v[2], v[3]);
                *(__half2*)(C16 + o0) = h0;
                *(__half2*)(C16 + o1) = h1;
            }
        }
    }
}

// ---------------- RMSNorm -> fp16 ----------------
__global__ void rmsnorm_kernel(const float* __restrict__ x,
                               const float* __restrict__ w,
                               __half* __restrict__ o16) {
    int row = blockIdx.x;
    const float* xr = x + (size_t)row * DIM;
    float s = 0.f;
    #pragma unroll
    for (int i = threadIdx.x; i < DIM; i += 256) {
        float v = xr[i];
        s += v * v;
    }
    __shared__ float red[8];
    #pragma unroll
    for (int o = 16; o; o >>= 1) s += __shfl_down_sync(0xffffffffu, s, o);
    if ((threadIdx.x & 31) == 0) red[threadIdx.x >> 5] = s;
    __syncthreads();
    if (threadIdx.x < 8) {
        float t = red[threadIdx.x];
        #pragma unroll
        for (int o = 4; o; o >>= 1) t += __shfl_down_sync(0xffu, t, o);
        if (threadIdx.x == 0) red[0] = t;
    }
    __syncthreads();
    float inv = rsqrtf(red[0] * (1.0f / DIM) + LN_EPS);
    #pragma unroll
    for (int i = threadIdx.x; i < DIM; i += 256) {
        float v = xr[i] * inv * w[i];
        o16[(size_t)row * DIM + i] = __float2half_rn(v);
    }
}

// ------------- RoPE on qkv buffer [rows,3072] -> hi/lo bf16 [B,H,S,HD] -----
#define QSCALE 0.18033688011111793f   // 0.125 * log2(e)
__global__ void rope_cvt_kernel(const float* __restrict__ QKV,
                                __nv_bfloat16* __restrict__ qhi, __nv_bfloat16* __restrict__ qlo,
                                __nv_bfloat16* __restrict__ khi, __nv_bfloat16* __restrict__ klo) {
    int idx = blockIdx.x * 256 + threadIdx.x;
    if (idx >= BATCH * SEQ * NHEAD * (HDIM / 2)) return;
    int d = idx & 31;
    int h = (idx >> 5) & (NHEAD - 1);
    int s = (idx >> 9) & (SEQ - 1);
    int b = idx >> 20;
    size_t ibase = ((size_t)b * SEQ + s) * (3 * DIM) + (size_t)h * HDIM;
    size_t obase = (((size_t)b * NHEAD + h) * SEQ + s) * HDIM;
    float inv = expf(-(float)d * (9.210340371976184f / 32.f));
    float ang = (float)s * inv;
    float sn, cs;
    sincosf(ang, &sn, &cs);
    {
        float x1 = QKV[ibase + d], x2 = QKV[ibase + d + 32];
        float r1 = (x1 * cs - x2 * sn) * QSCALE;
        float r2 = (x2 * cs + x1 * sn) * QSCALE;
        __nv_bfloat16 h1 = __float2bfloat16_rn(r1);
        __nv_bfloat16 h2 = __float2bfloat16_rn(r2);
        qhi[obase + d]      = h1;
        qhi[obase + d + 32] = h2;
        qlo[obase + d]      = __float2bfloat16_rn(r1 - __bfloat162float(h1));
        qlo[obase + d + 32] = __float2bfloat16_rn(r2 - __bfloat162float(h2));
    }
    {
        float x1 = QKV[ibase + DIM + d], x2 = QKV[ibase + DIM + d + 32];
        float r1 = x1 * cs - x2 * sn;
        float r2 = x2 * cs + x1 * sn;
        __nv_bfloat16 h1 = __float2bfloat16_rn(r1);
        __nv_bfloat16 h2 = __float2bfloat16_rn(r2);
        khi[obase + d]      = h1;
        khi[obase + d + 32] = h2;
        klo[obase + d]      = __float2bfloat16_rn(r1 - __bfloat162float(h1));
        klo[obase + d + 32] = __float2bfloat16_rn(r2 - __bfloat162float(h2));
    }
}

// ------------- V convert: qkv fp32 -> bf16 [B,H,S,HD] -------------
__global__ void v_cvt_kernel(const float* __restrict__ QKV, __nv_bfloat16* __restrict__ vb) {
    int t = blockIdx.x * 256 + threadIdx.x;
    if (t >= ROWS * DIM / 4) return;
    int e = t * 4;
    int c = e & 63;
    int h = (e >> 6) & (NHEAD - 1);
    int s = (e >> 10) & (SEQ - 1);
    int b = e >> 21;
    size_t ioff = ((size_t)b * SEQ + s) * (3 * DIM) + 2 * DIM + (size_t)h * HDIM + c;
    size_t ooff = (((size_t)b * NHEAD + h) * SEQ + s) * HDIM + c;
    float4 v = *(const float4*)(QKV + ioff);
    __nv_bfloat162 p0, p1;
    p0.x = __float2bfloat16_rn(v.x); p0.y = __float2bfloat16_rn(v.y);
    p1.x = __float2bfloat16_rn(v.z); p1.y = __float2bfloat16_rn(v.w);
    uint2 o = { *(uint32_t*)&p0, *(uint32_t*)&p1 };
    *(uint2*)(vb + ooff) = o;
}

// ================= MMA flash attention (bf16 3-term QK, bf16 PV) ==========
#define AROWB 144
#define A_QHI 0
#define A_QLO 9216
#define A_K0  18432
#define A_V0  55296
#define ASMEM 73728

__global__ __launch_bounds__(128)
void attn_mma(const __nv_bfloat16* __restrict__ qhi, const __nv_bfloat16* __restrict__ qlo,
              const __nv_bfloat16* __restrict__ khi, const __nv_bfloat16* __restrict__ klo,
              const __nv_bfloat16* __restrict__ vb,
              __half* __restrict__ O16) {
    extern __shared__ char smem[];
    uint32_t sb = smem_u32(smem);
    int tid = threadIdx.x, wid = tid >> 5, lane = tid & 31;
    int b = blockIdx.z, h = blockIdx.y;
    int q0 = blockIdx.x * 64;
    size_t hoff = ((size_t)b * NHEAD + h) * SEQ * HDIM;

    {
        const uint4* qh4 = (const uint4*)(qhi + hoff + (size_t)q0 * HDIM);
        const uint4* ql4 = (const uint4*)(qlo + hoff + (size_t)q0 * HDIM);
        #pragma unroll
        for (int j = 0; j < 4; j++) {
            int f = tid + j * 128;
            int r = f >> 3, c = f & 7;
            *(uint4*)(smem + A_QHI + r * AROWB + c * 16) = qh4[r * 8 + c];
            *(uint4*)(smem + A_QLO + r * AROWB + c * 16) = ql4[r * 8 + c];
        }
    }
    __syncthreads();

    uint32_t qh[4][4], ql[4][4];
    {
        uint32_t a_base = sb + (uint32_t)(wid * 16 + (lane & 15)) * AROWB + ((lane >> 4) & 1) * 16;
        #pragma unroll
        for (int ks = 0; ks < 4; ks++) {
            ldmx4(a_base + ks * 32,         qh[ks][0], qh[ks][1], qh[ks][2], qh[ks][3]);
            ldmx4(a_base + A_QLO + ks * 32, ql[ks][0], ql[ks][1], ql[ks][2], ql[ks][3]);
        }
    }

    float ctx[8][4];
    #pragma unroll
    for (int j = 0; j < 8; j++)
        #pragma unroll
        for (int r = 0; r < 4; r++) ctx[j][r] = 0.f;
    float m0 = -1e30f, m1 = -1e30f, l0 = 0.f, l1 = 0.f;

    const __nv_bfloat16* kh_g = khi + hoff;
    const __nv_bfloat16* kl_g = klo + hoff;
    const __nv_bfloat16* v_g  = vb + hoff;

    {
        #pragma unroll
        for (int j = 0; j < 4; j++) {
            int f = tid + j * 128;
            int r = f >> 3, c = f & 7;
            uint32_t so = (uint32_t)(r * AROWB + c * 16);
            CPA16(sb + A_K0 + so,        (const char*)(kh_g + r * 64 + c * 8));
            CPA16(sb + A_K0 + 9216 + so, (const char*)(kl_g + r * 64 + c * 8));
            CPA16(sb + A_V0 + so,        (const char*)(v_g  + r * 64 + c * 8));
        }
        CPA_COMMIT();
    }

    const int NT = SEQ / 64;
    for (int t = 0; t < NT; t++) {
        int s = t & 1;
        if (t + 1 < NT) {
            int nxt = s ^ 1;
            size_t goff = (size_t)(t + 1) * 64 * 64;
            #pragma unroll
            for (int j = 0; j < 4; j++) {
                int f = tid + j * 128;
                int r = f >> 3, c = f & 7;
                uint32_t so = (uint32_t)(r * AROWB + c * 16);
                CPA16(sb + A_K0 + nxt * 18432 + so,        (const char*)(kh_g + goff + r * 64 + c * 8));
                CPA16(sb + A_K0 + nxt * 18432 + 9216 + so, (const char*)(kl_g + goff + r * 64 + c * 8));
                CPA16(sb + A_V0 + nxt * 9216 + so,         (const char*)(v_g  + goff + r * 64 + c * 8));
            }
            CPA_COMMIT();
            CPA_WAIT(1);
        } else {
            CPA_WAIT(0);
        }
        __syncthreads();

        uint32_t kb_hi = sb + A_K0 + s * 18432;
        uint32_t kb_lo = kb_hi + 9216;
        uint32_t vbse  = sb + A_V0 + s * 9216;

        float sc[8][4];
        #pragma unroll
        for (int j = 0; j < 8; j++)
            #pragma unroll
            for (int r = 0; r < 4; r++) sc[j][r] = 0.f;

        uint32_t b_off = (uint32_t)((lane & 7) + ((lane >> 4) & 1) * 8) * AROWB +
                         ((lane >> 3) & 1) * 16;
        #pragma unroll
        for (int ks = 0; ks < 4; ks++) {
            #pragma unroll
            for (int ng = 0; ng < 4; ng++) {
                uint32_t bh0, bh1, bh2, bh3, bl0, bl1, bl2, bl3;
                uint32_t ad = b_off + (uint32_t)ng * (16 * AROWB) + ks * 32;
                ldmx4(kb_hi + ad, bh0, bh1, bh2, bh3);
                ldmx4(kb_lo + ad, bl0, bl1, bl2, bl3);
                mma16816(sc[2 * ng],     qh[ks][0], qh[ks][1], qh[ks][2], qh[ks][3], bh0, bh1);
                mma16816(sc[2 * ng + 1], qh[ks][0], qh[ks][1], qh[ks][2], qh[ks][3], bh2, bh3);
                mma16816(sc[2 * ng],     qh[ks][0], qh[ks][1], qh[ks][2], qh[ks][3], bl0, bl1);
                mma16816(sc[2 * ng + 1], qh[ks][0], qh[ks][1], qh[ks][2], qh[ks][3], bl2, bl3);
                mma16816(sc[2 * ng],     ql[ks][0], ql[ks][1], ql[ks][2], ql[ks][3], bh0, bh1);
                mma16816(sc[2 * ng + 1], ql[ks][0], ql[ks][1], ql[ks][2], ql[ks][3], bh2, bh3);
            }
        }

        float mn0 = m0, mn1 = m1;
        #pragma unroll
        for (int j = 0; j < 8; j++) {
            mn0 = fmaxf(mn0, fmaxf(sc[j][0], sc[j][1]));
            mn1 = fmaxf(mn1, fmaxf(sc[j][2], sc[j][3]));
        }
        mn0 = fmaxf(mn0, __shfl_xor_sync(0xffffffffu, mn0, 1));
        mn0 = fmaxf(mn0, __shfl_xor_sync(0xffffffffu, mn0, 2));
        mn1 = fmaxf(mn1, __shfl_xor_sync(0xffffffffu, mn1, 1));
        mn1 = fmaxf(mn1, __shfl_xor_sync(0xffffffffu, mn1, 2));
        float corr0 = ex2f(m0 - mn0);
        float corr1 = ex2f(m1 - mn1);
        m0 = mn0; m1 = mn1;
        l0 *= corr0; l1 *= corr1;
        #pragma unroll
        for (int j = 0; j < 8; j++) {
            ctx[j][0] *= corr0; ctx[j][1] *= corr0;
            ctx[j][2] *= corr1; ctx[j][3] *= corr1;
        }
        uint32_t pa[8], pb[8];
        #pragma unroll
        for (int j = 0; j < 8; j++) {
            float p0 = ex2f(sc[j][0] - mn0);
            float p1 = ex2f(sc[j][1] - mn0);
            float p2 = ex2f(sc[j][2] - mn1);
            float p3 = ex2f(sc[j][3] - mn1);
            l0 += p0 + p1; l1 += p2 + p3;
            __nv_bfloat162 t0 = __floats2bfloat162_rn(p0, p1);
            __nv_bfloat162 t1 = __floats2bfloat162_rn(p2, p3);
            pa[j] = *(uint32_t*)&t0;
            pb[j] = *(uint32_t*)&t1;
        }

        uint32_t v_off = (uint32_t)(lane & 15) * AROWB + ((lane >> 4) & 1) * 16;
        #pragma unroll
        for (int ks = 0; ks < 4; ks++) {
            #pragma unroll
            for (int nd = 0; nd < 4; nd++) {
                uint32_t r0, r1, r2, r3;
                ldmx4t(vbse + v_off + (uint32_t)ks * (16 * AROWB) + nd * 32, r0, r1, r2, r3);
                mma16816(ctx[nd * 2],     pa[2 * ks], pb[2 * ks], pa[2 * ks + 1], pb[2 * ks + 1], r0, r1);
                mma16816(ctx[nd * 2 + 1], pa[2 * ks], pb[2 * ks], pa[2 * ks + 1], pb[2 * ks + 1], r2, r3);
            }
        }
        __syncthreads();
    }

    l0 += __shfl_xor_sync(0xffffffffu, l0, 1);
    l0 += __shfl_xor_sync(0xffffffffu, l0, 2);
    l1 += __shfl_xor_sync(0xffffffffu, l1, 1);
    l1 += __shfl_xor_sync(0xffffffffu, l1, 2);
    float i0 = 1.f / l0, i1 = 1.f / l1;

    int tr = lane >> 2, tc = (lane & 3) * 2;
    int row0 = q0 + wid * 16 + tr;
    #pragma unroll
    for (int f = 0; f < 8; f++) {
        int d = f * 8 + tc;
        float* c = ctx[f];
        size_t o0 = ((size_t)b * SEQ + row0) * DIM + (size_t)h * HDIM + d;
        size_t o1 = ((size_t)b * SEQ + row0 + 8) * DIM + (size_t)h * HDIM + d;
        __half2 h0 = __floats2half2_rn(c[0] * i0, c[1] * i0);
        __half2 h1 = __floats2half2_rn(c[2] * i1, c[3] * i1);
        *(__half2*)(O16 + o0) = h0;
        *(__half2*)(O16 + o1) = h1;
    }
}

// ---------------- launch ----------------
extern "C" void kernel_launch(void* const* d_in, const int* in_sizes, int n_in,
                              void* d_out, int out_size) {
    const float* x_in   = (const float*)d_in[0];
    const float* Wq     = (const float*)d_in[1];
    const float* Wk     = (const float*)d_in[2];
    const float* Wv     = (const float*)d_in[3];
    const float* Wo     = (const float*)d_in[4];
    const float* ln1_w  = (const float*)d_in[5];
    const float* ln2_w  = (const float*)d_in[6];
    const float* Wgate  = (const float*)d_in[7];
    const float* Wup    = (const float*)d_in[8];
    const float* Wdown  = (const float*)d_in[9];
    const float* W_out  = (const float*)d_in[10];
    const float* b_out  = (const float*)d_in[11];
    float* out = (float*)d_out;

    float *x, *qkv, *f1;
    __half *h16, *c16, *f116, *x16, *whi, *wlo;
    __nv_bfloat16 *qhi, *qlo, *khi, *klo, *vbp;
    cudaGetSymbolAddress((void**)&x,    g_x);
    cudaGetSymbolAddress((void**)&qkv,  g_qkv);
    cudaGetSymbolAddress((void**)&f1,   g_f1);
    cudaGetSymbolAddress((void**)&h16,  g_h16);
    cudaGetSymbolAddress((void**)&c16,  g_c16);
    cudaGetSymbolAddress((void**)&f116, g_f116);
    cudaGetSymbolAddress((void**)&x16,  g_x16);
    cudaGetSymbolAddress((void**)&whi,  g_whi);
    cudaGetSymbolAddress((void**)&wlo,  g_wlo);
    cudaGetSymbolAddress((void**)&qhi,  g_qhi);
    cudaGetSymbolAddress((void**)&qlo,  g_qlo);
    cudaGetSymbolAddress((void**)&khi,  g_khi);
    cudaGetSymbolAddress((void**)&klo,  g_klo);
    cudaGetSymbolAddress((void**)&vbp,  g_vb);

    cudaFuncSetAttribute(gemm_s,   cudaFuncAttributeMaxDynamicSharedMemorySize, SMEM3);
    cudaFuncSetAttribute(attn_mma, cudaFuncAttributeMaxDynamicSharedMemorySize, ASMEM);

    const size_t xbytes = (size_t)ROWS * DIM * sizeof(float);
    cudaMemcpyAsync(x, x_in, xbytes, cudaMemcpyDeviceToDevice);

    // --- weight converts (fp32 -> fp16 hi/lo) ---
    const int DD4 = DIM * DIM / 4, FD4 = FFDIM * DIM / 4;
    wcvt_kernel<<<DD4 / 256, 256>>>(Wq,    whi + WOFF_Q, wlo + WOFF_Q, DD4);
    wcvt_kernel<<<DD4 / 256, 256>>>(Wk,    whi + WOFF_K, wlo + WOFF_K, DD4);
    wcvt_kernel<<<DD4 / 256, 256>>>(Wv,    whi + WOFF_V, wlo + WOFF_V, DD4);
    wcvt_kernel<<<DD4 / 256, 256>>>(Wo,    whi + WOFF_O, wlo + WOFF_O, DD4);
    wcvt_kernel<<<FD4 / 256, 256>>>(Wgate, whi + WOFF_G, wlo + WOFF_G, FD4);
    wcvt_kernel<<<FD4 / 256, 256>>>(Wup,   whi + WOFF_U, wlo + WOFF_U, FD4);
    wcvt_kernel<<<FD4 / 256, 256>>>(Wdown, whi + WOFF_D, wlo + WOFF_D, FD4);
    wcvt_kernel<<<DD4 / 256, 256>>>(W_out, whi + WOFF_H, wlo + WOFF_H, DD4);

    // --- attention block ---
    rmsnorm_kernel<<<ROWS, 256>>>(x, ln1_w, h16);

    // fused QKV GEMM: [8192,1024] @ [3072,1024]^T -> [8192,3072]
    dim3 gqkv(3 * DIM / SBN, ROWS / SBM);   // (24, 64)
    gemm_s<<<gqkv, 256, SMEM3>>>(h16, whi + WOFF_Q, wlo + WOFF_Q,
                                 nullptr, nullptr, nullptr,
                                 qkv, nullptr, ROWS, 3 * DIM, DIM);

    int rope_total = BATCH * SEQ * NHEAD * (HDIM / 2);
    rope_cvt_kernel<<<(rope_total + 255) / 256, 256>>>(qkv, qhi, qlo, khi, klo);
    v_cvt_kernel<<<(ROWS * DIM / 4 + 255) / 256, 256>>>(qkv, vbp);

    dim3 ga(SEQ / 64, NHEAD, BATCH);
    attn_mma<<<ga, 128, ASMEM>>>(qhi, qlo, khi, klo, vbp, c16);

    dim3 g1(DIM / SBN, ROWS / SBM);    // (8, 64)
    // x = x + ctx @ Wo^T (fp32 out for next rmsnorm + residual)
    gemm_s<<<g1, 256, SMEM3>>>(c16, whi + WOFF_O, wlo + WOFF_O,
                               nullptr, x, nullptr,
                               x, nullptr, ROWS, DIM, DIM);

    // --- MLP block ---
    rmsnorm_kernel<<<ROWS, 256>>>(x, ln2_w, h16);
    dim3 gff(FFDIM / SBN, ROWS / SBM); // (32, 64)
    // gate -> f1 (fp32)
    gemm_s<<<gff, 256, SMEM3>>>(h16, whi + WOFF_G, wlo + WOFF_G,
                                nullptr, nullptr, nullptr,
                                f1, nullptr, ROWS, FFDIM, DIM);
    // up with fused silu(gate)*up -> f116
    gemm_s<<<gff, 256, SMEM3>>>(h16, whi + WOFF_U, wlo + WOFF_U,
                                f1, nullptr, nullptr,
                                nullptr, f116, ROWS, FFDIM, DIM);

    // x_new = x + f1 @ Wdown^T -> fp16 (feeds head GEMM)
    gemm_s<<<g1, 256, SMEM3>>>(f116, whi + WOFF_D, wlo + WOFF_D,
                               nullptr, x, nullptr,
                               nullptr, x16, ROWS, DIM, FFDIM);

    // --- output head ---
    gemm_s<<<g1, 256, SMEM3>>>(x16, whi + WOFF_H, wlo + WOFF_H,
                               nullptr, nullptr, b_out,
                               out, nullptr, ROWS, DIM, DIM);
}

// round 11
// speedup vs baseline: 6.9484x; 1.3640x over previous
#include <cuda_runtime.h>
#include <cuda_bf16.h>
#include <cuda_fp16.h>
#include <cstdint>

// Problem constants
#define BATCH 4
#define SEQ   2048
#define DIM   1024
#define NHEAD 16
#define HDIM  64
#define FFDIM 4096
#define ROWS  (BATCH * SEQ)            // 8192
#define LN_EPS 1e-6f

// ---------------- scratch (device globals; no allocation) ----------------
__device__ float g_x  [(size_t)ROWS * DIM];
__device__ float g_qkv[(size_t)ROWS * 3 * DIM];
__device__ float g_f1 [(size_t)ROWS * FFDIM];
// fp16 single activation operands (GEMM A inputs)
__device__ __half g_h16 [(size_t)ROWS * DIM];
__device__ __half g_c16 [(size_t)ROWS * DIM];
__device__ __half g_f116[(size_t)ROWS * FFDIM];
__device__ __half g_x16 [(size_t)ROWS * DIM];
// fp16 weights hi (all) + lo (head only uses it)
#define WOFF_Q  0
#define WOFF_K  1048576
#define WOFF_V  2097152
#define WOFF_O  3145728
#define WOFF_G  4194304
#define WOFF_U  8388608
#define WOFF_D  12582912
#define WOFF_H  16777216
#define WTOT    17825792
__device__ __half g_whi[(size_t)WTOT];
__device__ __half g_wlo[(size_t)(DIM * DIM)];   // lo only for W_out
// bf16 attention operands, [B,H,S,HD] layout
__device__ __nv_bfloat16 g_qhi[(size_t)ROWS * DIM];
__device__ __nv_bfloat16 g_qlo[(size_t)ROWS * DIM];
__device__ __nv_bfloat16 g_khi[(size_t)ROWS * DIM];
__device__ __nv_bfloat16 g_klo[(size_t)ROWS * DIM];
__device__ __nv_bfloat16 g_vb [(size_t)ROWS * DIM];

__device__ __forceinline__ uint32_t smem_u32(const void* p) {
    uint32_t a;
    asm("{ .reg .u64 t; cvta.to.shared.u64 t, %1; cvt.u32.u64 %0, t; }"
        : "=r"(a) : "l"(p));
    return a;
}
__device__ __forceinline__ void ldmx4(uint32_t addr, uint32_t& r0, uint32_t& r1,
                                      uint32_t& r2, uint32_t& r3) {
    asm volatile("ldmatrix.sync.aligned.m8n8.x4.shared.b16 {%0,%1,%2,%3}, [%4];"
                 : "=r"(r0), "=r"(r1), "=r"(r2), "=r"(r3) : "r"(addr));
}
__device__ __forceinline__ void ldmx4t(uint32_t addr, uint32_t& r0, uint32_t& r1,
                                       uint32_t& r2, uint32_t& r3) {
    asm volatile("ldmatrix.sync.aligned.m8n8.x4.trans.shared.b16 {%0,%1,%2,%3}, [%4];"
                 : "=r"(r0), "=r"(r1), "=r"(r2), "=r"(r3) : "r"(addr));
}
// bf16 MMA (attention)
__device__ __forceinline__ void mma16816(float* c, uint32_t a0, uint32_t a1,
                                         uint32_t a2, uint32_t a3,
                                         uint32_t b0, uint32_t b1) {
    asm volatile(
        "mma.sync.aligned.m16n8k16.row.col.f32.bf16.bf16.f32 "
        "{%0,%1,%2,%3}, {%4,%5,%6,%7}, {%8,%9}, {%0,%1,%2,%3};"
        : "+f"(c[0]), "+f"(c[1]), "+f"(c[2]), "+f"(c[3])
        : "r"(a0), "r"(a1), "r"(a2), "r"(a3), "r"(b0), "r"(b1));
}
// fp16 MMA (GEMMs)
__device__ __forceinline__ void mma16816h(float* c, uint32_t a0, uint32_t a1,
                                          uint32_t a2, uint32_t a3,
                                          uint32_t b0, uint32_t b1) {
    asm volatile(
        "mma.sync.aligned.m16n8k16.row.col.f32.f16.f16.f32 "
        "{%0,%1,%2,%3}, {%4,%5,%6,%7}, {%8,%9}, {%0,%1,%2,%3};"
        : "+f"(c[0]), "+f"(c[1]), "+f"(c[2]), "+f"(c[3])
        : "r"(a0), "r"(a1), "r"(a2), "r"(a3), "r"(b0), "r"(b1));
}
__device__ __forceinline__ float ex2f(float x) {
    float r;
    asm("ex2.approx.f32 %0, %1;" : "=f"(r) : "f"(x));
    return r;
}
#define CPA16(dst, src) \
    asm volatile("cp.async.cg.shared.global [%0], [%1], 16;" :: "r"(dst), "l"(src))
#define CPA_COMMIT() asm volatile("cp.async.commit_group;" ::: "memory")
#define CPA_WAIT(n)  asm volatile("cp.async.wait_group %0;" :: "n"(n) : "memory")

// ---------------- weight convert: fp32 -> fp16 (hi; optional lo) ----------
__global__ void wcvt_kernel(const float* __restrict__ src,
                            __half* __restrict__ hi,
                            __half* __restrict__ lo, int n4) {
    int t = blockIdx.x * 256 + threadIdx.x;
    if (t >= n4) return;
    float4 v = *(const float4*)(src + (size_t)t * 4);
    __half h0 = __float2half_rn(v.x), h1 = __float2half_rn(v.y);
    __half h2 = __float2half_rn(v.z), h3 = __float2half_rn(v.w);
    __half2 hp0 = __halves2half2(h0, h1), hp1 = __halves2half2(h2, h3);
    uint2 ho = { *(uint32_t*)&hp0, *(uint32_t*)&hp1 };
    *(uint2*)(hi + (size_t)t * 4) = ho;
    if (lo) {
        __half l0 = __float2half_rn(v.x - __half2float(h0));
        __half l1 = __float2half_rn(v.y - __half2float(h1));
        __half l2 = __float2half_rn(v.z - __half2float(h2));
        __half l3 = __float2half_rn(v.w - __half2float(h3));
        __half2 lp0 = __halves2half2(l0, l1), lp1 = __halves2half2(l2, l3);
        uint2 lw = { *(uint32_t*)&lp0, *(uint32_t*)&lp1 };
        *(uint2*)(lo + (size_t)t * 4) = lw;
    }
}

// ================= gemm_s: fp16 GEMM (1 or 2 weight terms) =================
// C[M,N] = A[M,K] @ (Whi[+Wlo])[N,K]^T ; A single fp16.
// Tile 128x128, BK=32, 3-stage cp.async, SW64 swizzle, 2 CTAs/SM.
#define SBM 128
#define SBN 128
#define SBK 32
#define S_WHI 8192
#define S_WLO 16384
#define SSTG  24576
#define SMEM3 (3 * SSTG)       // 73728 -> 2 CTAs/SM

__global__ __launch_bounds__(256, 2)
void gemm_s(const __half* __restrict__ A,
            const __half* __restrict__ Whi, const __half* __restrict__ Wlo,
            const float* __restrict__ gate, const float* __restrict__ res,
            const float* __restrict__ bias,
            float* __restrict__ C, __half* __restrict__ C16,
            int M, int N, int K) {
    extern __shared__ char smem[];
    uint32_t sb = smem_u32(smem);
    int tid = threadIdx.x, wid = tid >> 5, lane = tid & 31;
    int bm = blockIdx.y * SBM, bn = blockIdx.x * SBN;
    int warp_m = (wid >> 2) * 64, warp_n = (wid & 3) * 32;
    const bool has_lo = (Wlo != nullptr);

    // --- cp.async mapping: 64 rows per pass, 4 x 16B chunks per 64B row ---
    uint32_t strow = (uint32_t)(tid >> 2);
    uint32_t stc   = (uint32_t)(tid & 3) * 16;
    uint32_t st_off = strow * 64 + (stc ^ (((strow >> 1) & 3u) << 4));
    const __half* Ap = A   + (size_t)(bm + strow) * K + (tid & 3) * 8;
    const __half* Wh = Whi + (size_t)(bn + strow) * K + (tid & 3) * 8;
    const __half* Wl = has_lo ? (Wlo + (size_t)(bn + strow) * K + (tid & 3) * 8) : nullptr;

    auto load_stage = [&](int s, int chunk) {
        uint32_t base = sb + (uint32_t)s * SSTG;
        size_t ko = (size_t)chunk * SBK;
        #pragma unroll
        for (int j = 0; j < 2; j++) {
            uint32_t d = base + st_off + j * 4096;     // 64 rows * 64B
            size_t ro = (size_t)j * 64 * K + ko;
            CPA16(d,         (const char*)(Ap + ro));
            CPA16(d + S_WHI, (const char*)(Wh + ro));
            if (has_lo) CPA16(d + S_WLO, (const char*)(Wl + ro));
        }
    };

    // --- ldmatrix addressing (SW64: col ^= ((row>>1)&3)<<4) ---
    int ra = warp_m + (lane & 15);
    uint32_t a_row = (uint32_t)ra * 64;
    uint32_t swa = (((uint32_t)ra >> 1) & 3u) << 4;
    int rb = warp_n + (lane & 7) + ((lane >> 4) & 1) * 8;
    uint32_t b_row = (uint32_t)rb * 64;
    uint32_t swb = (((uint32_t)rb >> 1) & 3u) << 4;
    uint32_t col_a[2], col_b[2];
    int ha = ((lane >> 4) & 1) * 16;
    int hb = ((lane >> 3) & 1) * 16;
    #pragma unroll
    for (int ks = 0; ks < 2; ks++) {
        col_a[ks] = ((uint32_t)(ks * 32 + ha)) ^ swa;
        col_b[ks] = ((uint32_t)(ks * 32 + hb)) ^ swb;
    }

    float acc[4][4][4];
    #pragma unroll
    for (int i = 0; i < 4; i++)
        #pragma unroll
        for (int j = 0; j < 4; j++)
            #pragma unroll
            for (int r = 0; r < 4; r++) acc[i][j][r] = 0.f;

    const int nk = K / SBK;
    load_stage(0, 0);
    CPA_COMMIT();
    if (nk > 1) load_stage(1, 1);
    CPA_COMMIT();

    int sc = 0;
    for (int i = 0; i < nk; i++) {
        int snx = sc + 2; if (snx >= 3) snx -= 3;
        if (i + 2 < nk) load_stage(snx, i + 2);
        CPA_COMMIT();
        CPA_WAIT(2);
        __syncthreads();

        uint32_t base = sb + (uint32_t)sc * SSTG;
        #pragma unroll
        for (int ks = 0; ks < 2; ks++) {
            uint32_t bhr[2][4];
            #pragma unroll
            for (int np = 0; np < 2; np++) {
                uint32_t bd = base + S_WHI + b_row + (uint32_t)np * 1024 + col_b[ks];
                ldmx4(bd, bhr[np][0], bhr[np][1], bhr[np][2], bhr[np][3]);
            }
            uint32_t ar[4][4];
            #pragma unroll
            for (int mf = 0; mf < 4; mf++) {
                uint32_t ad = base + a_row + (uint32_t)mf * 1024 + col_a[ks];
                ldmx4(ad, ar[mf][0], ar[mf][1], ar[mf][2], ar[mf][3]);
            }
            // term 1: A * Whi  (16 independent MMAs)
            #pragma unroll
            for (int mf = 0; mf < 4; mf++)
                #pragma unroll
                for (int nf = 0; nf < 4; nf++)
                    mma16816h(acc[mf][nf],
                              ar[mf][0], ar[mf][1], ar[mf][2], ar[mf][3],
                              bhr[nf >> 1][(nf & 1) * 2], bhr[nf >> 1][(nf & 1) * 2 + 1]);
            // term 2: A * Wlo (head GEMM only)
            if (has_lo) {
                uint32_t blr[2][4];
                #pragma unroll
                for (int np = 0; np < 2; np++) {
                    uint32_t bd = base + S_WLO + b_row + (uint32_t)np * 1024 + col_b[ks];
                    ldmx4(bd, blr[np][0], blr[np][1], blr[np][2], blr[np][3]);
                }
                #pragma unroll
                for (int mf = 0; mf < 4; mf++)
                    #pragma unroll
                    for (int nf = 0; nf < 4; nf++)
                        mma16816h(acc[mf][nf],
                                  ar[mf][0], ar[mf][1], ar[mf][2], ar[mf][3],
                                  blr[nf >> 1][(nf & 1) * 2], blr[nf >> 1][(nf & 1) * 2 + 1]);
            }
        }
        __syncthreads();
        sc = (sc == 2) ? 0 : sc + 1;
    }

    // ---- epilogue ----
    int tr = lane >> 2, tc = (lane & 3) * 2;
    #pragma unroll
    for (int mf = 0; mf < 4; mf++) {
        #pragma unroll
        for (int nf = 0; nf < 4; nf++) {
            int row0 = bm + warp_m + mf * 16 + tr;
            int col  = bn + warp_n + nf * 8 + tc;
            float* c = acc[mf][nf];
            float v[4] = {c[0], c[1], c[2], c[3]};
            size_t o0 = (size_t)row0 * N + col;
            size_t o1 = (size_t)(row0 + 8) * N + col;
            if (gate) {
                float2 g0 = *(const float2*)(gate + o0);
                float2 g1 = *(const float2*)(gate + o1);
                v[0] *= g0.x / (1.f + expf(-g0.x));
                v[1] *= g0.y / (1.f + expf(-g0.y));
                v[2] *= g1.x / (1.f + expf(-g1.x));
                v[3] *= g1.y / (1.f + expf(-g1.y));
            }
            if (res) {
                float2 r0 = *(const float2*)(res + o0);
                float2 r1 = *(const float2*)(res + o1);
                v[0] += r0.x; v[1] += r0.y; v[2] += r1.x; v[3] += r1.y;
            }
            if (bias) {
                float2 bb = *(const float2*)(bias + col);
                v[0] += bb.x; v[1] += bb.y; v[2] += bb.x; v[3] += bb.y;
            }
            if (C) {
                *(float2*)(C + o0) = {v[0], v[1]};
                *(float2*)(C + o1) = {v[2], v[3]};
            }
            if (C16) {
                __half2 h0 = __floats2half2_rn(v[0], v[1]);
                __half2 h1 = __floats2half2_rn(v[2], v[3]);
                *(__half2*)(C16 + o0) = h0;
                *(__half2*)(C16 + o1) = h1;
            }
        }
    }
}

// ---------------- RMSNorm -> fp16 ----------------
__global__ void rmsnorm_kernel(const float* __restrict__ x,
                               const float* __restrict__ w,
                               __half* __restrict__ o16) {
    int row = blockIdx.x;
    const float* xr = x + (size_t)row * DIM;
    float s = 0.f;
    #pragma unroll
    for (int i = threadIdx.x; i < DIM; i += 256) {
        float v = xr[i];
        s += v * v;
    }
    __shared__ float red[8];
    #pragma unroll
    for (int o = 16; o; o >>= 1) s += __shfl_down_sync(0xffffffffu, s, o);
    if ((threadIdx.x & 31) == 0) red[threadIdx.x >> 5] = s;
    __syncthreads();
    if (threadIdx.x < 8) {
        float t = red[threadIdx.x];
        #pragma unroll
        for (int o = 4; o; o >>= 1) t += __shfl_down_sync(0xffu, t, o);
        if (threadIdx.x == 0) red[0] = t;
    }
    __syncthreads();
    float inv = rsqrtf(red[0] * (1.0f / DIM) + LN_EPS);
    #pragma unroll
    for (int i = threadIdx.x; i < DIM; i += 256) {
        float v = xr[i] * inv * w[i];
        o16[(size_t)row * DIM + i] = __float2half_rn(v);
    }
}

// ------------- RoPE on qkv buffer [rows,3072] -> hi/lo bf16 [B,H,S,HD] -----
#define QSCALE 0.18033688011111793f   // 0.125 * log2(e)
__global__ void rope_cvt_kernel(const float* __restrict__ QKV,
                                __nv_bfloat16* __restrict__ qhi, __nv_bfloat16* __restrict__ qlo,
                                __nv_bfloat16* __restrict__ khi, __nv_bfloat16* __restrict__ klo) {
    int idx = blockIdx.x * 256 + threadIdx.x;
    if (idx >= BATCH * SEQ * NHEAD * (HDIM / 2)) return;
    int d = idx & 31;
    int h = (idx >> 5) & (NHEAD - 1);
    int s = (idx >> 9) & (SEQ - 1);
    int b = idx >> 20;
    size_t ibase = ((size_t)b * SEQ + s) * (3 * DIM) + (size_t)h * HDIM;
    size_t obase = (((size_t)b * NHEAD + h) * SEQ + s) * HDIM;
    float inv = expf(-(float)d * (9.210340371976184f / 32.f));
    float ang = (float)s * inv;
    float sn, cs;
    sincosf(ang, &sn, &cs);
    {
        float x1 = QKV[ibase + d], x2 = QKV[ibase + d + 32];
        float r1 = (x1 * cs - x2 * sn) * QSCALE;
        float r2 = (x2 * cs + x1 * sn) * QSCALE;
        __nv_bfloat16 h1 = __float2bfloat16_rn(r1);
        __nv_bfloat16 h2 = __float2bfloat16_rn(r2);
        qhi[obase + d]      = h1;
        qhi[obase + d + 32] = h2;
        qlo[obase + d]      = __float2bfloat16_rn(r1 - __bfloat162float(h1));
        qlo[obase + d + 32] = __float2bfloat16_rn(r2 - __bfloat162float(h2));
    }
    {
        float x1 = QKV[ibase + DIM + d], x2 = QKV[ibase + DIM + d + 32];
        float r1 = x1 * cs - x2 * sn;
        float r2 = x2 * cs + x1 * sn;
        __nv_bfloat16 h1 = __float2bfloat16_rn(r1);
        __nv_bfloat16 h2 = __float2bfloat16_rn(r2);
        khi[obase + d]      = h1;
        khi[obase + d + 32] = h2;
        klo[obase + d]      = __float2bfloat16_rn(r1 - __bfloat162float(h1));
        klo[obase + d + 32] = __float2bfloat16_rn(r2 - __bfloat162float(h2));
    }
}

// ------------- V convert: qkv fp32 -> bf16 [B,H,S,HD] -------------
__global__ void v_cvt_kernel(const float* __restrict__ QKV, __nv_bfloat16* __restrict__ vb) {
    int t = blockIdx.x * 256 + threadIdx.x;
    if (t >= ROWS * DIM / 4) return;
    int e = t * 4;
    int c = e & 63;
    int h = (e >> 6) & (NHEAD - 1);
    int s = (e >> 10) & (SEQ - 1);
    int b = e >> 21;
    size_t ioff = ((size_t)b * SEQ + s) * (3 * DIM) + 2 * DIM + (size_t)h * HDIM + c;
    size_t ooff = (((size_t)b * NHEAD + h) * SEQ + s) * HDIM + c;
    float4 v = *(const float4*)(QKV + ioff);
    __nv_bfloat162 p0, p1;
    p0.x = __float2bfloat16_rn(v.x); p0.y = __float2bfloat16_rn(v.y);
    p1.x = __float2bfloat16_rn(v.z); p1.y = __float2bfloat16_rn(v.w);
    uint2 o = { *(uint32_t*)&p0, *(uint32_t*)&p1 };
    *(uint2*)(vb + ooff) = o;
}

// ================= MMA flash attention (bf16 3-term QK, bf16 PV) ==========
#define AROWB 144
#define A_QHI 0
#define A_QLO 9216
#define A_K0  18432
#define A_V0  55296
#define ASMEM 73728

__global__ __launch_bounds__(128)
void attn_mma(const __nv_bfloat16* __restrict__ qhi, const __nv_bfloat16* __restrict__ qlo,
              const __nv_bfloat16* __restrict__ khi, const __nv_bfloat16* __restrict__ klo,
              const __nv_bfloat16* __restrict__ vb,
              __half* __restrict__ O16) {
    extern __shared__ char smem[];
    uint32_t sb = smem_u32(smem);
    int tid = threadIdx.x, wid = tid >> 5, lane = tid & 31;
    int b = blockIdx.z, h = blockIdx.y;
    int q0 = blockIdx.x * 64;
    size_t hoff = ((size_t)b * NHEAD + h) * SEQ * HDIM;

    {
        const uint4* qh4 = (const uint4*)(qhi + hoff + (size_t)q0 * HDIM);
        const uint4* ql4 = (const uint4*)(qlo + hoff + (size_t)q0 * HDIM);
        #pragma unroll
        for (int j = 0; j < 4; j++) {
            int f = tid + j * 128;
            int r = f >> 3, c = f & 7;
            *(uint4*)(smem + A_QHI + r * AROWB + c * 16) = qh4[r * 8 + c];
            *(uint4*)(smem + A_QLO + r * AROWB + c * 16) = ql4[r * 8 + c];
        }
    }
    __syncthreads();

    uint32_t qh[4][4], ql[4][4];
    {
        uint32_t a_base = sb + (uint32_t)(wid * 16 + (lane & 15)) * AROWB + ((lane >> 4) & 1) * 16;
        #pragma unroll
        for (int ks = 0; ks < 4; ks++) {
            ldmx4(a_base + ks * 32,         qh[ks][0], qh[ks][1], qh[ks][2], qh[ks][3]);
            ldmx4(a_base + A_QLO + ks * 32, ql[ks][0], ql[ks][1], ql[ks][2], ql[ks][3]);
        }
    }

    float ctx[8][4];
    #pragma unroll
    for (int j = 0; j < 8; j++)
        #pragma unroll
        for (int r = 0; r < 4; r++) ctx[j][r] = 0.f;
    float m0 = -1e30f, m1 = -1e30f, l0 = 0.f, l1 = 0.f;

    const __nv_bfloat16* kh_g = khi + hoff;
    const __nv_bfloat16* kl_g = klo + hoff;
    const __nv_bfloat16* v_g  = vb + hoff;

    {
        #pragma unroll
        for (int j = 0; j < 4; j++) {
            int f = tid + j * 128;
            int r = f >> 3, c = f & 7;
            uint32_t so = (uint32_t)(r * AROWB + c * 16);
            CPA16(sb + A_K0 + so,        (const char*)(kh_g + r * 64 + c * 8));
            CPA16(sb + A_K0 + 9216 + so, (const char*)(kl_g + r * 64 + c * 8));
            CPA16(sb + A_V0 + so,        (const char*)(v_g  + r * 64 + c * 8));
        }
        CPA_COMMIT();
    }

    const int NT = SEQ / 64;
    for (int t = 0; t < NT; t++) {
        int s = t & 1;
        if (t + 1 < NT) {
            int nxt = s ^ 1;
            size_t goff = (size_t)(t + 1) * 64 * 64;
            #pragma unroll
            for (int j = 0; j < 4; j++) {
                int f = tid + j * 128;
                int r = f >> 3, c = f & 7;
                uint32_t so = (uint32_t)(r * AROWB + c * 16);
                CPA16(sb + A_K0 + nxt * 18432 + so,        (const char*)(kh_g + goff + r * 64 + c * 8));
                CPA16(sb + A_K0 + nxt * 18432 + 9216 + so, (const char*)(kl_g + goff + r * 64 + c * 8));
                CPA16(sb + A_V0 + nxt * 9216 + so,         (const char*)(v_g  + goff + r * 64 + c * 8));
            }
            CPA_COMMIT();
            CPA_WAIT(1);
        } else {
            CPA_WAIT(0);
        }
        __syncthreads();

        uint32_t kb_hi = sb + A_K0 + s * 18432;
        uint32_t kb_lo = kb_hi + 9216;
        uint32_t vbse  = sb + A_V0 + s * 9216;

        float sc[8][4];
        #pragma unroll
        for (int j = 0; j < 8; j++)
            #pragma unroll
            for (int r = 0; r < 4; r++) sc[j][r] = 0.f;

        uint32_t b_off = (uint32_t)((lane & 7) + ((lane >> 4) & 1) * 8) * AROWB +
                         ((lane >> 3) & 1) * 16;
        #pragma unroll
        for (int ks = 0; ks < 4; ks++) {
            #pragma unroll
            for (int ng = 0; ng < 4; ng++) {
                uint32_t bh0, bh1, bh2, bh3, bl0, bl1, bl2, bl3;
                uint32_t ad = b_off + (uint32_t)ng * (16 * AROWB) + ks * 32;
                ldmx4(kb_hi + ad, bh0, bh1, bh2, bh3);
                ldmx4(kb_lo + ad, bl0, bl1, bl2, bl3);
                mma16816(sc[2 * ng],     qh[ks][0], qh[ks][1], qh[ks][2], qh[ks][3], bh0, bh1);
                mma16816(sc[2 * ng + 1], qh[ks][0], qh[ks][1], qh[ks][2], qh[ks][3], bh2, bh3);
                mma16816(sc[2 * ng],     qh[ks][0], qh[ks][1], qh[ks][2], qh[ks][3], bl0, bl1);
                mma16816(sc[2 * ng + 1], qh[ks][0], qh[ks][1], qh[ks][2], qh[ks][3], bl2, bl3);
                mma16816(sc[2 * ng],     ql[ks][0], ql[ks][1], ql[ks][2], ql[ks][3], bh0, bh1);
                mma16816(sc[2 * ng + 1], ql[ks][0], ql[ks][1], ql[ks][2], ql[ks][3], bh2, bh3);
            }
        }

        float mn0 = m0, mn1 = m1;
        #pragma unroll
        for (int j = 0; j < 8; j++) {
            mn0 = fmaxf(mn0, fmaxf(sc[j][0], sc[j][1]));
            mn1 = fmaxf(mn1, fmaxf(sc[j][2], sc[j][3]));
        }
        mn0 = fmaxf(mn0, __shfl_xor_sync(0xffffffffu, mn0, 1));
        mn0 = fmaxf(mn0, __shfl_xor_sync(0xffffffffu, mn0, 2));
        mn1 = fmaxf(mn1, __shfl_xor_sync(0xffffffffu, mn1, 1));
        mn1 = fmaxf(mn1, __shfl_xor_sync(0xffffffffu, mn1, 2));
        float corr0 = ex2f(m0 - mn0);
        float corr1 = ex2f(m1 - mn1);
        m0 = mn0; m1 = mn1;
        l0 *= corr0; l1 *= corr1;
        #pragma unroll
        for (int j = 0; j < 8; j++) {
            ctx[j][0] *= corr0; ctx[j][1] *= corr0;
            ctx[j][2] *= corr1; ctx[j][3] *= corr1;
        }
        uint32_t pa[8], pb[8];
        #pragma unroll
        for (int j = 0; j < 8; j++) {
            float p0 = ex2f(sc[j][0] - mn0);
            float p1 = ex2f(sc[j][1] - mn0);
            float p2 = ex2f(sc[j][2] - mn1);
            float p3 = ex2f(sc[j][3] - mn1);
            l0 += p0 + p1; l1 += p2 + p3;
            __nv_bfloat162 t0 = __floats2bfloat162_rn(p0, p1);
            __nv_bfloat162 t1 = __floats2bfloat162_rn(p2, p3);
            pa[j] = *(uint32_t*)&t0;
            pb[j] = *(uint32_t*)&t1;
        }

        uint32_t v_off = (uint32_t)(lane & 15) * AROWB + ((lane >> 4) & 1) * 16;
        #pragma unroll
        for (int ks = 0; ks < 4; ks++) {
            #pragma unroll
            for (int nd = 0; nd < 4; nd++) {
                uint32_t r0, r1, r2, r3;
                ldmx4t(vbse + v_off + (uint32_t)ks * (16 * AROWB) + nd * 32, r0, r1, r2, r3);
                mma16816(ctx[nd * 2],     pa[2 * ks], pb[2 * ks], pa[2 * ks + 1], pb[2 * ks + 1], r0, r1);
                mma16816(ctx[nd * 2 + 1], pa[2 * ks], pb[2 * ks], pa[2 * ks + 1], pb[2 * ks + 1], r2, r3);
            }
        }
        __syncthreads();
    }

    l0 += __shfl_xor_sync(0xffffffffu, l0, 1);
    l0 += __shfl_xor_sync(0xffffffffu, l0, 2);
    l1 += __shfl_xor_sync(0xffffffffu, l1, 1);
    l1 += __shfl_xor_sync(0xffffffffu, l1, 2);
    float i0 = 1.f / l0, i1 = 1.f / l1;

    int tr = lane >> 2, tc = (lane & 3) * 2;
    int row0 = q0 + wid * 16 + tr;
    #pragma unroll
    for (int f = 0; f < 8; f++) {
        int d = f * 8 + tc;
        float* c = ctx[f];
        size_t o0 = ((size_t)b * SEQ + row0) * DIM + (size_t)h * HDIM + d;
        size_t o1 = ((size_t)b * SEQ + row0 + 8) * DIM + (size_t)h * HDIM + d;
        __half2 h0 = __floats2half2_rn(c[0] * i0, c[1] * i0);
        __half2 h1 = __floats2half2_rn(c[2] * i1, c[3] * i1);
        *(__half2*)(O16 + o0) = h0;
        *(__half2*)(O16 + o1) = h1;
    }
}

// ---------------- launch ----------------
extern "C" void kernel_launch(void* const* d_in, const int* in_sizes, int n_in,
                              void* d_out, int out_size) {
    const float* x_in   = (const float*)d_in[0];
    const float* Wq     = (const float*)d_in[1];
    const float* Wk     = (const float*)d_in[2];
    const float* Wv     = (const float*)d_in[3];
    const float* Wo     = (const float*)d_in[4];
    const float* ln1_w  = (const float*)d_in[5];
    const float* ln2_w  = (const float*)d_in[6];
    const float* Wgate  = (const float*)d_in[7];
    const float* Wup    = (const float*)d_in[8];
    const float* Wdown  = (const float*)d_in[9];
    const float* W_out  = (const float*)d_in[10];
    const float* b_out  = (const float*)d_in[11];
    float* out = (float*)d_out;

    float *x, *qkv, *f1;
    __half *h16, *c16, *f116, *x16, *whi, *wlo;
    __nv_bfloat16 *qhi, *qlo, *khi, *klo, *vbp;
    cudaGetSymbolAddress((void**)&x,    g_x);
    cudaGetSymbolAddress((void**)&qkv,  g_qkv);
    cudaGetSymbolAddress((void**)&f1,   g_f1);
    cudaGetSymbolAddress((void**)&h16,  g_h16);
    cudaGetSymbolAddress((void**)&c16,  g_c16);
    cudaGetSymbolAddress((void**)&f116, g_f116);
    cudaGetSymbolAddress((void**)&x16,  g_x16);
    cudaGetSymbolAddress((void**)&whi,  g_whi);
    cudaGetSymbolAddress((void**)&wlo,  g_wlo);
    cudaGetSymbolAddress((void**)&qhi,  g_qhi);
    cudaGetSymbolAddress((void**)&qlo,  g_qlo);
    cudaGetSymbolAddress((void**)&khi,  g_khi);
    cudaGetSymbolAddress((void**)&klo,  g_klo);
    cudaGetSymbolAddress((void**)&vbp,  g_vb);

    cudaFuncSetAttribute(gemm_s,   cudaFuncAttributeMaxDynamicSharedMemorySize, SMEM3);
    cudaFuncSetAttribute(attn_mma, cudaFuncAttributeMaxDynamicSharedMemorySize, ASMEM);

    const size_t xbytes = (size_t)ROWS * DIM * sizeof(float);
    cudaMemcpyAsync(x, x_in, xbytes, cudaMemcpyDeviceToDevice);

    // --- weight converts (fp32 -> fp16; lo only for W_out) ---
    const int DD4 = DIM * DIM / 4, FD4 = FFDIM * DIM / 4;
    wcvt_kernel<<<DD4 / 256, 256>>>(Wq,    whi + WOFF_Q, nullptr, DD4);
    wcvt_kernel<<<DD4 / 256, 256>>>(Wk,    whi + WOFF_K, nullptr, DD4);
    wcvt_kernel<<<DD4 / 256, 256>>>(Wv,    whi + WOFF_V, nullptr, DD4);
    wcvt_kernel<<<DD4 / 256, 256>>>(Wo,    whi + WOFF_O, nullptr, DD4);
    wcvt_kernel<<<FD4 / 256, 256>>>(Wgate, whi + WOFF_G, nullptr, FD4);
    wcvt_kernel<<<FD4 / 256, 256>>>(Wup,   whi + WOFF_U, nullptr, FD4);
    wcvt_kernel<<<FD4 / 256, 256>>>(Wdown, whi + WOFF_D, nullptr, FD4);
    wcvt_kernel<<<DD4 / 256, 256>>>(W_out, whi + WOFF_H, wlo, DD4);

    // --- attention block ---
    rmsnorm_kernel<<<ROWS, 256>>>(x, ln1_w, h16);

    // fused QKV GEMM: [8192,1024] @ [3072,1024]^T -> [8192,3072]
    dim3 gqkv(3 * DIM / SBN, ROWS / SBM);   // (24, 64)
    gemm_s<<<gqkv, 256, SMEM3>>>(h16, whi + WOFF_Q, nullptr,
                                 nullptr, nullptr, nullptr,
                                 qkv, nullptr, ROWS, 3 * DIM, DIM);

    int rope_total = BATCH * SEQ * NHEAD * (HDIM / 2);
    rope_cvt_kernel<<<(rope_total + 255) / 256, 256>>>(qkv, qhi, qlo, khi, klo);
    v_cvt_kernel<<<(ROWS * DIM / 4 + 255) / 256, 256>>>(qkv, vbp);

    dim3 ga(SEQ / 64, NHEAD, BATCH);
    attn_mma<<<ga, 128, ASMEM>>>(qhi, qlo, khi, klo, vbp, c16);

    dim3 g1(DIM / SBN, ROWS / SBM);    // (8, 64)
    // x = x + ctx @ Wo^T (fp32 out for next rmsnorm + residual)
    gemm_s<<<g1, 256, SMEM3>>>(c16, whi + WOFF_O, nullptr,
                               nullptr, x, nullptr,
                               x, nullptr, ROWS, DIM, DIM);

    // --- MLP block ---
    rmsnorm_kernel<<<ROWS, 256>>>(x, ln2_w, h16);
    dim3 gff(FFDIM / SBN, ROWS / SBM); // (32, 64)
    // gate -> f1 (fp32)
    gemm_s<<<gff, 256, SMEM3>>>(h16, whi + WOFF_G, nullptr,
                                nullptr, nullptr, nullptr,
                                f1, nullptr, ROWS, FFDIM, DIM);
    // up with fused silu(gate)*up -> f116
    gemm_s<<<gff, 256, SMEM3>>>(h16, whi + WOFF_U, nullptr,
                                f1, nullptr, nullptr,
                                nullptr, f116, ROWS, FFDIM, DIM);

    // x_new = x + f1 @ Wdown^T -> fp16 (feeds head GEMM)
    gemm_s<<<g1, 256, SMEM3>>>(f116, whi + WOFF_D, nullptr,
                               nullptr, x, nullptr,
                               nullptr, x16, ROWS, DIM, FFDIM);

    // --- output head (2-term: W_out hi+lo) ---
    gemm_s<<<g1, 256, SMEM3>>>(x16, whi + WOFF_H, wlo,
                               nullptr, nullptr, b_out,
                               out, nullptr, ROWS, DIM, DIM);
}

// round 12
// speedup vs baseline: 7.2966x; 1.0501x over previous
#include <cuda_runtime.h>
#include <cuda_bf16.h>
#include <cuda_fp16.h>
#include <cstdint>

// Problem constants
#define BATCH 4
#define SEQ   2048
#define DIM   1024
#define NHEAD 16
#define HDIM  64
#define FFDIM 4096
#define ROWS  (BATCH * SEQ)            // 8192
#define LN_EPS 1e-6f

// ---------------- scratch (device globals; no allocation) ----------------
__device__ float g_x  [(size_t)ROWS * DIM];
__device__ float g_qkv[(size_t)ROWS * 3 * DIM];
// fp16 single activation operands (GEMM A inputs)
__device__ __half g_h16 [(size_t)ROWS * DIM];
__device__ __half g_c16 [(size_t)ROWS * DIM];
__device__ __half g_f116[(size_t)ROWS * FFDIM];
__device__ __half g_x16 [(size_t)ROWS * DIM];
// fp16 weights hi (all) + lo (head only)
// layout: Wq|Wk|Wv|Wo|WgateUp(interleaved 8192 rows)|Wdown|W_out
#define WOFF_Q  0
#define WOFF_K  1048576
#define WOFF_V  2097152
#define WOFF_O  3145728
#define WOFF_GU 4194304           // 8192 rows x 1024 (gate/up interleaved)
#define WOFF_D  12582912
#define WOFF_H  16777216
#define WTOT    17825792
__device__ __half g_whi[(size_t)WTOT];
__device__ __half g_wlo[(size_t)(DIM * DIM)];   // lo only for W_out
// bf16 attention operands, [B,H,S,HD] layout
__device__ __nv_bfloat16 g_qhi[(size_t)ROWS * DIM];
__device__ __nv_bfloat16 g_qlo[(size_t)ROWS * DIM];
__device__ __nv_bfloat16 g_khi[(size_t)ROWS * DIM];
__device__ __nv_bfloat16 g_klo[(size_t)ROWS * DIM];
__device__ __nv_bfloat16 g_vb [(size_t)ROWS * DIM];

__device__ __forceinline__ uint32_t smem_u32(const void* p) {
    uint32_t a;
    asm("{ .reg .u64 t; cvta.to.shared.u64 t, %1; cvt.u32.u64 %0, t; }"
        : "=r"(a) : "l"(p));
    return a;
}
__device__ __forceinline__ void ldmx4(uint32_t addr, uint32_t& r0, uint32_t& r1,
                                      uint32_t& r2, uint32_t& r3) {
    asm volatile("ldmatrix.sync.aligned.m8n8.x4.shared.b16 {%0,%1,%2,%3}, [%4];"
                 : "=r"(r0), "=r"(r1), "=r"(r2), "=r"(r3) : "r"(addr));
}
__device__ __forceinline__ void ldmx4t(uint32_t addr, uint32_t& r0, uint32_t& r1,
                                       uint32_t& r2, uint32_t& r3) {
    asm volatile("ldmatrix.sync.aligned.m8n8.x4.trans.shared.b16 {%0,%1,%2,%3}, [%4];"
                 : "=r"(r0), "=r"(r1), "=r"(r2), "=r"(r3) : "r"(addr));
}
// bf16 MMA (attention)
__device__ __forceinline__ void mma16816(float* c, uint32_t a0, uint32_t a1,
                                         uint32_t a2, uint32_t a3,
                                         uint32_t b0, uint32_t b1) {
    asm volatile(
        "mma.sync.aligned.m16n8k16.row.col.f32.bf16.bf16.f32 "
        "{%0,%1,%2,%3}, {%4,%5,%6,%7}, {%8,%9}, {%0,%1,%2,%3};"
        : "+f"(c[0]), "+f"(c[1]), "+f"(c[2]), "+f"(c[3])
        : "r"(a0), "r"(a1), "r"(a2), "r"(a3), "r"(b0), "r"(b1));
}
// fp16 MMA (GEMMs)
__device__ __forceinline__ void mma16816h(float* c, uint32_t a0, uint32_t a1,
                                          uint32_t a2, uint32_t a3,
                                          uint32_t b0, uint32_t b1) {
    asm volatile(
        "mma.sync.aligned.m16n8k16.row.col.f32.f16.f16.f32 "
        "{%0,%1,%2,%3}, {%4,%5,%6,%7}, {%8,%9}, {%0,%1,%2,%3};"
        : "+f"(c[0]), "+f"(c[1]), "+f"(c[2]), "+f"(c[3])
        : "r"(a0), "r"(a1), "r"(a2), "r"(a3), "r"(b0), "r"(b1));
}
__device__ __forceinline__ float ex2f(float x) {
    float r;
    asm("ex2.approx.f32 %0, %1;" : "=f"(r) : "f"(x));
    return r;
}
#define CPA16(dst, src) \
    asm volatile("cp.async.cg.shared.global [%0], [%1], 16;" :: "r"(dst), "l"(src))
#define CPA_COMMIT() asm volatile("cp.async.commit_group;" ::: "memory")
#define CPA_WAIT(n)  asm volatile("cp.async.wait_group %0;" :: "n"(n) : "memory")

// ---------------- weight convert: fp32 -> fp16 (hi; optional lo) ----------
__global__ void wcvt_kernel(const float* __restrict__ src,
                            __half* __restrict__ hi,
                            __half* __restrict__ lo, int n4) {
    int t = blockIdx.x * 256 + threadIdx.x;
    if (t >= n4) return;
    float4 v = *(const float4*)(src + (size_t)t * 4);
    __half h0 = __float2half_rn(v.x), h1 = __float2half_rn(v.y);
    __half h2 = __float2half_rn(v.z), h3 = __float2half_rn(v.w);
    __half2 hp0 = __halves2half2(h0, h1), hp1 = __halves2half2(h2, h3);
    uint2 ho = { *(uint32_t*)&hp0, *(uint32_t*)&hp1 };
    *(uint2*)(hi + (size_t)t * 4) = ho;
    if (lo) {
        __half l0 = __float2half_rn(v.x - __half2float(h0));
        __half l1 = __float2half_rn(v.y - __half2float(h1));
        __half l2 = __float2half_rn(v.z - __half2float(h2));
        __half l3 = __float2half_rn(v.w - __half2float(h3));
        __half2 lp0 = __halves2half2(l0, l1), lp1 = __halves2half2(l2, l3);
        uint2 lw = { *(uint32_t*)&lp0, *(uint32_t*)&lp1 };
        *(uint2*)(lo + (size_t)t * 4) = lw;
    }
}

// ------- gate/up interleaved convert: gate row r -> 2r, up row r -> 2r+1 ---
__global__ void wcvt_gu_kernel(const float* __restrict__ gate,
                               const float* __restrict__ up,
                               __half* __restrict__ hi, int n4) {
    int t = blockIdx.x * 256 + threadIdx.x;
    if (t >= n4) return;                 // n4 = FFDIM*DIM/4
    int r  = t >> 8;                     // row (K/4 = 256 float4 per row)
    int c4 = t & 255;
    float4 vg = *(const float4*)(gate + (size_t)t * 4);
    float4 vu = *(const float4*)(up   + (size_t)t * 4);
    __half2 g0 = __floats2half2_rn(vg.x, vg.y), g1 = __floats2half2_rn(vg.z, vg.w);
    __half2 u0 = __floats2half2_rn(vu.x, vu.y), u1 = __floats2half2_rn(vu.z, vu.w);
    uint2 go = { *(uint32_t*)&g0, *(uint32_t*)&g1 };
    uint2 uo = { *(uint32_t*)&u0, *(uint32_t*)&u1 };
    *(uint2*)(hi + (size_t)(2 * r) * DIM + c4 * 4)     = go;
    *(uint2*)(hi + (size_t)(2 * r + 1) * DIM + c4 * 4) = uo;
}

// ================= gemm_s: fp16 GEMM (1 or 2 weight terms) =================
// C[M,N] = A[M,K] @ (Whi[+Wlo])[N,K]^T ; A single fp16.
// Outputs: fp32 C, fp16 C16, or gate-up fused GU (silu(even)*odd, width N/2).
// Tile 128x128, BK=32, 3-stage cp.async, SW64 swizzle, 2 CTAs/SM.
#define SBM 128
#define SBN 128
#define SBK 32
#define S_WHI 8192
#define S_WLO 16384
#define SSTG  24576
#define SMEM3 (3 * SSTG)       // 73728 -> 2 CTAs/SM

__global__ __launch_bounds__(256, 2)
void gemm_s(const __half* __restrict__ A,
            const __half* __restrict__ Whi, const __half* __restrict__ Wlo,
            const float* __restrict__ res, const float* __restrict__ bias,
            float* __restrict__ C, __half* __restrict__ C16,
            __half* __restrict__ GU,
            int M, int N, int K) {
    extern __shared__ char smem[];
    uint32_t sb = smem_u32(smem);
    int tid = threadIdx.x, wid = tid >> 5, lane = tid & 31;
    int bm = blockIdx.y * SBM, bn = blockIdx.x * SBN;
    int warp_m = (wid >> 2) * 64, warp_n = (wid & 3) * 32;
    const bool has_lo = (Wlo != nullptr);

    // --- cp.async mapping: 64 rows per pass, 4 x 16B chunks per 64B row ---
    uint32_t strow = (uint32_t)(tid >> 2);
    uint32_t stc   = (uint32_t)(tid & 3) * 16;
    uint32_t st_off = strow * 64 + (stc ^ (((strow >> 1) & 3u) << 4));
    const __half* Ap = A   + (size_t)(bm + strow) * K + (tid & 3) * 8;
    const __half* Wh = Whi + (size_t)(bn + strow) * K + (tid & 3) * 8;
    const __half* Wl = has_lo ? (Wlo + (size_t)(bn + strow) * K + (tid & 3) * 8) : nullptr;

    auto load_stage = [&](int s, int chunk) {
        uint32_t base = sb + (uint32_t)s * SSTG;
        size_t ko = (size_t)chunk * SBK;
        #pragma unroll
        for (int j = 0; j < 2; j++) {
            uint32_t d = base + st_off + j * 4096;     // 64 rows * 64B
            size_t ro = (size_t)j * 64 * K + ko;
            CPA16(d,         (const char*)(Ap + ro));
            CPA16(d + S_WHI, (const char*)(Wh + ro));
            if (has_lo) CPA16(d + S_WLO, (const char*)(Wl + ro));
        }
    };

    // --- ldmatrix addressing (SW64: col ^= ((row>>1)&3)<<4) ---
    int ra = warp_m + (lane & 15);
    uint32_t a_row = (uint32_t)ra * 64;
    uint32_t swa = (((uint32_t)ra >> 1) & 3u) << 4;
    int rb = warp_n + (lane & 7) + ((lane >> 4) & 1) * 8;
    uint32_t b_row = (uint32_t)rb * 64;
    uint32_t swb = (((uint32_t)rb >> 1) & 3u) << 4;
    uint32_t col_a[2], col_b[2];
    int ha = ((lane >> 4) & 1) * 16;
    int hb = ((lane >> 3) & 1) * 16;
    #pragma unroll
    for (int ks = 0; ks < 2; ks++) {
        col_a[ks] = ((uint32_t)(ks * 32 + ha)) ^ swa;
        col_b[ks] = ((uint32_t)(ks * 32 + hb)) ^ swb;
    }

    float acc[4][4][4];
    #pragma unroll
    for (int i = 0; i < 4; i++)
        #pragma unroll
        for (int j = 0; j < 4; j++)
            #pragma unroll
            for (int r = 0; r < 4; r++) acc[i][j][r] = 0.f;

    const int nk = K / SBK;
    load_stage(0, 0);
    CPA_COMMIT();
    if (nk > 1) load_stage(1, 1);
    CPA_COMMIT();

    int sc = 0;
    for (int i = 0; i < nk; i++) {
        int snx = sc + 2; if (snx >= 3) snx -= 3;
        if (i + 2 < nk) load_stage(snx, i + 2);
        CPA_COMMIT();
        CPA_WAIT(2);
        __syncthreads();

        uint32_t base = sb + (uint32_t)sc * SSTG;
        #pragma unroll
        for (int ks = 0; ks < 2; ks++) {
            uint32_t bhr[2][4];
            #pragma unroll
            for (int np = 0; np < 2; np++) {
                uint32_t bd = base + S_WHI + b_row + (uint32_t)np * 1024 + col_b[ks];
                ldmx4(bd, bhr[np][0], bhr[np][1], bhr[np][2], bhr[np][3]);
            }
            uint32_t ar[4][4];
            #pragma unroll
            for (int mf = 0; mf < 4; mf++) {
                uint32_t ad = base + a_row + (uint32_t)mf * 1024 + col_a[ks];
                ldmx4(ad, ar[mf][0], ar[mf][1], ar[mf][2], ar[mf][3]);
            }
            #pragma unroll
            for (int mf = 0; mf < 4; mf++)
                #pragma unroll
                for (int nf = 0; nf < 4; nf++)
                    mma16816h(acc[mf][nf],
                              ar[mf][0], ar[mf][1], ar[mf][2], ar[mf][3],
                              bhr[nf >> 1][(nf & 1) * 2], bhr[nf >> 1][(nf & 1) * 2 + 1]);
            if (has_lo) {
                uint32_t blr[2][4];
                #pragma unroll
                for (int np = 0; np < 2; np++) {
                    uint32_t bd = base + S_WLO + b_row + (uint32_t)np * 1024 + col_b[ks];
                    ldmx4(bd, blr[np][0], blr[np][1], blr[np][2], blr[np][3]);
                }
                #pragma unroll
                for (int mf = 0; mf < 4; mf++)
                    #pragma unroll
                    for (int nf = 0; nf < 4; nf++)
                        mma16816h(acc[mf][nf],
                                  ar[mf][0], ar[mf][1], ar[mf][2], ar[mf][3],
                                  blr[nf >> 1][(nf & 1) * 2], blr[nf >> 1][(nf & 1) * 2 + 1]);
            }
        }
        __syncthreads();
        sc = (sc == 2) ? 0 : sc + 1;
    }

    // ---- epilogue ----
    int tr = lane >> 2, tc = (lane & 3) * 2;
    #pragma unroll
    for (int mf = 0; mf < 4; mf++) {
        #pragma unroll
        for (int nf = 0; nf < 4; nf++) {
            int row0 = bm + warp_m + mf * 16 + tr;
            int col  = bn + warp_n + nf * 8 + tc;
            float* c = acc[mf][nf];
            float v[4] = {c[0], c[1], c[2], c[3]};
            size_t o0 = (size_t)row0 * N + col;
            size_t o1 = (size_t)(row0 + 8) * N + col;
            if (GU) {
                // (v0,v1) = (gate,up) at pair index col/2; same for (v2,v3)
                float r0 = v[1] * (v[0] / (1.f + expf(-v[0])));
                float r1 = v[3] * (v[2] / (1.f + expf(-v[2])));
                size_t p0 = (size_t)row0 * (N / 2) + (col >> 1);
                size_t p1 = (size_t)(row0 + 8) * (N / 2) + (col >> 1);
                GU[p0] = __float2half_rn(r0);
                GU[p1] = __float2half_rn(r1);
                continue;
            }
            if (res) {
                float2 r0 = *(const float2*)(res + o0);
                float2 r1 = *(const float2*)(res + o1);
                v[0] += r0.x; v[1] += r0.y; v[2] += r1.x; v[3] += r1.y;
            }
            if (bias) {
                float2 bb = *(const float2*)(bias + col);
                v[0] += bb.x; v[1] += bb.y; v[2] += bb.x; v[3] += bb.y;
            }
            if (C) {
                *(float2*)(C + o0) = {v[0], v[1]};
                *(float2*)(C + o1) = {v[2], v[3]};
            }
            if (C16) {
                __half2 h0 = __floats2half2_rn(v[0], v[1]);
                __half2 h1 = __floats2half2_rn(v[2], v[3]);
                *(__half2*)(C16 + o0) = h0;
                *(__half2*)(C16 + o1) = h1;
            }
        }
    }
}

// ---------------- RMSNorm -> fp16 ----------------
__global__ void rmsnorm_kernel(const float* __restrict__ x,
                               const float* __restrict__ w,
                               __half* __restrict__ o16) {
    int row = blockIdx.x;
    const float* xr = x + (size_t)row * DIM;
    float s = 0.f;
    #pragma unroll
    for (int i = threadIdx.x; i < DIM; i += 256) {
        float v = xr[i];
        s += v * v;
    }
    __shared__ float red[8];
    #pragma unroll
    for (int o = 16; o; o >>= 1) s += __shfl_down_sync(0xffffffffu, s, o);
    if ((threadIdx.x & 31) == 0) red[threadIdx.x >> 5] = s;
    __syncthreads();
    if (threadIdx.x < 8) {
        float t = red[threadIdx.x];
        #pragma unroll
        for (int o = 4; o; o >>= 1) t += __shfl_down_sync(0xffu, t, o);
        if (threadIdx.x == 0) red[0] = t;
    }
    __syncthreads();
    float inv = rsqrtf(red[0] * (1.0f / DIM) + LN_EPS);
    #pragma unroll
    for (int i = threadIdx.x; i < DIM; i += 256) {
        float v = xr[i] * inv * w[i];
        o16[(size_t)row * DIM + i] = __float2half_rn(v);
    }
}

// ------ RoPE + V convert on qkv buffer [rows,3072] -> [B,H,S,HD] ----------
#define QSCALE 0.18033688011111793f   // 0.125 * log2(e)
__global__ void rope_v_cvt_kernel(const float* __restrict__ QKV,
                                  __nv_bfloat16* __restrict__ qhi, __nv_bfloat16* __restrict__ qlo,
                                  __nv_bfloat16* __restrict__ khi, __nv_bfloat16* __restrict__ klo,
                                  __nv_bfloat16* __restrict__ vb) {
    int idx = blockIdx.x * 256 + threadIdx.x;
    if (idx >= BATCH * SEQ * NHEAD * (HDIM / 2)) return;
    int d = idx & 31;
    int h = (idx >> 5) & (NHEAD - 1);
    int s = (idx >> 9) & (SEQ - 1);
    int b = idx >> 20;
    size_t ibase = ((size_t)b * SEQ + s) * (3 * DIM) + (size_t)h * HDIM;
    size_t obase = (((size_t)b * NHEAD + h) * SEQ + s) * HDIM;
    float inv = expf(-(float)d * (9.210340371976184f / 32.f));
    float ang = (float)s * inv;
    float sn, cs;
    sincosf(ang, &sn, &cs);
    {
        float x1 = QKV[ibase + d], x2 = QKV[ibase + d + 32];
        float r1 = (x1 * cs - x2 * sn) * QSCALE;
        float r2 = (x2 * cs + x1 * sn) * QSCALE;
        __nv_bfloat16 h1 = __float2bfloat16_rn(r1);
        __nv_bfloat16 h2 = __float2bfloat16_rn(r2);
        qhi[obase + d]      = h1;
        qhi[obase + d + 32] = h2;
        qlo[obase + d]      = __float2bfloat16_rn(r1 - __bfloat162float(h1));
        qlo[obase + d + 32] = __float2bfloat16_rn(r2 - __bfloat162float(h2));
    }
    {
        float x1 = QKV[ibase + DIM + d], x2 = QKV[ibase + DIM + d + 32];
        float r1 = x1 * cs - x2 * sn;
        float r2 = x2 * cs + x1 * sn;
        __nv_bfloat16 h1 = __float2bfloat16_rn(r1);
        __nv_bfloat16 h2 = __float2bfloat16_rn(r2);
        khi[obase + d]      = h1;
        khi[obase + d + 32] = h2;
        klo[obase + d]      = __float2bfloat16_rn(r1 - __bfloat162float(h1));
        klo[obase + d + 32] = __float2bfloat16_rn(r2 - __bfloat162float(h2));
    }
    {
        float v1 = QKV[ibase + 2 * DIM + d], v2 = QKV[ibase + 2 * DIM + d + 32];
        vb[obase + d]      = __float2bfloat16_rn(v1);
        vb[obase + d + 32] = __float2bfloat16_rn(v2);
    }
}

// ================= MMA flash attention (bf16 3-term QK, bf16 PV) ==========
#define AROWB 144
#define A_QHI 0
#define A_QLO 9216
#define A_K0  18432
#define A_V0  55296
#define ASMEM 73728

__global__ __launch_bounds__(128)
void attn_mma(const __nv_bfloat16* __restrict__ qhi, const __nv_bfloat16* __restrict__ qlo,
              const __nv_bfloat16* __restrict__ khi, const __nv_bfloat16* __restrict__ klo,
              const __nv_bfloat16* __restrict__ vb,
              __half* __restrict__ O16) {
    extern __shared__ char smem[];
    uint32_t sb = smem_u32(smem);
    int tid = threadIdx.x, wid = tid >> 5, lane = tid & 31;
    int b = blockIdx.z, h = blockIdx.y;
    int q0 = blockIdx.x * 64;
    size_t hoff = ((size_t)b * NHEAD + h) * SEQ * HDIM;

    {
        const uint4* qh4 = (const uint4*)(qhi + hoff + (size_t)q0 * HDIM);
        const uint4* ql4 = (const uint4*)(qlo + hoff + (size_t)q0 * HDIM);
        #pragma unroll
        for (int j = 0; j < 4; j++) {
            int f = tid + j * 128;
            int r = f >> 3, c = f & 7;
            *(uint4*)(smem + A_QHI + r * AROWB + c * 16) = qh4[r * 8 + c];
            *(uint4*)(smem + A_QLO + r * AROWB + c * 16) = ql4[r * 8 + c];
        }
    }
    __syncthreads();

    uint32_t qh[4][4], ql[4][4];
    {
        uint32_t a_base = sb + (uint32_t)(wid * 16 + (lane & 15)) * AROWB + ((lane >> 4) & 1) * 16;
        #pragma unroll
        for (int ks = 0; ks < 4; ks++) {
            ldmx4(a_base + ks * 32,         qh[ks][0], qh[ks][1], qh[ks][2], qh[ks][3]);
            ldmx4(a_base + A_QLO + ks * 32, ql[ks][0], ql[ks][1], ql[ks][2], ql[ks][3]);
        }
    }

    float ctx[8][4];
    #pragma unroll
    for (int j = 0; j < 8; j++)
        #pragma unroll
        for (int r = 0; r < 4; r++) ctx[j][r] = 0.f;
    float m0 = -1e30f, m1 = -1e30f, l0 = 0.f, l1 = 0.f;

    const __nv_bfloat16* kh_g = khi + hoff;
    const __nv_bfloat16* kl_g = klo + hoff;
    const __nv_bfloat16* v_g  = vb + hoff;

    {
        #pragma unroll
        for (int j = 0; j < 4; j++) {
            int f = tid + j * 128;
            int r = f >> 3, c = f & 7;
            uint32_t so = (uint32_t)(r * AROWB + c * 16);
            CPA16(sb + A_K0 + so,        (const char*)(kh_g + r * 64 + c * 8));
            CPA16(sb + A_K0 + 9216 + so, (const char*)(kl_g + r * 64 + c * 8));
            CPA16(sb + A_V0 + so,        (const char*)(v_g  + r * 64 + c * 8));
        }
        CPA_COMMIT();
    }

    const int NT = SEQ / 64;
    for (int t = 0; t < NT; t++) {
        int s = t & 1;
        if (t + 1 < NT) {
            int nxt = s ^ 1;
            size_t goff = (size_t)(t + 1) * 64 * 64;
            #pragma unroll
            for (int j = 0; j < 4; j++) {
                int f = tid + j * 128;
                int r = f >> 3, c = f & 7;
                uint32_t so = (uint32_t)(r * AROWB + c * 16);
                CPA16(sb + A_K0 + nxt * 18432 + so,        (const char*)(kh_g + goff + r * 64 + c * 8));
                CPA16(sb + A_K0 + nxt * 18432 + 9216 + so, (const char*)(kl_g + goff + r * 64 + c * 8));
                CPA16(sb + A_V0 + nxt * 9216 + so,         (const char*)(v_g  + goff + r * 64 + c * 8));
            }
            CPA_COMMIT();
            CPA_WAIT(1);
        } else {
            CPA_WAIT(0);
        }
        __syncthreads();

        uint32_t kb_hi = sb + A_K0 + s * 18432;
        uint32_t kb_lo = kb_hi + 9216;
        uint32_t vbse  = sb + A_V0 + s * 9216;

        float sc[8][4];
        #pragma unroll
        for (int j = 0; j < 8; j++)
            #pragma unroll
            for (int r = 0; r < 4; r++) sc[j][r] = 0.f;

        uint32_t b_off = (uint32_t)((lane & 7) + ((lane >> 4) & 1) * 8) * AROWB +
                         ((lane >> 3) & 1) * 16;
        #pragma unroll
        for (int ks = 0; ks < 4; ks++) {
            #pragma unroll
            for (int ng = 0; ng < 4; ng++) {
                uint32_t bh0, bh1, bh2, bh3, bl0, bl1, bl2, bl3;
                uint32_t ad = b_off + (uint32_t)ng * (16 * AROWB) + ks * 32;
                ldmx4(kb_hi + ad, bh0, bh1, bh2, bh3);
                ldmx4(kb_lo + ad, bl0, bl1, bl2, bl3);
                mma16816(sc[2 * ng],     qh[ks][0], qh[ks][1], qh[ks][2], qh[ks][3], bh0, bh1);
                mma16816(sc[2 * ng + 1], qh[ks][0], qh[ks][1], qh[ks][2], qh[ks][3], bh2, bh3);
                mma16816(sc[2 * ng],     qh[ks][0], qh[ks][1], qh[ks][2], qh[ks][3], bl0, bl1);
                mma16816(sc[2 * ng + 1], qh[ks][0], qh[ks][1], qh[ks][2], qh[ks][3], bl2, bl3);
                mma16816(sc[2 * ng],     ql[ks][0], ql[ks][1], ql[ks][2], ql[ks][3], bh0, bh1);
                mma16816(sc[2 * ng + 1], ql[ks][0], ql[ks][1], ql[ks][2], ql[ks][3], bh2, bh3);
            }
        }

        float mn0 = m0, mn1 = m1;
        #pragma unroll
        for (int j = 0; j < 8; j++) {
            mn0 = fmaxf(mn0, fmaxf(sc[j][0], sc[j][1]));
            mn1 = fmaxf(mn1, fmaxf(sc[j][2], sc[j][3]));
        }
        mn0 = fmaxf(mn0, __shfl_xor_sync(0xffffffffu, mn0, 1));
        mn0 = fmaxf(mn0, __shfl_xor_sync(0xffffffffu, mn0, 2));
        mn1 = fmaxf(mn1, __shfl_xor_sync(0xffffffffu, mn1, 1));
        mn1 = fmaxf(mn1, __shfl_xor_sync(0xffffffffu, mn1, 2));
        float corr0 = ex2f(m0 - mn0);
        float corr1 = ex2f(m1 - mn1);
        m0 = mn0; m1 = mn1;
        l0 *= corr0; l1 *= corr1;
        #pragma unroll
        for (int j = 0; j < 8; j++) {
            ctx[j][0] *= corr0; ctx[j][1] *= corr0;
            ctx[j][2] *= corr1; ctx[j][3] *= corr1;
        }
        uint32_t pa[8], pb[8];
        #pragma unroll
        for (int j = 0; j < 8; j++) {
            float p0 = ex2f(sc[j][0] - mn0);
            float p1 = ex2f(sc[j][1] - mn0);
            float p2 = ex2f(sc[j][2] - mn1);
            float p3 = ex2f(sc[j][3] - mn1);
            l0 += p0 + p1; l1 += p2 + p3;
            __nv_bfloat162 t0 = __floats2bfloat162_rn(p0, p1);
            __nv_bfloat162 t1 = __floats2bfloat162_rn(p2, p3);
            pa[j] = *(uint32_t*)&t0;
            pb[j] = *(uint32_t*)&t1;
        }

        uint32_t v_off = (uint32_t)(lane & 15) * AROWB + ((lane >> 4) & 1) * 16;
        #pragma unroll
        for (int ks = 0; ks < 4; ks++) {
            #pragma unroll
            for (int nd = 0; nd < 4; nd++) {
                uint32_t r0, r1, r2, r3;
                ldmx4t(vbse + v_off + (uint32_t)ks * (16 * AROWB) + nd * 32, r0, r1, r2, r3);
                mma16816(ctx[nd * 2],     pa[2 * ks], pb[2 * ks], pa[2 * ks + 1], pb[2 * ks + 1], r0, r1);
                mma16816(ctx[nd * 2 + 1], pa[2 * ks], pb[2 * ks], pa[2 * ks + 1], pb[2 * ks + 1], r2, r3);
            }
        }
        __syncthreads();
    }

    l0 += __shfl_xor_sync(0xffffffffu, l0, 1);
    l0 += __shfl_xor_sync(0xffffffffu, l0, 2);
    l1 += __shfl_xor_sync(0xffffffffu, l1, 1);
    l1 += __shfl_xor_sync(0xffffffffu, l1, 2);
    float i0 = 1.f / l0, i1 = 1.f / l1;

    int tr = lane >> 2, tc = (lane & 3) * 2;
    int row0 = q0 + wid * 16 + tr;
    #pragma unroll
    for (int f = 0; f < 8; f++) {
        int d = f * 8 + tc;
        float* c = ctx[f];
        size_t o0 = ((size_t)b * SEQ + row0) * DIM + (size_t)h * HDIM + d;
        size_t o1 = ((size_t)b * SEQ + row0 + 8) * DIM + (size_t)h * HDIM + d;
        __half2 h0 = __floats2half2_rn(c[0] * i0, c[1] * i0);
        __half2 h1 = __floats2half2_rn(c[2] * i1, c[3] * i1);
        *(__half2*)(O16 + o0) = h0;
        *(__half2*)(O16 + o1) = h1;
    }
}

// ---------------- launch ----------------
extern "C" void kernel_launch(void* const* d_in, const int* in_sizes, int n_in,
                              void* d_out, int out_size) {
    const float* x_in   = (const float*)d_in[0];
    const float* Wq     = (const float*)d_in[1];
    const float* Wk     = (const float*)d_in[2];
    const float* Wv     = (const float*)d_in[3];
    const float* Wo     = (const float*)d_in[4];
    const float* ln1_w  = (const float*)d_in[5];
    const float* ln2_w  = (const float*)d_in[6];
    const float* Wgate  = (const float*)d_in[7];
    const float* Wup    = (const float*)d_in[8];
    const float* Wdown  = (const float*)d_in[9];
    const float* W_out  = (const float*)d_in[10];
    const float* b_out  = (const float*)d_in[11];
    float* out = (float*)d_out;

    float *x, *qkv;
    __half *h16, *c16, *f116, *x16, *whi, *wlo;
    __nv_bfloat16 *qhi, *qlo, *khi, *klo, *vbp;
    cudaGetSymbolAddress((void**)&x,    g_x);
    cudaGetSymbolAddress((void**)&qkv,  g_qkv);
    cudaGetSymbolAddress((void**)&h16,  g_h16);
    cudaGetSymbolAddress((void**)&c16,  g_c16);
    cudaGetSymbolAddress((void**)&f116, g_f116);
    cudaGetSymbolAddress((void**)&x16,  g_x16);
    cudaGetSymbolAddress((void**)&whi,  g_whi);
    cudaGetSymbolAddress((void**)&wlo,  g_wlo);
    cudaGetSymbolAddress((void**)&qhi,  g_qhi);
    cudaGetSymbolAddress((void**)&qlo,  g_qlo);
    cudaGetSymbolAddress((void**)&khi,  g_khi);
    cudaGetSymbolAddress((void**)&klo,  g_klo);
    cudaGetSymbolAddress((void**)&vbp,  g_vb);

    cudaFuncSetAttribute(gemm_s,   cudaFuncAttributeMaxDynamicSharedMemorySize, SMEM3);
    cudaFuncSetAttribute(attn_mma, cudaFuncAttributeMaxDynamicSharedMemorySize, ASMEM);

    // --- weight converts (fp32 -> fp16; lo only for W_out; gate/up interleaved)
    const int DD4 = DIM * DIM / 4, FD4 = FFDIM * DIM / 4;
    wcvt_kernel<<<DD4 / 256, 256>>>(Wq,    whi + WOFF_Q, nullptr, DD4);
    wcvt_kernel<<<DD4 / 256, 256>>>(Wk,    whi + WOFF_K, nullptr, DD4);
    wcvt_kernel<<<DD4 / 256, 256>>>(Wv,    whi + WOFF_V, nullptr, DD4);
    wcvt_kernel<<<DD4 / 256, 256>>>(Wo,    whi + WOFF_O, nullptr, DD4);
    wcvt_gu_kernel<<<FD4 / 256, 256>>>(Wgate, Wup, whi + WOFF_GU, FD4);
    wcvt_kernel<<<FD4 / 256, 256>>>(Wdown, whi + WOFF_D, nullptr, FD4);
    wcvt_kernel<<<DD4 / 256, 256>>>(W_out, whi + WOFF_H, wlo, DD4);

    // --- attention block ---
    rmsnorm_kernel<<<ROWS, 256>>>(x_in, ln1_w, h16);

    // fused QKV GEMM: [8192,1024] @ [3072,1024]^T -> [8192,3072]
    dim3 gqkv(3 * DIM / SBN, ROWS / SBM);   // (24, 64)
    gemm_s<<<gqkv, 256, SMEM3>>>(h16, whi + WOFF_Q, nullptr,
                                 nullptr, nullptr,
                                 qkv, nullptr, nullptr, ROWS, 3 * DIM, DIM);

    int rope_total = BATCH * SEQ * NHEAD * (HDIM / 2);
    rope_v_cvt_kernel<<<(rope_total + 255) / 256, 256>>>(qkv, qhi, qlo, khi, klo, vbp);

    dim3 ga(SEQ / 64, NHEAD, BATCH);
    attn_mma<<<ga, 128, ASMEM>>>(qhi, qlo, khi, klo, vbp, c16);

    dim3 g1(DIM / SBN, ROWS / SBM);    // (8, 64)
    // x = x_in + ctx @ Wo^T -> g_x (fp32)
    gemm_s<<<g1, 256, SMEM3>>>(c16, whi + WOFF_O, nullptr,
                               x_in, nullptr,
                               x, nullptr, nullptr, ROWS, DIM, DIM);

    // --- MLP block ---
    rmsnorm_kernel<<<ROWS, 256>>>(x, ln2_w, h16);
    // fused gate+up GEMM: N=8192 interleaved, silu epilogue -> f116 [8192,4096]
    dim3 ggu(2 * FFDIM / SBN, ROWS / SBM); // (64, 64)
    gemm_s<<<ggu, 256, SMEM3>>>(h16, whi + WOFF_GU, nullptr,
                                nullptr, nullptr,
                                nullptr, nullptr, f116, ROWS, 2 * FFDIM, DIM);

    // x_new = x + f1 @ Wdown^T -> fp16 (feeds head GEMM)
    gemm_s<<<g1, 256, SMEM3>>>(f116, whi + WOFF_D, nullptr,
                               x, nullptr,
                               nullptr, x16, nullptr, ROWS, DIM, FFDIM);

    // --- output head (2-term: W_out hi+lo) ---
    gemm_s<<<g1, 256, SMEM3>>>(x16, whi + WOFF_H, wlo,
                               nullptr, b_out,
                               out, nullptr, nullptr, ROWS, DIM, DIM);
}

// round 13
// speedup vs baseline: 7.4693x; 1.0237x over previous
#include <cuda_runtime.h>
#include <cuda_bf16.h>
#include <cuda_fp16.h>
#include <cstdint>

// Problem constants
#define BATCH 4
#define SEQ   2048
#define DIM   1024
#define NHEAD 16
#define HDIM  64
#define FFDIM 4096
#define ROWS  (BATCH * SEQ)            // 8192
#define LN_EPS 1e-6f

// ---------------- scratch (device globals; no allocation) ----------------
__device__ float g_x  [(size_t)ROWS * DIM];
__device__ float g_qkv[(size_t)ROWS * 3 * DIM];
// fp16 single activation operands (GEMM A inputs)
__device__ __half g_h16 [(size_t)ROWS * DIM];
__device__ __half g_c16 [(size_t)ROWS * DIM];
__device__ __half g_f116[(size_t)ROWS * FFDIM];
__device__ __half g_x16 [(size_t)ROWS * DIM];
// fp16 weights hi (all) + lo (head only)
// layout: Wq|Wk|Wv|Wo|WgateUp(interleaved 8192 rows)|Wdown|W_out
#define WOFF_Q  0
#define WOFF_K  1048576
#define WOFF_V  2097152
#define WOFF_O  3145728
#define WOFF_GU 4194304           // 8192 rows x 1024 (gate/up interleaved)
#define WOFF_D  12582912
#define WOFF_H  16777216
#define WTOT    17825792
__device__ __half g_whi[(size_t)WTOT];
__device__ __half g_wlo[(size_t)(DIM * DIM)];   // lo only for W_out
// bf16 attention operands, [B,H,S,HD] layout
__device__ __nv_bfloat16 g_qhi[(size_t)ROWS * DIM];
__device__ __nv_bfloat16 g_qlo[(size_t)ROWS * DIM];
__device__ __nv_bfloat16 g_khi[(size_t)ROWS * DIM];
__device__ __nv_bfloat16 g_klo[(size_t)ROWS * DIM];
__device__ __nv_bfloat16 g_vb [(size_t)ROWS * DIM];

__device__ __forceinline__ uint32_t smem_u32(const void* p) {
    uint32_t a;
    asm("{ .reg .u64 t; cvta.to.shared.u64 t, %1; cvt.u32.u64 %0, t; }"
        : "=r"(a) : "l"(p));
    return a;
}
__device__ __forceinline__ void ldmx4(uint32_t addr, uint32_t& r0, uint32_t& r1,
                                      uint32_t& r2, uint32_t& r3) {
    asm volatile("ldmatrix.sync.aligned.m8n8.x4.shared.b16 {%0,%1,%2,%3}, [%4];"
                 : "=r"(r0), "=r"(r1), "=r"(r2), "=r"(r3) : "r"(addr));
}
__device__ __forceinline__ void ldmx4t(uint32_t addr, uint32_t& r0, uint32_t& r1,
                                       uint32_t& r2, uint32_t& r3) {
    asm volatile("ldmatrix.sync.aligned.m8n8.x4.trans.shared.b16 {%0,%1,%2,%3}, [%4];"
                 : "=r"(r0), "=r"(r1), "=r"(r2), "=r"(r3) : "r"(addr));
}
// bf16 MMA (attention)
__device__ __forceinline__ void mma16816(float* c, uint32_t a0, uint32_t a1,
                                         uint32_t a2, uint32_t a3,
                                         uint32_t b0, uint32_t b1) {
    asm volatile(
        "mma.sync.aligned.m16n8k16.row.col.f32.bf16.bf16.f32 "
        "{%0,%1,%2,%3}, {%4,%5,%6,%7}, {%8,%9}, {%0,%1,%2,%3};"
        : "+f"(c[0]), "+f"(c[1]), "+f"(c[2]), "+f"(c[3])
        : "r"(a0), "r"(a1), "r"(a2), "r"(a3), "r"(b0), "r"(b1));
}
// fp16 MMA (GEMMs)
__device__ __forceinline__ void mma16816h(float* c, uint32_t a0, uint32_t a1,
                                          uint32_t a2, uint32_t a3,
                                          uint32_t b0, uint32_t b1) {
    asm volatile(
        "mma.sync.aligned.m16n8k16.row.col.f32.f16.f16.f32 "
        "{%0,%1,%2,%3}, {%4,%5,%6,%7}, {%8,%9}, {%0,%1,%2,%3};"
        : "+f"(c[0]), "+f"(c[1]), "+f"(c[2]), "+f"(c[3])
        : "r"(a0), "r"(a1), "r"(a2), "r"(a3), "r"(b0), "r"(b1));
}
__device__ __forceinline__ float ex2f(float x) {
    float r;
    asm("ex2.approx.f32 %0, %1;" : "=f"(r) : "f"(x));
    return r;
}
#define CPA16(dst, src) \
    asm volatile("cp.async.cg.shared.global [%0], [%1], 16;" :: "r"(dst), "l"(src))
#define CPA_COMMIT() asm volatile("cp.async.commit_group;" ::: "memory")
#define CPA_WAIT(n)  asm volatile("cp.async.wait_group %0;" :: "n"(n) : "memory")

// ---------------- weight convert: fp32 -> fp16 (hi; optional lo) ----------
__global__ void wcvt_kernel(const float* __restrict__ src,
                            __half* __restrict__ hi,
                            __half* __restrict__ lo, int n4) {
    int t = blockIdx.x * 256 + threadIdx.x;
    if (t >= n4) return;
    float4 v = *(const float4*)(src + (size_t)t * 4);
    __half h0 = __float2half_rn(v.x), h1 = __float2half_rn(v.y);
    __half h2 = __float2half_rn(v.z), h3 = __float2half_rn(v.w);
    __half2 hp0 = __halves2half2(h0, h1), hp1 = __halves2half2(h2, h3);
    uint2 ho = { *(uint32_t*)&hp0, *(uint32_t*)&hp1 };
    *(uint2*)(hi + (size_t)t * 4) = ho;
    if (lo) {
        __half l0 = __float2half_rn(v.x - __half2float(h0));
        __half l1 = __float2half_rn(v.y - __half2float(h1));
        __half l2 = __float2half_rn(v.z - __half2float(h2));
        __half l3 = __float2half_rn(v.w - __half2float(h3));
        __half2 lp0 = __halves2half2(l0, l1), lp1 = __halves2half2(l2, l3);
        uint2 lw = { *(uint32_t*)&lp0, *(uint32_t*)&lp1 };
        *(uint2*)(lo + (size_t)t * 4) = lw;
    }
}

// ------- gate/up interleaved convert: gate row r -> 2r, up row r -> 2r+1 ---
__global__ void wcvt_gu_kernel(const float* __restrict__ gate,
                               const float* __restrict__ up,
                               __half* __restrict__ hi, int n4) {
    int t = blockIdx.x * 256 + threadIdx.x;
    if (t >= n4) return;                 // n4 = FFDIM*DIM/4
    int r  = t >> 8;                     // row (K/4 = 256 float4 per row)
    int c4 = t & 255;
    float4 vg = *(const float4*)(gate + (size_t)t * 4);
    float4 vu = *(const float4*)(up   + (size_t)t * 4);
    __half2 g0 = __floats2half2_rn(vg.x, vg.y), g1 = __floats2half2_rn(vg.z, vg.w);
    __half2 u0 = __floats2half2_rn(vu.x, vu.y), u1 = __floats2half2_rn(vu.z, vu.w);
    uint2 go = { *(uint32_t*)&g0, *(uint32_t*)&g1 };
    uint2 uo = { *(uint32_t*)&u0, *(uint32_t*)&u1 };
    *(uint2*)(hi + (size_t)(2 * r) * DIM + c4 * 4)     = go;
    *(uint2*)(hi + (size_t)(2 * r + 1) * DIM + c4 * 4) = uo;
}

// ================= gemm_s: fp16 GEMM (1 or 2 weight terms) =================
// C[M,N] = A[M,K] @ (Whi[+Wlo])[N,K]^T ; A single fp16.
// Outputs: fp32 C, fp16 C16, or gate-up fused GU (silu(even)*odd, width N/2).
// Tile 128x128, BK=64 (2x 32-wide sub-blocks), 2-stage cp.async, SW64
// swizzle, single __syncthreads per K-chunk, 2 CTAs/SM.
#define SBM 128
#define SBN 128
#define SBK 64
#define S_WHI 16384
#define S_WLO 32768
#define SSTG  49152
#define SMEM2 (2 * SSTG)       // 98304 -> 2 CTAs/SM

__global__ __launch_bounds__(256, 2)
void gemm_s(const __half* __restrict__ A,
            const __half* __restrict__ Whi, const __half* __restrict__ Wlo,
            const float* __restrict__ res, const float* __restrict__ bias,
            float* __restrict__ C, __half* __restrict__ C16,
            __half* __restrict__ GU,
            int M, int N, int K) {
    extern __shared__ char smem[];
    uint32_t sb = smem_u32(smem);
    int tid = threadIdx.x, wid = tid >> 5, lane = tid & 31;
    int bm = blockIdx.y * SBM, bn = blockIdx.x * SBN;
    int warp_m = (wid >> 2) * 64, warp_n = (wid & 3) * 32;
    const bool has_lo = (Wlo != nullptr);

    // --- cp.async mapping: 64 rows per j-pass, 4 x 16B chunks per 64B row ---
    uint32_t strow = (uint32_t)(tid >> 2);
    uint32_t stc   = (uint32_t)(tid & 3) * 16;
    uint32_t st_off = strow * 64 + (stc ^ (((strow >> 1) & 3u) << 4));
    const __half* Ap = A   + (size_t)(bm + strow) * K + (tid & 3) * 8;
    const __half* Wh = Whi + (size_t)(bn + strow) * K + (tid & 3) * 8;
    const __half* Wl = has_lo ? (Wlo + (size_t)(bn + strow) * K + (tid & 3) * 8) : nullptr;

    auto load_stage = [&](int s, int chunk) {
        uint32_t base = sb + (uint32_t)s * SSTG;
        size_t ko = (size_t)chunk * SBK;
        #pragma unroll
        for (int sub = 0; sub < 2; sub++) {
            #pragma unroll
            for (int j = 0; j < 2; j++) {
                uint32_t d = base + sub * 8192 + st_off + j * 4096;
                size_t ro = (size_t)j * 64 * K + ko + sub * 32;
                CPA16(d,         (const char*)(Ap + ro));
                CPA16(d + S_WHI, (const char*)(Wh + ro));
                if (has_lo) CPA16(d + S_WLO, (const char*)(Wl + ro));
            }
        }
    };

    // --- ldmatrix addressing (SW64 within each 32-wide sub-block) ---
    int ra = warp_m + (lane & 15);
    uint32_t a_row = (uint32_t)ra * 64;
    uint32_t swa = (((uint32_t)ra >> 1) & 3u) << 4;
    int rb = warp_n + (lane & 7) + ((lane >> 4) & 1) * 8;
    uint32_t b_row = (uint32_t)rb * 64;
    uint32_t swb = (((uint32_t)rb >> 1) & 3u) << 4;
    uint32_t col_a[2], col_b[2];
    int ha = ((lane >> 4) & 1) * 16;
    int hb = ((lane >> 3) & 1) * 16;
    #pragma unroll
    for (int ks = 0; ks < 2; ks++) {
        col_a[ks] = ((uint32_t)(ks * 32 + ha)) ^ swa;
        col_b[ks] = ((uint32_t)(ks * 32 + hb)) ^ swb;
    }

    float acc[4][4][4];
    #pragma unroll
    for (int i = 0; i < 4; i++)
        #pragma unroll
        for (int j = 0; j < 4; j++)
            #pragma unroll
            for (int r = 0; r < 4; r++) acc[i][j][r] = 0.f;

    const int nk = K / SBK;
    load_stage(0, 0);
    CPA_COMMIT();

    for (int i = 0; i < nk; i++) {
        CPA_WAIT(0);
        __syncthreads();
        if (i + 1 < nk) {
            load_stage((i + 1) & 1, i + 1);
            CPA_COMMIT();
        }

        uint32_t base = sb + (uint32_t)(i & 1) * SSTG;
        #pragma unroll
        for (int ks = 0; ks < 4; ks++) {
            uint32_t soff = (uint32_t)(ks >> 1) * 8192;
            uint32_t ca = col_a[ks & 1], cb = col_b[ks & 1];
            uint32_t bhr[2][4];
            #pragma unroll
            for (int np = 0; np < 2; np++) {
                uint32_t bd = base + S_WHI + soff + b_row + (uint32_t)np * 1024 + cb;
                ldmx4(bd, bhr[np][0], bhr[np][1], bhr[np][2], bhr[np][3]);
            }
            uint32_t ar[4][4];
            #pragma unroll
            for (int mf = 0; mf < 4; mf++) {
                uint32_t ad = base + soff + a_row + (uint32_t)mf * 1024 + ca;
                ldmx4(ad, ar[mf][0], ar[mf][1], ar[mf][2], ar[mf][3]);
            }
            #pragma unroll
            for (int mf = 0; mf < 4; mf++)
                #pragma unroll
                for (int nf = 0; nf < 4; nf++)
                    mma16816h(acc[mf][nf],
                              ar[mf][0], ar[mf][1], ar[mf][2], ar[mf][3],
                              bhr[nf >> 1][(nf & 1) * 2], bhr[nf >> 1][(nf & 1) * 2 + 1]);
            if (has_lo) {
                uint32_t blr[2][4];
                #pragma unroll
                for (int np = 0; np < 2; np++) {
                    uint32_t bd = base + S_WLO + soff + b_row + (uint32_t)np * 1024 + cb;
                    ldmx4(bd, blr[np][0], blr[np][1], blr[np][2], blr[np][3]);
                }
                #pragma unroll
                for (int mf = 0; mf < 4; mf++)
                    #pragma unroll
                    for (int nf = 0; nf < 4; nf++)
                        mma16816h(acc[mf][nf],
                                  ar[mf][0], ar[mf][1], ar[mf][2], ar[mf][3],
                                  blr[nf >> 1][(nf & 1) * 2], blr[nf >> 1][(nf & 1) * 2 + 1]);
            }
        }
    }

    // ---- epilogue ----
    int tr = lane >> 2, tc = (lane & 3) * 2;
    #pragma unroll
    for (int mf = 0; mf < 4; mf++) {
        #pragma unroll
        for (int nf = 0; nf < 4; nf++) {
            int row0 = bm + warp_m + mf * 16 + tr;
            int col  = bn + warp_n + nf * 8 + tc;
            float* c = acc[mf][nf];
            float v[4] = {c[0], c[1], c[2], c[3]};
            size_t o0 = (size_t)row0 * N + col;
            size_t o1 = (size_t)(row0 + 8) * N + col;
            if (GU) {
                float r0 = v[1] * (v[0] / (1.f + expf(-v[0])));
                float r1 = v[3] * (v[2] / (1.f + expf(-v[2])));
                size_t p0 = (size_t)row0 * (N / 2) + (col >> 1);
                size_t p1 = (size_t)(row0 + 8) * (N / 2) + (col >> 1);
                GU[p0] = __float2half_rn(r0);
                GU[p1] = __float2half_rn(r1);
                continue;
            }
            if (res) {
                float2 r0 = *(const float2*)(res + o0);
                float2 r1 = *(const float2*)(res + o1);
                v[0] += r0.x; v[1] += r0.y; v[2] += r1.x; v[3] += r1.y;
            }
            if (bias) {
                float2 bb = *(const float2*)(bias + col);
                v[0] += bb.x; v[1] += bb.y; v[2] += bb.x; v[3] += bb.y;
            }
            if (C) {
                *(float2*)(C + o0) = {v[0], v[1]};
                *(float2*)(C + o1) = {v[2], v[3]};
            }
            if (C16) {
                __half2 h0 = __floats2half2_rn(v[0], v[1]);
                __half2 h1 = __floats2half2_rn(v[2], v[3]);
                *(__half2*)(C16 + o0) = h0;
                *(__half2*)(C16 + o1) = h1;
            }
        }
    }
}

// ---------------- RMSNorm -> fp16 ----------------
__global__ void rmsnorm_kernel(const float* __restrict__ x,
                               const float* __restrict__ w,
                               __half* __restrict__ o16) {
    int row = blockIdx.x;
    const float* xr = x + (size_t)row * DIM;
    float s = 0.f;
    #pragma unroll
    for (int i = threadIdx.x; i < DIM; i += 256) {
        float v = xr[i];
        s += v * v;
    }
    __shared__ float red[8];
    #pragma unroll
    for (int o = 16; o; o >>= 1) s += __shfl_down_sync(0xffffffffu, s, o);
    if ((threadIdx.x & 31) == 0) red[threadIdx.x >> 5] = s;
    __syncthreads();
    if (threadIdx.x < 8) {
        float t = red[threadIdx.x];
        #pragma unroll
        for (int o = 4; o; o >>= 1) t += __shfl_down_sync(0xffu, t, o);
        if (threadIdx.x == 0) red[0] = t;
    }
    __syncthreads();
    float inv = rsqrtf(red[0] * (1.0f / DIM) + LN_EPS);
    #pragma unroll
    for (int i = threadIdx.x; i < DIM; i += 256) {
        float v = xr[i] * inv * w[i];
        o16[(size_t)row * DIM + i] = __float2half_rn(v);
    }
}

// ------ RoPE + V convert on qkv buffer [rows,3072] -> [B,H,S,HD] ----------
#define QSCALE 0.18033688011111793f   // 0.125 * log2(e)
__global__ void rope_v_cvt_kernel(const float* __restrict__ QKV,
                                  __nv_bfloat16* __restrict__ qhi, __nv_bfloat16* __restrict__ qlo,
                                  __nv_bfloat16* __restrict__ khi, __nv_bfloat16* __restrict__ klo,
                                  __nv_bfloat16* __restrict__ vb) {
    int idx = blockIdx.x * 256 + threadIdx.x;
    if (idx >= BATCH * SEQ * NHEAD * (HDIM / 2)) return;
    int d = idx & 31;
    int h = (idx >> 5) & (NHEAD - 1);
    int s = (idx >> 9) & (SEQ - 1);
    int b = idx >> 20;
    size_t ibase = ((size_t)b * SEQ + s) * (3 * DIM) + (size_t)h * HDIM;
    size_t obase = (((size_t)b * NHEAD + h) * SEQ + s) * HDIM;
    float inv = expf(-(float)d * (9.210340371976184f / 32.f));
    float ang = (float)s * inv;
    float sn, cs;
    sincosf(ang, &sn, &cs);
    {
        float x1 = QKV[ibase + d], x2 = QKV[ibase + d + 32];
        float r1 = (x1 * cs - x2 * sn) * QSCALE;
        float r2 = (x2 * cs + x1 * sn) * QSCALE;
        __nv_bfloat16 h1 = __float2bfloat16_rn(r1);
        __nv_bfloat16 h2 = __float2bfloat16_rn(r2);
        qhi[obase + d]      = h1;
        qhi[obase + d + 32] = h2;
        qlo[obase + d]      = __float2bfloat16_rn(r1 - __bfloat162float(h1));
        qlo[obase + d + 32] = __float2bfloat16_rn(r2 - __bfloat162float(h2));
    }
    {
        float x1 = QKV[ibase + DIM + d], x2 = QKV[ibase + DIM + d + 32];
        float r1 = x1 * cs - x2 * sn;
        float r2 = x2 * cs + x1 * sn;
        __nv_bfloat16 h1 = __float2bfloat16_rn(r1);
        __nv_bfloat16 h2 = __float2bfloat16_rn(r2);
        khi[obase + d]      = h1;
        khi[obase + d + 32] = h2;
        klo[obase + d]      = __float2bfloat16_rn(r1 - __bfloat162float(h1));
        klo[obase + d + 32] = __float2bfloat16_rn(r2 - __bfloat162float(h2));
    }
    {
        float v1 = QKV[ibase + 2 * DIM + d], v2 = QKV[ibase + 2 * DIM + d + 32];
        vb[obase + d]      = __float2bfloat16_rn(v1);
        vb[obase + d + 32] = __float2bfloat16_rn(v2);
    }
}

// ================= MMA flash attention (bf16 3-term QK, bf16 PV) ==========
#define AROWB 144
#define A_QHI 0
#define A_QLO 9216
#define A_K0  18432
#define A_V0  55296
#define ASMEM 73728

__global__ __launch_bounds__(128)
void attn_mma(const __nv_bfloat16* __restrict__ qhi, const __nv_bfloat16* __restrict__ qlo,
              const __nv_bfloat16* __restrict__ khi, const __nv_bfloat16* __restrict__ klo,
              const __nv_bfloat16* __restrict__ vb,
              __half* __restrict__ O16) {
    extern __shared__ char smem[];
    uint32_t sb = smem_u32(smem);
    int tid = threadIdx.x, wid = tid >> 5, lane = tid & 31;
    int b = blockIdx.z, h = blockIdx.y;
    int q0 = blockIdx.x * 64;
    size_t hoff = ((size_t)b * NHEAD + h) * SEQ * HDIM;

    {
        const uint4* qh4 = (const uint4*)(qhi + hoff + (size_t)q0 * HDIM);
        const uint4* ql4 = (const uint4*)(qlo + hoff + (size_t)q0 * HDIM);
        #pragma unroll
        for (int j = 0; j < 4; j++) {
            int f = tid + j * 128;
            int r = f >> 3, c = f & 7;
            *(uint4*)(smem + A_QHI + r * AROWB + c * 16) = qh4[r * 8 + c];
            *(uint4*)(smem + A_QLO + r * AROWB + c * 16) = ql4[r * 8 + c];
        }
    }
    __syncthreads();

    uint32_t qh[4][4], ql[4][4];
    {
        uint32_t a_base = sb + (uint32_t)(wid * 16 + (lane & 15)) * AROWB + ((lane >> 4) & 1) * 16;
        #pragma unroll
        for (int ks = 0; ks < 4; ks++) {
            ldmx4(a_base + ks * 32,         qh[ks][0], qh[ks][1], qh[ks][2], qh[ks][3]);
            ldmx4(a_base + A_QLO + ks * 32, ql[ks][0], ql[ks][1], ql[ks][2], ql[ks][3]);
        }
    }

    float ctx[8][4];
    #pragma unroll
    for (int j = 0; j < 8; j++)
        #pragma unroll
        for (int r = 0; r < 4; r++) ctx[j][r] = 0.f;
    float m0 = -1e30f, m1 = -1e30f, l0 = 0.f, l1 = 0.f;

    const __nv_bfloat16* kh_g = khi + hoff;
    const __nv_bfloat16* kl_g = klo + hoff;
    const __nv_bfloat16* v_g  = vb + hoff;

    {
        #pragma unroll
        for (int j = 0; j < 4; j++) {
            int f = tid + j * 128;
            int r = f >> 3, c = f & 7;
            uint32_t so = (uint32_t)(r * AROWB + c * 16);
            CPA16(sb + A_K0 + so,        (const char*)(kh_g + r * 64 + c * 8));
            CPA16(sb + A_K0 + 9216 + so, (const char*)(kl_g + r * 64 + c * 8));
            CPA16(sb + A_V0 + so,        (const char*)(v_g  + r * 64 + c * 8));
        }
        CPA_COMMIT();
    }

    const int NT = SEQ / 64;
    for (int t = 0; t < NT; t++) {
        int s = t & 1;
        if (t + 1 < NT) {
            int nxt = s ^ 1;
            size_t goff = (size_t)(t + 1) * 64 * 64;
            #pragma unroll
            for (int j = 0; j < 4; j++) {
                int f = tid + j * 128;
                int r = f >> 3, c = f & 7;
                uint32_t so = (uint32_t)(r * AROWB + c * 16);
                CPA16(sb + A_K0 + nxt * 18432 + so,        (const char*)(kh_g + goff + r * 64 + c * 8));
                CPA16(sb + A_K0 + nxt * 18432 + 9216 + so, (const char*)(kl_g + goff + r * 64 + c * 8));
                CPA16(sb + A_V0 + nxt * 9216 + so,         (const char*)(v_g  + goff + r * 64 + c * 8));
            }
            CPA_COMMIT();
            CPA_WAIT(1);
        } else {
            CPA_WAIT(0);
        }
        __syncthreads();

        uint32_t kb_hi = sb + A_K0 + s * 18432;
        uint32_t kb_lo = kb_hi + 9216;
        uint32_t vbse  = sb + A_V0 + s * 9216;

        float sc[8][4];
        #pragma unroll
        for (int j = 0; j < 8; j++)
            #pragma unroll
            for (int r = 0; r < 4; r++) sc[j][r] = 0.f;

        uint32_t b_off = (uint32_t)((lane & 7) + ((lane >> 4) & 1) * 8) * AROWB +
                         ((lane >> 3) & 1) * 16;
        #pragma unroll
        for (int ks = 0; ks < 4; ks++) {
            #pragma unroll
            for (int ng = 0; ng < 4; ng++) {
                uint32_t bh0, bh1, bh2, bh3, bl0, bl1, bl2, bl3;
                uint32_t ad = b_off + (uint32_t)ng * (16 * AROWB) + ks * 32;
                ldmx4(kb_hi + ad, bh0, bh1, bh2, bh3);
                ldmx4(kb_lo + ad, bl0, bl1, bl2, bl3);
                mma16816(sc[2 * ng],     qh[ks][0], qh[ks][1], qh[ks][2], qh[ks][3], bh0, bh1);
                mma16816(sc[2 * ng + 1], qh[ks][0], qh[ks][1], qh[ks][2], qh[ks][3], bh2, bh3);
                mma16816(sc[2 * ng],     qh[ks][0], qh[ks][1], qh[ks][2], qh[ks][3], bl0, bl1);
                mma16816(sc[2 * ng + 1], qh[ks][0], qh[ks][1], qh[ks][2], qh[ks][3], bl2, bl3);
                mma16816(sc[2 * ng],     ql[ks][0], ql[ks][1], ql[ks][2], ql[ks][3], bh0, bh1);
                mma16816(sc[2 * ng + 1], ql[ks][0], ql[ks][1], ql[ks][2], ql[ks][3], bh2, bh3);
            }
        }

        float mn0 = m0, mn1 = m1;
        #pragma unroll
        for (int j = 0; j < 8; j++) {
            mn0 = fmaxf(mn0, fmaxf(sc[j][0], sc[j][1]));
            mn1 = fmaxf(mn1, fmaxf(sc[j][2], sc[j][3]));
        }
        mn0 = fmaxf(mn0, __shfl_xor_sync(0xffffffffu, mn0, 1));
        mn0 = fmaxf(mn0, __shfl_xor_sync(0xffffffffu, mn0, 2));
        mn1 = fmaxf(mn1, __shfl_xor_sync(0xffffffffu, mn1, 1));
        mn1 = fmaxf(mn1, __shfl_xor_sync(0xffffffffu, mn1, 2));
        float corr0 = ex2f(m0 - mn0);
        float corr1 = ex2f(m1 - mn1);
        m0 = mn0; m1 = mn1;
        l0 *= corr0; l1 *= corr1;
        #pragma unroll
        for (int j = 0; j < 8; j++) {
            ctx[j][0] *= corr0; ctx[j][1] *= corr0;
            ctx[j][2] *= corr1; ctx[j][3] *= corr1;
        }
        uint32_t pa[8], pb[8];
        #pragma unroll
        for (int j = 0; j < 8; j++) {
            float p0 = ex2f(sc[j][0] - mn0);
            float p1 = ex2f(sc[j][1] - mn0);
            float p2 = ex2f(sc[j][2] - mn1);
            float p3 = ex2f(sc[j][3] - mn1);
            l0 += p0 + p1; l1 += p2 + p3;
            __nv_bfloat162 t0 = __floats2bfloat162_rn(p0, p1);
            __nv_bfloat162 t1 = __floats2bfloat162_rn(p2, p3);
            pa[j] = *(uint32_t*)&t0;
            pb[j] = *(uint32_t*)&t1;
        }

        uint32_t v_off = (uint32_t)(lane & 15) * AROWB + ((lane >> 4) & 1) * 16;
        #pragma unroll
        for (int ks = 0; ks < 4; ks++) {
            #pragma unroll
            for (int nd = 0; nd < 4; nd++) {
                uint32_t r0, r1, r2, r3;
                ldmx4t(vbse + v_off + (uint32_t)ks * (16 * AROWB) + nd * 32, r0, r1, r2, r3);
                mma16816(ctx[nd * 2],     pa[2 * ks], pb[2 * ks], pa[2 * ks + 1], pb[2 * ks + 1], r0, r1);
                mma16816(ctx[nd * 2 + 1], pa[2 * ks], pb[2 * ks], pa[2 * ks + 1], pb[2 * ks + 1], r2, r3);
            }
        }
        __syncthreads();
    }

    l0 += __shfl_xor_sync(0xffffffffu, l0, 1);
    l0 += __shfl_xor_sync(0xffffffffu, l0, 2);
    l1 += __shfl_xor_sync(0xffffffffu, l1, 1);
    l1 += __shfl_xor_sync(0xffffffffu, l1, 2);
    float i0 = 1.f / l0, i1 = 1.f / l1;

    int tr = lane >> 2, tc = (lane & 3) * 2;
    int row0 = q0 + wid * 16 + tr;
    #pragma unroll
    for (int f = 0; f < 8; f++) {
        int d = f * 8 + tc;
        float* c = ctx[f];
        size_t o0 = ((size_t)b * SEQ + row0) * DIM + (size_t)h * HDIM + d;
        size_t o1 = ((size_t)b * SEQ + row0 + 8) * DIM + (size_t)h * HDIM + d;
        __half2 h0 = __floats2half2_rn(c[0] * i0, c[1] * i0);
        __half2 h1 = __floats2half2_rn(c[2] * i1, c[3] * i1);
        *(__half2*)(O16 + o0) = h0;
        *(__half2*)(O16 + o1) = h1;
    }
}

// ---------------- launch ----------------
extern "C" void kernel_launch(void* const* d_in, const int* in_sizes, int n_in,
                              void* d_out, int out_size) {
    const float* x_in   = (const float*)d_in[0];
    const float* Wq     = (const float*)d_in[1];
    const float* Wk     = (const float*)d_in[2];
    const float* Wv     = (const float*)d_in[3];
    const float* Wo     = (const float*)d_in[4];
    const float* ln1_w  = (const float*)d_in[5];
    const float* ln2_w  = (const float*)d_in[6];
    const float* Wgate  = (const float*)d_in[7];
    const float* Wup    = (const float*)d_in[8];
    const float* Wdown  = (const float*)d_in[9];
    const float* W_out  = (const float*)d_in[10];
    const float* b_out  = (const float*)d_in[11];
    float* out = (float*)d_out;

    float *x, *qkv;
    __half *h16, *c16, *f116, *x16, *whi, *wlo;
    __nv_bfloat16 *qhi, *qlo, *khi, *klo, *vbp;
    cudaGetSymbolAddress((void**)&x,    g_x);
    cudaGetSymbolAddress((void**)&qkv,  g_qkv);
    cudaGetSymbolAddress((void**)&h16,  g_h16);
    cudaGetSymbolAddress((void**)&c16,  g_c16);
    cudaGetSymbolAddress((void**)&f116, g_f116);
    cudaGetSymbolAddress((void**)&x16,  g_x16);
    cudaGetSymbolAddress((void**)&whi,  g_whi);
    cudaGetSymbolAddress((void**)&wlo,  g_wlo);
    cudaGetSymbolAddress((void**)&qhi,  g_qhi);
    cudaGetSymbolAddress((void**)&qlo,  g_qlo);
    cudaGetSymbolAddress((void**)&khi,  g_khi);
    cudaGetSymbolAddress((void**)&klo,  g_klo);
    cudaGetSymbolAddress((void**)&vbp,  g_vb);

    cudaFuncSetAttribute(gemm_s,   cudaFuncAttributeMaxDynamicSharedMemorySize, SMEM2);
    cudaFuncSetAttribute(attn_mma, cudaFuncAttributeMaxDynamicSharedMemorySize, ASMEM);

    // --- weight converts (fp32 -> fp16; lo only for W_out; gate/up interleaved)
    const int DD4 = DIM * DIM / 4, FD4 = FFDIM * DIM / 4;
    wcvt_kernel<<<DD4 / 256, 256>>>(Wq,    whi + WOFF_Q, nullptr, DD4);
    wcvt_kernel<<<DD4 / 256, 256>>>(Wk,    whi + WOFF_K, nullptr, DD4);
    wcvt_kernel<<<DD4 / 256, 256>>>(Wv,    whi + WOFF_V, nullptr, DD4);
    wcvt_kernel<<<DD4 / 256, 256>>>(Wo,    whi + WOFF_O, nullptr, DD4);
    wcvt_gu_kernel<<<FD4 / 256, 256>>>(Wgate, Wup, whi + WOFF_GU, FD4);
    wcvt_kernel<<<FD4 / 256, 256>>>(Wdown, whi + WOFF_D, nullptr, FD4);
    wcvt_kernel<<<DD4 / 256, 256>>>(W_out, whi + WOFF_H, wlo, DD4);

    // --- attention block ---
    rmsnorm_kernel<<<ROWS, 256>>>(x_in, ln1_w, h16);

    // fused QKV GEMM: [8192,1024] @ [3072,1024]^T -> [8192,3072]
    dim3 gqkv(3 * DIM / SBN, ROWS / SBM);   // (24, 64)
    gemm_s<<<gqkv, 256, SMEM2>>>(h16, whi + WOFF_Q, nullptr,
                                 nullptr, nullptr,
                                 qkv, nullptr, nullptr, ROWS, 3 * DIM, DIM);

    int rope_total = BATCH * SEQ * NHEAD * (HDIM / 2);
    rope_v_cvt_kernel<<<(rope_total + 255) / 256, 256>>>(qkv, qhi, qlo, khi, klo, vbp);

    dim3 ga(SEQ / 64, NHEAD, BATCH);
    attn_mma<<<ga, 128, ASMEM>>>(qhi, qlo, khi, klo, vbp, c16);

    dim3 g1(DIM / SBN, ROWS / SBM);    // (8, 64)
    // x = x_in + ctx @ Wo^T -> g_x (fp32)
    gemm_s<<<g1, 256, SMEM2>>>(c16, whi + WOFF_O, nullptr,
                               x_in, nullptr,
                               x, nullptr, nullptr, ROWS, DIM, DIM);

    // --- MLP block ---
    rmsnorm_kernel<<<ROWS, 256>>>(x, ln2_w, h16);
    // fused gate+up GEMM: N=8192 interleaved, silu epilogue -> f116 [8192,4096]
    dim3 ggu(2 * FFDIM / SBN, ROWS / SBM); // (64, 64)
    gemm_s<<<ggu, 256, SMEM2>>>(h16, whi + WOFF_GU, nullptr,
                                nullptr, nullptr,
                                nullptr, nullptr, f116, ROWS, 2 * FFDIM, DIM);

    // x_new = x + f1 @ Wdown^T -> fp16 (feeds head GEMM)
    gemm_s<<<g1, 256, SMEM2>>>(f116, whi + WOFF_D, nullptr,
                               x, nullptr,
                               nullptr, x16, nullptr, ROWS, DIM, FFDIM);

    // --- output head (2-term: W_out hi+lo) ---
    gemm_s<<<g1, 256, SMEM2>>>(x16, whi + WOFF_H, wlo,
                               nullptr, b_out,
                               out, nullptr, nullptr, ROWS, DIM, DIM);
}

// round 14
// speedup vs baseline: 7.6474x; 1.0238x over previous
#include <cuda_runtime.h>
#include <cuda_bf16.h>
#include <cuda_fp16.h>
#include <cstdint>

// Problem constants
#define BATCH 4
#define SEQ   2048
#define DIM   1024
#define NHEAD 16
#define HDIM  64
#define FFDIM 4096
#define ROWS  (BATCH * SEQ)            // 8192
#define LN_EPS 1e-6f

// ---------------- scratch (device globals; no allocation) ----------------
__device__ float g_x  [(size_t)ROWS * DIM];
__device__ float g_qkv[(size_t)ROWS * 3 * DIM];
// fp16 single activation operands (GEMM A inputs)
__device__ __half g_h16 [(size_t)ROWS * DIM];
__device__ __half g_c16 [(size_t)ROWS * DIM];
__device__ __half g_f116[(size_t)ROWS * FFDIM];
__device__ __half g_x16 [(size_t)ROWS * DIM];
// fp16 weights hi (all) + lo (head only)
// layout: Wq|Wk|Wv|Wo|WgateUp(interleaved 8192 rows)|Wdown|W_out
#define WOFF_Q  0
#define WOFF_K  1048576
#define WOFF_V  2097152
#define WOFF_O  3145728
#define WOFF_GU 4194304           // 8192 rows x 1024 (gate/up interleaved)
#define WOFF_D  12582912
#define WOFF_H  16777216
#define WTOT    17825792
__device__ __half g_whi[(size_t)WTOT];
__device__ __half g_wlo[(size_t)(DIM * DIM)];   // lo only for W_out
// fp16 attention operands, [B,H,S,HD] layout
__device__ __half g_q16a[(size_t)ROWS * DIM];
__device__ __half g_khi [(size_t)ROWS * DIM];
__device__ __half g_klo [(size_t)ROWS * DIM];
__device__ __half g_v16 [(size_t)ROWS * DIM];

__device__ __forceinline__ uint32_t smem_u32(const void* p) {
    uint32_t a;
    asm("{ .reg .u64 t; cvta.to.shared.u64 t, %1; cvt.u32.u64 %0, t; }"
        : "=r"(a) : "l"(p));
    return a;
}
__device__ __forceinline__ void ldmx4(uint32_t addr, uint32_t& r0, uint32_t& r1,
                                      uint32_t& r2, uint32_t& r3) {
    asm volatile("ldmatrix.sync.aligned.m8n8.x4.shared.b16 {%0,%1,%2,%3}, [%4];"
                 : "=r"(r0), "=r"(r1), "=r"(r2), "=r"(r3) : "r"(addr));
}
__device__ __forceinline__ void ldmx4t(uint32_t addr, uint32_t& r0, uint32_t& r1,
                                       uint32_t& r2, uint32_t& r3) {
    asm volatile("ldmatrix.sync.aligned.m8n8.x4.trans.shared.b16 {%0,%1,%2,%3}, [%4];"
                 : "=r"(r0), "=r"(r1), "=r"(r2), "=r"(r3) : "r"(addr));
}
// fp16 MMA
__device__ __forceinline__ void mma16816h(float* c, uint32_t a0, uint32_t a1,
                                          uint32_t a2, uint32_t a3,
                                          uint32_t b0, uint32_t b1) {
    asm volatile(
        "mma.sync.aligned.m16n8k16.row.col.f32.f16.f16.f32 "
        "{%0,%1,%2,%3}, {%4,%5,%6,%7}, {%8,%9}, {%0,%1,%2,%3};"
        : "+f"(c[0]), "+f"(c[1]), "+f"(c[2]), "+f"(c[3])
        : "r"(a0), "r"(a1), "r"(a2), "r"(a3), "r"(b0), "r"(b1));
}
__device__ __forceinline__ float ex2f(float x) {
    float r;
    asm("ex2.approx.f32 %0, %1;" : "=f"(r) : "f"(x));
    return r;
}
#define CPA16(dst, src) \
    asm volatile("cp.async.cg.shared.global [%0], [%1], 16;" :: "r"(dst), "l"(src))
#define CPA_COMMIT() asm volatile("cp.async.commit_group;" ::: "memory")
#define CPA_WAIT(n)  asm volatile("cp.async.wait_group %0;" :: "n"(n) : "memory")

// ---- merged weight convert: all weights in ONE launch (block-segmented) ---
// blocks: [0,1024) Wq | [1024,2048) Wk | [2048,3072) Wv | [3072,4096) Wo |
//         [4096,8192) GU interleave | [8192,12288) Wdown | [12288,13312) W_out(+lo)
__global__ void wcvt_all(const float* __restrict__ Wq, const float* __restrict__ Wk,
                         const float* __restrict__ Wv, const float* __restrict__ Wo,
                         const float* __restrict__ Wg, const float* __restrict__ Wu,
                         const float* __restrict__ Wd, const float* __restrict__ Wh,
                         __half* __restrict__ whi, __half* __restrict__ wlo) {
    int blk = blockIdx.x;
    int tid = threadIdx.x;
    if (blk < 4096) {                       // Q,K,V,O
        int seg = blk >> 10;
        int t = (blk & 1023) * 256 + tid;
        const float* src = (seg == 0) ? Wq : (seg == 1) ? Wk : (seg == 2) ? Wv : Wo;
        __half* dst = whi + (size_t)seg * 1048576;
        float4 v = *(const float4*)(src + (size_t)t * 4);
        __half2 h0 = __floats2half2_rn(v.x, v.y), h1 = __floats2half2_rn(v.z, v.w);
        uint2 o = { *(uint32_t*)&h0, *(uint32_t*)&h1 };
        *(uint2*)(dst + (size_t)t * 4) = o;
    } else if (blk < 8192) {                // gate/up interleaved
        int t = (blk - 4096) * 256 + tid;
        int r = t >> 8, c4 = t & 255;
        float4 vg = *(const float4*)(Wg + (size_t)t * 4);
        float4 vu = *(const float4*)(Wu + (size_t)t * 4);
        __half2 g0 = __floats2half2_rn(vg.x, vg.y), g1 = __floats2half2_rn(vg.z, vg.w);
        __half2 u0 = __floats2half2_rn(vu.x, vu.y), u1 = __floats2half2_rn(vu.z, vu.w);
        uint2 go = { *(uint32_t*)&g0, *(uint32_t*)&g1 };
        uint2 uo = { *(uint32_t*)&u0, *(uint32_t*)&u1 };
        *(uint2*)(whi + WOFF_GU + (size_t)(2 * r) * DIM + c4 * 4)     = go;
        *(uint2*)(whi + WOFF_GU + (size_t)(2 * r + 1) * DIM + c4 * 4) = uo;
    } else if (blk < 12288) {               // Wdown
        int t = (blk - 8192) * 256 + tid;
        float4 v = *(const float4*)(Wd + (size_t)t * 4);
        __half2 h0 = __floats2half2_rn(v.x, v.y), h1 = __floats2half2_rn(v.z, v.w);
        uint2 o = { *(uint32_t*)&h0, *(uint32_t*)&h1 };
        *(uint2*)(whi + WOFF_D + (size_t)t * 4) = o;
    } else {                                // W_out hi + lo
        int t = (blk - 12288) * 256 + tid;
        float4 v = *(const float4*)(Wh + (size_t)t * 4);
        __half h0 = __float2half_rn(v.x), h1 = __float2half_rn(v.y);
        __half h2 = __float2half_rn(v.z), h3 = __float2half_rn(v.w);
        __half2 hp0 = __halves2half2(h0, h1), hp1 = __halves2half2(h2, h3);
        uint2 ho = { *(uint32_t*)&hp0, *(uint32_t*)&hp1 };
        *(uint2*)(whi + WOFF_H + (size_t)t * 4) = ho;
        __half l0 = __float2half_rn(v.x - __half2float(h0));
        __half l1 = __float2half_rn(v.y - __half2float(h1));
        __half l2 = __float2half_rn(v.z - __half2float(h2));
        __half l3 = __float2half_rn(v.w - __half2float(h3));
        __half2 lp0 = __halves2half2(l0, l1), lp1 = __halves2half2(l2, l3);
        uint2 lw = { *(uint32_t*)&lp0, *(uint32_t*)&lp1 };
        *(uint2*)(wlo + (size_t)t * 4) = lw;
    }
}

// ================= gemm_s: fp16 GEMM (1 or 2 weight terms) =================
// Tile 128x128, BK=64, 2-stage cp.async, SW64 swizzle, single sync, 2 CTAs/SM.
#define SBM 128
#define SBN 128
#define SBK 64
#define S_WHI 16384
#define S_WLO 32768
#define SSTG  49152
#define SMEM2 (2 * SSTG)       // 98304 -> 2 CTAs/SM

__global__ __launch_bounds__(256, 2)
void gemm_s(const __half* __restrict__ A,
            const __half* __restrict__ Whi, const __half* __restrict__ Wlo,
            const float* __restrict__ res, const float* __restrict__ bias,
            float* __restrict__ C, __half* __restrict__ C16,
            __half* __restrict__ GU,
            int M, int N, int K) {
    extern __shared__ char smem[];
    uint32_t sb = smem_u32(smem);
    int tid = threadIdx.x, wid = tid >> 5, lane = tid & 31;
    int bm = blockIdx.y * SBM, bn = blockIdx.x * SBN;
    int warp_m = (wid >> 2) * 64, warp_n = (wid & 3) * 32;
    const bool has_lo = (Wlo != nullptr);

    uint32_t strow = (uint32_t)(tid >> 2);
    uint32_t stc   = (uint32_t)(tid & 3) * 16;
    uint32_t st_off = strow * 64 + (stc ^ (((strow >> 1) & 3u) << 4));
    const __half* Ap = A   + (size_t)(bm + strow) * K + (tid & 3) * 8;
    const __half* Wh = Whi + (size_t)(bn + strow) * K + (tid & 3) * 8;
    const __half* Wl = has_lo ? (Wlo + (size_t)(bn + strow) * K + (tid & 3) * 8) : nullptr;

    auto load_stage = [&](int s, int chunk) {
        uint32_t base = sb + (uint32_t)s * SSTG;
        size_t ko = (size_t)chunk * SBK;
        #pragma unroll
        for (int sub = 0; sub < 2; sub++) {
            #pragma unroll
            for (int j = 0; j < 2; j++) {
                uint32_t d = base + sub * 8192 + st_off + j * 4096;
                size_t ro = (size_t)j * 64 * K + ko + sub * 32;
                CPA16(d,         (const char*)(Ap + ro));
                CPA16(d + S_WHI, (const char*)(Wh + ro));
                if (has_lo) CPA16(d + S_WLO, (const char*)(Wl + ro));
            }
        }
    };

    int ra = warp_m + (lane & 15);
    uint32_t a_row = (uint32_t)ra * 64;
    uint32_t swa = (((uint32_t)ra >> 1) & 3u) << 4;
    int rb = warp_n + (lane & 7) + ((lane >> 4) & 1) * 8;
    uint32_t b_row = (uint32_t)rb * 64;
    uint32_t swb = (((uint32_t)rb >> 1) & 3u) << 4;
    uint32_t col_a[2], col_b[2];
    int ha = ((lane >> 4) & 1) * 16;
    int hb = ((lane >> 3) & 1) * 16;
    #pragma unroll
    for (int ks = 0; ks < 2; ks++) {
        col_a[ks] = ((uint32_t)(ks * 32 + ha)) ^ swa;
        col_b[ks] = ((uint32_t)(ks * 32 + hb)) ^ swb;
    }

    float acc[4][4][4];
    #pragma unroll
    for (int i = 0; i < 4; i++)
        #pragma unroll
        for (int j = 0; j < 4; j++)
            #pragma unroll
            for (int r = 0; r < 4; r++) acc[i][j][r] = 0.f;

    const int nk = K / SBK;
    load_stage(0, 0);
    CPA_COMMIT();

    for (int i = 0; i < nk; i++) {
        CPA_WAIT(0);
        __syncthreads();
        if (i + 1 < nk) {
            load_stage((i + 1) & 1, i + 1);
            CPA_COMMIT();
        }

        uint32_t base = sb + (uint32_t)(i & 1) * SSTG;
        #pragma unroll
        for (int ks = 0; ks < 4; ks++) {
            uint32_t soff = (uint32_t)(ks >> 1) * 8192;
            uint32_t ca = col_a[ks & 1], cb = col_b[ks & 1];
            uint32_t bhr[2][4];
            #pragma unroll
            for (int np = 0; np < 2; np++) {
                uint32_t bd = base + S_WHI + soff + b_row + (uint32_t)np * 1024 + cb;
                ldmx4(bd, bhr[np][0], bhr[np][1], bhr[np][2], bhr[np][3]);
            }
            uint32_t ar[4][4];
            #pragma unroll
            for (int mf = 0; mf < 4; mf++) {
                uint32_t ad = base + soff + a_row + (uint32_t)mf * 1024 + ca;
                ldmx4(ad, ar[mf][0], ar[mf][1], ar[mf][2], ar[mf][3]);
            }
            #pragma unroll
            for (int mf = 0; mf < 4; mf++)
                #pragma unroll
                for (int nf = 0; nf < 4; nf++)
                    mma16816h(acc[mf][nf],
                              ar[mf][0], ar[mf][1], ar[mf][2], ar[mf][3],
                              bhr[nf >> 1][(nf & 1) * 2], bhr[nf >> 1][(nf & 1) * 2 + 1]);
            if (has_lo) {
                uint32_t blr[2][4];
                #pragma unroll
                for (int np = 0; np < 2; np++) {
                    uint32_t bd = base + S_WLO + soff + b_row + (uint32_t)np * 1024 + cb;
                    ldmx4(bd, blr[np][0], blr[np][1], blr[np][2], blr[np][3]);
                }
                #pragma unroll
                for (int mf = 0; mf < 4; mf++)
                    #pragma unroll
                    for (int nf = 0; nf < 4; nf++)
                        mma16816h(acc[mf][nf],
                                  ar[mf][0], ar[mf][1], ar[mf][2], ar[mf][3],
                                  blr[nf >> 1][(nf & 1) * 2], blr[nf >> 1][(nf & 1) * 2 + 1]);
            }
        }
    }

    // ---- epilogue ----
    int tr = lane >> 2, tc = (lane & 3) * 2;
    #pragma unroll
    for (int mf = 0; mf < 4; mf++) {
        #pragma unroll
        for (int nf = 0; nf < 4; nf++) {
            int row0 = bm + warp_m + mf * 16 + tr;
            int col  = bn + warp_n + nf * 8 + tc;
            float* c = acc[mf][nf];
            float v[4] = {c[0], c[1], c[2], c[3]};
            size_t o0 = (size_t)row0 * N + col;
            size_t o1 = (size_t)(row0 + 8) * N + col;
            if (GU) {
                float r0 = v[1] * (v[0] / (1.f + expf(-v[0])));
                float r1 = v[3] * (v[2] / (1.f + expf(-v[2])));
                size_t p0 = (size_t)row0 * (N / 2) + (col >> 1);
                size_t p1 = (size_t)(row0 + 8) * (N / 2) + (col >> 1);
                GU[p0] = __float2half_rn(r0);
                GU[p1] = __float2half_rn(r1);
                continue;
            }
            if (res) {
                float2 r0 = *(const float2*)(res + o0);
                float2 r1 = *(const float2*)(res + o1);
                v[0] += r0.x; v[1] += r0.y; v[2] += r1.x; v[3] += r1.y;
            }
            if (bias) {
                float2 bb = *(const float2*)(bias + col);
                v[0] += bb.x; v[1] += bb.y; v[2] += bb.x; v[3] += bb.y;
            }
            if (C) {
                *(float2*)(C + o0) = {v[0], v[1]};
                *(float2*)(C + o1) = {v[2], v[3]};
            }
            if (C16) {
                __half2 h0 = __floats2half2_rn(v[0], v[1]);
                __half2 h1 = __floats2half2_rn(v[2], v[3]);
                *(__half2*)(C16 + o0) = h0;
                *(__half2*)(C16 + o1) = h1;
            }
        }
    }
}

// ---------------- RMSNorm -> fp16 ----------------
__global__ void rmsnorm_kernel(const float* __restrict__ x,
                               const float* __restrict__ w,
                               __half* __restrict__ o16) {
    int row = blockIdx.x;
    const float* xr = x + (size_t)row * DIM;
    float s = 0.f;
    #pragma unroll
    for (int i = threadIdx.x; i < DIM; i += 256) {
        float v = xr[i];
        s += v * v;
    }
    __shared__ float red[8];
    #pragma unroll
    for (int o = 16; o; o >>= 1) s += __shfl_down_sync(0xffffffffu, s, o);
    if ((threadIdx.x & 31) == 0) red[threadIdx.x >> 5] = s;
    __syncthreads();
    if (threadIdx.x < 8) {
        float t = red[threadIdx.x];
        #pragma unroll
        for (int o = 4; o; o >>= 1) t += __shfl_down_sync(0xffu, t, o);
        if (threadIdx.x == 0) red[0] = t;
    }
    __syncthreads();
    float inv = rsqrtf(red[0] * (1.0f / DIM) + LN_EPS);
    #pragma unroll
    for (int i = threadIdx.x; i < DIM; i += 256) {
        float v = xr[i] * inv * w[i];
        o16[(size_t)row * DIM + i] = __float2half_rn(v);
    }
}

// ------ RoPE + V convert on qkv [rows,3072] -> fp16 [B,H,S,HD] -------------
#define QSCALE 0.18033688011111793f   // 0.125 * log2(e)
__global__ void rope_v_cvt_kernel(const float* __restrict__ QKV,
                                  __half* __restrict__ q16,
                                  __half* __restrict__ khi, __half* __restrict__ klo,
                                  __half* __restrict__ v16) {
    int idx = blockIdx.x * 256 + threadIdx.x;
    if (idx >= BATCH * SEQ * NHEAD * (HDIM / 2)) return;
    int d = idx & 31;
    int h = (idx >> 5) & (NHEAD - 1);
    int s = (idx >> 9) & (SEQ - 1);
    int b = idx >> 20;
    size_t ibase = ((size_t)b * SEQ + s) * (3 * DIM) + (size_t)h * HDIM;
    size_t obase = (((size_t)b * NHEAD + h) * SEQ + s) * HDIM;
    float inv = expf(-(float)d * (9.210340371976184f / 32.f));
    float ang = (float)s * inv;
    float sn, cs;
    sincosf(ang, &sn, &cs);
    {
        float x1 = QKV[ibase + d], x2 = QKV[ibase + d + 32];
        float r1 = (x1 * cs - x2 * sn) * QSCALE;
        float r2 = (x2 * cs + x1 * sn) * QSCALE;
        q16[obase + d]      = __float2half_rn(r1);
        q16[obase + d + 32] = __float2half_rn(r2);
    }
    {
        float x1 = QKV[ibase + DIM + d], x2 = QKV[ibase + DIM + d + 32];
        float r1 = x1 * cs - x2 * sn;
        float r2 = x2 * cs + x1 * sn;
        __half h1 = __float2half_rn(r1);
        __half h2 = __float2half_rn(r2);
        khi[obase + d]      = h1;
        khi[obase + d + 32] = h2;
        klo[obase + d]      = __float2half_rn(r1 - __half2float(h1));
        klo[obase + d + 32] = __float2half_rn(r2 - __half2float(h2));
    }
    {
        float v1 = QKV[ibase + 2 * DIM + d], v2 = QKV[ibase + 2 * DIM + d + 32];
        v16[obase + d]      = __float2half_rn(v1);
        v16[obase + d + 32] = __float2half_rn(v2);
    }
}

// ============ MMA flash attention (fp16: q single, K hi/lo, PV fp16) =======
#define AROWB 144
#define A_Q   0                 // 9216
#define A_K0  9216              // stage stride 18432 (hi | lo at +9216)
#define A_V0  46080             // stage stride 9216
#define ASMEM 64512

__global__ __launch_bounds__(128)
void attn_mma(const __half* __restrict__ q16,
              const __half* __restrict__ khi, const __half* __restrict__ klo,
              const __half* __restrict__ v16,
              __half* __restrict__ O16) {
    extern __shared__ char smem[];
    uint32_t sb = smem_u32(smem);
    int tid = threadIdx.x, wid = tid >> 5, lane = tid & 31;
    int b = blockIdx.z, h = blockIdx.y;
    int q0 = blockIdx.x * 64;
    size_t hoff = ((size_t)b * NHEAD + h) * SEQ * HDIM;

    {
        const uint4* q4 = (const uint4*)(q16 + hoff + (size_t)q0 * HDIM);
        #pragma unroll
        for (int j = 0; j < 4; j++) {
            int f = tid + j * 128;
            int r = f >> 3, c = f & 7;
            *(uint4*)(smem + A_Q + r * AROWB + c * 16) = q4[r * 8 + c];
        }
    }
    __syncthreads();

    uint32_t qf[4][4];
    {
        uint32_t a_base = sb + (uint32_t)(wid * 16 + (lane & 15)) * AROWB + ((lane >> 4) & 1) * 16;
        #pragma unroll
        for (int ks = 0; ks < 4; ks++)
            ldmx4(a_base + ks * 32, qf[ks][0], qf[ks][1], qf[ks][2], qf[ks][3]);
    }

    float ctx[8][4];
    #pragma unroll
    for (int j = 0; j < 8; j++)
        #pragma unroll
        for (int r = 0; r < 4; r++) ctx[j][r] = 0.f;
    float m0 = -1e30f, m1 = -1e30f, l0 = 0.f, l1 = 0.f;

    const __half* kh_g = khi + hoff;
    const __half* kl_g = klo + hoff;
    const __half* v_g  = v16 + hoff;

    {
        #pragma unroll
        for (int j = 0; j < 4; j++) {
            int f = tid + j * 128;
            int r = f >> 3, c = f & 7;
            uint32_t so = (uint32_t)(r * AROWB + c * 16);
            CPA16(sb + A_K0 + so,        (const char*)(kh_g + r * 64 + c * 8));
            CPA16(sb + A_K0 + 9216 + so, (const char*)(kl_g + r * 64 + c * 8));
            CPA16(sb + A_V0 + so,        (const char*)(v_g  + r * 64 + c * 8));
        }
        CPA_COMMIT();
    }

    const int NT = SEQ / 64;
    for (int t = 0; t < NT; t++) {
        int s = t & 1;
        if (t + 1 < NT) {
            int nxt = s ^ 1;
            size_t goff = (size_t)(t + 1) * 64 * 64;
            #pragma unroll
            for (int j = 0; j < 4; j++) {
                int f = tid + j * 128;
                int r = f >> 3, c = f & 7;
                uint32_t so = (uint32_t)(r * AROWB + c * 16);
                CPA16(sb + A_K0 + nxt * 18432 + so,        (const char*)(kh_g + goff + r * 64 + c * 8));
                CPA16(sb + A_K0 + nxt * 18432 + 9216 + so, (const char*)(kl_g + goff + r * 64 + c * 8));
                CPA16(sb + A_V0 + nxt * 9216 + so,         (const char*)(v_g  + goff + r * 64 + c * 8));
            }
            CPA_COMMIT();
            CPA_WAIT(1);
        } else {
            CPA_WAIT(0);
        }
        __syncthreads();

        uint32_t kb_hi = sb + A_K0 + s * 18432;
        uint32_t kb_lo = kb_hi + 9216;
        uint32_t vbse  = sb + A_V0 + s * 9216;

        float sc[8][4];
        #pragma unroll
        for (int j = 0; j < 8; j++)
            #pragma unroll
            for (int r = 0; r < 4; r++) sc[j][r] = 0.f;

        uint32_t b_off = (uint32_t)((lane & 7) + ((lane >> 4) & 1) * 8) * AROWB +
                         ((lane >> 3) & 1) * 16;
        #pragma unroll
        for (int ks = 0; ks < 4; ks++) {
            #pragma unroll
            for (int ng = 0; ng < 4; ng++) {
                uint32_t bh0, bh1, bh2, bh3, bl0, bl1, bl2, bl3;
                uint32_t ad = b_off + (uint32_t)ng * (16 * AROWB) + ks * 32;
                ldmx4(kb_hi + ad, bh0, bh1, bh2, bh3);
                ldmx4(kb_lo + ad, bl0, bl1, bl2, bl3);
                mma16816h(sc[2 * ng],     qf[ks][0], qf[ks][1], qf[ks][2], qf[ks][3], bh0, bh1);
                mma16816h(sc[2 * ng + 1], qf[ks][0], qf[ks][1], qf[ks][2], qf[ks][3], bh2, bh3);
                mma16816h(sc[2 * ng],     qf[ks][0], qf[ks][1], qf[ks][2], qf[ks][3], bl0, bl1);
                mma16816h(sc[2 * ng + 1], qf[ks][0], qf[ks][1], qf[ks][2], qf[ks][3], bl2, bl3);
            }
        }

        float mn0 = m0, mn1 = m1;
        #pragma unroll
        for (int j = 0; j < 8; j++) {
            mn0 = fmaxf(mn0, fmaxf(sc[j][0], sc[j][1]));
            mn1 = fmaxf(mn1, fmaxf(sc[j][2], sc[j][3]));
        }
        mn0 = fmaxf(mn0, __shfl_xor_sync(0xffffffffu, mn0, 1));
        mn0 = fmaxf(mn0, __shfl_xor_sync(0xffffffffu, mn0, 2));
        mn1 = fmaxf(mn1, __shfl_xor_sync(0xffffffffu, mn1, 1));
        mn1 = fmaxf(mn1, __shfl_xor_sync(0xffffffffu, mn1, 2));
        float corr0 = ex2f(m0 - mn0);
        float corr1 = ex2f(m1 - mn1);
        m0 = mn0; m1 = mn1;
        l0 *= corr0; l1 *= corr1;
        #pragma unroll
        for (int j = 0; j < 8; j++) {
            ctx[j][0] *= corr0; ctx[j][1] *= corr0;
            ctx[j][2] *= corr1; ctx[j][3] *= corr1;
        }
        uint32_t pa[8], pb[8];
        #pragma unroll
        for (int j = 0; j < 8; j++) {
            float p0 = ex2f(sc[j][0] - mn0);
            float p1 = ex2f(sc[j][1] - mn0);
            float p2 = ex2f(sc[j][2] - mn1);
            float p3 = ex2f(sc[j][3] - mn1);
            l0 += p0 + p1; l1 += p2 + p3;
            __half2 t0 = __floats2half2_rn(p0, p1);
            __half2 t1 = __floats2half2_rn(p2, p3);
            pa[j] = *(uint32_t*)&t0;
            pb[j] = *(uint32_t*)&t1;
        }

        uint32_t v_off = (uint32_t)(lane & 15) * AROWB + ((lane >> 4) & 1) * 16;
        #pragma unroll
        for (int ks = 0; ks < 4; ks++) {
            #pragma unroll
            for (int nd = 0; nd < 4; nd++) {
                uint32_t r0, r1, r2, r3;
                ldmx4t(vbse + v_off + (uint32_t)ks * (16 * AROWB) + nd * 32, r0, r1, r2, r3);
                mma16816h(ctx[nd * 2],     pa[2 * ks], pb[2 * ks], pa[2 * ks + 1], pb[2 * ks + 1], r0, r1);
                mma16816h(ctx[nd * 2 + 1], pa[2 * ks], pb[2 * ks], pa[2 * ks + 1], pb[2 * ks + 1], r2, r3);
            }
        }
        __syncthreads();
    }

    l0 += __shfl_xor_sync(0xffffffffu, l0, 1);
    l0 += __shfl_xor_sync(0xffffffffu, l0, 2);
    l1 += __shfl_xor_sync(0xffffffffu, l1, 1);
    l1 += __shfl_xor_sync(0xffffffffu, l1, 2);
    float i0 = 1.f / l0, i1 = 1.f / l1;

    int tr = lane >> 2, tc = (lane & 3) * 2;
    int row0 = q0 + wid * 16 + tr;
    #pragma unroll
    for (int f = 0; f < 8; f++) {
        int d = f * 8 + tc;
        float* c = ctx[f];
        size_t o0 = ((size_t)b * SEQ + row0) * DIM + (size_t)h * HDIM + d;
        size_t o1 = ((size_t)b * SEQ + row0 + 8) * DIM + (size_t)h * HDIM + d;
        __half2 h0 = __floats2half2_rn(c[0] * i0, c[1] * i0);
        __half2 h1 = __floats2half2_rn(c[2] * i1, c[3] * i1);
        *(__half2*)(O16 + o0) = h0;
        *(__half2*)(O16 + o1) = h1;
    }
}

// ---------------- launch ----------------
extern "C" void kernel_launch(void* const* d_in, const int* in_sizes, int n_in,
                              void* d_out, int out_size) {
    const float* x_in   = (const float*)d_in[0];
    const float* Wq     = (const float*)d_in[1];
    const float* Wk     = (const float*)d_in[2];
    const float* Wv     = (const float*)d_in[3];
    const float* Wo     = (const float*)d_in[4];
    const float* ln1_w  = (const float*)d_in[5];
    const float* ln2_w  = (const float*)d_in[6];
    const float* Wgate  = (const float*)d_in[7];
    const float* Wup    = (const float*)d_in[8];
    const float* Wdown  = (const float*)d_in[9];
    const float* W_out  = (const float*)d_in[10];
    const float* b_out  = (const float*)d_in[11];
    float* out = (float*)d_out;

    float *x, *qkv;
    __half *h16, *c16, *f116, *x16, *whi, *wlo;
    __half *q16a, *khi, *klo, *v16;
    cudaGetSymbolAddress((void**)&x,    g_x);
    cudaGetSymbolAddress((void**)&qkv,  g_qkv);
    cudaGetSymbolAddress((void**)&h16,  g_h16);
    cudaGetSymbolAddress((void**)&c16,  g_c16);
    cudaGetSymbolAddress((void**)&f116, g_f116);
    cudaGetSymbolAddress((void**)&x16,  g_x16);
    cudaGetSymbolAddress((void**)&whi,  g_whi);
    cudaGetSymbolAddress((void**)&wlo,  g_wlo);
    cudaGetSymbolAddress((void**)&q16a, g_q16a);
    cudaGetSymbolAddress((void**)&khi,  g_khi);
    cudaGetSymbolAddress((void**)&klo,  g_klo);
    cudaGetSymbolAddress((void**)&v16,  g_v16);

    cudaFuncSetAttribute(gemm_s,   cudaFuncAttributeMaxDynamicSharedMemorySize, SMEM2);
    cudaFuncSetAttribute(attn_mma, cudaFuncAttributeMaxDynamicSharedMemorySize, ASMEM);

    // --- all weight converts in one launch ---
    wcvt_all<<<13312, 256>>>(Wq, Wk, Wv, Wo, Wgate, Wup, Wdown, W_out, whi, wlo);

    // --- attention block ---
    rmsnorm_kernel<<<ROWS, 256>>>(x_in, ln1_w, h16);

    dim3 gqkv(3 * DIM / SBN, ROWS / SBM);   // (24, 64)
    gemm_s<<<gqkv, 256, SMEM2>>>(h16, whi + WOFF_Q, nullptr,
                                 nullptr, nullptr,
                                 qkv, nullptr, nullptr, ROWS, 3 * DIM, DIM);

    int rope_total = BATCH * SEQ * NHEAD * (HDIM / 2);
    rope_v_cvt_kernel<<<(rope_total + 255) / 256, 256>>>(qkv, q16a, khi, klo, v16);

    dim3 ga(SEQ / 64, NHEAD, BATCH);
    attn_mma<<<ga, 128, ASMEM>>>(q16a, khi, klo, v16, c16);

    dim3 g1(DIM / SBN, ROWS / SBM);    // (8, 64)
    // x = x_in + ctx @ Wo^T -> g_x (fp32)
    gemm_s<<<g1, 256, SMEM2>>>(c16, whi + WOFF_O, nullptr,
                               x_in, nullptr,
                               x, nullptr, nullptr, ROWS, DIM, DIM);

    // --- MLP block ---
    rmsnorm_kernel<<<ROWS, 256>>>(x, ln2_w, h16);
    dim3 ggu(2 * FFDIM / SBN, ROWS / SBM); // (64, 64)
    gemm_s<<<ggu, 256, SMEM2>>>(h16, whi + WOFF_GU, nullptr,
                                nullptr, nullptr,
                                nullptr, nullptr, f116, ROWS, 2 * FFDIM, DIM);

    // x_new = x + f1 @ Wdown^T -> fp16 (feeds head GEMM)
    gemm_s<<<g1, 256, SMEM2>>>(f116, whi + WOFF_D, nullptr,
                               x, nullptr,
                               nullptr, x16, nullptr, ROWS, DIM, FFDIM);

    // --- output head (2-term: W_out hi+lo) ---
    gemm_s<<<g1, 256, SMEM2>>>(x16, whi + WOFF_H, wlo,
                               nullptr, b_out,
                               out, nullptr, nullptr, ROWS, DIM, DIM);
}

// round 15
// speedup vs baseline: 8.6662x; 1.1332x over previous
#include <cuda_runtime.h>
#include <cuda_bf16.h>
#include <cuda_fp16.h>
#include <cstdint>

// Problem constants
#define BATCH 4
#define SEQ   2048
#define DIM   1024
#define NHEAD 16
#define HDIM  64
#define FFDIM 4096
#define ROWS  (BATCH * SEQ)            // 8192
#define LN_EPS 1e-6f

// ---------------- scratch (device globals; no allocation) ----------------
__device__ float g_x  [(size_t)ROWS * DIM];
__device__ __half g_qkv16[(size_t)ROWS * 3 * DIM];
// fp16 single activation operands (GEMM A inputs)
__device__ __half g_h16 [(size_t)ROWS * DIM];
__device__ __half g_c16 [(size_t)ROWS * DIM];
__device__ __half g_f116[(size_t)ROWS * FFDIM];
__device__ __half g_x16 [(size_t)ROWS * DIM];
// fp16 weights hi (all) + lo (head only)
#define WOFF_Q  0
#define WOFF_K  1048576
#define WOFF_V  2097152
#define WOFF_O  3145728
#define WOFF_GU 4194304           // 8192 rows x 1024 (gate/up interleaved)
#define WOFF_D  12582912
#define WOFF_H  16777216
#define WTOT    17825792
__device__ __half g_whi[(size_t)WTOT];
__device__ __half g_wlo[(size_t)(DIM * DIM)];   // lo only for W_out
// fp16 attention operands, [B,H,S,HD] layout
__device__ __half g_q16a[(size_t)ROWS * DIM];
__device__ __half g_k16 [(size_t)ROWS * DIM];
__device__ __half g_v16 [(size_t)ROWS * DIM];

__device__ __forceinline__ uint32_t smem_u32(const void* p) {
    uint32_t a;
    asm("{ .reg .u64 t; cvta.to.shared.u64 t, %1; cvt.u32.u64 %0, t; }"
        : "=r"(a) : "l"(p));
    return a;
}
__device__ __forceinline__ void ldmx4(uint32_t addr, uint32_t& r0, uint32_t& r1,
                                      uint32_t& r2, uint32_t& r3) {
    asm volatile("ldmatrix.sync.aligned.m8n8.x4.shared.b16 {%0,%1,%2,%3}, [%4];"
                 : "=r"(r0), "=r"(r1), "=r"(r2), "=r"(r3) : "r"(addr));
}
__device__ __forceinline__ void ldmx4t(uint32_t addr, uint32_t& r0, uint32_t& r1,
                                       uint32_t& r2, uint32_t& r3) {
    asm volatile("ldmatrix.sync.aligned.m8n8.x4.trans.shared.b16 {%0,%1,%2,%3}, [%4];"
                 : "=r"(r0), "=r"(r1), "=r"(r2), "=r"(r3) : "r"(addr));
}
// fp16 MMA
__device__ __forceinline__ void mma16816h(float* c, uint32_t a0, uint32_t a1,
                                          uint32_t a2, uint32_t a3,
                                          uint32_t b0, uint32_t b1) {
    asm volatile(
        "mma.sync.aligned.m16n8k16.row.col.f32.f16.f16.f32 "
        "{%0,%1,%2,%3}, {%4,%5,%6,%7}, {%8,%9}, {%0,%1,%2,%3};"
        : "+f"(c[0]), "+f"(c[1]), "+f"(c[2]), "+f"(c[3])
        : "r"(a0), "r"(a1), "r"(a2), "r"(a3), "r"(b0), "r"(b1));
}
__device__ __forceinline__ float ex2f(float x) {
    float r;
    asm("ex2.approx.f32 %0, %1;" : "=f"(r) : "f"(x));
    return r;
}
#define CPA16(dst, src) \
    asm volatile("cp.async.cg.shared.global [%0], [%1], 16;" :: "r"(dst), "l"(src))
#define CPA_COMMIT() asm volatile("cp.async.commit_group;" ::: "memory")
#define CPA_WAIT(n)  asm volatile("cp.async.wait_group %0;" :: "n"(n) : "memory")

// ---- merged weight convert: all weights in ONE launch (block-segmented) ---
__global__ void wcvt_all(const float* __restrict__ Wq, const float* __restrict__ Wk,
                         const float* __restrict__ Wv, const float* __restrict__ Wo,
                         const float* __restrict__ Wg, const float* __restrict__ Wu,
                         const float* __restrict__ Wd, const float* __restrict__ Wh,
                         __half* __restrict__ whi, __half* __restrict__ wlo) {
    int blk = blockIdx.x;
    int tid = threadIdx.x;
    if (blk < 4096) {                       // Q,K,V,O
        int seg = blk >> 10;
        int t = (blk & 1023) * 256 + tid;
        const float* src = (seg == 0) ? Wq : (seg == 1) ? Wk : (seg == 2) ? Wv : Wo;
        __half* dst = whi + (size_t)seg * 1048576;
        float4 v = *(const float4*)(src + (size_t)t * 4);
        __half2 h0 = __floats2half2_rn(v.x, v.y), h1 = __floats2half2_rn(v.z, v.w);
        uint2 o = { *(uint32_t*)&h0, *(uint32_t*)&h1 };
        *(uint2*)(dst + (size_t)t * 4) = o;
    } else if (blk < 8192) {                // gate/up interleaved
        int t = (blk - 4096) * 256 + tid;
        int r = t >> 8, c4 = t & 255;
        float4 vg = *(const float4*)(Wg + (size_t)t * 4);
        float4 vu = *(const float4*)(Wu + (size_t)t * 4);
        __half2 g0 = __floats2half2_rn(vg.x, vg.y), g1 = __floats2half2_rn(vg.z, vg.w);
        __half2 u0 = __floats2half2_rn(vu.x, vu.y), u1 = __floats2half2_rn(vu.z, vu.w);
        uint2 go = { *(uint32_t*)&g0, *(uint32_t*)&g1 };
        uint2 uo = { *(uint32_t*)&u0, *(uint32_t*)&u1 };
        *(uint2*)(whi + WOFF_GU + (size_t)(2 * r) * DIM + c4 * 4)     = go;
        *(uint2*)(whi + WOFF_GU + (size_t)(2 * r + 1) * DIM + c4 * 4) = uo;
    } else if (blk < 12288) {               // Wdown
        int t = (blk - 8192) * 256 + tid;
        float4 v = *(const float4*)(Wd + (size_t)t * 4);
        __half2 h0 = __floats2half2_rn(v.x, v.y), h1 = __floats2half2_rn(v.z, v.w);
        uint2 o = { *(uint32_t*)&h0, *(uint32_t*)&h1 };
        *(uint2*)(whi + WOFF_D + (size_t)t * 4) = o;
    } else {                                // W_out hi + lo
        int t = (blk - 12288) * 256 + tid;
        float4 v = *(const float4*)(Wh + (size_t)t * 4);
        __half h0 = __float2half_rn(v.x), h1 = __float2half_rn(v.y);
        __half h2 = __float2half_rn(v.z), h3 = __float2half_rn(v.w);
        __half2 hp0 = __halves2half2(h0, h1), hp1 = __halves2half2(h2, h3);
        uint2 ho = { *(uint32_t*)&hp0, *(uint32_t*)&hp1 };
        *(uint2*)(whi + WOFF_H + (size_t)t * 4) = ho;
        __half l0 = __float2half_rn(v.x - __half2float(h0));
        __half l1 = __float2half_rn(v.y - __half2float(h1));
        __half l2 = __float2half_rn(v.z - __half2float(h2));
        __half l3 = __float2half_rn(v.w - __half2float(h3));
        __half2 lp0 = __halves2half2(l0, l1), lp1 = __halves2half2(l2, l3);
        uint2 lw = { *(uint32_t*)&lp0, *(uint32_t*)&lp1 };
        *(uint2*)(wlo + (size_t)t * 4) = lw;
    }
}

// ================= gemm_s: fp16 GEMM (1 or 2 weight terms) =================
// Tile 128x128, BK=64, 2-stage cp.async, SW64 swizzle, single sync, 2 CTAs/SM.
#define SBM 128
#define SBN 128
#define SBK 64
#define S_WHI 16384
#define S_WLO 32768
#define SSTG  49152
#define SMEM2 (2 * SSTG)       // 98304 -> 2 CTAs/SM

__global__ __launch_bounds__(256, 2)
void gemm_s(const __half* __restrict__ A,
            const __half* __restrict__ Whi, const __half* __restrict__ Wlo,
            const float* __restrict__ res, const float* __restrict__ bias,
            float* __restrict__ C, __half* __restrict__ C16,
            __half* __restrict__ GU,
            int M, int N, int K) {
    extern __shared__ char smem[];
    uint32_t sb = smem_u32(smem);
    int tid = threadIdx.x, wid = tid >> 5, lane = tid & 31;
    int bm = blockIdx.y * SBM, bn = blockIdx.x * SBN;
    int warp_m = (wid >> 2) * 64, warp_n = (wid & 3) * 32;
    const bool has_lo = (Wlo != nullptr);

    uint32_t strow = (uint32_t)(tid >> 2);
    uint32_t stc   = (uint32_t)(tid & 3) * 16;
    uint32_t st_off = strow * 64 + (stc ^ (((strow >> 1) & 3u) << 4));
    const __half* Ap = A   + (size_t)(bm + strow) * K + (tid & 3) * 8;
    const __half* Wh = Whi + (size_t)(bn + strow) * K + (tid & 3) * 8;
    const __half* Wl = has_lo ? (Wlo + (size_t)(bn + strow) * K + (tid & 3) * 8) : nullptr;

    auto load_stage = [&](int s, int chunk) {
        uint32_t base = sb + (uint32_t)s * SSTG;
        size_t ko = (size_t)chunk * SBK;
        #pragma unroll
        for (int sub = 0; sub < 2; sub++) {
            #pragma unroll
            for (int j = 0; j < 2; j++) {
                uint32_t d = base + sub * 8192 + st_off + j * 4096;
                size_t ro = (size_t)j * 64 * K + ko + sub * 32;
                CPA16(d,         (const char*)(Ap + ro));
                CPA16(d + S_WHI, (const char*)(Wh + ro));
                if (has_lo) CPA16(d + S_WLO, (const char*)(Wl + ro));
            }
        }
    };

    int ra = warp_m + (lane & 15);
    uint32_t a_row = (uint32_t)ra * 64;
    uint32_t swa = (((uint32_t)ra >> 1) & 3u) << 4;
    int rb = warp_n + (lane & 7) + ((lane >> 4) & 1) * 8;
    uint32_t b_row = (uint32_t)rb * 64;
    uint32_t swb = (((uint32_t)rb >> 1) & 3u) << 4;
    uint32_t col_a[2], col_b[2];
    int ha = ((lane >> 4) & 1) * 16;
    int hb = ((lane >> 3) & 1) * 16;
    #pragma unroll
    for (int ks = 0; ks < 2; ks++) {
        col_a[ks] = ((uint32_t)(ks * 32 + ha)) ^ swa;
        col_b[ks] = ((uint32_t)(ks * 32 + hb)) ^ swb;
    }

    float acc[4][4][4];
    #pragma unroll
    for (int i = 0; i < 4; i++)
        #pragma unroll
        for (int j = 0; j < 4; j++)
            #pragma unroll
            for (int r = 0; r < 4; r++) acc[i][j][r] = 0.f;

    const int nk = K / SBK;
    load_stage(0, 0);
    CPA_COMMIT();

    for (int i = 0; i < nk; i++) {
        CPA_WAIT(0);
        __syncthreads();
        if (i + 1 < nk) {
            load_stage((i + 1) & 1, i + 1);
            CPA_COMMIT();
        }

        uint32_t base = sb + (uint32_t)(i & 1) * SSTG;
        #pragma unroll
        for (int ks = 0; ks < 4; ks++) {
            uint32_t soff = (uint32_t)(ks >> 1) * 8192;
            uint32_t ca = col_a[ks & 1], cb = col_b[ks & 1];
            uint32_t bhr[2][4];
            #pragma unroll
            for (int np = 0; np < 2; np++) {
                uint32_t bd = base + S_WHI + soff + b_row + (uint32_t)np * 1024 + cb;
                ldmx4(bd, bhr[np][0], bhr[np][1], bhr[np][2], bhr[np][3]);
            }
            uint32_t ar[4][4];
            #pragma unroll
            for (int mf = 0; mf < 4; mf++) {
                uint32_t ad = base + soff + a_row + (uint32_t)mf * 1024 + ca;
                ldmx4(ad, ar[mf][0], ar[mf][1], ar[mf][2], ar[mf][3]);
            }
            #pragma unroll
            for (int mf = 0; mf < 4; mf++)
                #pragma unroll
                for (int nf = 0; nf < 4; nf++)
                    mma16816h(acc[mf][nf],
                              ar[mf][0], ar[mf][1], ar[mf][2], ar[mf][3],
                              bhr[nf >> 1][(nf & 1) * 2], bhr[nf >> 1][(nf & 1) * 2 + 1]);
            if (has_lo) {
                uint32_t blr[2][4];
                #pragma unroll
                for (int np = 0; np < 2; np++) {
                    uint32_t bd = base + S_WLO + soff + b_row + (uint32_t)np * 1024 + cb;
                    ldmx4(bd, blr[np][0], blr[np][1], blr[np][2], blr[np][3]);
                }
                #pragma unroll
                for (int mf = 0; mf < 4; mf++)
                    #pragma unroll
                    for (int nf = 0; nf < 4; nf++)
                        mma16816h(acc[mf][nf],
                                  ar[mf][0], ar[mf][1], ar[mf][2], ar[mf][3],
                                  blr[nf >> 1][(nf & 1) * 2], blr[nf >> 1][(nf & 1) * 2 + 1]);
            }
        }
    }

    // ---- epilogue ----
    int tr = lane >> 2, tc = (lane & 3) * 2;
    #pragma unroll
    for (int mf = 0; mf < 4; mf++) {
        #pragma unroll
        for (int nf = 0; nf < 4; nf++) {
            int row0 = bm + warp_m + mf * 16 + tr;
            int col  = bn + warp_n + nf * 8 + tc;
            float* c = acc[mf][nf];
            float v[4] = {c[0], c[1], c[2], c[3]};
            size_t o0 = (size_t)row0 * N + col;
            size_t o1 = (size_t)(row0 + 8) * N + col;
            if (GU) {
                float r0 = v[1] * (v[0] / (1.f + expf(-v[0])));
                float r1 = v[3] * (v[2] / (1.f + expf(-v[2])));
                size_t p0 = (size_t)row0 * (N / 2) + (col >> 1);
                size_t p1 = (size_t)(row0 + 8) * (N / 2) + (col >> 1);
                GU[p0] = __float2half_rn(r0);
                GU[p1] = __float2half_rn(r1);
                continue;
            }
            if (res) {
                float2 r0 = *(const float2*)(res + o0);
                float2 r1 = *(const float2*)(res + o1);
                v[0] += r0.x; v[1] += r0.y; v[2] += r1.x; v[3] += r1.y;
            }
            if (bias) {
                float2 bb = *(const float2*)(bias + col);
                v[0] += bb.x; v[1] += bb.y; v[2] += bb.x; v[3] += bb.y;
            }
            if (C) {
                *(float2*)(C + o0) = {v[0], v[1]};
                *(float2*)(C + o1) = {v[2], v[3]};
            }
            if (C16) {
                __half2 h0 = __floats2half2_rn(v[0], v[1]);
                __half2 h1 = __floats2half2_rn(v[2], v[3]);
                *(__half2*)(C16 + o0) = h0;
                *(__half2*)(C16 + o1) = h1;
            }
        }
    }
}

// ---------------- RMSNorm -> fp16 ----------------
__global__ void rmsnorm_kernel(const float* __restrict__ x,
                               const float* __restrict__ w,
                               __half* __restrict__ o16) {
    int row = blockIdx.x;
    const float* xr = x + (size_t)row * DIM;
    float s = 0.f;
    #pragma unroll
    for (int i = threadIdx.x; i < DIM; i += 256) {
        float v = xr[i];
        s += v * v;
    }
    __shared__ float red[8];
    #pragma unroll
    for (int o = 16; o; o >>= 1) s += __shfl_down_sync(0xffffffffu, s, o);
    if ((threadIdx.x & 31) == 0) red[threadIdx.x >> 5] = s;
    __syncthreads();
    if (threadIdx.x < 8) {
        float t = red[threadIdx.x];
        #pragma unroll
        for (int o = 4; o; o >>= 1) t += __shfl_down_sync(0xffu, t, o);
        if (threadIdx.x == 0) red[0] = t;
    }
    __syncthreads();
    float inv = rsqrtf(red[0] * (1.0f / DIM) + LN_EPS);
    #pragma unroll
    for (int i = threadIdx.x; i < DIM; i += 256) {
        float v = xr[i] * inv * w[i];
        o16[(size_t)row * DIM + i] = __float2half_rn(v);
    }
}

// ------ RoPE + V convert on fp16 qkv [rows,3072] -> fp16 [B,H,S,HD] --------
#define QSCALE 0.18033688011111793f   // 0.125 * log2(e)
__global__ void rope_v_cvt_kernel(const __half* __restrict__ QKV,
                                  __half* __restrict__ q16,
                                  __half* __restrict__ k16,
                                  __half* __restrict__ v16) {
    int idx = blockIdx.x * 256 + threadIdx.x;
    if (idx >= BATCH * SEQ * NHEAD * (HDIM / 2)) return;
    int d = idx & 31;
    int h = (idx >> 5) & (NHEAD - 1);
    int s = (idx >> 9) & (SEQ - 1);
    int b = idx >> 20;
    size_t ibase = ((size_t)b * SEQ + s) * (3 * DIM) + (size_t)h * HDIM;
    size_t obase = (((size_t)b * NHEAD + h) * SEQ + s) * HDIM;
    float inv = expf(-(float)d * (9.210340371976184f / 32.f));
    float ang = (float)s * inv;
    float sn, cs;
    sincosf(ang, &sn, &cs);
    {
        float x1 = __half2float(QKV[ibase + d]);
        float x2 = __half2float(QKV[ibase + d + 32]);
        float r1 = (x1 * cs - x2 * sn) * QSCALE;
        float r2 = (x2 * cs + x1 * sn) * QSCALE;
        q16[obase + d]      = __float2half_rn(r1);
        q16[obase + d + 32] = __float2half_rn(r2);
    }
    {
        float x1 = __half2float(QKV[ibase + DIM + d]);
        float x2 = __half2float(QKV[ibase + DIM + d + 32]);
        float r1 = x1 * cs - x2 * sn;
        float r2 = x2 * cs + x1 * sn;
        k16[obase + d]      = __float2half_rn(r1);
        k16[obase + d + 32] = __float2half_rn(r2);
    }
    {
        k16 += 0;  // no-op
        v16[obase + d]      = QKV[ibase + 2 * DIM + d];
        v16[obase + d + 32] = QKV[ibase + 2 * DIM + d + 32];
    }
}

// ============ MMA flash attention (all fp16, single-term QK) ===============
#define AROWB 144
#define A_Q   0                 // 9216
#define A_K0  9216              // stage stride 9216
#define A_V0  27648             // stage stride 9216
#define ASMEM 46080

__global__ __launch_bounds__(128)
void attn_mma(const __half* __restrict__ q16,
              const __half* __restrict__ k16,
              const __half* __restrict__ v16,
              __half* __restrict__ O16) {
    extern __shared__ char smem[];
    uint32_t sb = smem_u32(smem);
    int tid = threadIdx.x, wid = tid >> 5, lane = tid & 31;
    int b = blockIdx.z, h = blockIdx.y;
    int q0 = blockIdx.x * 64;
    size_t hoff = ((size_t)b * NHEAD + h) * SEQ * HDIM;

    {
        const uint4* q4 = (const uint4*)(q16 + hoff + (size_t)q0 * HDIM);
        #pragma unroll
        for (int j = 0; j < 4; j++) {
            int f = tid + j * 128;
            int r = f >> 3, c = f & 7;
            *(uint4*)(smem + A_Q + r * AROWB + c * 16) = q4[r * 8 + c];
        }
    }
    __syncthreads();

    uint32_t qf[4][4];
    {
        uint32_t a_base = sb + (uint32_t)(wid * 16 + (lane & 15)) * AROWB + ((lane >> 4) & 1) * 16;
        #pragma unroll
        for (int ks = 0; ks < 4; ks++)
            ldmx4(a_base + ks * 32, qf[ks][0], qf[ks][1], qf[ks][2], qf[ks][3]);
    }

    float ctx[8][4];
    #pragma unroll
    for (int j = 0; j < 8; j++)
        #pragma unroll
        for (int r = 0; r < 4; r++) ctx[j][r] = 0.f;
    float m0 = -1e30f, m1 = -1e30f, l0 = 0.f, l1 = 0.f;

    const __half* k_g = k16 + hoff;
    const __half* v_g = v16 + hoff;

    {
        #pragma unroll
        for (int j = 0; j < 4; j++) {
            int f = tid + j * 128;
            int r = f >> 3, c = f & 7;
            uint32_t so = (uint32_t)(r * AROWB + c * 16);
            CPA16(sb + A_K0 + so, (const char*)(k_g + r * 64 + c * 8));
            CPA16(sb + A_V0 + so, (const char*)(v_g + r * 64 + c * 8));
        }
        CPA_COMMIT();
    }

    const int NT = SEQ / 64;
    for (int t = 0; t < NT; t++) {
        int s = t & 1;
        if (t + 1 < NT) {
            int nxt = s ^ 1;
            size_t goff = (size_t)(t + 1) * 64 * 64;
            #pragma unroll
            for (int j = 0; j < 4; j++) {
                int f = tid + j * 128;
                int r = f >> 3, c = f & 7;
                uint32_t so = (uint32_t)(r * AROWB + c * 16);
                CPA16(sb + A_K0 + nxt * 9216 + so, (const char*)(k_g + goff + r * 64 + c * 8));
                CPA16(sb + A_V0 + nxt * 9216 + so, (const char*)(v_g + goff + r * 64 + c * 8));
            }
            CPA_COMMIT();
            CPA_WAIT(1);
        } else {
            CPA_WAIT(0);
        }
        __syncthreads();

        uint32_t kbse = sb + A_K0 + s * 9216;
        uint32_t vbse = sb + A_V0 + s * 9216;

        float sc[8][4];
        #pragma unroll
        for (int j = 0; j < 8; j++)
            #pragma unroll
            for (int r = 0; r < 4; r++) sc[j][r] = 0.f;

        uint32_t b_off = (uint32_t)((lane & 7) + ((lane >> 4) & 1) * 8) * AROWB +
                         ((lane >> 3) & 1) * 16;
        #pragma unroll
        for (int ks = 0; ks < 4; ks++) {
            #pragma unroll
            for (int ng = 0; ng < 4; ng++) {
                uint32_t bh0, bh1, bh2, bh3;
                uint32_t ad = b_off + (uint32_t)ng * (16 * AROWB) + ks * 32;
                ldmx4(kbse + ad, bh0, bh1, bh2, bh3);
                mma16816h(sc[2 * ng],     qf[ks][0], qf[ks][1], qf[ks][2], qf[ks][3], bh0, bh1);
                mma16816h(sc[2 * ng + 1], qf[ks][0], qf[ks][1], qf[ks][2], qf[ks][3], bh2, bh3);
            }
        }

        float mn0 = m0, mn1 = m1;
        #pragma unroll
        for (int j = 0; j < 8; j++) {
            mn0 = fmaxf(mn0, fmaxf(sc[j][0], sc[j][1]));
            mn1 = fmaxf(mn1, fmaxf(sc[j][2], sc[j][3]));
        }
        mn0 = fmaxf(mn0, __shfl_xor_sync(0xffffffffu, mn0, 1));
        mn0 = fmaxf(mn0, __shfl_xor_sync(0xffffffffu, mn0, 2));
        mn1 = fmaxf(mn1, __shfl_xor_sync(0xffffffffu, mn1, 1));
        mn1 = fmaxf(mn1, __shfl_xor_sync(0xffffffffu, mn1, 2));
        float corr0 = ex2f(m0 - mn0);
        float corr1 = ex2f(m1 - mn1);
        m0 = mn0; m1 = mn1;
        l0 *= corr0; l1 *= corr1;
        #pragma unroll
        for (int j = 0; j < 8; j++) {
            ctx[j][0] *= corr0; ctx[j][1] *= corr0;
            ctx[j][2] *= corr1; ctx[j][3] *= corr1;
        }
        uint32_t pa[8], pb[8];
        #pragma unroll
        for (int j = 0; j < 8; j++) {
            float p0 = ex2f(sc[j][0] - mn0);
            float p1 = ex2f(sc[j][1] - mn0);
            float p2 = ex2f(sc[j][2] - mn1);
            float p3 = ex2f(sc[j][3] - mn1);
            l0 += p0 + p1; l1 += p2 + p3;
            __half2 t0 = __floats2half2_rn(p0, p1);
            __half2 t1 = __floats2half2_rn(p2, p3);
            pa[j] = *(uint32_t*)&t0;
            pb[j] = *(uint32_t*)&t1;
        }

        uint32_t v_off = (uint32_t)(lane & 15) * AROWB + ((lane >> 4) & 1) * 16;
        #pragma unroll
        for (int ks = 0; ks < 4; ks++) {
            #pragma unroll
            for (int nd = 0; nd < 4; nd++) {
                uint32_t r0, r1, r2, r3;
                ldmx4t(vbse + v_off + (uint32_t)ks * (16 * AROWB) + nd * 32, r0, r1, r2, r3);
                mma16816h(ctx[nd * 2],     pa[2 * ks], pb[2 * ks], pa[2 * ks + 1], pb[2 * ks + 1], r0, r1);
                mma16816h(ctx[nd * 2 + 1], pa[2 * ks], pb[2 * ks], pa[2 * ks + 1], pb[2 * ks + 1], r2, r3);
            }
        }
        __syncthreads();
    }

    l0 += __shfl_xor_sync(0xffffffffu, l0, 1);
    l0 += __shfl_xor_sync(0xffffffffu, l0, 2);
    l1 += __shfl_xor_sync(0xffffffffu, l1, 1);
    l1 += __shfl_xor_sync(0xffffffffu, l1, 2);
    float i0 = 1.f / l0, i1 = 1.f / l1;

    int tr = lane >> 2, tc = (lane & 3) * 2;
    int row0 = q0 + wid * 16 + tr;
    #pragma unroll
    for (int f = 0; f < 8; f++) {
        int d = f * 8 + tc;
        float* c = ctx[f];
        size_t o0 = ((size_t)b * SEQ + row0) * DIM + (size_t)h * HDIM + d;
        size_t o1 = ((size_t)b * SEQ + row0 + 8) * DIM + (size_t)h * HDIM + d;
        __half2 h0 = __floats2half2_rn(c[0] * i0, c[1] * i0);
        __half2 h1 = __floats2half2_rn(c[2] * i1, c[3] * i1);
        *(__half2*)(O16 + o0) = h0;
        *(__half2*)(O16 + o1) = h1;
    }
}

// ---------------- launch ----------------
extern "C" void kernel_launch(void* const* d_in, const int* in_sizes, int n_in,
                              void* d_out, int out_size) {
    const float* x_in   = (const float*)d_in[0];
    const float* Wq     = (const float*)d_in[1];
    const float* Wk     = (const float*)d_in[2];
    const float* Wv     = (const float*)d_in[3];
    const float* Wo     = (const float*)d_in[4];
    const float* ln1_w  = (const float*)d_in[5];
    const float* ln2_w  = (const float*)d_in[6];
    const float* Wgate  = (const float*)d_in[7];
    const float* Wup    = (const float*)d_in[8];
    const float* Wdown  = (const float*)d_in[9];
    const float* W_out  = (const float*)d_in[10];
    const float* b_out  = (const float*)d_in[11];
    float* out = (float*)d_out;

    float *x;
    __half *qkv16, *h16, *c16, *f116, *x16, *whi, *wlo;
    __half *q16a, *k16, *v16;
    cudaGetSymbolAddress((void**)&x,     g_x);
    cudaGetSymbolAddress((void**)&qkv16, g_qkv16);
    cudaGetSymbolAddress((void**)&h16,   g_h16);
    cudaGetSymbolAddress((void**)&c16,   g_c16);
    cudaGetSymbolAddress((void**)&f116,  g_f116);
    cudaGetSymbolAddress((void**)&x16,   g_x16);
    cudaGetSymbolAddress((void**)&whi,   g_whi);
    cudaGetSymbolAddress((void**)&wlo,   g_wlo);
    cudaGetSymbolAddress((void**)&q16a,  g_q16a);
    cudaGetSymbolAddress((void**)&k16,   g_k16);
    cudaGetSymbolAddress((void**)&v16,   g_v16);

    cudaFuncSetAttribute(gemm_s,   cudaFuncAttributeMaxDynamicSharedMemorySize, SMEM2);
    cudaFuncSetAttribute(attn_mma, cudaFuncAttributeMaxDynamicSharedMemorySize, ASMEM);

    // --- all weight converts in one launch ---
    wcvt_all<<<13312, 256>>>(Wq, Wk, Wv, Wo, Wgate, Wup, Wdown, W_out, whi, wlo);

    // --- attention block ---
    rmsnorm_kernel<<<ROWS, 256>>>(x_in, ln1_w, h16);

    dim3 gqkv(3 * DIM / SBN, ROWS / SBM);   // (24, 64)
    gemm_s<<<gqkv, 256, SMEM2>>>(h16, whi + WOFF_Q, nullptr,
                                 nullptr, nullptr,
                                 nullptr, qkv16, nullptr, ROWS, 3 * DIM, DIM);

    int rope_total = BATCH * SEQ * NHEAD * (HDIM / 2);
    rope_v_cvt_kernel<<<(rope_total + 255) / 256, 256>>>(qkv16, q16a, k16, v16);

    dim3 ga(SEQ / 64, NHEAD, BATCH);
    attn_mma<<<ga, 128, ASMEM>>>(q16a, k16, v16, c16);

    dim3 g1(DIM / SBN, ROWS / SBM);    // (8, 64)
    // x = x_in + ctx @ Wo^T -> g_x (fp32)
    gemm_s<<<g1, 256, SMEM2>>>(c16, whi + WOFF_O, nullptr,
                               x_in, nullptr,
                               x, nullptr, nullptr, ROWS, DIM, DIM);

    // --- MLP block ---
    rmsnorm_kernel<<<ROWS, 256>>>(x, ln2_w, h16);
    dim3 ggu(2 * FFDIM / SBN, ROWS / SBM); // (64, 64)
    gemm_s<<<ggu, 256, SMEM2>>>(h16, whi + WOFF_GU, nullptr,
                                nullptr, nullptr,
                                nullptr, nullptr, f116, ROWS, 2 * FFDIM, DIM);

    // x_new = x + f1 @ Wdown^T -> fp16 (feeds head GEMM)
    gemm_s<<<g1, 256, SMEM2>>>(f116, whi + WOFF_D, nullptr,
                               x, nullptr,
                               nullptr, x16, nullptr, ROWS, DIM, FFDIM);

    // --- output head (2-term: W_out hi+lo) ---
    gemm_s<<<g1, 256, SMEM2>>>(x16, whi + WOFF_H, wlo,
                               nullptr, b_out,
                               out, nullptr, nullptr, ROWS, DIM, DIM);
}

// round 16
// speedup vs baseline: 9.1661x; 1.0577x over previous
#include <cuda_runtime.h>
#include <cuda_bf16.h>
#include <cuda_fp16.h>
#include <cstdint>

// Problem constants
#define BATCH 4
#define SEQ   2048
#define DIM   1024
#define NHEAD 16
#define HDIM  64
#define FFDIM 4096
#define ROWS  (BATCH * SEQ)            // 8192
#define LN_EPS 1e-6f

// ---------------- scratch (device globals; no allocation) ----------------
__device__ float g_x  [(size_t)ROWS * DIM];
__device__ __half g_qkv16[(size_t)ROWS * 3 * DIM];
// fp16 single activation operands (GEMM A inputs)
__device__ __half g_h16 [(size_t)ROWS * DIM];
__device__ __half g_c16 [(size_t)ROWS * DIM];
__device__ __half g_f116[(size_t)ROWS * FFDIM];
__device__ __half g_x16 [(size_t)ROWS * DIM];
// fp16 weights: Wq|Wk|Wv|Wo|WgateUp(interleaved)|Wdown|W_out
#define WOFF_Q  0
#define WOFF_K  1048576
#define WOFF_V  2097152
#define WOFF_O  3145728
#define WOFF_GU 4194304
#define WOFF_D  12582912
#define WOFF_H  16777216
#define WTOT    17825792
__device__ __half g_whi[(size_t)WTOT];
// fp16 attention operands, [B,H,S,HD] layout
__device__ __half g_q16a[(size_t)ROWS * DIM];
__device__ __half g_k16 [(size_t)ROWS * DIM];
__device__ __half g_v16 [(size_t)ROWS * DIM];

__device__ __forceinline__ uint32_t smem_u32(const void* p) {
    uint32_t a;
    asm("{ .reg .u64 t; cvta.to.shared.u64 t, %1; cvt.u32.u64 %0, t; }"
        : "=r"(a) : "l"(p));
    return a;
}
__device__ __forceinline__ void ldmx4(uint32_t addr, uint32_t& r0, uint32_t& r1,
                                      uint32_t& r2, uint32_t& r3) {
    asm volatile("ldmatrix.sync.aligned.m8n8.x4.shared.b16 {%0,%1,%2,%3}, [%4];"
                 : "=r"(r0), "=r"(r1), "=r"(r2), "=r"(r3) : "r"(addr));
}
__device__ __forceinline__ void ldmx4t(uint32_t addr, uint32_t& r0, uint32_t& r1,
                                       uint32_t& r2, uint32_t& r3) {
    asm volatile("ldmatrix.sync.aligned.m8n8.x4.trans.shared.b16 {%0,%1,%2,%3}, [%4];"
                 : "=r"(r0), "=r"(r1), "=r"(r2), "=r"(r3) : "r"(addr));
}
__device__ __forceinline__ void mma16816h(float* c, uint32_t a0, uint32_t a1,
                                          uint32_t a2, uint32_t a3,
                                          uint32_t b0, uint32_t b1) {
    asm volatile(
        "mma.sync.aligned.m16n8k16.row.col.f32.f16.f16.f32 "
        "{%0,%1,%2,%3}, {%4,%5,%6,%7}, {%8,%9}, {%0,%1,%2,%3};"
        : "+f"(c[0]), "+f"(c[1]), "+f"(c[2]), "+f"(c[3])
        : "r"(a0), "r"(a1), "r"(a2), "r"(a3), "r"(b0), "r"(b1));
}
__device__ __forceinline__ float ex2f(float x) {
    float r;
    asm("ex2.approx.f32 %0, %1;" : "=f"(r) : "f"(x));
    return r;
}
#define CPA16(dst, src) \
    asm volatile("cp.async.cg.shared.global [%0], [%1], 16;" :: "r"(dst), "l"(src))
#define CPA_COMMIT() asm volatile("cp.async.commit_group;" ::: "memory")
#define CPA_WAIT(n)  asm volatile("cp.async.wait_group %0;" :: "n"(n) : "memory")

// ---- merged weight convert: all weights in ONE launch (block-segmented) ---
__global__ void wcvt_all(const float* __restrict__ Wq, const float* __restrict__ Wk,
                         const float* __restrict__ Wv, const float* __restrict__ Wo,
                         const float* __restrict__ Wg, const float* __restrict__ Wu,
                         const float* __restrict__ Wd, const float* __restrict__ Wh,
                         __half* __restrict__ whi) {
    int blk = blockIdx.x;
    int tid = threadIdx.x;
    if (blk < 4096) {                       // Q,K,V,O
        int seg = blk >> 10;
        int t = (blk & 1023) * 256 + tid;
        const float* src = (seg == 0) ? Wq : (seg == 1) ? Wk : (seg == 2) ? Wv : Wo;
        __half* dst = whi + (size_t)seg * 1048576;
        float4 v = *(const float4*)(src + (size_t)t * 4);
        __half2 h0 = __floats2half2_rn(v.x, v.y), h1 = __floats2half2_rn(v.z, v.w);
        uint2 o = { *(uint32_t*)&h0, *(uint32_t*)&h1 };
        *(uint2*)(dst + (size_t)t * 4) = o;
    } else if (blk < 8192) {                // gate/up interleaved
        int t = (blk - 4096) * 256 + tid;
        int r = t >> 8, c4 = t & 255;
        float4 vg = *(const float4*)(Wg + (size_t)t * 4);
        float4 vu = *(const float4*)(Wu + (size_t)t * 4);
        __half2 g0 = __floats2half2_rn(vg.x, vg.y), g1 = __floats2half2_rn(vg.z, vg.w);
        __half2 u0 = __floats2half2_rn(vu.x, vu.y), u1 = __floats2half2_rn(vu.z, vu.w);
        uint2 go = { *(uint32_t*)&g0, *(uint32_t*)&g1 };
        uint2 uo = { *(uint32_t*)&u0, *(uint32_t*)&u1 };
        *(uint2*)(whi + WOFF_GU + (size_t)(2 * r) * DIM + c4 * 4)     = go;
        *(uint2*)(whi + WOFF_GU + (size_t)(2 * r + 1) * DIM + c4 * 4) = uo;
    } else if (blk < 12288) {               // Wdown
        int t = (blk - 8192) * 256 + tid;
        float4 v = *(const float4*)(Wd + (size_t)t * 4);
        __half2 h0 = __floats2half2_rn(v.x, v.y), h1 = __floats2half2_rn(v.z, v.w);
        uint2 o = { *(uint32_t*)&h0, *(uint32_t*)&h1 };
        *(uint2*)(whi + WOFF_D + (size_t)t * 4) = o;
    } else {                                // W_out
        int t = (blk - 12288) * 256 + tid;
        float4 v = *(const float4*)(Wh + (size_t)t * 4);
        __half2 h0 = __floats2half2_rn(v.x, v.y), h1 = __floats2half2_rn(v.z, v.w);
        uint2 o = { *(uint32_t*)&h0, *(uint32_t*)&h1 };
        *(uint2*)(whi + WOFF_H + (size_t)t * 4) = o;
    }
}

// ================= gemm_s: single-term fp16 GEMM ===========================
// C[M,N] = A[M,K] @ W[N,K]^T ; outputs fp32 C / fp16 C16 / silu-fused GU.
// Tile 128x128, BK=64, 3-stage cp.async (32KB stage), SW64 swizzle,
// single __syncthreads per K-chunk, wait_group 1, 2 CTAs/SM.
#define SBM 128
#define SBN 128
#define SBK 64
#define S_W   16384
#define SSTG  32768
#define SMEM3 (3 * SSTG)       // 98304 -> 2 CTAs/SM

__global__ __launch_bounds__(256, 2)
void gemm_s(const __half* __restrict__ A, const __half* __restrict__ W,
            const float* __restrict__ res, const float* __restrict__ bias,
            float* __restrict__ C, __half* __restrict__ C16,
            __half* __restrict__ GU,
            int M, int N, int K) {
    extern __shared__ char smem[];
    uint32_t sb = smem_u32(smem);
    int tid = threadIdx.x, wid = tid >> 5, lane = tid & 31;
    int bm = blockIdx.y * SBM, bn = blockIdx.x * SBN;
    int warp_m = (wid >> 2) * 64, warp_n = (wid & 3) * 32;

    uint32_t strow = (uint32_t)(tid >> 2);
    uint32_t stc   = (uint32_t)(tid & 3) * 16;
    uint32_t st_off = strow * 64 + (stc ^ (((strow >> 1) & 3u) << 4));
    const __half* Ap = A + (size_t)(bm + strow) * K + (tid & 3) * 8;
    const __half* Wp = W + (size_t)(bn + strow) * K + (tid & 3) * 8;

    auto load_stage = [&](int s, int chunk) {
        uint32_t base = sb + (uint32_t)s * SSTG;
        size_t ko = (size_t)chunk * SBK;
        #pragma unroll
        for (int sub = 0; sub < 2; sub++) {
            #pragma unroll
            for (int j = 0; j < 2; j++) {
                uint32_t d = base + sub * 8192 + st_off + j * 4096;
                size_t ro = (size_t)j * 64 * K + ko + sub * 32;
                CPA16(d,       (const char*)(Ap + ro));
                CPA16(d + S_W, (const char*)(Wp + ro));
            }
        }
    };

    int ra = warp_m + (lane & 15);
    uint32_t a_row = (uint32_t)ra * 64;
    uint32_t swa = (((uint32_t)ra >> 1) & 3u) << 4;
    int rb = warp_n + (lane & 7) + ((lane >> 4) & 1) * 8;
    uint32_t b_row = (uint32_t)rb * 64;
    uint32_t swb = (((uint32_t)rb >> 1) & 3u) << 4;
    uint32_t col_a[2], col_b[2];
    int ha = ((lane >> 4) & 1) * 16;
    int hb = ((lane >> 3) & 1) * 16;
    #pragma unroll
    for (int ks = 0; ks < 2; ks++) {
        col_a[ks] = ((uint32_t)(ks * 32 + ha)) ^ swa;
        col_b[ks] = ((uint32_t)(ks * 32 + hb)) ^ swb;
    }

    float acc[4][4][4];
    #pragma unroll
    for (int i = 0; i < 4; i++)
        #pragma unroll
        for (int j = 0; j < 4; j++)
            #pragma unroll
            for (int r = 0; r < 4; r++) acc[i][j][r] = 0.f;

    const int nk = K / SBK;
    load_stage(0, 0);
    CPA_COMMIT();
    if (nk > 1) { load_stage(1, 1); CPA_COMMIT(); }

    int sc = 0;
    for (int i = 0; i < nk; i++) {
        if (i + 1 < nk) { CPA_WAIT(1); } else { CPA_WAIT(0); }
        __syncthreads();
        if (i + 2 < nk) {
            int snx = sc + 2; if (snx >= 3) snx -= 3;
            load_stage(snx, i + 2);
            CPA_COMMIT();
        }

        uint32_t base = sb + (uint32_t)sc * SSTG;
        #pragma unroll
        for (int ks = 0; ks < 4; ks++) {
            uint32_t soff = (uint32_t)(ks >> 1) * 8192;
            uint32_t ca = col_a[ks & 1], cb = col_b[ks & 1];
            uint32_t bhr[2][4];
            #pragma unroll
            for (int np = 0; np < 2; np++) {
                uint32_t bd = base + S_W + soff + b_row + (uint32_t)np * 1024 + cb;
                ldmx4(bd, bhr[np][0], bhr[np][1], bhr[np][2], bhr[np][3]);
            }
            uint32_t ar[4][4];
            #pragma unroll
            for (int mf = 0; mf < 4; mf++) {
                uint32_t ad = base + soff + a_row + (uint32_t)mf * 1024 + ca;
                ldmx4(ad, ar[mf][0], ar[mf][1], ar[mf][2], ar[mf][3]);
            }
            #pragma unroll
            for (int mf = 0; mf < 4; mf++)
                #pragma unroll
                for (int nf = 0; nf < 4; nf++)
                    mma16816h(acc[mf][nf],
                              ar[mf][0], ar[mf][1], ar[mf][2], ar[mf][3],
                              bhr[nf >> 1][(nf & 1) * 2], bhr[nf >> 1][(nf & 1) * 2 + 1]);
        }
        sc = (sc == 2) ? 0 : sc + 1;
    }

    // ---- epilogue ----
    int tr = lane >> 2, tc = (lane & 3) * 2;
    #pragma unroll
    for (int mf = 0; mf < 4; mf++) {
        #pragma unroll
        for (int nf = 0; nf < 4; nf++) {
            int row0 = bm + warp_m + mf * 16 + tr;
            int col  = bn + warp_n + nf * 8 + tc;
            float* c = acc[mf][nf];
            float v[4] = {c[0], c[1], c[2], c[3]};
            size_t o0 = (size_t)row0 * N + col;
            size_t o1 = (size_t)(row0 + 8) * N + col;
            if (GU) {
                float r0 = v[1] * (v[0] / (1.f + expf(-v[0])));
                float r1 = v[3] * (v[2] / (1.f + expf(-v[2])));
                size_t p0 = (size_t)row0 * (N / 2) + (col >> 1);
                size_t p1 = (size_t)(row0 + 8) * (N / 2) + (col >> 1);
                GU[p0] = __float2half_rn(r0);
                GU[p1] = __float2half_rn(r1);
                continue;
            }
            if (res) {
                float2 r0 = *(const float2*)(res + o0);
                float2 r1 = *(const float2*)(res + o1);
                v[0] += r0.x; v[1] += r0.y; v[2] += r1.x; v[3] += r1.y;
            }
            if (bias) {
                float2 bb = *(const float2*)(bias + col);
                v[0] += bb.x; v[1] += bb.y; v[2] += bb.x; v[3] += bb.y;
            }
            if (C) {
                *(float2*)(C + o0) = {v[0], v[1]};
                *(float2*)(C + o1) = {v[2], v[3]};
            }
            if (C16) {
                __half2 h0 = __floats2half2_rn(v[0], v[1]);
                __half2 h1 = __floats2half2_rn(v[2], v[3]);
                *(__half2*)(C16 + o0) = h0;
                *(__half2*)(C16 + o1) = h1;
            }
        }
    }
}

// ---------------- RMSNorm -> fp16 ----------------
__global__ void rmsnorm_kernel(const float* __restrict__ x,
                               const float* __restrict__ w,
                               __half* __restrict__ o16) {
    int row = blockIdx.x;
    const float* xr = x + (size_t)row * DIM;
    float s = 0.f;
    #pragma unroll
    for (int i = threadIdx.x; i < DIM; i += 256) {
        float v = xr[i];
        s += v * v;
    }
    __shared__ float red[8];
    #pragma unroll
    for (int o = 16; o; o >>= 1) s += __shfl_down_sync(0xffffffffu, s, o);
    if ((threadIdx.x & 31) == 0) red[threadIdx.x >> 5] = s;
    __syncthreads();
    if (threadIdx.x < 8) {
        float t = red[threadIdx.x];
        #pragma unroll
        for (int o = 4; o; o >>= 1) t += __shfl_down_sync(0xffu, t, o);
        if (threadIdx.x == 0) red[0] = t;
    }
    __syncthreads();
    float inv = rsqrtf(red[0] * (1.0f / DIM) + LN_EPS);
    #pragma unroll
    for (int i = threadIdx.x; i < DIM; i += 256) {
        float v = xr[i] * inv * w[i];
        o16[(size_t)row * DIM + i] = __float2half_rn(v);
    }
}

// ------ RoPE + V convert on fp16 qkv [rows,3072] -> fp16 [B,H,S,HD] --------
#define QSCALE 0.18033688011111793f   // 0.125 * log2(e)
__global__ void rope_v_cvt_kernel(const __half* __restrict__ QKV,
                                  __half* __restrict__ q16,
                                  __half* __restrict__ k16,
                                  __half* __restrict__ v16) {
    int idx = blockIdx.x * 256 + threadIdx.x;
    if (idx >= BATCH * SEQ * NHEAD * (HDIM / 2)) return;
    int d = idx & 31;
    int h = (idx >> 5) & (NHEAD - 1);
    int s = (idx >> 9) & (SEQ - 1);
    int b = idx >> 20;
    size_t ibase = ((size_t)b * SEQ + s) * (3 * DIM) + (size_t)h * HDIM;
    size_t obase = (((size_t)b * NHEAD + h) * SEQ + s) * HDIM;
    float inv = expf(-(float)d * (9.210340371976184f / 32.f));
    float ang = (float)s * inv;
    float sn, cs;
    sincosf(ang, &sn, &cs);
    {
        float x1 = __half2float(QKV[ibase + d]);
        float x2 = __half2float(QKV[ibase + d + 32]);
        float r1 = (x1 * cs - x2 * sn) * QSCALE;
        float r2 = (x2 * cs + x1 * sn) * QSCALE;
        q16[obase + d]      = __float2half_rn(r1);
        q16[obase + d + 32] = __float2half_rn(r2);
    }
    {
        float x1 = __half2float(QKV[ibase + DIM + d]);
        float x2 = __half2float(QKV[ibase + DIM + d + 32]);
        float r1 = x1 * cs - x2 * sn;
        float r2 = x2 * cs + x1 * sn;
        k16[obase + d]      = __float2half_rn(r1);
        k16[obase + d + 32] = __float2half_rn(r2);
    }
    {
        v16[obase + d]      = QKV[ibase + 2 * DIM + d];
        v16[obase + d + 32] = QKV[ibase + 2 * DIM + d + 32];
    }
}

// ============ MMA flash attention (all fp16, single-term QK) ===============
#define AROWB 144
#define A_Q   0
#define A_K0  9216
#define A_V0  27648
#define ASMEM 46080

__global__ __launch_bounds__(128)
void attn_mma(const __half* __restrict__ q16,
              const __half* __restrict__ k16,
              const __half* __restrict__ v16,
              __half* __restrict__ O16) {
    extern __shared__ char smem[];
    uint32_t sb = smem_u32(smem);
    int tid = threadIdx.x, wid = tid >> 5, lane = tid & 31;
    int b = blockIdx.z, h = blockIdx.y;
    int q0 = blockIdx.x * 64;
    size_t hoff = ((size_t)b * NHEAD + h) * SEQ * HDIM;

    {
        const uint4* q4 = (const uint4*)(q16 + hoff + (size_t)q0 * HDIM);
        #pragma unroll
        for (int j = 0; j < 4; j++) {
            int f = tid + j * 128;
            int r = f >> 3, c = f & 7;
            *(uint4*)(smem + A_Q + r * AROWB + c * 16) = q4[r * 8 + c];
        }
    }
    __syncthreads();

    uint32_t qf[4][4];
    {
        uint32_t a_base = sb + (uint32_t)(wid * 16 + (lane & 15)) * AROWB + ((lane >> 4) & 1) * 16;
        #pragma unroll
        for (int ks = 0; ks < 4; ks++)
            ldmx4(a_base + ks * 32, qf[ks][0], qf[ks][1], qf[ks][2], qf[ks][3]);
    }

    float ctx[8][4];
    #pragma unroll
    for (int j = 0; j < 8; j++)
        #pragma unroll
        for (int r = 0; r < 4; r++) ctx[j][r] = 0.f;
    float m0 = -1e30f, m1 = -1e30f, l0 = 0.f, l1 = 0.f;

    const __half* k_g = k16 + hoff;
    const __half* v_g = v16 + hoff;

    {
        #pragma unroll
        for (int j = 0; j < 4; j++) {
            int f = tid + j * 128;
            int r = f >> 3, c = f & 7;
            uint32_t so = (uint32_t)(r * AROWB + c * 16);
            CPA16(sb + A_K0 + so, (const char*)(k_g + r * 64 + c * 8));
            CPA16(sb + A_V0 + so, (const char*)(v_g + r * 64 + c * 8));
        }
        CPA_COMMIT();
    }

    const int NT = SEQ / 64;
    for (int t = 0; t < NT; t++) {
        int s = t & 1;
        if (t + 1 < NT) {
            int nxt = s ^ 1;
            size_t goff = (size_t)(t + 1) * 64 * 64;
            #pragma unroll
            for (int j = 0; j < 4; j++) {
                int f = tid + j * 128;
                int r = f >> 3, c = f & 7;
                uint32_t so = (uint32_t)(r * AROWB + c * 16);
                CPA16(sb + A_K0 + nxt * 9216 + so, (const char*)(k_g + goff + r * 64 + c * 8));
                CPA16(sb + A_V0 + nxt * 9216 + so, (const char*)(v_g + goff + r * 64 + c * 8));
            }
            CPA_COMMIT();
            CPA_WAIT(1);
        } else {
            CPA_WAIT(0);
        }
        __syncthreads();

        uint32_t kbse = sb + A_K0 + s * 9216;
        uint32_t vbse = sb + A_V0 + s * 9216;

        float sc[8][4];
        #pragma unroll
        for (int j = 0; j < 8; j++)
            #pragma unroll
            for (int r = 0; r < 4; r++) sc[j][r] = 0.f;

        uint32_t b_off = (uint32_t)((lane & 7) + ((lane >> 4) & 1) * 8) * AROWB +
                         ((lane >> 3) & 1) * 16;
        #pragma unroll
        for (int ks = 0; ks < 4; ks++) {
            #pragma unroll
            for (int ng = 0; ng < 4; ng++) {
                uint32_t bh0, bh1, bh2, bh3;
                uint32_t ad = b_off + (uint32_t)ng * (16 * AROWB) + ks * 32;
                ldmx4(kbse + ad, bh0, bh1, bh2, bh3);
                mma16816h(sc[2 * ng],     qf[ks][0], qf[ks][1], qf[ks][2], qf[ks][3], bh0, bh1);
                mma16816h(sc[2 * ng + 1], qf[ks][0], qf[ks][1], qf[ks][2], qf[ks][3], bh2, bh3);
            }
        }

        float mn0 = m0, mn1 = m1;
        #pragma unroll
        for (int j = 0; j < 8; j++) {
            mn0 = fmaxf(mn0, fmaxf(sc[j][0], sc[j][1]));
            mn1 = fmaxf(mn1, fmaxf(sc[j][2], sc[j][3]));
        }
        mn0 = fmaxf(mn0, __shfl_xor_sync(0xffffffffu, mn0, 1));
        mn0 = fmaxf(mn0, __shfl_xor_sync(0xffffffffu, mn0, 2));
        mn1 = fmaxf(mn1, __shfl_xor_sync(0xffffffffu, mn1, 1));
        mn1 = fmaxf(mn1, __shfl_xor_sync(0xffffffffu, mn1, 2));
        float corr0 = ex2f(m0 - mn0);
        float corr1 = ex2f(m1 - mn1);
        m0 = mn0; m1 = mn1;
        l0 *= corr0; l1 *= corr1;
        #pragma unroll
        for (int j = 0; j < 8; j++) {
            ctx[j][0] *= corr0; ctx[j][1] *= corr0;
            ctx[j][2] *= corr1; ctx[j][3] *= corr1;
        }
        uint32_t pa[8], pb[8];
        #pragma unroll
        for (int j = 0; j < 8; j++) {
            float p0 = ex2f(sc[j][0] - mn0);
            float p1 = ex2f(sc[j][1] - mn0);
            float p2 = ex2f(sc[j][2] - mn1);
            float p3 = ex2f(sc[j][3] - mn1);
            l0 += p0 + p1; l1 += p2 + p3;
            __half2 t0 = __floats2half2_rn(p0, p1);
            __half2 t1 = __floats2half2_rn(p2, p3);
            pa[j] = *(uint32_t*)&t0;
            pb[j] = *(uint32_t*)&t1;
        }

        uint32_t v_off = (uint32_t)(lane & 15) * AROWB + ((lane >> 4) & 1) * 16;
        #pragma unroll
        for (int ks = 0; ks < 4; ks++) {
            #pragma unroll
            for (int nd = 0; nd < 4; nd++) {
                uint32_t r0, r1, r2, r3;
                ldmx4t(vbse + v_off + (uint32_t)ks * (16 * AROWB) + nd * 32, r0, r1, r2, r3);
                mma16816h(ctx[nd * 2],     pa[2 * ks], pb[2 * ks], pa[2 * ks + 1], pb[2 * ks + 1], r0, r1);
                mma16816h(ctx[nd * 2 + 1], pa[2 * ks], pb[2 * ks], pa[2 * ks + 1], pb[2 * ks + 1], r2, r3);
            }
        }
        __syncthreads();
    }

    l0 += __shfl_xor_sync(0xffffffffu, l0, 1);
    l0 += __shfl_xor_sync(0xffffffffu, l0, 2);
    l1 += __shfl_xor_sync(0xffffffffu, l1, 1);
    l1 += __shfl_xor_sync(0xffffffffu, l1, 2);
    float i0 = 1.f / l0, i1 = 1.f / l1;

    int tr = lane >> 2, tc = (lane & 3) * 2;
    int row0 = q0 + wid * 16 + tr;
    #pragma unroll
    for (int f = 0; f < 8; f++) {
        int d = f * 8 + tc;
        float* c = ctx[f];
        size_t o0 = ((size_t)b * SEQ + row0) * DIM + (size_t)h * HDIM + d;
        size_t o1 = ((size_t)b * SEQ + row0 + 8) * DIM + (size_t)h * HDIM + d;
        __half2 h0 = __floats2half2_rn(c[0] * i0, c[1] * i0);
        __half2 h1 = __floats2half2_rn(c[2] * i1, c[3] * i1);
        *(__half2*)(O16 + o0) = h0;
        *(__half2*)(O16 + o1) = h1;
    }
}

// ---------------- launch ----------------
extern "C" void kernel_launch(void* const* d_in, const int* in_sizes, int n_in,
                              void* d_out, int out_size) {
    const float* x_in   = (const float*)d_in[0];
    const float* Wq     = (const float*)d_in[1];
    const float* Wk     = (const float*)d_in[2];
    const float* Wv     = (const float*)d_in[3];
    const float* Wo     = (const float*)d_in[4];
    const float* ln1_w  = (const float*)d_in[5];
    const float* ln2_w  = (const float*)d_in[6];
    const float* Wgate  = (const float*)d_in[7];
    const float* Wup    = (const float*)d_in[8];
    const float* Wdown  = (const float*)d_in[9];
    const float* W_out  = (const float*)d_in[10];
    const float* b_out  = (const float*)d_in[11];
    float* out = (float*)d_out;

    float *x;
    __half *qkv16, *h16, *c16, *f116, *x16, *whi;
    __half *q16a, *k16, *v16;
    cudaGetSymbolAddress((void**)&x,     g_x);
    cudaGetSymbolAddress((void**)&qkv16, g_qkv16);
    cudaGetSymbolAddress((void**)&h16,   g_h16);
    cudaGetSymbolAddress((void**)&c16,   g_c16);
    cudaGetSymbolAddress((void**)&f116,  g_f116);
    cudaGetSymbolAddress((void**)&x16,   g_x16);
    cudaGetSymbolAddress((void**)&whi,   g_whi);
    cudaGetSymbolAddress((void**)&q16a,  g_q16a);
    cudaGetSymbolAddress((void**)&k16,   g_k16);
    cudaGetSymbolAddress((void**)&v16,   g_v16);

    cudaFuncSetAttribute(gemm_s,   cudaFuncAttributeMaxDynamicSharedMemorySize, SMEM3);
    cudaFuncSetAttribute(attn_mma, cudaFuncAttributeMaxDynamicSharedMemorySize, ASMEM);

    // --- all weight converts in one launch ---
    wcvt_all<<<13312, 256>>>(Wq, Wk, Wv, Wo, Wgate, Wup, Wdown, W_out, whi);

    // --- attention block ---
    rmsnorm_kernel<<<ROWS, 256>>>(x_in, ln1_w, h16);

    dim3 gqkv(3 * DIM / SBN, ROWS / SBM);   // (24, 64)
    gemm_s<<<gqkv, 256, SMEM3>>>(h16, whi + WOFF_Q,
                                 nullptr, nullptr,
                                 nullptr, qkv16, nullptr, ROWS, 3 * DIM, DIM);

    int rope_total = BATCH * SEQ * NHEAD * (HDIM / 2);
    rope_v_cvt_kernel<<<(rope_total + 255) / 256, 256>>>(qkv16, q16a, k16, v16);

    dim3 ga(SEQ / 64, NHEAD, BATCH);
    attn_mma<<<ga, 128, ASMEM>>>(q16a, k16, v16, c16);

    dim3 g1(DIM / SBN, ROWS / SBM);    // (8, 64)
    // x = x_in + ctx @ Wo^T -> g_x (fp32)
    gemm_s<<<g1, 256, SMEM3>>>(c16, whi + WOFF_O,
                               x_in, nullptr,
                               x, nullptr, nullptr, ROWS, DIM, DIM);

    // --- MLP block ---
    rmsnorm_kernel<<<ROWS, 256>>>(x, ln2_w, h16);
    dim3 ggu(2 * FFDIM / SBN, ROWS / SBM); // (64, 64)
    gemm_s<<<ggu, 256, SMEM3>>>(h16, whi + WOFF_GU,
                                nullptr, nullptr,
                                nullptr, nullptr, f116, ROWS, 2 * FFDIM, DIM);

    // x_new = x + f1 @ Wdown^T -> fp16 (feeds head GEMM)
    gemm_s<<<g1, 256, SMEM3>>>(f116, whi + WOFF_D,
                               x, nullptr,
                               nullptr, x16, nullptr, ROWS, DIM, FFDIM);

    // --- output head (single-term fp16) ---
    gemm_s<<<g1, 256, SMEM3>>>(x16, whi + WOFF_H,
                               nullptr, b_out,
                               out, nullptr, nullptr, ROWS, DIM, DIM);
}